// round 1
// baseline (speedup 1.0000x reference)
#include <cuda_runtime.h>
#include <cuda_bf16.h>
#include <math.h>

// Problem constants (fixed by the dataset)
#define Bq 512
#define Hh 512
#define Ll 64
#define Vv 1024
#define Tt 46
#define TBq 23552          // T*B
#define PADROW 23552       // zero row index
#define MSr 24064          // TB + B  (stop / pred rows)
#define MAXNB 8

// ---------------- scratch (__device__ globals; no runtime allocation) ----------------
__device__ float g_hbuf[(size_t)(TBq + 1) * Hh];     // 48 MB
__device__ float g_x[Bq * Hh];
__device__ float g_sumh[Bq * Hh];
__device__ float g_zpre[Bq * Hh];
__device__ float g_xr[Bq * Hh];
__device__ float g_hpre[Bq * Hh];
__device__ float g_cat[(size_t)Bq * 2 * Hh];
__device__ float g_cat2[(size_t)Bq * 2 * Hh];
__device__ float g_hnei[(size_t)Bq * MAXNB * Hh];    // 8 MB
__device__ float g_gg[(size_t)Bq * MAXNB * Hh];      // 8 MB
__device__ float g_srows[(size_t)MSr * (2 * Hh + Ll)];   // 105 MB
__device__ float g_shid[(size_t)MSr * Hh];               // 49 MB
__device__ float g_prows[(size_t)MSr * (Hh + Ll)];       // 55 MB
__device__ float g_phid[(size_t)MSr * Hh];               // 49 MB
__device__ float g_logits[(size_t)MSr * Vv];             // 99 MB
__device__ double g_acc[5]; // 0 stop_loss, 1 stop_correct, 2 pred_loss, 3 pred_correct*mask, 4 mask_sum

// ---------------- generic tiled SGEMM: C = act(A @ B + bias) ----------------
// A: MxK row-major, B: KxN row-major, C: MxN row-major.
// Requires M%64==0, N%64==0, K%16==0 (all shapes here satisfy this).
#define BM 64
#define BN 64
#define BK 16

__global__ __launch_bounds__(256)
void sgemm_kernel(int M, int N, int K,
                  const float* __restrict__ A, const float* __restrict__ Bm,
                  const float* __restrict__ bias, float* __restrict__ C, int act)
{
    __shared__ float As[BK][BM];
    __shared__ float Bs[BK][BN];
    const int tid = threadIdx.x;            // 0..255
    const int tx = tid & 15;
    const int ty = tid >> 4;
    const int m0 = blockIdx.y * BM;
    const int n0 = blockIdx.x * BN;

    const int a_row  = tid >> 2;            // 0..63
    const int a_col4 = (tid & 3) << 2;      // 0,4,8,12
    const int b_row  = tid >> 4;            // 0..15
    const int b_col4 = (tid & 15) << 2;     // 0..60

    const float* Aptr = A + (size_t)(m0 + a_row) * K + a_col4;
    const float* Bptr = Bm + (size_t)b_row * N + n0 + b_col4;

    float acc[4][4];
    #pragma unroll
    for (int i = 0; i < 4; i++)
        #pragma unroll
        for (int j = 0; j < 4; j++) acc[i][j] = 0.f;

    for (int k0 = 0; k0 < K; k0 += BK) {
        float4 av = *(const float4*)(Aptr + k0);
        float4 bv = *(const float4*)(Bptr + (size_t)k0 * N);
        As[a_col4 + 0][a_row] = av.x;
        As[a_col4 + 1][a_row] = av.y;
        As[a_col4 + 2][a_row] = av.z;
        As[a_col4 + 3][a_row] = av.w;
        *(float4*)&Bs[b_row][b_col4] = bv;
        __syncthreads();
        #pragma unroll
        for (int k = 0; k < BK; k++) {
            float4 a4 = *(const float4*)&As[k][ty << 2];
            float4 b4 = *(const float4*)&Bs[k][tx << 2];
            float a[4] = {a4.x, a4.y, a4.z, a4.w};
            float b[4] = {b4.x, b4.y, b4.z, b4.w};
            #pragma unroll
            for (int i = 0; i < 4; i++)
                #pragma unroll
                for (int j = 0; j < 4; j++) acc[i][j] = fmaf(a[i], b[j], acc[i][j]);
        }
        __syncthreads();
    }

    #pragma unroll
    for (int i = 0; i < 4; i++) {
        int row = m0 + (ty << 2) + i;
        int col = n0 + (tx << 2);
        float4 out;
        float b0 = bias ? bias[col + 0] : 0.f;
        float b1 = bias ? bias[col + 1] : 0.f;
        float b2 = bias ? bias[col + 2] : 0.f;
        float b3 = bias ? bias[col + 3] : 0.f;
        out.x = acc[i][0] + b0; out.y = acc[i][1] + b1;
        out.z = acc[i][2] + b2; out.w = acc[i][3] + b3;
        if (act) {
            out.x = fmaxf(out.x, 0.f); out.y = fmaxf(out.y, 0.f);
            out.z = fmaxf(out.z, 0.f); out.w = fmaxf(out.w, 0.f);
        }
        *(float4*)&C[(size_t)row * N + col] = out;
    }
}

// ---------------- housekeeping ----------------
__global__ void zero_kernel()
{
    int tid = threadIdx.x;
    if (tid < 5) g_acc[tid] = 0.0;
    for (int h = tid; h < Hh; h += blockDim.x)
        g_hbuf[(size_t)PADROW * Hh + h] = 0.f;
}

// ---------------- GRU step kernels ----------------
__global__ __launch_bounds__(Hh)
void gru_gather(int t, const float* __restrict__ emb, const int* __restrict__ wid,
                const int* __restrict__ hni)
{
    int b = blockIdx.x, h = threadIdx.x;
    __shared__ int ids[MAXNB];
    __shared__ int w;
    if (h < MAXNB) ids[h] = hni[((size_t)(t * Bq + b)) * MAXNB + h];
    if (h == MAXNB) w = wid[t * Bq + b];
    __syncthreads();
    float x = emb[(size_t)w * Hh + h];
    g_x[b * Hh + h] = x;
    g_cat[(size_t)b * 2 * Hh + h] = x;
    float s = 0.f;
    #pragma unroll
    for (int n = 0; n < MAXNB; n++) {
        float v = g_hbuf[(size_t)ids[n] * Hh + h];
        g_hnei[((size_t)b * MAXNB + n) * Hh + h] = v;
        s += v;
    }
    g_sumh[b * Hh + h] = s;
    g_cat[(size_t)b * 2 * Hh + Hh + h] = s;
}

__global__ __launch_bounds__(Hh)
void gru_mid()
{
    int b = blockIdx.x, k = threadIdx.x;
    float xr = g_xr[b * Hh + k];
    float sg = 0.f;
    #pragma unroll
    for (int n = 0; n < MAXNB; n++) {
        float gpre = xr + g_gg[((size_t)b * MAXNB + n) * Hh + k];
        float r = 1.f / (1.f + expf(-gpre));
        sg += r * g_hnei[((size_t)b * MAXNB + n) * Hh + k];
    }
    g_cat2[(size_t)b * 2 * Hh + k] = g_x[b * Hh + k];
    g_cat2[(size_t)b * 2 * Hh + Hh + k] = sg;
}

__global__ __launch_bounds__(Hh)
void gru_final(int t)
{
    int b = blockIdx.x, k = threadIdx.x;
    float z = 1.f / (1.f + expf(-g_zpre[b * Hh + k]));
    float ht = tanhf(g_hpre[b * Hh + k]);
    g_hbuf[((size_t)(t * Bq + b)) * Hh + k] = (1.f - z) * g_sumh[b * Hh + k] + z * ht;
}

// ---------------- post-scan row builders ----------------
__global__ __launch_bounds__(256)
void build_srows(const float* __restrict__ emb, const int* __restrict__ wid,
                 const int* __restrict__ oni, const int* __restrict__ root_wid,
                 const int* __restrict__ roni, const float* __restrict__ mol)
{
    int i = blockIdx.x, tid = threadIdx.x;
    __shared__ int ids[MAXNB];
    __shared__ int w, bcol;
    if (tid == 0) {
        if (i < TBq) { w = wid[i]; bcol = i % Bq; }
        else         { int b = i - TBq; w = root_wid[b]; bcol = b; }
    }
    if (tid < MAXNB)
        ids[tid] = (i < TBq) ? oni[(size_t)i * MAXNB + tid]
                             : roni[(size_t)(i - TBq) * MAXNB + tid];
    __syncthreads();
    const int Wd = 2 * Hh + Ll;
    for (int h = tid; h < Wd; h += blockDim.x) {
        float v;
        if (h < Hh) v = emb[(size_t)w * Hh + h];
        else if (h < 2 * Hh) {
            int hh = h - Hh;
            v = 0.f;
            #pragma unroll
            for (int n = 0; n < MAXNB; n++) v += g_hbuf[(size_t)ids[n] * Hh + hh];
        } else v = mol[(size_t)bcol * Ll + (h - 2 * Hh)];
        g_srows[(size_t)i * Wd + h] = v;
    }
}

__global__ __launch_bounds__(256)
void build_prows(const float* __restrict__ mol)
{
    int i = blockIdx.x, tid = threadIdx.x;
    const int Wd = Hh + Ll;
    if (i < Bq) {
        for (int h = tid; h < Wd; h += blockDim.x) {
            float v = (h < Hh) ? 0.f : mol[(size_t)i * Ll + (h - Hh)];
            g_prows[(size_t)i * Wd + h] = v;
        }
    } else {
        int j = i - Bq;
        int b = j % Bq;
        for (int h = tid; h < Wd; h += blockDim.x) {
            float v = (h < Hh) ? g_hbuf[(size_t)j * Hh + h]
                               : mol[(size_t)b * Ll + (h - Hh)];
            g_prows[(size_t)i * Wd + h] = v;
        }
    }
}

// ---------------- stop head: s = hid @ Us + bs; BCE + acc ----------------
__global__ __launch_bounds__(256)
void stop_reduce_kernel(const float* __restrict__ Us, const float* __restrict__ bs,
                        const int* __restrict__ dirs)
{
    int i = blockIdx.x, tid = threadIdx.x;
    float p = 0.f;
    for (int k = tid; k < Hh; k += 256) p += g_shid[(size_t)i * Hh + k] * Us[k];
    __shared__ float red[256];
    red[tid] = p; __syncthreads();
    for (int s = 128; s > 0; s >>= 1) {
        if (tid < s) red[tid] += red[tid + s];
        __syncthreads();
    }
    if (tid == 0) {
        float sv = red[0] + bs[0];
        float tgt = (i < TBq) ? (float)dirs[i] : 0.f;
        float loss = fmaxf(sv, 0.f) - sv * tgt + log1pf(expf(-fabsf(sv)));
        atomicAdd(&g_acc[0], (double)loss);
        bool c = ((sv >= 0.5f) == (tgt > 0.5f));
        if (c) atomicAdd(&g_acc[1], 1.0);
    }
}

// ---------------- pred head: log-softmax CE + argmax acc ----------------
__global__ __launch_bounds__(256)
void pred_rows_kernel(const int* __restrict__ root_wid, const int* __restrict__ y_wid,
                      const int* __restrict__ dirs)
{
    int i = blockIdx.x, tid = threadIdx.x;
    const float* row = g_logits + (size_t)i * Vv;
    int tgt; float mask;
    if (i < Bq) { tgt = root_wid[i]; mask = 1.f; }
    else        { tgt = y_wid[i - Bq]; mask = (float)dirs[i - Bq]; }

    float mval = -1e30f; int midx = Vv;
    for (int k = tid; k < Vv; k += 256) {
        float v = row[k];
        if (v > mval) { mval = v; midx = k; }
    }
    __shared__ float rv[256];
    __shared__ int ri[256];
    rv[tid] = mval; ri[tid] = midx; __syncthreads();
    for (int s = 128; s > 0; s >>= 1) {
        if (tid < s) {
            if (rv[tid + s] > rv[tid] ||
                (rv[tid + s] == rv[tid] && ri[tid + s] < ri[tid])) {
                rv[tid] = rv[tid + s]; ri[tid] = ri[tid + s];
            }
        }
        __syncthreads();
    }
    float gmax = rv[0]; int gidx = ri[0];
    __syncthreads();
    float p = 0.f;
    for (int k = tid; k < Vv; k += 256) p += expf(row[k] - gmax);
    rv[tid] = p; __syncthreads();
    for (int s = 128; s > 0; s >>= 1) {
        if (tid < s) rv[tid] += rv[tid + s];
        __syncthreads();
    }
    if (tid == 0) {
        float lse = gmax + logf(rv[0]);
        float ce = -(row[tgt] - lse);
        atomicAdd(&g_acc[2], (double)(ce * mask));
        if (gidx == tgt) atomicAdd(&g_acc[3], (double)mask);
        atomicAdd(&g_acc[4], (double)mask);
    }
}

__global__ void finalize_kernel(float* out)
{
    out[0] = (float)(g_acc[2] / (double)Bq);   // pred_loss
    out[1] = (float)(g_acc[0] / (double)Bq);   // stop_loss
    out[2] = (float)(g_acc[3] / g_acc[4]);     // pred_acc
    out[3] = (float)(g_acc[1] / (double)MSr);  // stop_acc
}

// ---------------- launch ----------------
extern "C" void kernel_launch(void* const* d_in, const int* in_sizes, int n_in,
                              void* d_out, int out_size)
{
    const float* mol_vec = (const float*)d_in[0];
    const int*   wid     = (const int*)d_in[1];
    const int*   y_wid   = (const int*)d_in[2];
    const int*   dirs    = (const int*)d_in[3];
    const int*   hni     = (const int*)d_in[4];
    const int*   oni     = (const int*)d_in[5];
    const int*   root_wid = (const int*)d_in[6];
    const int*   roni    = (const int*)d_in[7];
    const float* emb     = (const float*)d_in[8];
    const float* Wz      = (const float*)d_in[9];
    const float* bz      = (const float*)d_in[10];
    const float* Wr      = (const float*)d_in[11];
    const float* br      = (const float*)d_in[12];
    const float* Ur      = (const float*)d_in[13];
    const float* Wh      = (const float*)d_in[14];
    const float* bh      = (const float*)d_in[15];
    const float* Wm      = (const float*)d_in[16];
    const float* bW      = (const float*)d_in[17];
    const float* U       = (const float*)d_in[18];
    const float* bU      = (const float*)d_in[19];
    const float* Wo      = (const float*)d_in[20];
    const float* bo      = (const float*)d_in[21];
    const float* Us      = (const float*)d_in[22];
    const float* bs      = (const float*)d_in[23];

    float* gx, *gsumh, *gzpre, *gxr, *ghpre, *gcat, *gcat2, *ghnei, *ggg;
    float* gsrows, *gshid, *gprows, *gphid, *glogits;
    cudaGetSymbolAddress((void**)&gx, g_x);
    cudaGetSymbolAddress((void**)&gsumh, g_sumh);
    cudaGetSymbolAddress((void**)&gzpre, g_zpre);
    cudaGetSymbolAddress((void**)&gxr, g_xr);
    cudaGetSymbolAddress((void**)&ghpre, g_hpre);
    cudaGetSymbolAddress((void**)&gcat, g_cat);
    cudaGetSymbolAddress((void**)&gcat2, g_cat2);
    cudaGetSymbolAddress((void**)&ghnei, g_hnei);
    cudaGetSymbolAddress((void**)&ggg, g_gg);
    cudaGetSymbolAddress((void**)&gsrows, g_srows);
    cudaGetSymbolAddress((void**)&gshid, g_shid);
    cudaGetSymbolAddress((void**)&gprows, g_prows);
    cudaGetSymbolAddress((void**)&gphid, g_phid);
    cudaGetSymbolAddress((void**)&glogits, g_logits);

    zero_kernel<<<1, 512>>>();

    for (int t = 0; t < Tt; t++) {
        gru_gather<<<Bq, Hh>>>(t, emb, wid, hni);
        // z_pre = [x | sum_h] @ Wz + bz
        sgemm_kernel<<<dim3(Hh / BN, Bq / BM), 256>>>(Bq, Hh, 2 * Hh, gcat, Wz, bz, gzpre, 0);
        // xr = x @ Wr + br
        sgemm_kernel<<<dim3(Hh / BN, Bq / BM), 256>>>(Bq, Hh, Hh, gx, Wr, br, gxr, 0);
        // g = h_nei @ Ur   (4096 x 512 x 512)
        sgemm_kernel<<<dim3(Hh / BN, (Bq * MAXNB) / BM), 256>>>(Bq * MAXNB, Hh, Hh, ghnei, Ur, nullptr, ggg, 0);
        gru_mid<<<Bq, Hh>>>();
        // h_pre = [x | sum_g] @ Wh + bh
        sgemm_kernel<<<dim3(Hh / BN, Bq / BM), 256>>>(Bq, Hh, 2 * Hh, gcat2, Wh, bh, ghpre, 0);
        gru_final<<<Bq, Hh>>>(t);
    }

    // stop head
    build_srows<<<MSr, 256>>>(emb, wid, oni, root_wid, roni, mol_vec);
    sgemm_kernel<<<dim3(Hh / BN, MSr / BM), 256>>>(MSr, Hh, 2 * Hh + Ll, gsrows, U, bU, gshid, 1);
    stop_reduce_kernel<<<MSr, 256>>>(Us, bs, dirs);

    // pred head
    build_prows<<<MSr, 256>>>(mol_vec);
    sgemm_kernel<<<dim3(Hh / BN, MSr / BM), 256>>>(MSr, Hh, Hh + Ll, gprows, Wm, bW, gphid, 1);
    sgemm_kernel<<<dim3(Vv / BN, MSr / BM), 256>>>(MSr, Vv, Hh, gphid, Wo, bo, glogits, 0);
    pred_rows_kernel<<<MSr, 256>>>(root_wid, y_wid, dirs);

    finalize_kernel<<<1, 1>>>((float*)d_out);
}

// round 2
// speedup vs baseline: 2.7245x; 2.7245x over previous
#include <cuda_runtime.h>
#include <cuda_bf16.h>
#include <math.h>

// Problem constants
#define Bq 512
#define Hh 512
#define Ll 64
#define Vv 1024
#define Tt 46
#define TBq 23552          // T*B
#define PADROW 23552
#define MSr 24064          // TB + B
#define MAXNB 8

// ---------------- scratch ----------------
__device__ float g_hbuf[(size_t)(TBq + 1) * Hh];
__device__ float g_hbufUr[(size_t)(TBq + 1) * Hh];
__device__ float g_Pz[(size_t)Vv * Hh];
__device__ float g_Pr[(size_t)Vv * Hh];
__device__ float g_Ph[(size_t)Vv * Hh];
__device__ float g_PembU[(size_t)Vv * Hh];
__device__ float g_PmolU[(size_t)Bq * Hh];
__device__ float g_PmolW[(size_t)Bq * Hh];
__device__ float g_sumhg[(size_t)2 * Bq * Hh];   // [0:B) sum_h, [B:2B) sum_g
__device__ float g_z[(size_t)Bq * Hh];
__device__ float g_th[(size_t)Bq * Hh];
__device__ float g_curo[(size_t)MSr * Hh];
__device__ float g_shid[(size_t)MSr * Hh];
__device__ float g_phid[(size_t)MSr * Hh];
__device__ float g_logits[(size_t)MSr * Vv];
__device__ double g_acc[5];

// ---------------- generic 64x64 SGEMM: C = act(A@B + bias) ----------------
#define BM 64
#define BN 64
#define BK 16

__global__ __launch_bounds__(256)
void sgemm_kernel(int M, int N, int K,
                  const float* __restrict__ A, const float* __restrict__ Bm,
                  const float* __restrict__ bias, float* __restrict__ C, int act)
{
    __shared__ float As[BK][BM];
    __shared__ float Bs[BK][BN];
    const int tid = threadIdx.x;
    const int tx = tid & 15;
    const int ty = tid >> 4;
    const int m0 = blockIdx.y * BM;
    const int n0 = blockIdx.x * BN;

    const int a_row  = tid >> 2;
    const int a_col4 = (tid & 3) << 2;
    const int b_row  = tid >> 4;
    const int b_col4 = (tid & 15) << 2;

    const float* Aptr = A + (size_t)(m0 + a_row) * K + a_col4;
    const float* Bptr = Bm + (size_t)b_row * N + n0 + b_col4;

    float acc[4][4];
    #pragma unroll
    for (int i = 0; i < 4; i++)
        #pragma unroll
        for (int j = 0; j < 4; j++) acc[i][j] = 0.f;

    for (int k0 = 0; k0 < K; k0 += BK) {
        float4 av = *(const float4*)(Aptr + k0);
        float4 bv = *(const float4*)(Bptr + (size_t)k0 * N);
        As[a_col4 + 0][a_row] = av.x;
        As[a_col4 + 1][a_row] = av.y;
        As[a_col4 + 2][a_row] = av.z;
        As[a_col4 + 3][a_row] = av.w;
        *(float4*)&Bs[b_row][b_col4] = bv;
        __syncthreads();
        #pragma unroll
        for (int k = 0; k < BK; k++) {
            float4 a4 = *(const float4*)&As[k][ty << 2];
            float4 b4 = *(const float4*)&Bs[k][tx << 2];
            float a[4] = {a4.x, a4.y, a4.z, a4.w};
            float b[4] = {b4.x, b4.y, b4.z, b4.w};
            #pragma unroll
            for (int i = 0; i < 4; i++)
                #pragma unroll
                for (int j = 0; j < 4; j++) acc[i][j] = fmaf(a[i], b[j], acc[i][j]);
        }
        __syncthreads();
    }

    #pragma unroll
    for (int i = 0; i < 4; i++) {
        int row = m0 + (ty << 2) + i;
        int col = n0 + (tx << 2);
        float4 out;
        float b0 = bias ? bias[col + 0] : 0.f;
        float b1 = bias ? bias[col + 1] : 0.f;
        float b2 = bias ? bias[col + 2] : 0.f;
        float b3 = bias ? bias[col + 3] : 0.f;
        out.x = acc[i][0] + b0; out.y = acc[i][1] + b1;
        out.z = acc[i][2] + b2; out.w = acc[i][3] + b3;
        if (act) {
            out.x = fmaxf(out.x, 0.f); out.y = fmaxf(out.y, 0.f);
            out.z = fmaxf(out.z, 0.f); out.w = fmaxf(out.w, 0.f);
        }
        *(float4*)&C[(size_t)row * N + col] = out;
    }
}

// ---------------- per-step combined GEMM: [sum_h; sum_g] @ [Wz_bot ; Wh_bot] ----------------
// M = 1024 (rows 0..511 -> z path, 512..1023 -> h_tilde path), N = K = 512.
__global__ __launch_bounds__(256)
void gemm_ac_kernel(int t, const float* __restrict__ Wz, const float* __restrict__ Wh,
                    const int* __restrict__ wid)
{
    __shared__ float As[BK][BM];
    __shared__ float Bs[BK][BN];
    const int tid = threadIdx.x;
    const int tx = tid & 15;
    const int ty = tid >> 4;
    const int m0 = blockIdx.y * BM;
    const int n0 = blockIdx.x * BN;
    const int grp = (m0 >= Bq);
    const float* Bm = grp ? (Wh + (size_t)Hh * Hh) : (Wz + (size_t)Hh * Hh);
    const float* A = g_sumhg;
    const int K = Hh, N = Hh;

    const int a_row  = tid >> 2;
    const int a_col4 = (tid & 3) << 2;
    const int b_row  = tid >> 4;
    const int b_col4 = (tid & 15) << 2;

    const float* Aptr = A + (size_t)(m0 + a_row) * K + a_col4;
    const float* Bptr = Bm + (size_t)b_row * N + n0 + b_col4;

    float acc[4][4];
    #pragma unroll
    for (int i = 0; i < 4; i++)
        #pragma unroll
        for (int j = 0; j < 4; j++) acc[i][j] = 0.f;

    for (int k0 = 0; k0 < K; k0 += BK) {
        float4 av = *(const float4*)(Aptr + k0);
        float4 bv = *(const float4*)(Bptr + (size_t)k0 * N);
        As[a_col4 + 0][a_row] = av.x;
        As[a_col4 + 1][a_row] = av.y;
        As[a_col4 + 2][a_row] = av.z;
        As[a_col4 + 3][a_row] = av.w;
        *(float4*)&Bs[b_row][b_col4] = bv;
        __syncthreads();
        #pragma unroll
        for (int k = 0; k < BK; k++) {
            float4 a4 = *(const float4*)&As[k][ty << 2];
            float4 b4 = *(const float4*)&Bs[k][tx << 2];
            float a[4] = {a4.x, a4.y, a4.z, a4.w};
            float b[4] = {b4.x, b4.y, b4.z, b4.w};
            #pragma unroll
            for (int i = 0; i < 4; i++)
                #pragma unroll
                for (int j = 0; j < 4; j++) acc[i][j] = fmaf(a[i], b[j], acc[i][j]);
        }
        __syncthreads();
    }

    const float* P = grp ? g_Ph : g_Pz;
    float* Cout = grp ? g_th : g_z;
    #pragma unroll
    for (int i = 0; i < 4; i++) {
        int row = m0 + (ty << 2) + i;
        int b = row & (Bq - 1);
        int w = wid[t * Bq + b];
        int col = n0 + (tx << 2);
        #pragma unroll
        for (int j = 0; j < 4; j++) {
            float v = acc[i][j] + P[(size_t)w * Hh + col + j];
            Cout[(size_t)b * Hh + col + j] = grp ? tanhf(v) : (1.f / (1.f + expf(-v)));
        }
    }
}

// ---------------- 128x64 SGEMM with fused epilogues ----------------
// mode 0: C = act(acc + bias)
// mode 1 (stop): C = relu(acc + PembU[w] + PmolU[bcol]), w/bcol from row index
// mode 2 (pred): C = relu(acc + PmolW[row & 511])
#define CM 128
#define CN 64
#define CK 16

__global__ __launch_bounds__(256)
void sgemm128_kernel(int M, int N, int K,
                     const float* __restrict__ A, const float* __restrict__ Bm,
                     const float* __restrict__ bias, float* __restrict__ C,
                     int act, int mode,
                     const int* __restrict__ wid, const int* __restrict__ root_wid)
{
    __shared__ float As[CK][CM];
    __shared__ float Bs[CK][CN];
    const int tid = threadIdx.x;
    const int m0 = blockIdx.y * CM;
    const int n0 = blockIdx.x * CN;

    const int a_row = tid >> 1;             // 0..127
    const int a_c8  = (tid & 1) << 3;       // 0 or 8
    const int b_row = tid >> 4;
    const int b_c4  = (tid & 15) << 2;
    const int ty = tid >> 4;                // 0..15 -> rows ty*8..+7
    const int tx = tid & 15;                // cols tx*4

    const float* Aptr = A + (size_t)(m0 + a_row) * K + a_c8;
    const float* Bptr = Bm + (size_t)b_row * N + n0 + b_c4;

    float acc[8][4];
    #pragma unroll
    for (int i = 0; i < 8; i++)
        #pragma unroll
        for (int j = 0; j < 4; j++) acc[i][j] = 0.f;

    for (int k0 = 0; k0 < K; k0 += CK) {
        float4 av0 = *(const float4*)(Aptr + k0);
        float4 av1 = *(const float4*)(Aptr + k0 + 4);
        float4 bv  = *(const float4*)(Bptr + (size_t)k0 * N);
        As[a_c8 + 0][a_row] = av0.x;
        As[a_c8 + 1][a_row] = av0.y;
        As[a_c8 + 2][a_row] = av0.z;
        As[a_c8 + 3][a_row] = av0.w;
        As[a_c8 + 4][a_row] = av1.x;
        As[a_c8 + 5][a_row] = av1.y;
        As[a_c8 + 6][a_row] = av1.z;
        As[a_c8 + 7][a_row] = av1.w;
        *(float4*)&Bs[b_row][b_c4] = bv;
        __syncthreads();
        #pragma unroll
        for (int k = 0; k < CK; k++) {
            float4 a0 = *(const float4*)&As[k][ty << 3];
            float4 a1 = *(const float4*)&As[k][(ty << 3) + 4];
            float4 b4 = *(const float4*)&Bs[k][tx << 2];
            float a[8] = {a0.x, a0.y, a0.z, a0.w, a1.x, a1.y, a1.z, a1.w};
            float b[4] = {b4.x, b4.y, b4.z, b4.w};
            #pragma unroll
            for (int i = 0; i < 8; i++)
                #pragma unroll
                for (int j = 0; j < 4; j++) acc[i][j] = fmaf(a[i], b[j], acc[i][j]);
        }
        __syncthreads();
    }

    #pragma unroll
    for (int i = 0; i < 8; i++) {
        int row = m0 + (ty << 3) + i;
        int col = n0 + (tx << 2);
        float4 out;
        if (mode == 0) {
            float b0 = bias ? bias[col + 0] : 0.f;
            float b1 = bias ? bias[col + 1] : 0.f;
            float b2 = bias ? bias[col + 2] : 0.f;
            float b3 = bias ? bias[col + 3] : 0.f;
            out.x = acc[i][0] + b0; out.y = acc[i][1] + b1;
            out.z = acc[i][2] + b2; out.w = acc[i][3] + b3;
            if (act) {
                out.x = fmaxf(out.x, 0.f); out.y = fmaxf(out.y, 0.f);
                out.z = fmaxf(out.z, 0.f); out.w = fmaxf(out.w, 0.f);
            }
        } else if (mode == 1) {
            int w, bcol;
            if (row < TBq) { w = wid[row]; bcol = row & (Bq - 1); }
            else           { w = root_wid[row - TBq]; bcol = row - TBq; }
            const float* Pe = g_PembU + (size_t)w * Hh + col;
            const float* Pm = g_PmolU + (size_t)bcol * Hh + col;
            out.x = fmaxf(acc[i][0] + Pe[0] + Pm[0], 0.f);
            out.y = fmaxf(acc[i][1] + Pe[1] + Pm[1], 0.f);
            out.z = fmaxf(acc[i][2] + Pe[2] + Pm[2], 0.f);
            out.w = fmaxf(acc[i][3] + Pe[3] + Pm[3], 0.f);
        } else {
            int b = row & (Bq - 1);
            const float* Pm = g_PmolW + (size_t)b * Hh + col;
            out.x = fmaxf(acc[i][0] + Pm[0], 0.f);
            out.y = fmaxf(acc[i][1] + Pm[1], 0.f);
            out.z = fmaxf(acc[i][2] + Pm[2], 0.f);
            out.w = fmaxf(acc[i][3] + Pm[3], 0.f);
        }
        *(float4*)&C[(size_t)row * N + col] = out;
    }
}

// ---------------- housekeeping ----------------
__global__ void zero_kernel()
{
    int tid = threadIdx.x;
    if (tid < 5) g_acc[tid] = 0.0;
    for (int h = tid; h < Hh; h += blockDim.x) {
        g_hbuf[(size_t)PADROW * Hh + h] = 0.f;
        g_hbufUr[(size_t)PADROW * Hh + h] = 0.f;
    }
}

// ---------------- GRU step: fused gather (sum_h, sum_g) ----------------
__global__ __launch_bounds__(512)
void gru_gather2(int t, const int* __restrict__ wid, const int* __restrict__ hni)
{
    int b = blockIdx.x, h = threadIdx.x;
    __shared__ int ids[MAXNB];
    __shared__ int w;
    if (h < MAXNB) ids[h] = hni[((size_t)(t * Bq + b)) * MAXNB + h];
    if (h == MAXNB) w = wid[t * Bq + b];
    __syncthreads();
    float xr = g_Pr[(size_t)w * Hh + h];
    float sh = 0.f, sg = 0.f;
    #pragma unroll
    for (int n = 0; n < MAXNB; n++) {
        int id = ids[n];
        float hv = g_hbuf[(size_t)id * Hh + h];
        float gv = g_hbufUr[(size_t)id * Hh + h];
        float r = 1.f / (1.f + expf(-(xr + gv)));
        sh += hv;
        sg += r * hv;
    }
    g_sumhg[(size_t)b * Hh + h] = sh;
    g_sumhg[(size_t)(Bq + b) * Hh + h] = sg;
}

__global__ __launch_bounds__(512)
void gru_final(int t)
{
    int b = blockIdx.x, h = threadIdx.x;
    float z = g_z[(size_t)b * Hh + h];
    float th = g_th[(size_t)b * Hh + h];
    float sh = g_sumhg[(size_t)b * Hh + h];
    g_hbuf[((size_t)(t * Bq + b)) * Hh + h] = (1.f - z) * sh + z * th;
}

// ---------------- post: cur_o gather ----------------
__global__ __launch_bounds__(256)
void build_curo(const int* __restrict__ oni, const int* __restrict__ roni)
{
    int i = blockIdx.x, tid = threadIdx.x;
    __shared__ int ids[MAXNB];
    if (tid < MAXNB)
        ids[tid] = (i < TBq) ? oni[(size_t)i * MAXNB + tid]
                             : roni[(size_t)(i - TBq) * MAXNB + tid];
    __syncthreads();
    for (int h = tid; h < Hh; h += 256) {
        float v = 0.f;
        #pragma unroll
        for (int n = 0; n < MAXNB; n++) v += g_hbuf[(size_t)ids[n] * Hh + h];
        g_curo[(size_t)i * Hh + h] = v;
    }
}

__global__ __launch_bounds__(512)
void phid0_kernel()
{
    int b = blockIdx.x, h = threadIdx.x;
    g_phid[(size_t)b * Hh + h] = fmaxf(g_PmolW[(size_t)b * Hh + h], 0.f);
}

// ---------------- stop head reduction ----------------
__global__ __launch_bounds__(256)
void stop_reduce_kernel(const float* __restrict__ Us, const float* __restrict__ bs,
                        const int* __restrict__ dirs)
{
    int i = blockIdx.x, tid = threadIdx.x;
    float p = 0.f;
    for (int k = tid; k < Hh; k += 256) p += g_shid[(size_t)i * Hh + k] * Us[k];
    __shared__ float red[256];
    red[tid] = p; __syncthreads();
    for (int s = 128; s > 0; s >>= 1) {
        if (tid < s) red[tid] += red[tid + s];
        __syncthreads();
    }
    if (tid == 0) {
        float sv = red[0] + bs[0];
        float tgt = (i < TBq) ? (float)dirs[i] : 0.f;
        float loss = fmaxf(sv, 0.f) - sv * tgt + log1pf(expf(-fabsf(sv)));
        atomicAdd(&g_acc[0], (double)loss);
        if ((sv >= 0.5f) == (tgt > 0.5f)) atomicAdd(&g_acc[1], 1.0);
    }
}

// ---------------- pred head: log-softmax CE + argmax ----------------
__global__ __launch_bounds__(256)
void pred_rows_kernel(const int* __restrict__ root_wid, const int* __restrict__ y_wid,
                      const int* __restrict__ dirs)
{
    int i = blockIdx.x, tid = threadIdx.x;
    const float* row = g_logits + (size_t)i * Vv;
    int tgt; float mask;
    if (i < Bq) { tgt = root_wid[i]; mask = 1.f; }
    else        { tgt = y_wid[i - Bq]; mask = (float)dirs[i - Bq]; }

    float mval = -1e30f; int midx = Vv;
    for (int k = tid; k < Vv; k += 256) {
        float v = row[k];
        if (v > mval) { mval = v; midx = k; }
    }
    __shared__ float rv[256];
    __shared__ int ri[256];
    rv[tid] = mval; ri[tid] = midx; __syncthreads();
    for (int s = 128; s > 0; s >>= 1) {
        if (tid < s) {
            if (rv[tid + s] > rv[tid] ||
                (rv[tid + s] == rv[tid] && ri[tid + s] < ri[tid])) {
                rv[tid] = rv[tid + s]; ri[tid] = ri[tid + s];
            }
        }
        __syncthreads();
    }
    float gmax = rv[0]; int gidx = ri[0];
    __syncthreads();
    float p = 0.f;
    for (int k = tid; k < Vv; k += 256) p += expf(row[k] - gmax);
    rv[tid] = p; __syncthreads();
    for (int s = 128; s > 0; s >>= 1) {
        if (tid < s) rv[tid] += rv[tid + s];
        __syncthreads();
    }
    if (tid == 0) {
        float lse = gmax + logf(rv[0]);
        float ce = -(row[tgt] - lse);
        atomicAdd(&g_acc[2], (double)(ce * mask));
        if (gidx == tgt) atomicAdd(&g_acc[3], (double)mask);
        atomicAdd(&g_acc[4], (double)mask);
    }
}

__global__ void finalize_kernel(float* out)
{
    out[0] = (float)(g_acc[2] / (double)Bq);
    out[1] = (float)(g_acc[0] / (double)Bq);
    out[2] = (float)(g_acc[3] / g_acc[4]);
    out[3] = (float)(g_acc[1] / (double)MSr);
}

// ---------------- launch ----------------
extern "C" void kernel_launch(void* const* d_in, const int* in_sizes, int n_in,
                              void* d_out, int out_size)
{
    const float* mol_vec  = (const float*)d_in[0];
    const int*   wid      = (const int*)d_in[1];
    const int*   y_wid    = (const int*)d_in[2];
    const int*   dirs     = (const int*)d_in[3];
    const int*   hni      = (const int*)d_in[4];
    const int*   oni      = (const int*)d_in[5];
    const int*   root_wid = (const int*)d_in[6];
    const int*   roni     = (const int*)d_in[7];
    const float* emb      = (const float*)d_in[8];
    const float* Wz       = (const float*)d_in[9];
    const float* bz       = (const float*)d_in[10];
    const float* Wr       = (const float*)d_in[11];
    const float* br       = (const float*)d_in[12];
    const float* Ur       = (const float*)d_in[13];
    const float* Wh       = (const float*)d_in[14];
    const float* bh       = (const float*)d_in[15];
    const float* Wm       = (const float*)d_in[16];
    const float* bW       = (const float*)d_in[17];
    const float* U        = (const float*)d_in[18];
    const float* bU       = (const float*)d_in[19];
    const float* Wo       = (const float*)d_in[20];
    const float* bo       = (const float*)d_in[21];
    const float* Us       = (const float*)d_in[22];
    const float* bs       = (const float*)d_in[23];

    float *gPz, *gPr, *gPh, *gPembU, *gPmolU, *gPmolW;
    float *ghbuf, *ghbufUr, *gcuro, *gshid, *gphid, *glogits;
    cudaGetSymbolAddress((void**)&gPz, g_Pz);
    cudaGetSymbolAddress((void**)&gPr, g_Pr);
    cudaGetSymbolAddress((void**)&gPh, g_Ph);
    cudaGetSymbolAddress((void**)&gPembU, g_PembU);
    cudaGetSymbolAddress((void**)&gPmolU, g_PmolU);
    cudaGetSymbolAddress((void**)&gPmolW, g_PmolW);
    cudaGetSymbolAddress((void**)&ghbuf, g_hbuf);
    cudaGetSymbolAddress((void**)&ghbufUr, g_hbufUr);
    cudaGetSymbolAddress((void**)&gcuro, g_curo);
    cudaGetSymbolAddress((void**)&gshid, g_shid);
    cudaGetSymbolAddress((void**)&gphid, g_phid);
    cudaGetSymbolAddress((void**)&glogits, g_logits);

    zero_kernel<<<1, 512>>>();

    // one-time precomputes
    sgemm_kernel<<<dim3(Hh / BN, Vv / BM), 256>>>(Vv, Hh, Hh, emb, Wz, bz, gPz, 0);
    sgemm_kernel<<<dim3(Hh / BN, Vv / BM), 256>>>(Vv, Hh, Hh, emb, Wr, br, gPr, 0);
    sgemm_kernel<<<dim3(Hh / BN, Vv / BM), 256>>>(Vv, Hh, Hh, emb, Wh, bh, gPh, 0);
    sgemm_kernel<<<dim3(Hh / BN, Vv / BM), 256>>>(Vv, Hh, Hh, emb, U, bU, gPembU, 0);
    sgemm_kernel<<<dim3(Hh / BN, Bq / BM), 256>>>(Bq, Hh, Ll, mol_vec, U + (size_t)2 * Hh * Hh, nullptr, gPmolU, 0);
    sgemm_kernel<<<dim3(Hh / BN, Bq / BM), 256>>>(Bq, Hh, Ll, mol_vec, Wm + (size_t)Hh * Hh, bW, gPmolW, 0);

    // GRU scan
    for (int t = 0; t < Tt; t++) {
        gru_gather2<<<Bq, Hh>>>(t, wid, hni);
        gemm_ac_kernel<<<dim3(Hh / BN, (2 * Bq) / BM), 256>>>(t, Wz, Wh, wid);
        gru_final<<<Bq, Hh>>>(t);
        // hbufUr[t*B : (t+1)*B] = h_new @ Ur
        sgemm_kernel<<<dim3(Hh / BN, Bq / BM), 256>>>(
            Bq, Hh, Hh, ghbuf + (size_t)t * Bq * Hh, Ur, nullptr,
            ghbufUr + (size_t)t * Bq * Hh, 0);
    }

    // stop head
    build_curo<<<MSr, 256>>>(oni, roni);
    sgemm128_kernel<<<dim3(Hh / CN, MSr / CM), 256>>>(
        MSr, Hh, Hh, gcuro, U + (size_t)Hh * Hh, nullptr, gshid, 0, 1, wid, root_wid);
    stop_reduce_kernel<<<MSr, 256>>>(Us, bs, dirs);

    // pred head
    phid0_kernel<<<Bq, Hh>>>();
    sgemm128_kernel<<<dim3(Hh / CN, TBq / CM), 256>>>(
        TBq, Hh, Hh, ghbuf, Wm, nullptr, gphid + (size_t)Bq * Hh, 0, 2, nullptr, nullptr);
    sgemm128_kernel<<<dim3(Vv / CN, MSr / CM), 256>>>(
        MSr, Vv, Hh, gphid, Wo, bo, glogits, 0, 0, nullptr, nullptr);
    pred_rows_kernel<<<MSr, 256>>>(root_wid, y_wid, dirs);

    finalize_kernel<<<1, 1>>>((float*)d_out);
}

// round 3
// speedup vs baseline: 2.7470x; 1.0082x over previous
#include <cuda_runtime.h>
#include <cuda_bf16.h>
#include <math.h>

// Problem constants
#define Bq 512
#define Hh 512
#define Ll 64
#define Vv 1024
#define Tt 46
#define TBq 23552          // T*B
#define PADROW 23552
#define MSr 24064          // TB + B
#define MAXNB 8
#define NCMP 11776         // compacted pred rows (dirs==1): exactly (N-1)*B
#define MPRED 12288        // B + NCMP
#define NBLK 128           // persistent scan grid

// ---------------- scratch ----------------
__device__ float g_hbuf[(size_t)(TBq + 1) * Hh];
__device__ float g_hbufUr[(size_t)(TBq + 1) * Hh];
__device__ float g_Pz[(size_t)Vv * Hh];
__device__ float g_Pr[(size_t)Vv * Hh];
__device__ float g_Ph[(size_t)Vv * Hh];
__device__ float g_PembU[(size_t)Vv * Hh];
__device__ float g_PmolU[(size_t)Bq * Hh];
__device__ float g_PmolW[(size_t)Bq * Hh];
__device__ float g_sumhg[(size_t)2 * Bq * Hh];
__device__ float g_z[(size_t)Bq * Hh];
__device__ float g_th[(size_t)Bq * Hh];
__device__ float g_curo[(size_t)MSr * Hh];
__device__ float g_phidc[(size_t)MPRED * Hh];
__device__ float g_logitsc[(size_t)MPRED * Vv];
__device__ float g_spart[(size_t)4 * MSr];
__device__ int   g_cmap[NCMP + 256];
__device__ int   g_ccount;
__device__ int   g_barc;
__device__ volatile int g_bars;
__device__ double g_acc[5];

// ---------------- software grid barrier ----------------
__device__ __forceinline__ void grid_bar(int nb)
{
    __syncthreads();
    if (threadIdx.x == 0) {
        int s = g_bars;
        __threadfence();                 // release (also CCTL.IVALL -> L1 flush)
        int t = atomicAdd(&g_barc, 1);
        if (t == nb - 1) {
            g_barc = 0;
            __threadfence();
            g_bars = s + 1;
        } else {
            while (g_bars == s) { __nanosleep(32); }
        }
        __threadfence();                 // acquire + L1 invalidate
    }
    __syncthreads();
}

// ---------------- generic 64x64 SGEMM (precomputes) ----------------
#define BM 64
#define BN 64
#define BK 16

__global__ __launch_bounds__(256)
void sgemm_kernel(int M, int N, int K,
                  const float* __restrict__ A, const float* __restrict__ Bm,
                  const float* __restrict__ bias, float* __restrict__ C)
{
    __shared__ float As[BK][BM];
    __shared__ float Bs[BK][BN];
    const int tid = threadIdx.x;
    const int tx = tid & 15;
    const int ty = tid >> 4;
    const int m0 = blockIdx.y * BM;
    const int n0 = blockIdx.x * BN;

    const int a_row  = tid >> 2;
    const int a_col4 = (tid & 3) << 2;
    const int b_row  = tid >> 4;
    const int b_col4 = (tid & 15) << 2;

    const float* Aptr = A + (size_t)(m0 + a_row) * K + a_col4;
    const float* Bptr = Bm + (size_t)b_row * N + n0 + b_col4;

    float acc[4][4];
    #pragma unroll
    for (int i = 0; i < 4; i++)
        #pragma unroll
        for (int j = 0; j < 4; j++) acc[i][j] = 0.f;

    for (int k0 = 0; k0 < K; k0 += BK) {
        float4 av = *(const float4*)(Aptr + k0);
        float4 bv = *(const float4*)(Bptr + (size_t)k0 * N);
        As[a_col4 + 0][a_row] = av.x;
        As[a_col4 + 1][a_row] = av.y;
        As[a_col4 + 2][a_row] = av.z;
        As[a_col4 + 3][a_row] = av.w;
        *(float4*)&Bs[b_row][b_col4] = bv;
        __syncthreads();
        #pragma unroll
        for (int k = 0; k < BK; k++) {
            float4 a4 = *(const float4*)&As[k][ty << 2];
            float4 b4 = *(const float4*)&Bs[k][tx << 2];
            float a[4] = {a4.x, a4.y, a4.z, a4.w};
            float b[4] = {b4.x, b4.y, b4.z, b4.w};
            #pragma unroll
            for (int i = 0; i < 4; i++)
                #pragma unroll
                for (int j = 0; j < 4; j++) acc[i][j] = fmaf(a[i], b[j], acc[i][j]);
        }
        __syncthreads();
    }

    #pragma unroll
    for (int i = 0; i < 4; i++) {
        int row = m0 + (ty << 2) + i;
        int col = n0 + (tx << 2);
        float4 out;
        float b0 = bias ? bias[col + 0] : 0.f;
        float b1 = bias ? bias[col + 1] : 0.f;
        float b2 = bias ? bias[col + 2] : 0.f;
        float b3 = bias ? bias[col + 3] : 0.f;
        out.x = acc[i][0] + b0; out.y = acc[i][1] + b1;
        out.z = acc[i][2] + b2; out.w = acc[i][3] + b3;
        *(float4*)&C[(size_t)row * N + col] = out;
    }
}

// ---------------- persistent fused GRU scan ----------------
__global__ __launch_bounds__(256)
void scan_kernel(const int* __restrict__ wid, const int* __restrict__ hni,
                 const float* __restrict__ Wz, const float* __restrict__ Wh,
                 const float* __restrict__ Ur)
{
    __shared__ float sm[2048];
    __shared__ int s_ids[MAXNB];
    __shared__ int s_w;
    const int tid = threadIdx.x;
    const int nb = (int)gridDim.x;

    for (int t = 0; t < Tt; t++) {
        // ---- P1: gather (sum_h, sum_g) ----
        for (int b = (int)blockIdx.x; b < Bq; b += nb) {
            __syncthreads();
            if (tid < MAXNB) s_ids[tid] = hni[((size_t)(t * Bq + b)) * MAXNB + tid];
            if (tid == MAXNB) s_w = wid[t * Bq + b];
            __syncthreads();
            int w = s_w;
            #pragma unroll
            for (int hh = 0; hh < Hh; hh += 256) {
                int h = hh + tid;
                float xr = g_Pr[(size_t)w * Hh + h];
                float sh = 0.f, sg = 0.f;
                #pragma unroll
                for (int n = 0; n < MAXNB; n++) {
                    int id = s_ids[n];
                    float hv = g_hbuf[(size_t)id * Hh + h];
                    float gv = g_hbufUr[(size_t)id * Hh + h];
                    float r = 1.f / (1.f + expf(-(xr + gv)));
                    sh += hv;
                    sg += r * hv;
                }
                g_sumhg[(size_t)b * Hh + h] = sh;
                g_sumhg[(size_t)(Bq + b) * Hh + h] = sg;
            }
        }
        grid_bar(nb);

        // ---- P2: z / h_tilde GEMM (128 tiles 64x64 over M=1024) ----
        {
            const int tt = (int)blockIdx.x;
            const int m0 = (tt >> 3) * 64;
            const int n0 = (tt & 7) * 64;
            const int grp = (m0 >= Bq);
            const float* Bm = grp ? (Wh + (size_t)Hh * Hh) : (Wz + (size_t)Hh * Hh);
            float* As = sm;             // [16][64]
            float* Bs = sm + 1024;      // [16][64]
            const int a_row = tid >> 2, a_c4 = (tid & 3) << 2;
            const int b_row = tid >> 4, b_c4 = (tid & 15) << 2;
            const int ty = tid >> 4, tx = tid & 15;
            const float* Aptr = g_sumhg + (size_t)(m0 + a_row) * Hh + a_c4;
            const float* Bptr = Bm + (size_t)b_row * Hh + n0 + b_c4;

            float acc[4][4];
            #pragma unroll
            for (int i = 0; i < 4; i++)
                #pragma unroll
                for (int j = 0; j < 4; j++) acc[i][j] = 0.f;

            for (int k0 = 0; k0 < Hh; k0 += 16) {
                float4 av = *(const float4*)(Aptr + k0);
                float4 bv = *(const float4*)(Bptr + (size_t)k0 * Hh);
                As[(a_c4 + 0) * 64 + a_row] = av.x;
                As[(a_c4 + 1) * 64 + a_row] = av.y;
                As[(a_c4 + 2) * 64 + a_row] = av.z;
                As[(a_c4 + 3) * 64 + a_row] = av.w;
                *(float4*)&Bs[b_row * 64 + b_c4] = bv;
                __syncthreads();
                #pragma unroll
                for (int k = 0; k < 16; k++) {
                    float4 a4 = *(const float4*)&As[k * 64 + (ty << 2)];
                    float4 b4 = *(const float4*)&Bs[k * 64 + (tx << 2)];
                    float a[4] = {a4.x, a4.y, a4.z, a4.w};
                    float b[4] = {b4.x, b4.y, b4.z, b4.w};
                    #pragma unroll
                    for (int i = 0; i < 4; i++)
                        #pragma unroll
                        for (int j = 0; j < 4; j++) acc[i][j] = fmaf(a[i], b[j], acc[i][j]);
                }
                __syncthreads();
            }
            const float* P = grp ? g_Ph : g_Pz;
            float* Cout = grp ? g_th : g_z;
            #pragma unroll
            for (int i = 0; i < 4; i++) {
                int row = m0 + (ty << 2) + i;
                int b = row & (Bq - 1);
                int w = wid[t * Bq + b];
                int col = n0 + (tx << 2);
                float4 out;
                float v0 = acc[i][0] + P[(size_t)w * Hh + col + 0];
                float v1 = acc[i][1] + P[(size_t)w * Hh + col + 1];
                float v2 = acc[i][2] + P[(size_t)w * Hh + col + 2];
                float v3 = acc[i][3] + P[(size_t)w * Hh + col + 3];
                if (grp) {
                    out.x = tanhf(v0); out.y = tanhf(v1);
                    out.z = tanhf(v2); out.w = tanhf(v3);
                } else {
                    out.x = 1.f / (1.f + expf(-v0));
                    out.y = 1.f / (1.f + expf(-v1));
                    out.z = 1.f / (1.f + expf(-v2));
                    out.w = 1.f / (1.f + expf(-v3));
                }
                *(float4*)&Cout[(size_t)b * Hh + col] = out;
            }
        }
        grid_bar(nb);

        // ---- P3: h_new = (1-z)*sum_h + z*th ----
        {
            float* hdst = g_hbuf + (size_t)t * Bq * Hh;
            for (int i = (int)blockIdx.x * 256 + tid; i < Bq * Hh; i += nb * 256) {
                float z = g_z[i];
                hdst[i] = (1.f - z) * g_sumhg[i] + z * g_th[i];
            }
        }
        grid_bar(nb);

        // ---- P4: hbufUr[t] = h_new @ Ur  (128 tiles 64x32) ----
        {
            const int tt = (int)blockIdx.x;
            const int m0 = (tt >> 4) * 64;
            const int n0 = (tt & 15) * 32;
            float* As = sm;           // [16][64]
            float* Bs = sm + 1024;    // [16][32]
            const float* A = g_hbuf + (size_t)t * Bq * Hh;
            float* Cc = g_hbufUr + (size_t)t * Bq * Hh;
            const int a_row = tid >> 2, a_c4 = (tid & 3) << 2;
            const int b_row = tid >> 4, b_c2 = (tid & 15) << 1;
            const int ty = tid >> 4, tx = tid & 15;

            float acc[4][2];
            #pragma unroll
            for (int i = 0; i < 4; i++) { acc[i][0] = 0.f; acc[i][1] = 0.f; }

            for (int k0 = 0; k0 < Hh; k0 += 16) {
                float4 av = *(const float4*)(A + (size_t)(m0 + a_row) * Hh + k0 + a_c4);
                float2 bv = *(const float2*)(Ur + (size_t)(k0 + b_row) * Hh + n0 + b_c2);
                As[(a_c4 + 0) * 64 + a_row] = av.x;
                As[(a_c4 + 1) * 64 + a_row] = av.y;
                As[(a_c4 + 2) * 64 + a_row] = av.z;
                As[(a_c4 + 3) * 64 + a_row] = av.w;
                Bs[b_row * 32 + b_c2] = bv.x;
                Bs[b_row * 32 + b_c2 + 1] = bv.y;
                __syncthreads();
                #pragma unroll
                for (int k = 0; k < 16; k++) {
                    float4 a4 = *(const float4*)&As[k * 64 + (ty << 2)];
                    float b0 = Bs[k * 32 + (tx << 1)];
                    float b1 = Bs[k * 32 + (tx << 1) + 1];
                    float a[4] = {a4.x, a4.y, a4.z, a4.w};
                    #pragma unroll
                    for (int i = 0; i < 4; i++) {
                        acc[i][0] = fmaf(a[i], b0, acc[i][0]);
                        acc[i][1] = fmaf(a[i], b1, acc[i][1]);
                    }
                }
                __syncthreads();
            }
            #pragma unroll
            for (int i = 0; i < 4; i++) {
                int row = m0 + (ty << 2) + i;
                float2 out = {acc[i][0], acc[i][1]};
                *(float2*)&Cc[(size_t)row * Hh + n0 + (tx << 1)] = out;
            }
        }
        grid_bar(nb);
    }
}

// ---------------- big 128x128 GEMM with fused epilogues ----------------
// mode 0: C = acc + bias                       (logits)
// mode 1: stop head: partial dot with Us of relu(acc + PembU[w] + PmolU[b])
// mode 2: pred phid: A gathered via cmap; C = relu(acc + PmolW[idx&511])
__global__ __launch_bounds__(256, 2)
void dgemm_kernel(int N, const float* __restrict__ A,
                  const float* __restrict__ Bm, const float* __restrict__ bias,
                  float* __restrict__ C, int mode,
                  const int* __restrict__ wid, const int* __restrict__ root_wid,
                  const float* __restrict__ Us)
{
    __shared__ float As[16 * 128];
    __shared__ float Bs[16 * 128];
    const int tid = threadIdx.x;
    const int m0 = blockIdx.y * 128;
    const int n0 = blockIdx.x * 128;
    const int a_row = tid >> 1, a_c8 = (tid & 1) << 3;
    const int b_row = tid >> 4, b_c8 = (tid & 15) << 3;
    const int ty = tid >> 4, tx = tid & 15;

    const float* Arow;
    if (mode == 2) {
        int idx = g_cmap[m0 + a_row];
        Arow = g_hbuf + (size_t)idx * Hh + a_c8;
    } else {
        Arow = A + (size_t)(m0 + a_row) * Hh + a_c8;
    }
    const float* Bptr = Bm + (size_t)b_row * N + n0 + b_c8;

    float acc[8][8];
    #pragma unroll
    for (int i = 0; i < 8; i++)
        #pragma unroll
        for (int j = 0; j < 8; j++) acc[i][j] = 0.f;

    for (int k0 = 0; k0 < Hh; k0 += 16) {
        float4 av0 = *(const float4*)(Arow + k0);
        float4 av1 = *(const float4*)(Arow + k0 + 4);
        As[(a_c8 + 0) * 128 + a_row] = av0.x;
        As[(a_c8 + 1) * 128 + a_row] = av0.y;
        As[(a_c8 + 2) * 128 + a_row] = av0.z;
        As[(a_c8 + 3) * 128 + a_row] = av0.w;
        As[(a_c8 + 4) * 128 + a_row] = av1.x;
        As[(a_c8 + 5) * 128 + a_row] = av1.y;
        As[(a_c8 + 6) * 128 + a_row] = av1.z;
        As[(a_c8 + 7) * 128 + a_row] = av1.w;
        float4 bv0 = *(const float4*)(Bptr + (size_t)k0 * N);
        float4 bv1 = *(const float4*)(Bptr + (size_t)k0 * N + 4);
        *(float4*)&Bs[b_row * 128 + b_c8] = bv0;
        *(float4*)&Bs[b_row * 128 + b_c8 + 4] = bv1;
        __syncthreads();
        #pragma unroll
        for (int k = 0; k < 16; k++) {
            float a[8], b[8];
            *(float4*)(a)     = *(const float4*)&As[k * 128 + (ty << 3)];
            *(float4*)(a + 4) = *(const float4*)&As[k * 128 + (ty << 3) + 4];
            *(float4*)(b)     = *(const float4*)&Bs[k * 128 + (tx << 3)];
            *(float4*)(b + 4) = *(const float4*)&Bs[k * 128 + (tx << 3) + 4];
            #pragma unroll
            for (int i = 0; i < 8; i++)
                #pragma unroll
                for (int j = 0; j < 8; j++) acc[i][j] = fmaf(a[i], b[j], acc[i][j]);
        }
        __syncthreads();
    }

    if (mode == 0) {
        #pragma unroll
        for (int i = 0; i < 8; i++) {
            int row = m0 + (ty << 3) + i;
            int col = n0 + (tx << 3);
            float4 o0, o1;
            o0.x = acc[i][0] + bias[col + 0];
            o0.y = acc[i][1] + bias[col + 1];
            o0.z = acc[i][2] + bias[col + 2];
            o0.w = acc[i][3] + bias[col + 3];
            o1.x = acc[i][4] + bias[col + 4];
            o1.y = acc[i][5] + bias[col + 5];
            o1.z = acc[i][6] + bias[col + 6];
            o1.w = acc[i][7] + bias[col + 7];
            *(float4*)&C[(size_t)row * N + col] = o0;
            *(float4*)&C[(size_t)row * N + col + 4] = o1;
        }
    } else if (mode == 1) {
        float us[8];
        #pragma unroll
        for (int j = 0; j < 8; j++) us[j] = Us[n0 + (tx << 3) + j];
        #pragma unroll
        for (int i = 0; i < 8; i++) {
            int row = m0 + (ty << 3) + i;
            int w, bcol;
            if (row < TBq) { w = wid[row]; bcol = row & (Bq - 1); }
            else           { w = root_wid[row - TBq]; bcol = row - TBq; }
            const float* Pe = g_PembU + (size_t)w * Hh + n0 + (tx << 3);
            const float* Pm = g_PmolU + (size_t)bcol * Hh + n0 + (tx << 3);
            float p = 0.f;
            #pragma unroll
            for (int j = 0; j < 8; j++)
                p += fmaxf(acc[i][j] + Pe[j] + Pm[j], 0.f) * us[j];
            #pragma unroll
            for (int o = 8; o; o >>= 1) p += __shfl_xor_sync(0xffffffffu, p, o, 16);
            if (tx == 0) g_spart[(size_t)blockIdx.x * MSr + row] = p;
        }
    } else {
        #pragma unroll
        for (int i = 0; i < 8; i++) {
            int j = m0 + (ty << 3) + i;
            int idx = g_cmap[j];
            int bcol = idx & (Bq - 1);
            const float* Pm = g_PmolW + (size_t)bcol * Hh + n0 + (tx << 3);
            float* dst = g_phidc + (size_t)(Bq + j) * Hh + n0 + (tx << 3);
            float4 o0, o1;
            o0.x = fmaxf(acc[i][0] + Pm[0], 0.f);
            o0.y = fmaxf(acc[i][1] + Pm[1], 0.f);
            o0.z = fmaxf(acc[i][2] + Pm[2], 0.f);
            o0.w = fmaxf(acc[i][3] + Pm[3], 0.f);
            o1.x = fmaxf(acc[i][4] + Pm[4], 0.f);
            o1.y = fmaxf(acc[i][5] + Pm[5], 0.f);
            o1.z = fmaxf(acc[i][6] + Pm[6], 0.f);
            o1.w = fmaxf(acc[i][7] + Pm[7], 0.f);
            *(float4*)dst = o0;
            *(float4*)(dst + 4) = o1;
        }
    }
}

// ---------------- housekeeping ----------------
__global__ __launch_bounds__(256)
void prep_kernel()
{
    int i = blockIdx.x * 256 + threadIdx.x;
    if (i < 5) g_acc[i] = 0.0;
    if (i == 5) { g_barc = 0; g_ccount = 0; }
    if (i == 6) g_bars = 0;
    if (i < Hh) {
        g_hbuf[(size_t)PADROW * Hh + i] = 0.f;
        g_hbufUr[(size_t)PADROW * Hh + i] = 0.f;
    }
    if (i < NCMP + 256) g_cmap[i] = 0;
}

__global__ __launch_bounds__(256)
void compact_kernel(const int* __restrict__ dirs)
{
    int i = blockIdx.x * 256 + threadIdx.x;   // grid 92*256 = 23552 exact
    if (dirs[i]) {
        int s = atomicAdd(&g_ccount, 1);
        g_cmap[s] = i;
    }
}

__global__ __launch_bounds__(256)
void build_curo(const int* __restrict__ oni, const int* __restrict__ roni)
{
    int i = blockIdx.x, tid = threadIdx.x;
    __shared__ int ids[MAXNB];
    if (tid < MAXNB)
        ids[tid] = (i < TBq) ? oni[(size_t)i * MAXNB + tid]
                             : roni[(size_t)(i - TBq) * MAXNB + tid];
    __syncthreads();
    for (int h = tid; h < Hh; h += 256) {
        float v = 0.f;
        #pragma unroll
        for (int n = 0; n < MAXNB; n++) v += g_hbuf[(size_t)ids[n] * Hh + h];
        g_curo[(size_t)i * Hh + h] = v;
    }
}

__global__ __launch_bounds__(512)
void phid0_kernel()
{
    int b = blockIdx.x, h = threadIdx.x;
    g_phidc[(size_t)b * Hh + h] = fmaxf(g_PmolW[(size_t)b * Hh + h], 0.f);
}

// ---------------- stop head finalize ----------------
__global__ __launch_bounds__(256)
void stop_final_kernel(const float* __restrict__ bs, const int* __restrict__ dirs)
{
    int i = blockIdx.x * 256 + threadIdx.x;   // grid 94*256 = 24064 exact
    float s = g_spart[i] + g_spart[MSr + i] + g_spart[2 * MSr + i] +
              g_spart[3 * MSr + i] + bs[0];
    float tgt = (i < TBq) ? (float)dirs[i] : 0.f;
    float loss = fmaxf(s, 0.f) - s * tgt + log1pf(expf(-fabsf(s)));
    float corr = ((s >= 0.5f) == (tgt > 0.5f)) ? 1.f : 0.f;
    __shared__ double r0[256], r1[256];
    int tid = threadIdx.x;
    r0[tid] = (double)loss;
    r1[tid] = (double)corr;
    __syncthreads();
    for (int o = 128; o > 0; o >>= 1) {
        if (tid < o) { r0[tid] += r0[tid + o]; r1[tid] += r1[tid + o]; }
        __syncthreads();
    }
    if (tid == 0) {
        atomicAdd(&g_acc[0], r0[0]);
        atomicAdd(&g_acc[1], r1[0]);
    }
}

// ---------------- pred head: log-softmax CE + argmax ----------------
__global__ __launch_bounds__(256)
void pred_rows_kernel(const int* __restrict__ root_wid, const int* __restrict__ y_wid)
{
    int j = blockIdx.x, tid = threadIdx.x;
    const float* row = g_logitsc + (size_t)j * Vv;
    int tgt = (j < Bq) ? root_wid[j] : y_wid[g_cmap[j - Bq]];

    float mval = -1e30f; int midx = Vv;
    for (int k = tid; k < Vv; k += 256) {
        float v = row[k];
        if (v > mval) { mval = v; midx = k; }
    }
    __shared__ float rv[256];
    __shared__ int ri[256];
    rv[tid] = mval; ri[tid] = midx; __syncthreads();
    for (int s = 128; s > 0; s >>= 1) {
        if (tid < s) {
            if (rv[tid + s] > rv[tid] ||
                (rv[tid + s] == rv[tid] && ri[tid + s] < ri[tid])) {
                rv[tid] = rv[tid + s]; ri[tid] = ri[tid + s];
            }
        }
        __syncthreads();
    }
    float gmax = rv[0]; int gidx = ri[0];
    __syncthreads();
    float p = 0.f;
    for (int k = tid; k < Vv; k += 256) p += expf(row[k] - gmax);
    rv[tid] = p; __syncthreads();
    for (int s = 128; s > 0; s >>= 1) {
        if (tid < s) rv[tid] += rv[tid + s];
        __syncthreads();
    }
    if (tid == 0) {
        float lse = gmax + logf(rv[0]);
        float ce = -(row[tgt] - lse);
        atomicAdd(&g_acc[2], (double)ce);
        if (gidx == tgt) atomicAdd(&g_acc[3], 1.0);
        atomicAdd(&g_acc[4], 1.0);
    }
}

__global__ void finalize_kernel(float* out)
{
    out[0] = (float)(g_acc[2] / (double)Bq);   // pred_loss
    out[1] = (float)(g_acc[0] / (double)Bq);   // stop_loss
    out[2] = (float)(g_acc[3] / g_acc[4]);     // pred_acc
    out[3] = (float)(g_acc[1] / (double)MSr);  // stop_acc
}

// ---------------- launch ----------------
extern "C" void kernel_launch(void* const* d_in, const int* in_sizes, int n_in,
                              void* d_out, int out_size)
{
    const float* mol_vec  = (const float*)d_in[0];
    const int*   wid      = (const int*)d_in[1];
    const int*   y_wid    = (const int*)d_in[2];
    const int*   dirs     = (const int*)d_in[3];
    const int*   hni      = (const int*)d_in[4];
    const int*   oni      = (const int*)d_in[5];
    const int*   root_wid = (const int*)d_in[6];
    const int*   roni     = (const int*)d_in[7];
    const float* emb      = (const float*)d_in[8];
    const float* Wz       = (const float*)d_in[9];
    const float* bz       = (const float*)d_in[10];
    const float* Wr       = (const float*)d_in[11];
    const float* br       = (const float*)d_in[12];
    const float* Ur       = (const float*)d_in[13];
    const float* Wh       = (const float*)d_in[14];
    const float* bh       = (const float*)d_in[15];
    const float* Wm       = (const float*)d_in[16];
    const float* bW       = (const float*)d_in[17];
    const float* U        = (const float*)d_in[18];
    const float* bU       = (const float*)d_in[19];
    const float* Wo       = (const float*)d_in[20];
    const float* bo       = (const float*)d_in[21];
    const float* Us       = (const float*)d_in[22];
    const float* bs       = (const float*)d_in[23];

    float *gPz, *gPr, *gPh, *gPembU, *gPmolU, *gPmolW, *gcuro, *gphidc, *glogitsc;
    cudaGetSymbolAddress((void**)&gPz, g_Pz);
    cudaGetSymbolAddress((void**)&gPr, g_Pr);
    cudaGetSymbolAddress((void**)&gPh, g_Ph);
    cudaGetSymbolAddress((void**)&gPembU, g_PembU);
    cudaGetSymbolAddress((void**)&gPmolU, g_PmolU);
    cudaGetSymbolAddress((void**)&gPmolW, g_PmolW);
    cudaGetSymbolAddress((void**)&gcuro, g_curo);
    cudaGetSymbolAddress((void**)&gphidc, g_phidc);
    cudaGetSymbolAddress((void**)&glogitsc, g_logitsc);

    prep_kernel<<<47, 256>>>();
    compact_kernel<<<92, 256>>>(dirs);

    // one-time precomputes
    sgemm_kernel<<<dim3(Hh / BN, Vv / BM), 256>>>(Vv, Hh, Hh, emb, Wz, bz, gPz);
    sgemm_kernel<<<dim3(Hh / BN, Vv / BM), 256>>>(Vv, Hh, Hh, emb, Wr, br, gPr);
    sgemm_kernel<<<dim3(Hh / BN, Vv / BM), 256>>>(Vv, Hh, Hh, emb, Wh, bh, gPh);
    sgemm_kernel<<<dim3(Hh / BN, Vv / BM), 256>>>(Vv, Hh, Hh, emb, U, bU, gPembU);
    sgemm_kernel<<<dim3(Hh / BN, Bq / BM), 256>>>(Bq, Hh, Ll, mol_vec, U + (size_t)2 * Hh * Hh, nullptr, gPmolU);
    sgemm_kernel<<<dim3(Hh / BN, Bq / BM), 256>>>(Bq, Hh, Ll, mol_vec, Wm + (size_t)Hh * Hh, bW, gPmolW);

    // persistent fused GRU scan (all 46 steps, 1 launch)
    scan_kernel<<<NBLK, 256>>>(wid, hni, Wz, Wh, Ur);

    // stop head: curo gather -> GEMM with fused relu + Us dot (partials)
    build_curo<<<MSr, 256>>>(oni, roni);
    dgemm_kernel<<<dim3(Hh / 128, MSr / 128), 256>>>(
        Hh, gcuro, U + (size_t)Hh * Hh, nullptr, nullptr, 1, wid, root_wid, Us);
    stop_final_kernel<<<94, 256>>>(bs, dirs);

    // pred head (compacted rows)
    phid0_kernel<<<Bq, Hh>>>();
    dgemm_kernel<<<dim3(Hh / 128, NCMP / 128), 256>>>(
        Hh, nullptr, Wm, nullptr, nullptr, 2, nullptr, nullptr, nullptr);
    dgemm_kernel<<<dim3(Vv / 128, MPRED / 128), 256>>>(
        Vv, gphidc, Wo, bo, glogitsc, 0, nullptr, nullptr, nullptr);
    pred_rows_kernel<<<MPRED, 256>>>(root_wid, y_wid);

    finalize_kernel<<<1, 1>>>((float*)d_out);
}

// round 5
// speedup vs baseline: 2.9921x; 1.0892x over previous
#include <cuda_runtime.h>
#include <cuda_bf16.h>
#include <math.h>
#include <stdint.h>

// Problem constants
#define Bq 512
#define Hh 512
#define Ll 64
#define Vv 1024
#define Tt 46
#define TBq 23552          // T*B
#define PADROW 23552
#define MSr 24064          // TB + B
#define MAXNB 8
#define NCMP 11776         // compacted pred rows (dirs==1)
#define MPRED 12288        // B + NCMP
#define NBLK 128           // persistent scan grid

// ---------------- scratch ----------------
__device__ float g_hbuf[(size_t)(TBq + 1) * Hh];
__device__ float g_hbufUr[(size_t)(TBq + 1) * Hh];
__device__ float g_Pz[(size_t)Vv * Hh];
__device__ float g_Pr[(size_t)Vv * Hh];
__device__ float g_Ph[(size_t)Vv * Hh];
__device__ float g_PembU[(size_t)Vv * Hh];
__device__ float g_PmolU[(size_t)Bq * Hh];
__device__ float g_PmolW[(size_t)Bq * Hh];
__device__ float g_sumhg[(size_t)2 * Bq * Hh];
__device__ float g_z[(size_t)Bq * Hh];
__device__ float g_th[(size_t)Bq * Hh];
__device__ float g_curo[(size_t)MSr * Hh];
__device__ float g_phidc[(size_t)MPRED * Hh];
__device__ float g_logitsc[(size_t)MPRED * Vv];
__device__ float g_spart[(size_t)8 * MSr];
__device__ int   g_cmap[NCMP + 256];
__device__ int   g_ccount;
__device__ int   g_barc;
__device__ volatile int g_bars;
__device__ double g_acc[5];
// bf16 split weights, stored [N, K]
__device__ __nv_bfloat16 g_Bu_hi[(size_t)Hh * Hh];
__device__ __nv_bfloat16 g_Bu_lo[(size_t)Hh * Hh];
__device__ __nv_bfloat16 g_Bw_hi[(size_t)Hh * Hh];
__device__ __nv_bfloat16 g_Bw_lo[(size_t)Hh * Hh];
__device__ __nv_bfloat16 g_Bo_hi[(size_t)Vv * Hh];
__device__ __nv_bfloat16 g_Bo_lo[(size_t)Vv * Hh];

// ---------------- helpers ----------------
__device__ __forceinline__ uint32_t smem_u32(const void* p) {
    uint32_t a;
    asm("{ .reg .u64 t; cvta.to.shared.u64 t, %1; cvt.u32.u64 %0, t; }"
        : "=r"(a) : "l"(p));
    return a;
}
__device__ __forceinline__ uint32_t lds32(uint32_t addr) {
    uint32_t v;
    asm volatile("ld.shared.b32 %0, [%1];" : "=r"(v) : "r"(addr));
    return v;
}
__device__ __forceinline__ void mma16816(float* d, const uint32_t* a,
                                         uint32_t b0, uint32_t b1) {
    asm volatile(
        "mma.sync.aligned.m16n8k16.row.col.f32.bf16.bf16.f32 "
        "{%0,%1,%2,%3}, {%4,%5,%6,%7}, {%8,%9}, {%0,%1,%2,%3};"
        : "+f"(d[0]), "+f"(d[1]), "+f"(d[2]), "+f"(d[3])
        : "r"(a[0]), "r"(a[1]), "r"(a[2]), "r"(a[3]), "r"(b0), "r"(b1));
}

// ---------------- software grid barrier ----------------
__device__ __forceinline__ void grid_bar(int nb)
{
    __syncthreads();
    if (threadIdx.x == 0) {
        int s = g_bars;
        __threadfence();
        int t = atomicAdd(&g_barc, 1);
        if (t == nb - 1) {
            g_barc = 0;
            __threadfence();
            g_bars = s + 1;
        } else {
            while (g_bars == s) { __nanosleep(32); }
        }
        __threadfence();
    }
    __syncthreads();
}

// ---------------- generic 64x64 SGEMM (precomputes) ----------------
#define BM 64
#define BN 64
#define BK 16

__global__ __launch_bounds__(256)
void sgemm_kernel(int M, int N, int K,
                  const float* __restrict__ A, const float* __restrict__ Bm,
                  const float* __restrict__ bias, float* __restrict__ C)
{
    __shared__ float As[BK][BM];
    __shared__ float Bs[BK][BN];
    const int tid = threadIdx.x;
    const int tx = tid & 15;
    const int ty = tid >> 4;
    const int m0 = blockIdx.y * BM;
    const int n0 = blockIdx.x * BN;

    const int a_row  = tid >> 2;
    const int a_col4 = (tid & 3) << 2;
    const int b_row  = tid >> 4;
    const int b_col4 = (tid & 15) << 2;

    const float* Aptr = A + (size_t)(m0 + a_row) * K + a_col4;
    const float* Bptr = Bm + (size_t)b_row * N + n0 + b_col4;

    float acc[4][4];
    #pragma unroll
    for (int i = 0; i < 4; i++)
        #pragma unroll
        for (int j = 0; j < 4; j++) acc[i][j] = 0.f;

    for (int k0 = 0; k0 < K; k0 += BK) {
        float4 av = *(const float4*)(Aptr + k0);
        float4 bv = *(const float4*)(Bptr + (size_t)k0 * N);
        As[a_col4 + 0][a_row] = av.x;
        As[a_col4 + 1][a_row] = av.y;
        As[a_col4 + 2][a_row] = av.z;
        As[a_col4 + 3][a_row] = av.w;
        *(float4*)&Bs[b_row][b_col4] = bv;
        __syncthreads();
        #pragma unroll
        for (int k = 0; k < BK; k++) {
            float4 a4 = *(const float4*)&As[k][ty << 2];
            float4 b4 = *(const float4*)&Bs[k][tx << 2];
            float a[4] = {a4.x, a4.y, a4.z, a4.w};
            float b[4] = {b4.x, b4.y, b4.z, b4.w};
            #pragma unroll
            for (int i = 0; i < 4; i++)
                #pragma unroll
                for (int j = 0; j < 4; j++) acc[i][j] = fmaf(a[i], b[j], acc[i][j]);
        }
        __syncthreads();
    }

    #pragma unroll
    for (int i = 0; i < 4; i++) {
        int row = m0 + (ty << 2) + i;
        int col = n0 + (tx << 2);
        float4 out;
        float b0 = bias ? bias[col + 0] : 0.f;
        float b1 = bias ? bias[col + 1] : 0.f;
        float b2 = bias ? bias[col + 2] : 0.f;
        float b3 = bias ? bias[col + 3] : 0.f;
        out.x = acc[i][0] + b0; out.y = acc[i][1] + b1;
        out.z = acc[i][2] + b2; out.w = acc[i][3] + b3;
        *(float4*)&C[(size_t)row * N + col] = out;
    }
}

// ---------------- weight transpose + bf16 split ----------------
__global__ __launch_bounds__(256)
void convT_kernel(const float* __restrict__ src, int K, int N,
                  __nv_bfloat16* __restrict__ hi, __nv_bfloat16* __restrict__ lo)
{
    __shared__ float t[32][33];
    int k0 = blockIdx.y * 32, n0 = blockIdx.x * 32;
    int tx = threadIdx.x & 31, ty = threadIdx.x >> 5;
    for (int r = ty; r < 32; r += 8)
        t[r][tx] = src[(size_t)(k0 + r) * N + n0 + tx];
    __syncthreads();
    for (int r = ty; r < 32; r += 8) {
        float v = t[tx][r];
        __nv_bfloat16 h = __float2bfloat16(v);
        float rem = v - __bfloat162float(h);
        hi[(size_t)(n0 + r) * K + k0 + tx] = h;
        lo[(size_t)(n0 + r) * K + k0 + tx] = __float2bfloat16(rem);
    }
}

// ---------------- persistent fused GRU scan ----------------
__global__ __launch_bounds__(256)
void scan_kernel(const int* __restrict__ wid, const int* __restrict__ hni,
                 const float* __restrict__ Wz, const float* __restrict__ Wh,
                 const float* __restrict__ Ur)
{
    __shared__ float sm[2048];
    __shared__ int s_ids[MAXNB];
    __shared__ int s_w;
    const int tid = threadIdx.x;
    const int nb = (int)gridDim.x;

    for (int t = 0; t < Tt; t++) {
        // ---- P1: gather (sum_h, sum_g) ----
        for (int b = (int)blockIdx.x; b < Bq; b += nb) {
            __syncthreads();
            if (tid < MAXNB) s_ids[tid] = hni[((size_t)(t * Bq + b)) * MAXNB + tid];
            if (tid == MAXNB) s_w = wid[t * Bq + b];
            __syncthreads();
            int w = s_w;
            #pragma unroll
            for (int hh = 0; hh < Hh; hh += 256) {
                int h = hh + tid;
                float xr = g_Pr[(size_t)w * Hh + h];
                float sh = 0.f, sg = 0.f;
                #pragma unroll
                for (int n = 0; n < MAXNB; n++) {
                    int id = s_ids[n];
                    float hv = g_hbuf[(size_t)id * Hh + h];
                    float gv = g_hbufUr[(size_t)id * Hh + h];
                    float r = 1.f / (1.f + expf(-(xr + gv)));
                    sh += hv;
                    sg += r * hv;
                }
                g_sumhg[(size_t)b * Hh + h] = sh;
                g_sumhg[(size_t)(Bq + b) * Hh + h] = sg;
            }
        }
        grid_bar(nb);

        // ---- P2: z / h_tilde GEMM ----
        {
            const int tt = (int)blockIdx.x;
            const int m0 = (tt >> 3) * 64;
            const int n0 = (tt & 7) * 64;
            const int grp = (m0 >= Bq);
            const float* Bm = grp ? (Wh + (size_t)Hh * Hh) : (Wz + (size_t)Hh * Hh);
            float* As = sm;
            float* Bs = sm + 1024;
            const int a_row = tid >> 2, a_c4 = (tid & 3) << 2;
            const int b_row = tid >> 4, b_c4 = (tid & 15) << 2;
            const int ty = tid >> 4, tx = tid & 15;
            const float* Aptr = g_sumhg + (size_t)(m0 + a_row) * Hh + a_c4;
            const float* Bptr = Bm + (size_t)b_row * Hh + n0 + b_c4;

            float acc[4][4];
            #pragma unroll
            for (int i = 0; i < 4; i++)
                #pragma unroll
                for (int j = 0; j < 4; j++) acc[i][j] = 0.f;

            for (int k0 = 0; k0 < Hh; k0 += 16) {
                float4 av = *(const float4*)(Aptr + k0);
                float4 bv = *(const float4*)(Bptr + (size_t)k0 * Hh);
                As[(a_c4 + 0) * 64 + a_row] = av.x;
                As[(a_c4 + 1) * 64 + a_row] = av.y;
                As[(a_c4 + 2) * 64 + a_row] = av.z;
                As[(a_c4 + 3) * 64 + a_row] = av.w;
                *(float4*)&Bs[b_row * 64 + b_c4] = bv;
                __syncthreads();
                #pragma unroll
                for (int k = 0; k < 16; k++) {
                    float4 a4 = *(const float4*)&As[k * 64 + (ty << 2)];
                    float4 b4 = *(const float4*)&Bs[k * 64 + (tx << 2)];
                    float a[4] = {a4.x, a4.y, a4.z, a4.w};
                    float b[4] = {b4.x, b4.y, b4.z, b4.w};
                    #pragma unroll
                    for (int i = 0; i < 4; i++)
                        #pragma unroll
                        for (int j = 0; j < 4; j++) acc[i][j] = fmaf(a[i], b[j], acc[i][j]);
                }
                __syncthreads();
            }
            const float* P = grp ? g_Ph : g_Pz;
            float* Cout = grp ? g_th : g_z;
            #pragma unroll
            for (int i = 0; i < 4; i++) {
                int row = m0 + (ty << 2) + i;
                int b = row & (Bq - 1);
                int w = wid[t * Bq + b];
                int col = n0 + (tx << 2);
                float4 out;
                float v0 = acc[i][0] + P[(size_t)w * Hh + col + 0];
                float v1 = acc[i][1] + P[(size_t)w * Hh + col + 1];
                float v2 = acc[i][2] + P[(size_t)w * Hh + col + 2];
                float v3 = acc[i][3] + P[(size_t)w * Hh + col + 3];
                if (grp) {
                    out.x = tanhf(v0); out.y = tanhf(v1);
                    out.z = tanhf(v2); out.w = tanhf(v3);
                } else {
                    out.x = 1.f / (1.f + expf(-v0));
                    out.y = 1.f / (1.f + expf(-v1));
                    out.z = 1.f / (1.f + expf(-v2));
                    out.w = 1.f / (1.f + expf(-v3));
                }
                *(float4*)&Cout[(size_t)b * Hh + col] = out;
            }
        }
        grid_bar(nb);

        // ---- P3: h_new ----
        {
            float* hdst = g_hbuf + (size_t)t * Bq * Hh;
            for (int i = (int)blockIdx.x * 256 + tid; i < Bq * Hh; i += nb * 256) {
                float z = g_z[i];
                hdst[i] = (1.f - z) * g_sumhg[i] + z * g_th[i];
            }
        }
        grid_bar(nb);

        // ---- P4: hbufUr[t] = h_new @ Ur ----
        {
            const int tt = (int)blockIdx.x;
            const int m0 = (tt >> 4) * 64;
            const int n0 = (tt & 15) * 32;
            float* As = sm;
            float* Bs = sm + 1024;
            const float* A = g_hbuf + (size_t)t * Bq * Hh;
            float* Cc = g_hbufUr + (size_t)t * Bq * Hh;
            const int a_row = tid >> 2, a_c4 = (tid & 3) << 2;
            const int b_row = tid >> 4, b_c2 = (tid & 15) << 1;
            const int ty = tid >> 4, tx = tid & 15;

            float acc[4][2];
            #pragma unroll
            for (int i = 0; i < 4; i++) { acc[i][0] = 0.f; acc[i][1] = 0.f; }

            for (int k0 = 0; k0 < Hh; k0 += 16) {
                float4 av = *(const float4*)(A + (size_t)(m0 + a_row) * Hh + k0 + a_c4);
                float2 bv = *(const float2*)(Ur + (size_t)(k0 + b_row) * Hh + n0 + b_c2);
                As[(a_c4 + 0) * 64 + a_row] = av.x;
                As[(a_c4 + 1) * 64 + a_row] = av.y;
                As[(a_c4 + 2) * 64 + a_row] = av.z;
                As[(a_c4 + 3) * 64 + a_row] = av.w;
                Bs[b_row * 32 + b_c2] = bv.x;
                Bs[b_row * 32 + b_c2 + 1] = bv.y;
                __syncthreads();
                #pragma unroll
                for (int k = 0; k < 16; k++) {
                    float4 a4 = *(const float4*)&As[k * 64 + (ty << 2)];
                    float b0 = Bs[k * 32 + (tx << 1)];
                    float b1 = Bs[k * 32 + (tx << 1) + 1];
                    float a[4] = {a4.x, a4.y, a4.z, a4.w};
                    #pragma unroll
                    for (int i = 0; i < 4; i++) {
                        acc[i][0] = fmaf(a[i], b0, acc[i][0]);
                        acc[i][1] = fmaf(a[i], b1, acc[i][1]);
                    }
                }
                __syncthreads();
            }
            #pragma unroll
            for (int i = 0; i < 4; i++) {
                int row = m0 + (ty << 2) + i;
                float2 out = {acc[i][0], acc[i][1]};
                *(float2*)&Cc[(size_t)row * Hh + n0 + (tx << 1)] = out;
            }
        }
        grid_bar(nb);
    }
}

// ---------------- tensor-core (mma.sync) split-bf16 GEMM, post heads ----------------
// 128x128 CTA tile, 8 warps each 32(M)x64(N), K=512 in 8 chunks of 64.
// D = A_hi@B_hi + A_hi@B_lo + A_lo@B_hi  (fp32 accum)
// mode 0: C[row][col] = d + bias[col]           (logits)
// mode 1: g_spart[(bx*2+wn)*MSr+row] = per-row dot(relu(d+Pe+Pm), Us)
// mode 2: g_phidc[Bq+j] = relu(d + PmolW[bc]) ; A rows via g_cmap
#define LDA_B 144          // padded row: 72 bf16 = 144 bytes
#define OFF_ALO 18432
#define OFF_BHI 36864
#define OFF_BLO 55296
#define TCSM_BYTES 73728

__global__ __launch_bounds__(256)
void tc_gemm_kernel(const float* __restrict__ A,
                    const __nv_bfloat16* __restrict__ Bhi,
                    const __nv_bfloat16* __restrict__ Blo,
                    const float* __restrict__ bias, float* __restrict__ C, int ldc,
                    int mode, const int* __restrict__ widp,
                    const int* __restrict__ rootp, const float* __restrict__ Us)
{
    extern __shared__ char smc[];
    const uint32_t sbase = smem_u32(smc);
    __shared__ int s_rows[128];

    const int tid = threadIdx.x;
    const int wid_ = tid >> 5;
    const int lane = tid & 31;
    const int wm = wid_ & 3;         // M group (32 rows)
    const int wn = wid_ >> 2;        // N group (64 cols)
    const int qrow = lane >> 2;      // 0..7
    const int qk = (lane & 3) << 1;  // 0,2,4,6
    const int m0 = blockIdx.y * 128;
    const int n0 = blockIdx.x * 128;

    if (tid < 128) s_rows[tid] = (mode == 2) ? g_cmap[m0 + tid] : (m0 + tid);
    __syncthreads();

    const int ar = tid >> 1;             // A row 0..127
    const int ac = (tid & 1) * 32;       // A col offset
    const int br = tid >> 1;
    const int bo = (tid & 1) * 64;       // byte offset in 128B source row

    const float* Abase = A + (size_t)s_rows[ar] * Hh + ac;
    const char* BhiBase = (const char*)(Bhi + (size_t)(n0 + br) * Hh) + bo;
    const char* BloBase = (const char*)(Blo + (size_t)(n0 + br) * Hh) + bo;

    float acc[2][8][4];
    #pragma unroll
    for (int mf = 0; mf < 2; mf++)
        #pragma unroll
        for (int nf = 0; nf < 8; nf++)
            #pragma unroll
            for (int r = 0; r < 4; r++) acc[mf][nf][r] = 0.f;

    for (int c = 0; c < 8; c++) {
        float4 av[8];
        uint4 bh[4], bl[4];
        #pragma unroll
        for (int f = 0; f < 8; f++)
            av[f] = *(const float4*)(Abase + c * 64 + f * 4);
        #pragma unroll
        for (int u = 0; u < 4; u++) {
            bh[u] = *(const uint4*)(BhiBase + c * 128 + u * 16);
            bl[u] = *(const uint4*)(BloBase + c * 128 + u * 16);
        }
        __syncthreads();   // prior compute done before overwrite

        // store A hi/lo (convert + split)
        {
            char* sa = smc + ar * LDA_B + ac * 2;
            char* sl = sa + OFF_ALO;
            #pragma unroll
            for (int f = 0; f < 8; f++) {
                float vx = av[f].x, vy = av[f].y, vz = av[f].z, vw = av[f].w;
                __nv_bfloat16 h0 = __float2bfloat16(vx);
                __nv_bfloat16 h1 = __float2bfloat16(vy);
                __nv_bfloat16 h2 = __float2bfloat16(vz);
                __nv_bfloat16 h3 = __float2bfloat16(vw);
                __nv_bfloat162 hh0, hh1, ll0, ll1;
                hh0.x = h0; hh0.y = h1; hh1.x = h2; hh1.y = h3;
                ll0.x = __float2bfloat16(vx - __bfloat162float(h0));
                ll0.y = __float2bfloat16(vy - __bfloat162float(h1));
                ll1.x = __float2bfloat16(vz - __bfloat162float(h2));
                ll1.y = __float2bfloat16(vw - __bfloat162float(h3));
                uint2 hv = {*(uint32_t*)&hh0, *(uint32_t*)&hh1};
                uint2 lv = {*(uint32_t*)&ll0, *(uint32_t*)&ll1};
                *(uint2*)(sa + f * 8) = hv;
                *(uint2*)(sl + f * 8) = lv;
            }
        }
        // store B hi/lo
        {
            char* sb = smc + OFF_BHI + br * LDA_B + bo;
            char* sbl = smc + OFF_BLO + br * LDA_B + bo;
            #pragma unroll
            for (int u = 0; u < 4; u++) {
                *(uint4*)(sb + u * 16) = bh[u];
                *(uint4*)(sbl + u * 16) = bl[u];
            }
        }
        __syncthreads();

        // compute: 4 k16 steps
        #pragma unroll
        for (int kk = 0; kk < 4; kk++) {
            const uint32_t koff = (kk * 16 + qk) * 2;
            uint32_t ah[2][4], al[2][4];
            #pragma unroll
            for (int mf = 0; mf < 2; mf++) {
                uint32_t base = sbase + (wm * 32 + mf * 16 + qrow) * LDA_B + koff;
                ah[mf][0] = lds32(base);
                ah[mf][1] = lds32(base + 8 * LDA_B);
                ah[mf][2] = lds32(base + 16);
                ah[mf][3] = lds32(base + 8 * LDA_B + 16);
                al[mf][0] = lds32(base + OFF_ALO);
                al[mf][1] = lds32(base + OFF_ALO + 8 * LDA_B);
                al[mf][2] = lds32(base + OFF_ALO + 16);
                al[mf][3] = lds32(base + OFF_ALO + 8 * LDA_B + 16);
            }
            #pragma unroll
            for (int nf = 0; nf < 8; nf++) {
                uint32_t bb = sbase + OFF_BHI + (wn * 64 + nf * 8 + qrow) * LDA_B + koff;
                uint32_t bh0 = lds32(bb);
                uint32_t bh1 = lds32(bb + 16);
                uint32_t bl0 = lds32(bb + (OFF_BLO - OFF_BHI));
                uint32_t bl1 = lds32(bb + (OFF_BLO - OFF_BHI) + 16);
                #pragma unroll
                for (int mf = 0; mf < 2; mf++) {
                    mma16816(acc[mf][nf], ah[mf], bh0, bh1);
                    mma16816(acc[mf][nf], ah[mf], bl0, bl1);
                    mma16816(acc[mf][nf], al[mf], bh0, bh1);
                }
            }
        }
    }

    // ---- epilogue ----
    if (mode == 0) {
        #pragma unroll
        for (int mf = 0; mf < 2; mf++) {
            int r0 = m0 + wm * 32 + mf * 16 + qrow;
            #pragma unroll
            for (int nf = 0; nf < 8; nf++) {
                int col = n0 + wn * 64 + nf * 8 + qk;
                float2 o0 = {acc[mf][nf][0] + bias[col], acc[mf][nf][1] + bias[col + 1]};
                float2 o1 = {acc[mf][nf][2] + bias[col], acc[mf][nf][3] + bias[col + 1]};
                *(float2*)&C[(size_t)r0 * ldc + col] = o0;
                *(float2*)&C[(size_t)(r0 + 8) * ldc + col] = o1;
            }
        }
    } else if (mode == 1) {
        int slot = blockIdx.x * 2 + wn;
        #pragma unroll
        for (int mf = 0; mf < 2; mf++) {
            int r0 = m0 + wm * 32 + mf * 16 + qrow;
            int r1 = r0 + 8;
            int w0, b0, w1, b1;
            if (r0 < TBq) { w0 = widp[r0]; b0 = r0 & (Bq - 1); }
            else          { w0 = rootp[r0 - TBq]; b0 = r0 - TBq; }
            if (r1 < TBq) { w1 = widp[r1]; b1 = r1 & (Bq - 1); }
            else          { w1 = rootp[r1 - TBq]; b1 = r1 - TBq; }
            const float* Pe0 = g_PembU + (size_t)w0 * Hh;
            const float* Pm0 = g_PmolU + (size_t)b0 * Hh;
            const float* Pe1 = g_PembU + (size_t)w1 * Hh;
            const float* Pm1 = g_PmolU + (size_t)b1 * Hh;
            float p0 = 0.f, p1 = 0.f;
            #pragma unroll
            for (int nf = 0; nf < 8; nf++) {
                int col = wn * 64 + nf * 8 + qk;   // N total = 512, n0 = bx*128
                int gc = blockIdx.x * 128 + col;
                float u0 = Us[gc], u1 = Us[gc + 1];
                p0 += fmaxf(acc[mf][nf][0] + Pe0[gc] + Pm0[gc], 0.f) * u0;
                p0 += fmaxf(acc[mf][nf][1] + Pe0[gc + 1] + Pm0[gc + 1], 0.f) * u1;
                p1 += fmaxf(acc[mf][nf][2] + Pe1[gc] + Pm1[gc], 0.f) * u0;
                p1 += fmaxf(acc[mf][nf][3] + Pe1[gc + 1] + Pm1[gc + 1], 0.f) * u1;
            }
            p0 += __shfl_xor_sync(0xffffffffu, p0, 1);
            p0 += __shfl_xor_sync(0xffffffffu, p0, 2);
            p1 += __shfl_xor_sync(0xffffffffu, p1, 1);
            p1 += __shfl_xor_sync(0xffffffffu, p1, 2);
            if ((lane & 3) == 0) {
                g_spart[(size_t)slot * MSr + r0] = p0;
                g_spart[(size_t)slot * MSr + r1] = p1;
            }
        }
    } else {
        #pragma unroll
        for (int mf = 0; mf < 2; mf++) {
            int rl0 = wm * 32 + mf * 16 + qrow;
            int j0 = m0 + rl0;
            int bc0 = s_rows[rl0] & (Bq - 1);
            int bc1 = s_rows[rl0 + 8] & (Bq - 1);
            const float* Pm0 = g_PmolW + (size_t)bc0 * Hh;
            const float* Pm1 = g_PmolW + (size_t)bc1 * Hh;
            float* d0 = g_phidc + (size_t)(Bq + j0) * Hh;
            float* d1 = g_phidc + (size_t)(Bq + j0 + 8) * Hh;
            #pragma unroll
            for (int nf = 0; nf < 8; nf++) {
                int col = n0 + wn * 64 + nf * 8 + qk;
                float2 o0 = {fmaxf(acc[mf][nf][0] + Pm0[col], 0.f),
                             fmaxf(acc[mf][nf][1] + Pm0[col + 1], 0.f)};
                float2 o1 = {fmaxf(acc[mf][nf][2] + Pm1[col], 0.f),
                             fmaxf(acc[mf][nf][3] + Pm1[col + 1], 0.f)};
                *(float2*)(d0 + col) = o0;
                *(float2*)(d1 + col) = o1;
            }
        }
    }
}

// ---------------- housekeeping ----------------
__global__ __launch_bounds__(256)
void prep_kernel()
{
    int i = blockIdx.x * 256 + threadIdx.x;
    if (i < 5) g_acc[i] = 0.0;
    if (i == 5) { g_barc = 0; g_ccount = 0; }
    if (i == 6) g_bars = 0;
    if (i < Hh) {
        g_hbuf[(size_t)PADROW * Hh + i] = 0.f;
        g_hbufUr[(size_t)PADROW * Hh + i] = 0.f;
    }
    if (i < NCMP + 256) g_cmap[i] = 0;
}

__global__ __launch_bounds__(256)
void compact_kernel(const int* __restrict__ dirs)
{
    int i = blockIdx.x * 256 + threadIdx.x;
    if (dirs[i]) {
        int s = atomicAdd(&g_ccount, 1);
        g_cmap[s] = i;
    }
}

__global__ __launch_bounds__(256)
void build_curo(const int* __restrict__ oni, const int* __restrict__ roni)
{
    int i = blockIdx.x, tid = threadIdx.x;
    __shared__ int ids[MAXNB];
    if (tid < MAXNB)
        ids[tid] = (i < TBq) ? oni[(size_t)i * MAXNB + tid]
                             : roni[(size_t)(i - TBq) * MAXNB + tid];
    __syncthreads();
    for (int h = tid; h < Hh; h += 256) {
        float v = 0.f;
        #pragma unroll
        for (int n = 0; n < MAXNB; n++) v += g_hbuf[(size_t)ids[n] * Hh + h];
        g_curo[(size_t)i * Hh + h] = v;
    }
}

__global__ __launch_bounds__(512)
void phid0_kernel()
{
    int b = blockIdx.x, h = threadIdx.x;
    g_phidc[(size_t)b * Hh + h] = fmaxf(g_PmolW[(size_t)b * Hh + h], 0.f);
}

// ---------------- stop head finalize ----------------
__global__ __launch_bounds__(256)
void stop_final_kernel(const float* __restrict__ bs, const int* __restrict__ dirs)
{
    int i = blockIdx.x * 256 + threadIdx.x;
    float s = bs[0];
    #pragma unroll
    for (int k = 0; k < 8; k++) s += g_spart[(size_t)k * MSr + i];
    float tgt = (i < TBq) ? (float)dirs[i] : 0.f;
    float loss = fmaxf(s, 0.f) - s * tgt + log1pf(expf(-fabsf(s)));
    float corr = ((s >= 0.5f) == (tgt > 0.5f)) ? 1.f : 0.f;
    __shared__ double r0[256], r1[256];
    int tid = threadIdx.x;
    r0[tid] = (double)loss;
    r1[tid] = (double)corr;
    __syncthreads();
    for (int o = 128; o > 0; o >>= 1) {
        if (tid < o) { r0[tid] += r0[tid + o]; r1[tid] += r1[tid + o]; }
        __syncthreads();
    }
    if (tid == 0) {
        atomicAdd(&g_acc[0], r0[0]);
        atomicAdd(&g_acc[1], r1[0]);
    }
}

// ---------------- pred head: log-softmax CE + argmax ----------------
__global__ __launch_bounds__(256)
void pred_rows_kernel(const int* __restrict__ root_wid, const int* __restrict__ y_wid)
{
    int j = blockIdx.x, tid = threadIdx.x;
    const float* row = g_logitsc + (size_t)j * Vv;
    int tgt = (j < Bq) ? root_wid[j] : y_wid[g_cmap[j - Bq]];

    float mval = -1e30f; int midx = Vv;
    for (int k = tid; k < Vv; k += 256) {
        float v = row[k];
        if (v > mval) { mval = v; midx = k; }
    }
    __shared__ float rv[256];
    __shared__ int ri[256];
    rv[tid] = mval; ri[tid] = midx; __syncthreads();
    for (int s = 128; s > 0; s >>= 1) {
        if (tid < s) {
            if (rv[tid + s] > rv[tid] ||
                (rv[tid + s] == rv[tid] && ri[tid + s] < ri[tid])) {
                rv[tid] = rv[tid + s]; ri[tid] = ri[tid + s];
            }
        }
        __syncthreads();
    }
    float gmax = rv[0]; int gidx = ri[0];
    __syncthreads();
    float p = 0.f;
    for (int k = tid; k < Vv; k += 256) p += expf(row[k] - gmax);
    rv[tid] = p; __syncthreads();
    for (int s = 128; s > 0; s >>= 1) {
        if (tid < s) rv[tid] += rv[tid + s];
        __syncthreads();
    }
    if (tid == 0) {
        float lse = gmax + logf(rv[0]);
        float ce = -(row[tgt] - lse);
        atomicAdd(&g_acc[2], (double)ce);
        if (gidx == tgt) atomicAdd(&g_acc[3], 1.0);
        atomicAdd(&g_acc[4], 1.0);
    }
}

__global__ void finalize_kernel(float* out)
{
    out[0] = (float)(g_acc[2] / (double)Bq);
    out[1] = (float)(g_acc[0] / (double)Bq);
    out[2] = (float)(g_acc[3] / g_acc[4]);
    out[3] = (float)(g_acc[1] / (double)MSr);
}

// ---------------- launch ----------------
extern "C" void kernel_launch(void* const* d_in, const int* in_sizes, int n_in,
                              void* d_out, int out_size)
{
    const float* mol_vec  = (const float*)d_in[0];
    const int*   wid      = (const int*)d_in[1];
    const int*   y_wid    = (const int*)d_in[2];
    const int*   dirs     = (const int*)d_in[3];
    const int*   hni      = (const int*)d_in[4];
    const int*   oni      = (const int*)d_in[5];
    const int*   root_wid = (const int*)d_in[6];
    const int*   roni     = (const int*)d_in[7];
    const float* emb      = (const float*)d_in[8];
    const float* Wz       = (const float*)d_in[9];
    const float* bz       = (const float*)d_in[10];
    const float* Wr       = (const float*)d_in[11];
    const float* br       = (const float*)d_in[12];
    const float* Ur       = (const float*)d_in[13];
    const float* Wh       = (const float*)d_in[14];
    const float* bh       = (const float*)d_in[15];
    const float* Wm       = (const float*)d_in[16];
    const float* bW       = (const float*)d_in[17];
    const float* U        = (const float*)d_in[18];
    const float* bU       = (const float*)d_in[19];
    const float* Wo       = (const float*)d_in[20];
    const float* bo       = (const float*)d_in[21];
    const float* Us       = (const float*)d_in[22];
    const float* bs       = (const float*)d_in[23];

    float *gPz, *gPr, *gPh, *gPembU, *gPmolU, *gPmolW, *gcuro, *gphidc, *glogitsc, *ghbuf;
    __nv_bfloat16 *gBuH, *gBuL, *gBwH, *gBwL, *gBoH, *gBoL;
    cudaGetSymbolAddress((void**)&gPz, g_Pz);
    cudaGetSymbolAddress((void**)&gPr, g_Pr);
    cudaGetSymbolAddress((void**)&gPh, g_Ph);
    cudaGetSymbolAddress((void**)&gPembU, g_PembU);
    cudaGetSymbolAddress((void**)&gPmolU, g_PmolU);
    cudaGetSymbolAddress((void**)&gPmolW, g_PmolW);
    cudaGetSymbolAddress((void**)&gcuro, g_curo);
    cudaGetSymbolAddress((void**)&gphidc, g_phidc);
    cudaGetSymbolAddress((void**)&glogitsc, g_logitsc);
    cudaGetSymbolAddress((void**)&ghbuf, g_hbuf);
    cudaGetSymbolAddress((void**)&gBuH, g_Bu_hi);
    cudaGetSymbolAddress((void**)&gBuL, g_Bu_lo);
    cudaGetSymbolAddress((void**)&gBwH, g_Bw_hi);
    cudaGetSymbolAddress((void**)&gBwL, g_Bw_lo);
    cudaGetSymbolAddress((void**)&gBoH, g_Bo_hi);
    cudaGetSymbolAddress((void**)&gBoL, g_Bo_lo);

    cudaFuncSetAttribute(tc_gemm_kernel,
                         cudaFuncAttributeMaxDynamicSharedMemorySize, TCSM_BYTES);

    prep_kernel<<<47, 256>>>();
    compact_kernel<<<92, 256>>>(dirs);

    // weight transposes + bf16 split
    convT_kernel<<<dim3(Hh / 32, Hh / 32), 256>>>(U + (size_t)Hh * Hh, Hh, Hh, gBuH, gBuL);
    convT_kernel<<<dim3(Hh / 32, Hh / 32), 256>>>(Wm, Hh, Hh, gBwH, gBwL);
    convT_kernel<<<dim3(Vv / 32, Hh / 32), 256>>>(Wo, Hh, Vv, gBoH, gBoL);

    // one-time precomputes
    sgemm_kernel<<<dim3(Hh / BN, Vv / BM), 256>>>(Vv, Hh, Hh, emb, Wz, bz, gPz);
    sgemm_kernel<<<dim3(Hh / BN, Vv / BM), 256>>>(Vv, Hh, Hh, emb, Wr, br, gPr);
    sgemm_kernel<<<dim3(Hh / BN, Vv / BM), 256>>>(Vv, Hh, Hh, emb, Wh, bh, gPh);
    sgemm_kernel<<<dim3(Hh / BN, Vv / BM), 256>>>(Vv, Hh, Hh, emb, U, bU, gPembU);
    sgemm_kernel<<<dim3(Hh / BN, Bq / BM), 256>>>(Bq, Hh, Ll, mol_vec, U + (size_t)2 * Hh * Hh, nullptr, gPmolU);
    sgemm_kernel<<<dim3(Hh / BN, Bq / BM), 256>>>(Bq, Hh, Ll, mol_vec, Wm + (size_t)Hh * Hh, bW, gPmolW);

    // persistent fused GRU scan
    scan_kernel<<<NBLK, 256>>>(wid, hni, Wz, Wh, Ur);

    // stop head
    build_curo<<<MSr, 256>>>(oni, roni);
    tc_gemm_kernel<<<dim3(4, MSr / 128), 256, TCSM_BYTES>>>(
        gcuro, gBuH, gBuL, nullptr, nullptr, 0, 1, wid, root_wid, Us);
    stop_final_kernel<<<94, 256>>>(bs, dirs);

    // pred head (compacted)
    phid0_kernel<<<Bq, Hh>>>();
    tc_gemm_kernel<<<dim3(4, NCMP / 128), 256, TCSM_BYTES>>>(
        ghbuf, gBwH, gBwL, nullptr, nullptr, 0, 2, nullptr, nullptr, nullptr);
    tc_gemm_kernel<<<dim3(8, MPRED / 128), 256, TCSM_BYTES>>>(
        gphidc, gBoH, gBoL, bo, glogitsc, Vv, 0, nullptr, nullptr, nullptr);
    pred_rows_kernel<<<MPRED, 256>>>(root_wid, y_wid);

    finalize_kernel<<<1, 1>>>((float*)d_out);
}

// round 6
// speedup vs baseline: 4.4748x; 1.4956x over previous
#include <cuda_runtime.h>
#include <cuda_bf16.h>
#include <math.h>
#include <stdint.h>

// Problem constants
#define Bq 512
#define Hh 512
#define Ll 64
#define Vv 1024
#define Tt 46
#define TBq 23552          // T*B
#define PADROW 23552
#define MSr 24064          // TB + B
#define MAXNB 8
#define NCMP 11776         // compacted pred rows (dirs==1)
#define MPRED 12288        // B + NCMP
#define NBLK 128           // persistent scan grid

// ---------------- scratch ----------------
__device__ float g_hbuf[(size_t)(TBq + 1) * Hh];
__device__ float g_hbufUr[(size_t)(TBq + 1) * Hh];
__device__ float g_Pz[(size_t)Vv * Hh];
__device__ float g_Pr[(size_t)Vv * Hh];
__device__ float g_Ph[(size_t)Vv * Hh];
__device__ float g_PembU[(size_t)Vv * Hh];
__device__ float g_PmolU[(size_t)Bq * Hh];
__device__ float g_PmolW[(size_t)Bq * Hh];
__device__ float g_sumh[(size_t)Bq * Hh];
__device__ float g_z[(size_t)Bq * Hh];
__device__ float g_th[(size_t)Bq * Hh];
__device__ float g_curo[(size_t)MSr * Hh];
__device__ float g_phidc[(size_t)MPRED * Hh];
__device__ float g_logitsc[(size_t)MPRED * Vv];
__device__ float g_spart[(size_t)8 * MSr];
__device__ int   g_cmap[NCMP + 256];
__device__ int   g_ccount;
__device__ int   g_barc;
__device__ volatile int g_bars;
__device__ double g_acc[5];
// scan split activations
__device__ __nv_bfloat16 g_shg_hi[(size_t)2 * Bq * Hh];
__device__ __nv_bfloat16 g_shg_lo[(size_t)2 * Bq * Hh];
__device__ __nv_bfloat16 g_h_hi[(size_t)Bq * Hh];
__device__ __nv_bfloat16 g_h_lo[(size_t)Bq * Hh];
// bf16 split weights, stored [N, K]
__device__ __nv_bfloat16 g_Bu_hi[(size_t)Hh * Hh];
__device__ __nv_bfloat16 g_Bu_lo[(size_t)Hh * Hh];
__device__ __nv_bfloat16 g_Bw_hi[(size_t)Hh * Hh];
__device__ __nv_bfloat16 g_Bw_lo[(size_t)Hh * Hh];
__device__ __nv_bfloat16 g_Bo_hi[(size_t)Vv * Hh];
__device__ __nv_bfloat16 g_Bo_lo[(size_t)Vv * Hh];
__device__ __nv_bfloat16 g_Bzh_hi[(size_t)2 * Hh * Hh];  // rows 0-511 Wz_bot^T, 512-1023 Wh_bot^T
__device__ __nv_bfloat16 g_Bzh_lo[(size_t)2 * Hh * Hh];
__device__ __nv_bfloat16 g_BUr_hi[(size_t)Hh * Hh];
__device__ __nv_bfloat16 g_BUr_lo[(size_t)Hh * Hh];
__device__ __nv_bfloat16 g_Bz0_hi[(size_t)Hh * Hh];
__device__ __nv_bfloat16 g_Bz0_lo[(size_t)Hh * Hh];
__device__ __nv_bfloat16 g_Br0_hi[(size_t)Hh * Hh];
__device__ __nv_bfloat16 g_Br0_lo[(size_t)Hh * Hh];
__device__ __nv_bfloat16 g_Bh0_hi[(size_t)Hh * Hh];
__device__ __nv_bfloat16 g_Bh0_lo[(size_t)Hh * Hh];
__device__ __nv_bfloat16 g_BU0_hi[(size_t)Hh * Hh];
__device__ __nv_bfloat16 g_BU0_lo[(size_t)Hh * Hh];

// ---------------- helpers ----------------
__device__ __forceinline__ uint32_t smem_u32(const void* p) {
    uint32_t a;
    asm("{ .reg .u64 t; cvta.to.shared.u64 t, %1; cvt.u32.u64 %0, t; }"
        : "=r"(a) : "l"(p));
    return a;
}
__device__ __forceinline__ uint32_t lds32(uint32_t addr) {
    uint32_t v;
    asm volatile("ld.shared.b32 %0, [%1];" : "=r"(v) : "r"(addr));
    return v;
}
__device__ __forceinline__ void mma16816(float* d, const uint32_t* a,
                                         uint32_t b0, uint32_t b1) {
    asm volatile(
        "mma.sync.aligned.m16n8k16.row.col.f32.bf16.bf16.f32 "
        "{%0,%1,%2,%3}, {%4,%5,%6,%7}, {%8,%9}, {%0,%1,%2,%3};"
        : "+f"(d[0]), "+f"(d[1]), "+f"(d[2]), "+f"(d[3])
        : "r"(a[0]), "r"(a[1]), "r"(a[2]), "r"(a[3]), "r"(b0), "r"(b1));
}
__device__ __forceinline__ void splitbf(float v, __nv_bfloat16& h, __nv_bfloat16& l) {
    h = __float2bfloat16(v);
    l = __float2bfloat16(v - __bfloat162float(h));
}

// ---------------- software grid barrier ----------------
__device__ __forceinline__ void grid_bar(int nb)
{
    __syncthreads();
    if (threadIdx.x == 0) {
        int s = g_bars;
        __threadfence();
        int t = atomicAdd(&g_barc, 1);
        if (t == nb - 1) {
            g_barc = 0;
            __threadfence();
            g_bars = s + 1;
        } else {
            while (g_bars == s) { __nanosleep(32); }
        }
        __threadfence();
    }
    __syncthreads();
}

// ---------------- generic 64x64 SGEMM (small precomputes) ----------------
#define BM 64
#define BN 64
#define BK 16

__global__ __launch_bounds__(256)
void sgemm_kernel(int M, int N, int K,
                  const float* __restrict__ A, const float* __restrict__ Bm,
                  const float* __restrict__ bias, float* __restrict__ C)
{
    __shared__ float As[BK][BM];
    __shared__ float Bs[BK][BN];
    const int tid = threadIdx.x;
    const int tx = tid & 15;
    const int ty = tid >> 4;
    const int m0 = blockIdx.y * BM;
    const int n0 = blockIdx.x * BN;

    const int a_row  = tid >> 2;
    const int a_col4 = (tid & 3) << 2;
    const int b_row  = tid >> 4;
    const int b_col4 = (tid & 15) << 2;

    const float* Aptr = A + (size_t)(m0 + a_row) * K + a_col4;
    const float* Bptr = Bm + (size_t)b_row * N + n0 + b_col4;

    float acc[4][4];
    #pragma unroll
    for (int i = 0; i < 4; i++)
        #pragma unroll
        for (int j = 0; j < 4; j++) acc[i][j] = 0.f;

    for (int k0 = 0; k0 < K; k0 += BK) {
        float4 av = *(const float4*)(Aptr + k0);
        float4 bv = *(const float4*)(Bptr + (size_t)k0 * N);
        As[a_col4 + 0][a_row] = av.x;
        As[a_col4 + 1][a_row] = av.y;
        As[a_col4 + 2][a_row] = av.z;
        As[a_col4 + 3][a_row] = av.w;
        *(float4*)&Bs[b_row][b_col4] = bv;
        __syncthreads();
        #pragma unroll
        for (int k = 0; k < BK; k++) {
            float4 a4 = *(const float4*)&As[k][ty << 2];
            float4 b4 = *(const float4*)&Bs[k][tx << 2];
            float a[4] = {a4.x, a4.y, a4.z, a4.w};
            float b[4] = {b4.x, b4.y, b4.z, b4.w};
            #pragma unroll
            for (int i = 0; i < 4; i++)
                #pragma unroll
                for (int j = 0; j < 4; j++) acc[i][j] = fmaf(a[i], b[j], acc[i][j]);
        }
        __syncthreads();
    }

    #pragma unroll
    for (int i = 0; i < 4; i++) {
        int row = m0 + (ty << 2) + i;
        int col = n0 + (tx << 2);
        float4 out;
        float b0 = bias ? bias[col + 0] : 0.f;
        float b1 = bias ? bias[col + 1] : 0.f;
        float b2 = bias ? bias[col + 2] : 0.f;
        float b3 = bias ? bias[col + 3] : 0.f;
        out.x = acc[i][0] + b0; out.y = acc[i][1] + b1;
        out.z = acc[i][2] + b2; out.w = acc[i][3] + b3;
        *(float4*)&C[(size_t)row * N + col] = out;
    }
}

// ---------------- weight transpose + bf16 split ----------------
__global__ __launch_bounds__(256)
void convT_kernel(const float* __restrict__ src, int K, int N,
                  __nv_bfloat16* __restrict__ hi, __nv_bfloat16* __restrict__ lo)
{
    __shared__ float t[32][33];
    int k0 = blockIdx.y * 32, n0 = blockIdx.x * 32;
    int tx = threadIdx.x & 31, ty = threadIdx.x >> 5;
    for (int r = ty; r < 32; r += 8)
        t[r][tx] = src[(size_t)(k0 + r) * N + n0 + tx];
    __syncthreads();
    for (int r = ty; r < 32; r += 8) {
        float v = t[tx][r];
        __nv_bfloat16 h, l;
        splitbf(v, h, l);
        hi[(size_t)(n0 + r) * K + k0 + tx] = h;
        lo[(size_t)(n0 + r) * K + k0 + tx] = l;
    }
}

// ---------------- persistent fused GRU scan (tensor-core GEMMs) ----------------
#define SLDA 144    // padded smem row: 64 bf16 = 128B + 16B pad

__global__ __launch_bounds__(256)
void scan_kernel(const int* __restrict__ wid, const int* __restrict__ hni)
{
    __shared__ __align__(16) char smAhi[64 * SLDA];
    __shared__ __align__(16) char smAlo[64 * SLDA];
    __shared__ __align__(16) char smBhi[64 * SLDA];
    __shared__ __align__(16) char smBlo[64 * SLDA];
    __shared__ int s_ids[MAXNB];
    __shared__ int s_w;
    const uint32_t uAhi = smem_u32(smAhi);
    const uint32_t uAlo = smem_u32(smAlo);
    const uint32_t uBhi = smem_u32(smBhi);
    const uint32_t uBlo = smem_u32(smBlo);

    const int tid = threadIdx.x;
    const int nb = (int)gridDim.x;
    const int wid_ = tid >> 5;
    const int lane = tid & 31;
    const int wm = wid_ & 3;
    const int wn = wid_ >> 2;
    const int qrow = lane >> 2;
    const int qk = (lane & 3) << 1;

    for (int t = 0; t < Tt; t++) {
        // ---- P1: gather sum_h / sum_g, emit fp32 sum_h + bf16 splits ----
        for (int b = (int)blockIdx.x; b < Bq; b += nb) {
            __syncthreads();
            if (tid < MAXNB) s_ids[tid] = hni[((size_t)(t * Bq + b)) * MAXNB + tid];
            if (tid == MAXNB) s_w = wid[t * Bq + b];
            __syncthreads();
            int w = s_w;
            #pragma unroll
            for (int hh = 0; hh < Hh; hh += 256) {
                int h = hh + tid;
                float xr = g_Pr[(size_t)w * Hh + h];
                float sh = 0.f, sg = 0.f;
                #pragma unroll
                for (int n = 0; n < MAXNB; n++) {
                    int id = s_ids[n];
                    float hv = g_hbuf[(size_t)id * Hh + h];
                    float gv = g_hbufUr[(size_t)id * Hh + h];
                    float r = 1.f / (1.f + expf(-(xr + gv)));
                    sh += hv;
                    sg += r * hv;
                }
                g_sumh[(size_t)b * Hh + h] = sh;
                __nv_bfloat16 hi, lo;
                splitbf(sh, hi, lo);
                g_shg_hi[(size_t)b * Hh + h] = hi;
                g_shg_lo[(size_t)b * Hh + h] = lo;
                splitbf(sg, hi, lo);
                g_shg_hi[(size_t)(Bq + b) * Hh + h] = hi;
                g_shg_lo[(size_t)(Bq + b) * Hh + h] = lo;
            }
        }
        grid_bar(nb);

        // ---- P2: [sum_h; sum_g] @ [WzbT; WhbT] via mma (64x64 tile, 128 tiles) ----
        {
            const int blk = (int)blockIdx.x;
            const int m0 = (blk >> 3) * 64;
            const int n0 = (blk & 7) * 64;
            const int grp = (m0 >= Bq);
            const int brow0 = grp * Bq + n0;

            float acc[4][4];
            #pragma unroll
            for (int nf = 0; nf < 4; nf++)
                #pragma unroll
                for (int r = 0; r < 4; r++) acc[nf][r] = 0.f;

            const int lr = tid >> 2, lq = tid & 3;
            const char* gAh = (const char*)(g_shg_hi + (size_t)(m0 + lr) * Hh) + lq * 32;
            const char* gAl = (const char*)(g_shg_lo + (size_t)(m0 + lr) * Hh) + lq * 32;
            const char* gBh = (const char*)(g_Bzh_hi + (size_t)(brow0 + lr) * Hh) + lq * 32;
            const char* gBl = (const char*)(g_Bzh_lo + (size_t)(brow0 + lr) * Hh) + lq * 32;

            for (int c = 0; c < 8; c++) {
                uint4 ah0 = *(const uint4*)(gAh + c * 128);
                uint4 ah1 = *(const uint4*)(gAh + c * 128 + 16);
                uint4 al0 = *(const uint4*)(gAl + c * 128);
                uint4 al1 = *(const uint4*)(gAl + c * 128 + 16);
                uint4 bh0 = *(const uint4*)(gBh + c * 128);
                uint4 bh1 = *(const uint4*)(gBh + c * 128 + 16);
                uint4 bl0 = *(const uint4*)(gBl + c * 128);
                uint4 bl1 = *(const uint4*)(gBl + c * 128 + 16);
                __syncthreads();
                char* d = smAhi + lr * SLDA + lq * 32;
                *(uint4*)d = ah0; *(uint4*)(d + 16) = ah1;
                d = smAlo + lr * SLDA + lq * 32;
                *(uint4*)d = al0; *(uint4*)(d + 16) = al1;
                d = smBhi + lr * SLDA + lq * 32;
                *(uint4*)d = bh0; *(uint4*)(d + 16) = bh1;
                d = smBlo + lr * SLDA + lq * 32;
                *(uint4*)d = bl0; *(uint4*)(d + 16) = bl1;
                __syncthreads();
                #pragma unroll
                for (int kk = 0; kk < 4; kk++) {
                    const uint32_t koff = (kk * 16 + qk) * 2;
                    uint32_t base = (wm * 16 + qrow) * SLDA + koff;
                    uint32_t ah[4], al[4];
                    ah[0] = lds32(uAhi + base);
                    ah[1] = lds32(uAhi + base + 8 * SLDA);
                    ah[2] = lds32(uAhi + base + 16);
                    ah[3] = lds32(uAhi + base + 8 * SLDA + 16);
                    al[0] = lds32(uAlo + base);
                    al[1] = lds32(uAlo + base + 8 * SLDA);
                    al[2] = lds32(uAlo + base + 16);
                    al[3] = lds32(uAlo + base + 8 * SLDA + 16);
                    #pragma unroll
                    for (int nf = 0; nf < 4; nf++) {
                        uint32_t bb = (wn * 32 + nf * 8 + qrow) * SLDA + koff;
                        uint32_t b0 = lds32(uBhi + bb);
                        uint32_t b1 = lds32(uBhi + bb + 16);
                        uint32_t c0 = lds32(uBlo + bb);
                        uint32_t c1 = lds32(uBlo + bb + 16);
                        mma16816(acc[nf], ah, b0, b1);
                        mma16816(acc[nf], ah, c0, c1);
                        mma16816(acc[nf], al, b0, b1);
                    }
                }
            }
            // epilogue: + P[w], activation
            const float* P = grp ? g_Ph : g_Pz;
            float* Cout = grp ? g_th : g_z;
            int r0 = m0 + wm * 16 + qrow;
            int b0 = r0 & (Bq - 1), b1 = (r0 + 8) & (Bq - 1);
            int w0 = wid[t * Bq + b0], w1 = wid[t * Bq + b1];
            #pragma unroll
            for (int nf = 0; nf < 4; nf++) {
                int col = n0 + wn * 32 + nf * 8 + qk;
                float v00 = acc[nf][0] + P[(size_t)w0 * Hh + col];
                float v01 = acc[nf][1] + P[(size_t)w0 * Hh + col + 1];
                float v10 = acc[nf][2] + P[(size_t)w1 * Hh + col];
                float v11 = acc[nf][3] + P[(size_t)w1 * Hh + col + 1];
                float2 o0, o1;
                if (grp) {
                    o0.x = tanhf(v00); o0.y = tanhf(v01);
                    o1.x = tanhf(v10); o1.y = tanhf(v11);
                } else {
                    o0.x = 1.f / (1.f + expf(-v00));
                    o0.y = 1.f / (1.f + expf(-v01));
                    o1.x = 1.f / (1.f + expf(-v10));
                    o1.y = 1.f / (1.f + expf(-v11));
                }
                *(float2*)&Cout[(size_t)b0 * Hh + col] = o0;
                *(float2*)&Cout[(size_t)b1 * Hh + col] = o1;
            }
        }
        grid_bar(nb);

        // ---- P3: h_new (fp32 + bf16 split) ----
        {
            float* hdst = g_hbuf + (size_t)t * Bq * Hh;
            for (int i = (int)blockIdx.x * 256 + tid; i < Bq * Hh; i += nb * 256) {
                float z = g_z[i];
                float h = (1.f - z) * g_sumh[i] + z * g_th[i];
                hdst[i] = h;
                __nv_bfloat16 hi, lo;
                splitbf(h, hi, lo);
                g_h_hi[i] = hi;
                g_h_lo[i] = lo;
            }
        }
        grid_bar(nb);

        // ---- P4: hbufUr[t] = h_new @ Ur via mma (64x32 tile, 128 tiles) ----
        {
            const int blk = (int)blockIdx.x;
            const int m0 = (blk >> 4) * 64;
            const int n0 = (blk & 15) * 32;

            float acc[2][4];
            #pragma unroll
            for (int nf = 0; nf < 2; nf++)
                #pragma unroll
                for (int r = 0; r < 4; r++) acc[nf][r] = 0.f;

            const int lr = tid >> 2, lq = tid & 3;   // A: 64 rows, 32B each
            const int br = tid >> 3, bq = tid & 7;   // B: 32 rows, 16B each
            const char* gAh = (const char*)(g_h_hi + (size_t)(m0 + lr) * Hh) + lq * 32;
            const char* gAl = (const char*)(g_h_lo + (size_t)(m0 + lr) * Hh) + lq * 32;
            const char* gBh = (const char*)(g_BUr_hi + (size_t)(n0 + br) * Hh) + bq * 16;
            const char* gBl = (const char*)(g_BUr_lo + (size_t)(n0 + br) * Hh) + bq * 16;

            for (int c = 0; c < 8; c++) {
                uint4 ah0 = *(const uint4*)(gAh + c * 128);
                uint4 ah1 = *(const uint4*)(gAh + c * 128 + 16);
                uint4 al0 = *(const uint4*)(gAl + c * 128);
                uint4 al1 = *(const uint4*)(gAl + c * 128 + 16);
                uint4 bh0 = *(const uint4*)(gBh + c * 128);
                uint4 bl0 = *(const uint4*)(gBl + c * 128);
                __syncthreads();
                char* d = smAhi + lr * SLDA + lq * 32;
                *(uint4*)d = ah0; *(uint4*)(d + 16) = ah1;
                d = smAlo + lr * SLDA + lq * 32;
                *(uint4*)d = al0; *(uint4*)(d + 16) = al1;
                *(uint4*)(smBhi + br * SLDA + bq * 16) = bh0;
                *(uint4*)(smBlo + br * SLDA + bq * 16) = bl0;
                __syncthreads();
                #pragma unroll
                for (int kk = 0; kk < 4; kk++) {
                    const uint32_t koff = (kk * 16 + qk) * 2;
                    uint32_t base = (wm * 16 + qrow) * SLDA + koff;
                    uint32_t ah[4], al[4];
                    ah[0] = lds32(uAhi + base);
                    ah[1] = lds32(uAhi + base + 8 * SLDA);
                    ah[2] = lds32(uAhi + base + 16);
                    ah[3] = lds32(uAhi + base + 8 * SLDA + 16);
                    al[0] = lds32(uAlo + base);
                    al[1] = lds32(uAlo + base + 8 * SLDA);
                    al[2] = lds32(uAlo + base + 16);
                    al[3] = lds32(uAlo + base + 8 * SLDA + 16);
                    #pragma unroll
                    for (int nf = 0; nf < 2; nf++) {
                        uint32_t bb = (wn * 16 + nf * 8 + qrow) * SLDA + koff;
                        uint32_t b0 = lds32(uBhi + bb);
                        uint32_t b1 = lds32(uBhi + bb + 16);
                        uint32_t c0 = lds32(uBlo + bb);
                        uint32_t c1 = lds32(uBlo + bb + 16);
                        mma16816(acc[nf], ah, b0, b1);
                        mma16816(acc[nf], ah, c0, c1);
                        mma16816(acc[nf], al, b0, b1);
                    }
                }
            }
            float* Cc = g_hbufUr + (size_t)t * Bq * Hh;
            int r0 = m0 + wm * 16 + qrow;
            #pragma unroll
            for (int nf = 0; nf < 2; nf++) {
                int col = n0 + wn * 16 + nf * 8 + qk;
                float2 o0 = {acc[nf][0], acc[nf][1]};
                float2 o1 = {acc[nf][2], acc[nf][3]};
                *(float2*)&Cc[(size_t)r0 * Hh + col] = o0;
                *(float2*)&Cc[(size_t)(r0 + 8) * Hh + col] = o1;
            }
        }
        grid_bar(nb);
    }
}

// ---------------- tensor-core (mma.sync) split-bf16 GEMM, post heads ----------------
#define LDA_B 144
#define OFF_ALO 18432
#define OFF_BHI 36864
#define OFF_BLO 55296
#define TCSM_BYTES 73728

__global__ __launch_bounds__(256)
void tc_gemm_kernel(const float* __restrict__ A,
                    const __nv_bfloat16* __restrict__ Bhi,
                    const __nv_bfloat16* __restrict__ Blo,
                    const float* __restrict__ bias, float* __restrict__ C, int ldc,
                    int mode, const int* __restrict__ widp,
                    const int* __restrict__ rootp, const float* __restrict__ Us)
{
    extern __shared__ char smc[];
    const uint32_t sbase = smem_u32(smc);
    __shared__ int s_rows[128];

    const int tid = threadIdx.x;
    const int wid_ = tid >> 5;
    const int lane = tid & 31;
    const int wm = wid_ & 3;
    const int wn = wid_ >> 2;
    const int qrow = lane >> 2;
    const int qk = (lane & 3) << 1;
    const int m0 = blockIdx.y * 128;
    const int n0 = blockIdx.x * 128;

    if (tid < 128) s_rows[tid] = (mode == 2) ? g_cmap[m0 + tid] : (m0 + tid);
    __syncthreads();

    const int ar = tid >> 1;
    const int ac = (tid & 1) * 32;
    const int br = tid >> 1;
    const int bo = (tid & 1) * 64;

    const float* Abase = A + (size_t)s_rows[ar] * Hh + ac;
    const char* BhiBase = (const char*)(Bhi + (size_t)(n0 + br) * Hh) + bo;
    const char* BloBase = (const char*)(Blo + (size_t)(n0 + br) * Hh) + bo;

    float acc[2][8][4];
    #pragma unroll
    for (int mf = 0; mf < 2; mf++)
        #pragma unroll
        for (int nf = 0; nf < 8; nf++)
            #pragma unroll
            for (int r = 0; r < 4; r++) acc[mf][nf][r] = 0.f;

    for (int c = 0; c < 8; c++) {
        float4 av[8];
        uint4 bh[4], bl[4];
        #pragma unroll
        for (int f = 0; f < 8; f++)
            av[f] = *(const float4*)(Abase + c * 64 + f * 4);
        #pragma unroll
        for (int u = 0; u < 4; u++) {
            bh[u] = *(const uint4*)(BhiBase + c * 128 + u * 16);
            bl[u] = *(const uint4*)(BloBase + c * 128 + u * 16);
        }
        __syncthreads();

        {
            char* sa = smc + ar * LDA_B + ac * 2;
            char* sl = sa + OFF_ALO;
            #pragma unroll
            for (int f = 0; f < 8; f++) {
                __nv_bfloat16 h0, h1, h2, h3, l0, l1, l2, l3;
                splitbf(av[f].x, h0, l0);
                splitbf(av[f].y, h1, l1);
                splitbf(av[f].z, h2, l2);
                splitbf(av[f].w, h3, l3);
                __nv_bfloat162 hh0, hh1, ll0, ll1;
                hh0.x = h0; hh0.y = h1; hh1.x = h2; hh1.y = h3;
                ll0.x = l0; ll0.y = l1; ll1.x = l2; ll1.y = l3;
                uint2 hv = {*(uint32_t*)&hh0, *(uint32_t*)&hh1};
                uint2 lv = {*(uint32_t*)&ll0, *(uint32_t*)&ll1};
                *(uint2*)(sa + f * 8) = hv;
                *(uint2*)(sl + f * 8) = lv;
            }
        }
        {
            char* sb = smc + OFF_BHI + br * LDA_B + bo;
            char* sbl = smc + OFF_BLO + br * LDA_B + bo;
            #pragma unroll
            for (int u = 0; u < 4; u++) {
                *(uint4*)(sb + u * 16) = bh[u];
                *(uint4*)(sbl + u * 16) = bl[u];
            }
        }
        __syncthreads();

        #pragma unroll
        for (int kk = 0; kk < 4; kk++) {
            const uint32_t koff = (kk * 16 + qk) * 2;
            uint32_t ah[2][4], al[2][4];
            #pragma unroll
            for (int mf = 0; mf < 2; mf++) {
                uint32_t base = sbase + (wm * 32 + mf * 16 + qrow) * LDA_B + koff;
                ah[mf][0] = lds32(base);
                ah[mf][1] = lds32(base + 8 * LDA_B);
                ah[mf][2] = lds32(base + 16);
                ah[mf][3] = lds32(base + 8 * LDA_B + 16);
                al[mf][0] = lds32(base + OFF_ALO);
                al[mf][1] = lds32(base + OFF_ALO + 8 * LDA_B);
                al[mf][2] = lds32(base + OFF_ALO + 16);
                al[mf][3] = lds32(base + OFF_ALO + 8 * LDA_B + 16);
            }
            #pragma unroll
            for (int nf = 0; nf < 8; nf++) {
                uint32_t bb = sbase + OFF_BHI + (wn * 64 + nf * 8 + qrow) * LDA_B + koff;
                uint32_t bh0 = lds32(bb);
                uint32_t bh1 = lds32(bb + 16);
                uint32_t bl0 = lds32(bb + (OFF_BLO - OFF_BHI));
                uint32_t bl1 = lds32(bb + (OFF_BLO - OFF_BHI) + 16);
                #pragma unroll
                for (int mf = 0; mf < 2; mf++) {
                    mma16816(acc[mf][nf], ah[mf], bh0, bh1);
                    mma16816(acc[mf][nf], ah[mf], bl0, bl1);
                    mma16816(acc[mf][nf], al[mf], bh0, bh1);
                }
            }
        }
    }

    if (mode == 0) {
        #pragma unroll
        for (int mf = 0; mf < 2; mf++) {
            int r0 = m0 + wm * 32 + mf * 16 + qrow;
            #pragma unroll
            for (int nf = 0; nf < 8; nf++) {
                int col = n0 + wn * 64 + nf * 8 + qk;
                float2 o0 = {acc[mf][nf][0] + bias[col], acc[mf][nf][1] + bias[col + 1]};
                float2 o1 = {acc[mf][nf][2] + bias[col], acc[mf][nf][3] + bias[col + 1]};
                *(float2*)&C[(size_t)r0 * ldc + col] = o0;
                *(float2*)&C[(size_t)(r0 + 8) * ldc + col] = o1;
            }
        }
    } else if (mode == 1) {
        int slot = blockIdx.x * 2 + wn;
        #pragma unroll
        for (int mf = 0; mf < 2; mf++) {
            int r0 = m0 + wm * 32 + mf * 16 + qrow;
            int r1 = r0 + 8;
            int w0, b0, w1, b1;
            if (r0 < TBq) { w0 = widp[r0]; b0 = r0 & (Bq - 1); }
            else          { w0 = rootp[r0 - TBq]; b0 = r0 - TBq; }
            if (r1 < TBq) { w1 = widp[r1]; b1 = r1 & (Bq - 1); }
            else          { w1 = rootp[r1 - TBq]; b1 = r1 - TBq; }
            const float* Pe0 = g_PembU + (size_t)w0 * Hh;
            const float* Pm0 = g_PmolU + (size_t)b0 * Hh;
            const float* Pe1 = g_PembU + (size_t)w1 * Hh;
            const float* Pm1 = g_PmolU + (size_t)b1 * Hh;
            float p0 = 0.f, p1 = 0.f;
            #pragma unroll
            for (int nf = 0; nf < 8; nf++) {
                int col = wn * 64 + nf * 8 + qk;
                int gc = blockIdx.x * 128 + col;
                float u0 = Us[gc], u1 = Us[gc + 1];
                p0 += fmaxf(acc[mf][nf][0] + Pe0[gc] + Pm0[gc], 0.f) * u0;
                p0 += fmaxf(acc[mf][nf][1] + Pe0[gc + 1] + Pm0[gc + 1], 0.f) * u1;
                p1 += fmaxf(acc[mf][nf][2] + Pe1[gc] + Pm1[gc], 0.f) * u0;
                p1 += fmaxf(acc[mf][nf][3] + Pe1[gc + 1] + Pm1[gc + 1], 0.f) * u1;
            }
            p0 += __shfl_xor_sync(0xffffffffu, p0, 1);
            p0 += __shfl_xor_sync(0xffffffffu, p0, 2);
            p1 += __shfl_xor_sync(0xffffffffu, p1, 1);
            p1 += __shfl_xor_sync(0xffffffffu, p1, 2);
            if ((lane & 3) == 0) {
                g_spart[(size_t)slot * MSr + r0] = p0;
                g_spart[(size_t)slot * MSr + r1] = p1;
            }
        }
    } else {
        #pragma unroll
        for (int mf = 0; mf < 2; mf++) {
            int rl0 = wm * 32 + mf * 16 + qrow;
            int j0 = m0 + rl0;
            int bc0 = s_rows[rl0] & (Bq - 1);
            int bc1 = s_rows[rl0 + 8] & (Bq - 1);
            const float* Pm0 = g_PmolW + (size_t)bc0 * Hh;
            const float* Pm1 = g_PmolW + (size_t)bc1 * Hh;
            float* d0 = g_phidc + (size_t)(Bq + j0) * Hh;
            float* d1 = g_phidc + (size_t)(Bq + j0 + 8) * Hh;
            #pragma unroll
            for (int nf = 0; nf < 8; nf++) {
                int col = n0 + wn * 64 + nf * 8 + qk;
                float2 o0 = {fmaxf(acc[mf][nf][0] + Pm0[col], 0.f),
                             fmaxf(acc[mf][nf][1] + Pm0[col + 1], 0.f)};
                float2 o1 = {fmaxf(acc[mf][nf][2] + Pm1[col], 0.f),
                             fmaxf(acc[mf][nf][3] + Pm1[col + 1], 0.f)};
                *(float2*)(d0 + col) = o0;
                *(float2*)(d1 + col) = o1;
            }
        }
    }
}

// ---------------- housekeeping ----------------
__global__ __launch_bounds__(256)
void prep_kernel()
{
    int i = blockIdx.x * 256 + threadIdx.x;
    if (i < 5) g_acc[i] = 0.0;
    if (i == 5) { g_barc = 0; g_ccount = 0; }
    if (i == 6) g_bars = 0;
    if (i < Hh) {
        g_hbuf[(size_t)PADROW * Hh + i] = 0.f;
        g_hbufUr[(size_t)PADROW * Hh + i] = 0.f;
    }
    if (i < NCMP + 256) g_cmap[i] = 0;
}

__global__ __launch_bounds__(256)
void compact_kernel(const int* __restrict__ dirs)
{
    int i = blockIdx.x * 256 + threadIdx.x;
    if (dirs[i]) {
        int s = atomicAdd(&g_ccount, 1);
        g_cmap[s] = i;
    }
}

__global__ __launch_bounds__(256)
void build_curo(const int* __restrict__ oni, const int* __restrict__ roni)
{
    int i = blockIdx.x, tid = threadIdx.x;
    __shared__ int ids[MAXNB];
    if (tid < MAXNB)
        ids[tid] = (i < TBq) ? oni[(size_t)i * MAXNB + tid]
                             : roni[(size_t)(i - TBq) * MAXNB + tid];
    __syncthreads();
    for (int h = tid; h < Hh; h += 256) {
        float v = 0.f;
        #pragma unroll
        for (int n = 0; n < MAXNB; n++) v += g_hbuf[(size_t)ids[n] * Hh + h];
        g_curo[(size_t)i * Hh + h] = v;
    }
}

__global__ __launch_bounds__(512)
void phid0_kernel()
{
    int b = blockIdx.x, h = threadIdx.x;
    g_phidc[(size_t)b * Hh + h] = fmaxf(g_PmolW[(size_t)b * Hh + h], 0.f);
}

// ---------------- stop head finalize ----------------
__global__ __launch_bounds__(256)
void stop_final_kernel(const float* __restrict__ bs, const int* __restrict__ dirs)
{
    int i = blockIdx.x * 256 + threadIdx.x;
    float s = bs[0];
    #pragma unroll
    for (int k = 0; k < 8; k++) s += g_spart[(size_t)k * MSr + i];
    float tgt = (i < TBq) ? (float)dirs[i] : 0.f;
    float loss = fmaxf(s, 0.f) - s * tgt + log1pf(expf(-fabsf(s)));
    float corr = ((s >= 0.5f) == (tgt > 0.5f)) ? 1.f : 0.f;
    __shared__ double r0[256], r1[256];
    int tid = threadIdx.x;
    r0[tid] = (double)loss;
    r1[tid] = (double)corr;
    __syncthreads();
    for (int o = 128; o > 0; o >>= 1) {
        if (tid < o) { r0[tid] += r0[tid + o]; r1[tid] += r1[tid + o]; }
        __syncthreads();
    }
    if (tid == 0) {
        atomicAdd(&g_acc[0], r0[0]);
        atomicAdd(&g_acc[1], r1[0]);
    }
}

// ---------------- pred head: log-softmax CE + argmax ----------------
__global__ __launch_bounds__(256)
void pred_rows_kernel(const int* __restrict__ root_wid, const int* __restrict__ y_wid)
{
    int j = blockIdx.x, tid = threadIdx.x;
    const float* row = g_logitsc + (size_t)j * Vv;
    int tgt = (j < Bq) ? root_wid[j] : y_wid[g_cmap[j - Bq]];

    float mval = -1e30f; int midx = Vv;
    for (int k = tid; k < Vv; k += 256) {
        float v = row[k];
        if (v > mval) { mval = v; midx = k; }
    }
    __shared__ float rv[256];
    __shared__ int ri[256];
    rv[tid] = mval; ri[tid] = midx; __syncthreads();
    for (int s = 128; s > 0; s >>= 1) {
        if (tid < s) {
            if (rv[tid + s] > rv[tid] ||
                (rv[tid + s] == rv[tid] && ri[tid + s] < ri[tid])) {
                rv[tid] = rv[tid + s]; ri[tid] = ri[tid + s];
            }
        }
        __syncthreads();
    }
    float gmax = rv[0]; int gidx = ri[0];
    __syncthreads();
    float p = 0.f;
    for (int k = tid; k < Vv; k += 256) p += expf(row[k] - gmax);
    rv[tid] = p; __syncthreads();
    for (int s = 128; s > 0; s >>= 1) {
        if (tid < s) rv[tid] += rv[tid + s];
        __syncthreads();
    }
    if (tid == 0) {
        float lse = gmax + logf(rv[0]);
        float ce = -(row[tgt] - lse);
        atomicAdd(&g_acc[2], (double)ce);
        if (gidx == tgt) atomicAdd(&g_acc[3], 1.0);
        atomicAdd(&g_acc[4], 1.0);
    }
}

__global__ void finalize_kernel(float* out)
{
    out[0] = (float)(g_acc[2] / (double)Bq);
    out[1] = (float)(g_acc[0] / (double)Bq);
    out[2] = (float)(g_acc[3] / g_acc[4]);
    out[3] = (float)(g_acc[1] / (double)MSr);
}

// ---------------- launch ----------------
extern "C" void kernel_launch(void* const* d_in, const int* in_sizes, int n_in,
                              void* d_out, int out_size)
{
    const float* mol_vec  = (const float*)d_in[0];
    const int*   wid      = (const int*)d_in[1];
    const int*   y_wid    = (const int*)d_in[2];
    const int*   dirs     = (const int*)d_in[3];
    const int*   hni      = (const int*)d_in[4];
    const int*   oni      = (const int*)d_in[5];
    const int*   root_wid = (const int*)d_in[6];
    const int*   roni     = (const int*)d_in[7];
    const float* emb      = (const float*)d_in[8];
    const float* Wz       = (const float*)d_in[9];
    const float* bz       = (const float*)d_in[10];
    const float* Wr       = (const float*)d_in[11];
    const float* br       = (const float*)d_in[12];
    const float* Ur       = (const float*)d_in[13];
    const float* Wh       = (const float*)d_in[14];
    const float* bh       = (const float*)d_in[15];
    const float* Wm       = (const float*)d_in[16];
    const float* bW       = (const float*)d_in[17];
    const float* U        = (const float*)d_in[18];
    const float* bU       = (const float*)d_in[19];
    const float* Wo       = (const float*)d_in[20];
    const float* bo       = (const float*)d_in[21];
    const float* Us       = (const float*)d_in[22];
    const float* bs       = (const float*)d_in[23];

    float *gPz, *gPr, *gPh, *gPembU, *gPmolU, *gPmolW, *gcuro, *gphidc, *glogitsc, *ghbuf;
    __nv_bfloat16 *gBuH, *gBuL, *gBwH, *gBwL, *gBoH, *gBoL;
    __nv_bfloat16 *gBzhH, *gBzhL, *gBUrH, *gBUrL;
    __nv_bfloat16 *gBz0H, *gBz0L, *gBr0H, *gBr0L, *gBh0H, *gBh0L, *gBU0H, *gBU0L;
    cudaGetSymbolAddress((void**)&gPz, g_Pz);
    cudaGetSymbolAddress((void**)&gPr, g_Pr);
    cudaGetSymbolAddress((void**)&gPh, g_Ph);
    cudaGetSymbolAddress((void**)&gPembU, g_PembU);
    cudaGetSymbolAddress((void**)&gPmolU, g_PmolU);
    cudaGetSymbolAddress((void**)&gPmolW, g_PmolW);
    cudaGetSymbolAddress((void**)&gcuro, g_curo);
    cudaGetSymbolAddress((void**)&gphidc, g_phidc);
    cudaGetSymbolAddress((void**)&glogitsc, g_logitsc);
    cudaGetSymbolAddress((void**)&ghbuf, g_hbuf);
    cudaGetSymbolAddress((void**)&gBuH, g_Bu_hi);
    cudaGetSymbolAddress((void**)&gBuL, g_Bu_lo);
    cudaGetSymbolAddress((void**)&gBwH, g_Bw_hi);
    cudaGetSymbolAddress((void**)&gBwL, g_Bw_lo);
    cudaGetSymbolAddress((void**)&gBoH, g_Bo_hi);
    cudaGetSymbolAddress((void**)&gBoL, g_Bo_lo);
    cudaGetSymbolAddress((void**)&gBzhH, g_Bzh_hi);
    cudaGetSymbolAddress((void**)&gBzhL, g_Bzh_lo);
    cudaGetSymbolAddress((void**)&gBUrH, g_BUr_hi);
    cudaGetSymbolAddress((void**)&gBUrL, g_BUr_lo);
    cudaGetSymbolAddress((void**)&gBz0H, g_Bz0_hi);
    cudaGetSymbolAddress((void**)&gBz0L, g_Bz0_lo);
    cudaGetSymbolAddress((void**)&gBr0H, g_Br0_hi);
    cudaGetSymbolAddress((void**)&gBr0L, g_Br0_lo);
    cudaGetSymbolAddress((void**)&gBh0H, g_Bh0_hi);
    cudaGetSymbolAddress((void**)&gBh0L, g_Bh0_lo);
    cudaGetSymbolAddress((void**)&gBU0H, g_BU0_hi);
    cudaGetSymbolAddress((void**)&gBU0L, g_BU0_lo);

    cudaFuncSetAttribute(tc_gemm_kernel,
                         cudaFuncAttributeMaxDynamicSharedMemorySize, TCSM_BYTES);

    prep_kernel<<<47, 256>>>();
    compact_kernel<<<92, 256>>>(dirs);

    // weight transposes + bf16 split
    convT_kernel<<<dim3(16, 16), 256>>>(U + (size_t)Hh * Hh, Hh, Hh, gBuH, gBuL);
    convT_kernel<<<dim3(16, 16), 256>>>(Wm, Hh, Hh, gBwH, gBwL);
    convT_kernel<<<dim3(32, 16), 256>>>(Wo, Hh, Vv, gBoH, gBoL);
    convT_kernel<<<dim3(16, 16), 256>>>(Wz + (size_t)Hh * Hh, Hh, Hh, gBzhH, gBzhL);
    convT_kernel<<<dim3(16, 16), 256>>>(Wh + (size_t)Hh * Hh, Hh, Hh,
                                        gBzhH + (size_t)Hh * Hh, gBzhL + (size_t)Hh * Hh);
    convT_kernel<<<dim3(16, 16), 256>>>(Ur, Hh, Hh, gBUrH, gBUrL);
    convT_kernel<<<dim3(16, 16), 256>>>(Wz, Hh, Hh, gBz0H, gBz0L);
    convT_kernel<<<dim3(16, 16), 256>>>(Wr, Hh, Hh, gBr0H, gBr0L);
    convT_kernel<<<dim3(16, 16), 256>>>(Wh, Hh, Hh, gBh0H, gBh0L);
    convT_kernel<<<dim3(16, 16), 256>>>(U, Hh, Hh, gBU0H, gBU0L);

    // one-time precomputes via tensor cores (emb is fp32 A)
    tc_gemm_kernel<<<dim3(4, 8), 256, TCSM_BYTES>>>(
        emb, gBz0H, gBz0L, bz, gPz, Hh, 0, nullptr, nullptr, nullptr);
    tc_gemm_kernel<<<dim3(4, 8), 256, TCSM_BYTES>>>(
        emb, gBr0H, gBr0L, br, gPr, Hh, 0, nullptr, nullptr, nullptr);
    tc_gemm_kernel<<<dim3(4, 8), 256, TCSM_BYTES>>>(
        emb, gBh0H, gBh0L, bh, gPh, Hh, 0, nullptr, nullptr, nullptr);
    tc_gemm_kernel<<<dim3(4, 8), 256, TCSM_BYTES>>>(
        emb, gBU0H, gBU0L, bU, gPembU, Hh, 0, nullptr, nullptr, nullptr);
    // small K=64 mol projections stay fp32
    sgemm_kernel<<<dim3(Hh / BN, Bq / BM), 256>>>(Bq, Hh, Ll, mol_vec, U + (size_t)2 * Hh * Hh, nullptr, gPmolU);
    sgemm_kernel<<<dim3(Hh / BN, Bq / BM), 256>>>(Bq, Hh, Ll, mol_vec, Wm + (size_t)Hh * Hh, bW, gPmolW);

    // persistent fused GRU scan (tensor-core GEMMs)
    scan_kernel<<<NBLK, 256>>>(wid, hni);

    // stop head
    build_curo<<<MSr, 256>>>(oni, roni);
    tc_gemm_kernel<<<dim3(4, MSr / 128), 256, TCSM_BYTES>>>(
        gcuro, gBuH, gBuL, nullptr, nullptr, 0, 1, wid, root_wid, Us);
    stop_final_kernel<<<94, 256>>>(bs, dirs);

    // pred head (compacted)
    phid0_kernel<<<Bq, Hh>>>();
    tc_gemm_kernel<<<dim3(4, NCMP / 128), 256, TCSM_BYTES>>>(
        ghbuf, gBwH, gBwL, nullptr, nullptr, 0, 2, nullptr, nullptr, nullptr);
    tc_gemm_kernel<<<dim3(8, MPRED / 128), 256, TCSM_BYTES>>>(
        gphidc, gBoH, gBoL, bo, glogitsc, Vv, 0, nullptr, nullptr, nullptr);
    pred_rows_kernel<<<MPRED, 256>>>(root_wid, y_wid);

    finalize_kernel<<<1, 1>>>((float*)d_out);
}

// round 7
// speedup vs baseline: 4.9500x; 1.1062x over previous
#include <cuda_runtime.h>
#include <cuda_bf16.h>
#include <math.h>
#include <stdint.h>

// Problem constants
#define Bq 512
#define Hh 512
#define Ll 64
#define Vv 1024
#define Tt 46
#define TBq 23552          // T*B
#define PADROW 23552
#define MSr 24064          // TB + B
#define MAXNB 8
#define NCMP 11776         // compacted pred rows (dirs==1)
#define MPRED 12288        // B + NCMP
#define NBLK 128           // persistent scan grid

// ---------------- scratch ----------------
__device__ float g_hbuf[(size_t)(TBq + 1) * Hh];
__device__ float g_hbufUr[(size_t)(TBq + 1) * Hh];
__device__ float g_Pz[(size_t)Vv * Hh];
__device__ float g_Pr[(size_t)Vv * Hh];
__device__ float g_Ph[(size_t)Vv * Hh];
__device__ float g_PembU[(size_t)Vv * Hh];
__device__ float g_PmolU[(size_t)Bq * Hh];
__device__ float g_PmolW[(size_t)Bq * Hh];
__device__ float g_sumh[(size_t)Bq * Hh];
__device__ float g_curo[(size_t)MSr * Hh];
__device__ float g_phidc[(size_t)MPRED * Hh];
__device__ float g_logitsc[(size_t)MPRED * Vv];
__device__ float g_spart[(size_t)8 * MSr];
__device__ int   g_cmap[NCMP + 256];
__device__ int   g_ccount;
__device__ int   g_barc;
__device__ volatile int g_bars;
__device__ double g_acc[5];
// scan split activations
__device__ __nv_bfloat16 g_shg_hi[(size_t)2 * Bq * Hh];
__device__ __nv_bfloat16 g_shg_lo[(size_t)2 * Bq * Hh];
__device__ __nv_bfloat16 g_h_hi[(size_t)Bq * Hh];
__device__ __nv_bfloat16 g_h_lo[(size_t)Bq * Hh];
// bf16 split weights, stored [N, K]
__device__ __nv_bfloat16 g_Bu_hi[(size_t)Hh * Hh];
__device__ __nv_bfloat16 g_Bu_lo[(size_t)Hh * Hh];
__device__ __nv_bfloat16 g_Bw_hi[(size_t)Hh * Hh];
__device__ __nv_bfloat16 g_Bw_lo[(size_t)Hh * Hh];
__device__ __nv_bfloat16 g_Bo_hi[(size_t)Vv * Hh];
__device__ __nv_bfloat16 g_Bo_lo[(size_t)Vv * Hh];
__device__ __nv_bfloat16 g_Bzh_hi[(size_t)2 * Hh * Hh];  // rows 0-511 Wz_bot^T, 512-1023 Wh_bot^T
__device__ __nv_bfloat16 g_Bzh_lo[(size_t)2 * Hh * Hh];
__device__ __nv_bfloat16 g_BUr_hi[(size_t)Hh * Hh];
__device__ __nv_bfloat16 g_BUr_lo[(size_t)Hh * Hh];
__device__ __nv_bfloat16 g_Bz0_hi[(size_t)Hh * Hh];
__device__ __nv_bfloat16 g_Bz0_lo[(size_t)Hh * Hh];
__device__ __nv_bfloat16 g_Br0_hi[(size_t)Hh * Hh];
__device__ __nv_bfloat16 g_Br0_lo[(size_t)Hh * Hh];
__device__ __nv_bfloat16 g_Bh0_hi[(size_t)Hh * Hh];
__device__ __nv_bfloat16 g_Bh0_lo[(size_t)Hh * Hh];
__device__ __nv_bfloat16 g_BU0_hi[(size_t)Hh * Hh];
__device__ __nv_bfloat16 g_BU0_lo[(size_t)Hh * Hh];

// ---------------- helpers ----------------
__device__ __forceinline__ uint32_t smem_u32(const void* p) {
    uint32_t a;
    asm("{ .reg .u64 t; cvta.to.shared.u64 t, %1; cvt.u32.u64 %0, t; }"
        : "=r"(a) : "l"(p));
    return a;
}
__device__ __forceinline__ uint32_t lds32(uint32_t addr) {
    uint32_t v;
    asm volatile("ld.shared.b32 %0, [%1];" : "=r"(v) : "r"(addr));
    return v;
}
__device__ __forceinline__ void mma16816(float* d, const uint32_t* a,
                                         uint32_t b0, uint32_t b1) {
    asm volatile(
        "mma.sync.aligned.m16n8k16.row.col.f32.bf16.bf16.f32 "
        "{%0,%1,%2,%3}, {%4,%5,%6,%7}, {%8,%9}, {%0,%1,%2,%3};"
        : "+f"(d[0]), "+f"(d[1]), "+f"(d[2]), "+f"(d[3])
        : "r"(a[0]), "r"(a[1]), "r"(a[2]), "r"(a[3]), "r"(b0), "r"(b1));
}
__device__ __forceinline__ void splitbf(float v, __nv_bfloat16& h, __nv_bfloat16& l) {
    h = __float2bfloat16(v);
    l = __float2bfloat16(v - __bfloat162float(h));
}
__device__ __forceinline__ float fast_sigmoid(float x) {
    return __fdividef(1.f, 1.f + __expf(-x));
}

// ---------------- software grid barrier ----------------
__device__ __forceinline__ void grid_bar(int nb)
{
    __syncthreads();
    if (threadIdx.x == 0) {
        int s = g_bars;
        __threadfence();
        int t = atomicAdd(&g_barc, 1);
        if (t == nb - 1) {
            g_barc = 0;
            __threadfence();
            g_bars = s + 1;
        } else {
            while (g_bars == s) { __nanosleep(32); }
        }
        __threadfence();
    }
    __syncthreads();
}

// ---------------- generic 64x64 SGEMM (small precomputes) ----------------
#define BM 64
#define BN 64
#define BK 16

__global__ __launch_bounds__(256)
void sgemm_kernel(int M, int N, int K,
                  const float* __restrict__ A, const float* __restrict__ Bm,
                  const float* __restrict__ bias, float* __restrict__ C)
{
    __shared__ float As[BK][BM];
    __shared__ float Bs[BK][BN];
    const int tid = threadIdx.x;
    const int tx = tid & 15;
    const int ty = tid >> 4;
    const int m0 = blockIdx.y * BM;
    const int n0 = blockIdx.x * BN;

    const int a_row  = tid >> 2;
    const int a_col4 = (tid & 3) << 2;
    const int b_row  = tid >> 4;
    const int b_col4 = (tid & 15) << 2;

    const float* Aptr = A + (size_t)(m0 + a_row) * K + a_col4;
    const float* Bptr = Bm + (size_t)b_row * N + n0 + b_col4;

    float acc[4][4];
    #pragma unroll
    for (int i = 0; i < 4; i++)
        #pragma unroll
        for (int j = 0; j < 4; j++) acc[i][j] = 0.f;

    for (int k0 = 0; k0 < K; k0 += BK) {
        float4 av = *(const float4*)(Aptr + k0);
        float4 bv = *(const float4*)(Bptr + (size_t)k0 * N);
        As[a_col4 + 0][a_row] = av.x;
        As[a_col4 + 1][a_row] = av.y;
        As[a_col4 + 2][a_row] = av.z;
        As[a_col4 + 3][a_row] = av.w;
        *(float4*)&Bs[b_row][b_col4] = bv;
        __syncthreads();
        #pragma unroll
        for (int k = 0; k < BK; k++) {
            float4 a4 = *(const float4*)&As[k][ty << 2];
            float4 b4 = *(const float4*)&Bs[k][tx << 2];
            float a[4] = {a4.x, a4.y, a4.z, a4.w};
            float b[4] = {b4.x, b4.y, b4.z, b4.w};
            #pragma unroll
            for (int i = 0; i < 4; i++)
                #pragma unroll
                for (int j = 0; j < 4; j++) acc[i][j] = fmaf(a[i], b[j], acc[i][j]);
        }
        __syncthreads();
    }

    #pragma unroll
    for (int i = 0; i < 4; i++) {
        int row = m0 + (ty << 2) + i;
        int col = n0 + (tx << 2);
        float4 out;
        float b0 = bias ? bias[col + 0] : 0.f;
        float b1 = bias ? bias[col + 1] : 0.f;
        float b2 = bias ? bias[col + 2] : 0.f;
        float b3 = bias ? bias[col + 3] : 0.f;
        out.x = acc[i][0] + b0; out.y = acc[i][1] + b1;
        out.z = acc[i][2] + b2; out.w = acc[i][3] + b3;
        *(float4*)&C[(size_t)row * N + col] = out;
    }
}

// ---------------- weight transpose + bf16 split ----------------
__global__ __launch_bounds__(256)
void convT_kernel(const float* __restrict__ src, int K, int N,
                  __nv_bfloat16* __restrict__ hi, __nv_bfloat16* __restrict__ lo)
{
    __shared__ float t[32][33];
    int k0 = blockIdx.y * 32, n0 = blockIdx.x * 32;
    int tx = threadIdx.x & 31, ty = threadIdx.x >> 5;
    for (int r = ty; r < 32; r += 8)
        t[r][tx] = src[(size_t)(k0 + r) * N + n0 + tx];
    __syncthreads();
    for (int r = ty; r < 32; r += 8) {
        float v = t[tx][r];
        __nv_bfloat16 h, l;
        splitbf(v, h, l);
        hi[(size_t)(n0 + r) * K + k0 + tx] = h;
        lo[(size_t)(n0 + r) * K + k0 + tx] = l;
    }
}

// ---------------- persistent fused GRU scan (tensor-core GEMMs) ----------------
#define SLDA 144
// dynamic smem offsets
#define SA0 0
#define SA1 9216
#define SA2 18432
#define SA3 27648
#define SB0 36864
#define SB1 41472
#define SB2 46080
#define SB3 50688
#define SCAN_SMEM 55296

__global__ __launch_bounds__(256)
void scan_kernel(const int* __restrict__ wid, const int* __restrict__ hni)
{
    extern __shared__ char sms[];
    const uint32_t u0 = smem_u32(sms);
    __shared__ int s_raw[MAXNB];
    __shared__ int s_w;

    const int tid = threadIdx.x;
    const int nb = (int)gridDim.x;
    const int wid_ = tid >> 5;
    const int lane = tid & 31;
    const int wm = wid_ & 3;
    const int wg = wid_ >> 2;
    const int qrow = lane >> 2;
    const int qk = (lane & 3) << 1;

    for (int t = 0; t < Tt; t++) {
        // ---- P1: gather sum_h / sum_g (skip PAD neighbors) ----
        for (int b = (int)blockIdx.x; b < Bq; b += nb) {
            __syncthreads();
            if (tid < MAXNB) s_raw[tid] = hni[((size_t)(t * Bq + b)) * MAXNB + tid];
            if (tid == MAXNB) s_w = wid[t * Bq + b];
            __syncthreads();
            int w = s_w;
            #pragma unroll
            for (int hh = 0; hh < Hh; hh += 256) {
                int h = hh + tid;
                float xr = g_Pr[(size_t)w * Hh + h];
                float sh = 0.f, sg = 0.f;
                #pragma unroll
                for (int n = 0; n < MAXNB; n++) {
                    int id = s_raw[n];
                    if (id == PADROW) continue;   // uniform branch
                    float hv = g_hbuf[(size_t)id * Hh + h];
                    float gv = g_hbufUr[(size_t)id * Hh + h];
                    float r = fast_sigmoid(xr + gv);
                    sh += hv;
                    sg += r * hv;
                }
                g_sumh[(size_t)b * Hh + h] = sh;
                __nv_bfloat16 hi, lo;
                splitbf(sh, hi, lo);
                g_shg_hi[(size_t)b * Hh + h] = hi;
                g_shg_lo[(size_t)b * Hh + h] = lo;
                splitbf(sg, hi, lo);
                g_shg_hi[(size_t)(Bq + b) * Hh + h] = hi;
                g_shg_lo[(size_t)(Bq + b) * Hh + h] = lo;
            }
        }
        grid_bar(nb);

        // ---- P2': dual 64x32 MMA (z & h_tilde) + fused h_new ----
        {
            const int blk = (int)blockIdx.x;
            const int m0 = (blk >> 4) * 64;
            const int n0 = (blk & 15) * 32;

            float acc[4][4];
            #pragma unroll
            for (int nf = 0; nf < 4; nf++)
                #pragma unroll
                for (int r = 0; r < 4; r++) acc[nf][r] = 0.f;

            const int lr = tid >> 2, lq = tid & 3;   // A rows, 32B units
            const int rb = tid >> 3, qb = tid & 7;   // B rows, 16B units
            const char* gShH = (const char*)(g_shg_hi + (size_t)(m0 + lr) * Hh) + lq * 32;
            const char* gShL = (const char*)(g_shg_lo + (size_t)(m0 + lr) * Hh) + lq * 32;
            const char* gSgH = (const char*)(g_shg_hi + (size_t)(Bq + m0 + lr) * Hh) + lq * 32;
            const char* gSgL = (const char*)(g_shg_lo + (size_t)(Bq + m0 + lr) * Hh) + lq * 32;
            const char* gBzH = (const char*)(g_Bzh_hi + (size_t)(n0 + rb) * Hh) + qb * 16;
            const char* gBzL = (const char*)(g_Bzh_lo + (size_t)(n0 + rb) * Hh) + qb * 16;
            const char* gBtH = (const char*)(g_Bzh_hi + (size_t)(Hh + n0 + rb) * Hh) + qb * 16;
            const char* gBtL = (const char*)(g_Bzh_lo + (size_t)(Hh + n0 + rb) * Hh) + qb * 16;

            const uint32_t uAh = u0 + (wg ? SA2 : SA0);
            const uint32_t uAl = u0 + (wg ? SA3 : SA1);
            const uint32_t uBh = u0 + (wg ? SB2 : SB0);
            const uint32_t uBl = u0 + (wg ? SB3 : SB1);

            for (int c = 0; c < 8; c++) {
                uint4 a0 = *(const uint4*)(gShH + c * 128);
                uint4 a0b = *(const uint4*)(gShH + c * 128 + 16);
                uint4 a1 = *(const uint4*)(gShL + c * 128);
                uint4 a1b = *(const uint4*)(gShL + c * 128 + 16);
                uint4 a2 = *(const uint4*)(gSgH + c * 128);
                uint4 a2b = *(const uint4*)(gSgH + c * 128 + 16);
                uint4 a3 = *(const uint4*)(gSgL + c * 128);
                uint4 a3b = *(const uint4*)(gSgL + c * 128 + 16);
                uint4 b0 = *(const uint4*)(gBzH + c * 128);
                uint4 b1 = *(const uint4*)(gBzL + c * 128);
                uint4 b2 = *(const uint4*)(gBtH + c * 128);
                uint4 b3 = *(const uint4*)(gBtL + c * 128);
                __syncthreads();
                char* d;
                d = sms + SA0 + lr * SLDA + lq * 32; *(uint4*)d = a0; *(uint4*)(d + 16) = a0b;
                d = sms + SA1 + lr * SLDA + lq * 32; *(uint4*)d = a1; *(uint4*)(d + 16) = a1b;
                d = sms + SA2 + lr * SLDA + lq * 32; *(uint4*)d = a2; *(uint4*)(d + 16) = a2b;
                d = sms + SA3 + lr * SLDA + lq * 32; *(uint4*)d = a3; *(uint4*)(d + 16) = a3b;
                *(uint4*)(sms + SB0 + rb * SLDA + qb * 16) = b0;
                *(uint4*)(sms + SB1 + rb * SLDA + qb * 16) = b1;
                *(uint4*)(sms + SB2 + rb * SLDA + qb * 16) = b2;
                *(uint4*)(sms + SB3 + rb * SLDA + qb * 16) = b3;
                __syncthreads();
                #pragma unroll
                for (int kk = 0; kk < 4; kk++) {
                    const uint32_t koff = (kk * 16 + qk) * 2;
                    uint32_t base = (wm * 16 + qrow) * SLDA + koff;
                    uint32_t ah[4], al[4];
                    ah[0] = lds32(uAh + base);
                    ah[1] = lds32(uAh + base + 8 * SLDA);
                    ah[2] = lds32(uAh + base + 16);
                    ah[3] = lds32(uAh + base + 8 * SLDA + 16);
                    al[0] = lds32(uAl + base);
                    al[1] = lds32(uAl + base + 8 * SLDA);
                    al[2] = lds32(uAl + base + 16);
                    al[3] = lds32(uAl + base + 8 * SLDA + 16);
                    #pragma unroll
                    for (int nf = 0; nf < 4; nf++) {
                        uint32_t bb = (nf * 8 + qrow) * SLDA + koff;
                        uint32_t bh0 = lds32(uBh + bb);
                        uint32_t bh1 = lds32(uBh + bb + 16);
                        uint32_t cl0 = lds32(uBl + bb);
                        uint32_t cl1 = lds32(uBl + bb + 16);
                        mma16816(acc[nf], ah, bh0, bh1);
                        mma16816(acc[nf], ah, cl0, cl1);
                        mma16816(acc[nf], al, bh0, bh1);
                    }
                }
            }
            // epilogue: activation into exchange buffers
            const float* P = wg ? g_Ph : g_Pz;
            const int rl0 = wm * 16 + qrow;
            const int row0 = m0 + rl0, row1 = row0 + 8;
            const int w0 = wid[t * Bq + row0], w1 = wid[t * Bq + row1];
            float* xbuf = (float*)(sms + (wg ? 8192 : 0));
            __syncthreads();
            #pragma unroll
            for (int nf = 0; nf < 4; nf++) {
                int cl = nf * 8 + qk;
                int col = n0 + cl;
                float v00 = acc[nf][0] + P[(size_t)w0 * Hh + col];
                float v01 = acc[nf][1] + P[(size_t)w0 * Hh + col + 1];
                float v10 = acc[nf][2] + P[(size_t)w1 * Hh + col];
                float v11 = acc[nf][3] + P[(size_t)w1 * Hh + col + 1];
                if (wg) {
                    v00 = tanhf(v00); v01 = tanhf(v01);
                    v10 = tanhf(v10); v11 = tanhf(v11);
                } else {
                    v00 = fast_sigmoid(v00); v01 = fast_sigmoid(v01);
                    v10 = fast_sigmoid(v10); v11 = fast_sigmoid(v11);
                }
                xbuf[rl0 * 32 + cl] = v00;
                xbuf[rl0 * 32 + cl + 1] = v01;
                xbuf[(rl0 + 8) * 32 + cl] = v10;
                xbuf[(rl0 + 8) * 32 + cl + 1] = v11;
            }
            __syncthreads();
            const float* zbuf = (const float*)(sms);
            const float* tbuf = (const float*)(sms + 8192);
            float* hdst = g_hbuf + (size_t)t * Bq * Hh;
            #pragma unroll
            for (int e = tid; e < 64 * 32; e += 256) {
                int rl = e >> 5, cl = e & 31;
                size_t gi = (size_t)(m0 + rl) * Hh + (n0 + cl);
                float z = zbuf[e], th = tbuf[e];
                float h = (1.f - z) * g_sumh[gi] + z * th;
                hdst[gi] = h;
                __nv_bfloat16 hi, lo;
                splitbf(h, hi, lo);
                g_h_hi[gi] = hi;
                g_h_lo[gi] = lo;
            }
        }
        grid_bar(nb);

        // ---- P4: hbufUr[t] = h_new @ Ur via mma (64x32 tile, 128 tiles) ----
        {
            const int blk = (int)blockIdx.x;
            const int m0 = (blk >> 4) * 64;
            const int n0 = (blk & 15) * 32;

            float acc[2][4];
            #pragma unroll
            for (int nf = 0; nf < 2; nf++)
                #pragma unroll
                for (int r = 0; r < 4; r++) acc[nf][r] = 0.f;

            const int lr = tid >> 2, lq = tid & 3;
            const int br = tid >> 3, bq = tid & 7;
            const char* gAh = (const char*)(g_h_hi + (size_t)(m0 + lr) * Hh) + lq * 32;
            const char* gAl = (const char*)(g_h_lo + (size_t)(m0 + lr) * Hh) + lq * 32;
            const char* gBh = (const char*)(g_BUr_hi + (size_t)(n0 + br) * Hh) + bq * 16;
            const char* gBl = (const char*)(g_BUr_lo + (size_t)(n0 + br) * Hh) + bq * 16;
            const int wn = wg;

            for (int c = 0; c < 8; c++) {
                uint4 ah0 = *(const uint4*)(gAh + c * 128);
                uint4 ah1 = *(const uint4*)(gAh + c * 128 + 16);
                uint4 al0 = *(const uint4*)(gAl + c * 128);
                uint4 al1 = *(const uint4*)(gAl + c * 128 + 16);
                uint4 bh0 = *(const uint4*)(gBh + c * 128);
                uint4 bl0 = *(const uint4*)(gBl + c * 128);
                __syncthreads();
                char* d = sms + SA0 + lr * SLDA + lq * 32;
                *(uint4*)d = ah0; *(uint4*)(d + 16) = ah1;
                d = sms + SA1 + lr * SLDA + lq * 32;
                *(uint4*)d = al0; *(uint4*)(d + 16) = al1;
                *(uint4*)(sms + SB0 + br * SLDA + bq * 16) = bh0;
                *(uint4*)(sms + SB1 + br * SLDA + bq * 16) = bl0;
                __syncthreads();
                #pragma unroll
                for (int kk = 0; kk < 4; kk++) {
                    const uint32_t koff = (kk * 16 + qk) * 2;
                    uint32_t base = (wm * 16 + qrow) * SLDA + koff;
                    uint32_t ah[4], al[4];
                    ah[0] = lds32(u0 + SA0 + base);
                    ah[1] = lds32(u0 + SA0 + base + 8 * SLDA);
                    ah[2] = lds32(u0 + SA0 + base + 16);
                    ah[3] = lds32(u0 + SA0 + base + 8 * SLDA + 16);
                    al[0] = lds32(u0 + SA1 + base);
                    al[1] = lds32(u0 + SA1 + base + 8 * SLDA);
                    al[2] = lds32(u0 + SA1 + base + 16);
                    al[3] = lds32(u0 + SA1 + base + 8 * SLDA + 16);
                    #pragma unroll
                    for (int nf = 0; nf < 2; nf++) {
                        uint32_t bb = (wn * 16 + nf * 8 + qrow) * SLDA + koff;
                        uint32_t b0 = lds32(u0 + SB0 + bb);
                        uint32_t b1 = lds32(u0 + SB0 + bb + 16);
                        uint32_t c0 = lds32(u0 + SB1 + bb);
                        uint32_t c1 = lds32(u0 + SB1 + bb + 16);
                        mma16816(acc[nf], ah, b0, b1);
                        mma16816(acc[nf], ah, c0, c1);
                        mma16816(acc[nf], al, b0, b1);
                    }
                }
            }
            float* Cc = g_hbufUr + (size_t)t * Bq * Hh;
            int r0 = m0 + wm * 16 + qrow;
            #pragma unroll
            for (int nf = 0; nf < 2; nf++) {
                int col = n0 + wn * 16 + nf * 8 + qk;
                float2 o0 = {acc[nf][0], acc[nf][1]};
                float2 o1 = {acc[nf][2], acc[nf][3]};
                *(float2*)&Cc[(size_t)r0 * Hh + col] = o0;
                *(float2*)&Cc[(size_t)(r0 + 8) * Hh + col] = o1;
            }
        }
        grid_bar(nb);
    }
}

// ---------------- tensor-core (mma.sync) split-bf16 GEMM, post heads ----------------
#define LDA_B 144
#define OFF_ALO 18432
#define OFF_BHI 36864
#define OFF_BLO 55296
#define TCSM_BYTES 73728

__global__ __launch_bounds__(256)
void tc_gemm_kernel(const float* __restrict__ A,
                    const __nv_bfloat16* __restrict__ Bhi,
                    const __nv_bfloat16* __restrict__ Blo,
                    const float* __restrict__ bias, float* __restrict__ C, int ldc,
                    int mode, const int* __restrict__ widp,
                    const int* __restrict__ rootp, const float* __restrict__ Us)
{
    extern __shared__ char smc[];
    const uint32_t sbase = smem_u32(smc);
    __shared__ int s_rows[128];

    const int tid = threadIdx.x;
    const int wid_ = tid >> 5;
    const int lane = tid & 31;
    const int wm = wid_ & 3;
    const int wn = wid_ >> 2;
    const int qrow = lane >> 2;
    const int qk = (lane & 3) << 1;
    const int m0 = blockIdx.y * 128;
    const int n0 = blockIdx.x * 128;

    if (tid < 128) s_rows[tid] = (mode == 2) ? g_cmap[m0 + tid] : (m0 + tid);
    __syncthreads();

    const int ar = tid >> 1;
    const int ac = (tid & 1) * 32;
    const int br = tid >> 1;
    const int bo = (tid & 1) * 64;

    const float* Abase = A + (size_t)s_rows[ar] * Hh + ac;
    const char* BhiBase = (const char*)(Bhi + (size_t)(n0 + br) * Hh) + bo;
    const char* BloBase = (const char*)(Blo + (size_t)(n0 + br) * Hh) + bo;

    float acc[2][8][4];
    #pragma unroll
    for (int mf = 0; mf < 2; mf++)
        #pragma unroll
        for (int nf = 0; nf < 8; nf++)
            #pragma unroll
            for (int r = 0; r < 4; r++) acc[mf][nf][r] = 0.f;

    for (int c = 0; c < 8; c++) {
        float4 av[8];
        uint4 bh[4], bl[4];
        #pragma unroll
        for (int f = 0; f < 8; f++)
            av[f] = *(const float4*)(Abase + c * 64 + f * 4);
        #pragma unroll
        for (int u = 0; u < 4; u++) {
            bh[u] = *(const uint4*)(BhiBase + c * 128 + u * 16);
            bl[u] = *(const uint4*)(BloBase + c * 128 + u * 16);
        }
        __syncthreads();

        {
            char* sa = smc + ar * LDA_B + ac * 2;
            char* sl = sa + OFF_ALO;
            #pragma unroll
            for (int f = 0; f < 8; f++) {
                __nv_bfloat16 h0, h1, h2, h3, l0, l1, l2, l3;
                splitbf(av[f].x, h0, l0);
                splitbf(av[f].y, h1, l1);
                splitbf(av[f].z, h2, l2);
                splitbf(av[f].w, h3, l3);
                __nv_bfloat162 hh0, hh1, ll0, ll1;
                hh0.x = h0; hh0.y = h1; hh1.x = h2; hh1.y = h3;
                ll0.x = l0; ll0.y = l1; ll1.x = l2; ll1.y = l3;
                uint2 hv = {*(uint32_t*)&hh0, *(uint32_t*)&hh1};
                uint2 lv = {*(uint32_t*)&ll0, *(uint32_t*)&ll1};
                *(uint2*)(sa + f * 8) = hv;
                *(uint2*)(sl + f * 8) = lv;
            }
        }
        {
            char* sb = smc + OFF_BHI + br * LDA_B + bo;
            char* sbl = smc + OFF_BLO + br * LDA_B + bo;
            #pragma unroll
            for (int u = 0; u < 4; u++) {
                *(uint4*)(sb + u * 16) = bh[u];
                *(uint4*)(sbl + u * 16) = bl[u];
            }
        }
        __syncthreads();

        #pragma unroll
        for (int kk = 0; kk < 4; kk++) {
            const uint32_t koff = (kk * 16 + qk) * 2;
            uint32_t ah[2][4], al[2][4];
            #pragma unroll
            for (int mf = 0; mf < 2; mf++) {
                uint32_t base = sbase + (wm * 32 + mf * 16 + qrow) * LDA_B + koff;
                ah[mf][0] = lds32(base);
                ah[mf][1] = lds32(base + 8 * LDA_B);
                ah[mf][2] = lds32(base + 16);
                ah[mf][3] = lds32(base + 8 * LDA_B + 16);
                al[mf][0] = lds32(base + OFF_ALO);
                al[mf][1] = lds32(base + OFF_ALO + 8 * LDA_B);
                al[mf][2] = lds32(base + OFF_ALO + 16);
                al[mf][3] = lds32(base + OFF_ALO + 8 * LDA_B + 16);
            }
            #pragma unroll
            for (int nf = 0; nf < 8; nf++) {
                uint32_t bb = sbase + OFF_BHI + (wn * 64 + nf * 8 + qrow) * LDA_B + koff;
                uint32_t bh0 = lds32(bb);
                uint32_t bh1 = lds32(bb + 16);
                uint32_t bl0 = lds32(bb + (OFF_BLO - OFF_BHI));
                uint32_t bl1 = lds32(bb + (OFF_BLO - OFF_BHI) + 16);
                #pragma unroll
                for (int mf = 0; mf < 2; mf++) {
                    mma16816(acc[mf][nf], ah[mf], bh0, bh1);
                    mma16816(acc[mf][nf], ah[mf], bl0, bl1);
                    mma16816(acc[mf][nf], al[mf], bh0, bh1);
                }
            }
        }
    }

    if (mode == 0) {
        #pragma unroll
        for (int mf = 0; mf < 2; mf++) {
            int r0 = m0 + wm * 32 + mf * 16 + qrow;
            #pragma unroll
            for (int nf = 0; nf < 8; nf++) {
                int col = n0 + wn * 64 + nf * 8 + qk;
                float2 o0 = {acc[mf][nf][0] + bias[col], acc[mf][nf][1] + bias[col + 1]};
                float2 o1 = {acc[mf][nf][2] + bias[col], acc[mf][nf][3] + bias[col + 1]};
                *(float2*)&C[(size_t)r0 * ldc + col] = o0;
                *(float2*)&C[(size_t)(r0 + 8) * ldc + col] = o1;
            }
        }
    } else if (mode == 1) {
        int slot = blockIdx.x * 2 + wn;
        #pragma unroll
        for (int mf = 0; mf < 2; mf++) {
            int r0 = m0 + wm * 32 + mf * 16 + qrow;
            int r1 = r0 + 8;
            int w0, b0, w1, b1;
            if (r0 < TBq) { w0 = widp[r0]; b0 = r0 & (Bq - 1); }
            else          { w0 = rootp[r0 - TBq]; b0 = r0 - TBq; }
            if (r1 < TBq) { w1 = widp[r1]; b1 = r1 & (Bq - 1); }
            else          { w1 = rootp[r1 - TBq]; b1 = r1 - TBq; }
            const float* Pe0 = g_PembU + (size_t)w0 * Hh;
            const float* Pm0 = g_PmolU + (size_t)b0 * Hh;
            const float* Pe1 = g_PembU + (size_t)w1 * Hh;
            const float* Pm1 = g_PmolU + (size_t)b1 * Hh;
            float p0 = 0.f, p1 = 0.f;
            #pragma unroll
            for (int nf = 0; nf < 8; nf++) {
                int col = wn * 64 + nf * 8 + qk;
                int gc = blockIdx.x * 128 + col;
                float u0 = Us[gc], u1 = Us[gc + 1];
                p0 += fmaxf(acc[mf][nf][0] + Pe0[gc] + Pm0[gc], 0.f) * u0;
                p0 += fmaxf(acc[mf][nf][1] + Pe0[gc + 1] + Pm0[gc + 1], 0.f) * u1;
                p1 += fmaxf(acc[mf][nf][2] + Pe1[gc] + Pm1[gc], 0.f) * u0;
                p1 += fmaxf(acc[mf][nf][3] + Pe1[gc + 1] + Pm1[gc + 1], 0.f) * u1;
            }
            p0 += __shfl_xor_sync(0xffffffffu, p0, 1);
            p0 += __shfl_xor_sync(0xffffffffu, p0, 2);
            p1 += __shfl_xor_sync(0xffffffffu, p1, 1);
            p1 += __shfl_xor_sync(0xffffffffu, p1, 2);
            if ((lane & 3) == 0) {
                g_spart[(size_t)slot * MSr + r0] = p0;
                g_spart[(size_t)slot * MSr + r1] = p1;
            }
        }
    } else {
        #pragma unroll
        for (int mf = 0; mf < 2; mf++) {
            int rl0 = wm * 32 + mf * 16 + qrow;
            int j0 = m0 + rl0;
            int bc0 = s_rows[rl0] & (Bq - 1);
            int bc1 = s_rows[rl0 + 8] & (Bq - 1);
            const float* Pm0 = g_PmolW + (size_t)bc0 * Hh;
            const float* Pm1 = g_PmolW + (size_t)bc1 * Hh;
            float* d0 = g_phidc + (size_t)(Bq + j0) * Hh;
            float* d1 = g_phidc + (size_t)(Bq + j0 + 8) * Hh;
            #pragma unroll
            for (int nf = 0; nf < 8; nf++) {
                int col = n0 + wn * 64 + nf * 8 + qk;
                float2 o0 = {fmaxf(acc[mf][nf][0] + Pm0[col], 0.f),
                             fmaxf(acc[mf][nf][1] + Pm0[col + 1], 0.f)};
                float2 o1 = {fmaxf(acc[mf][nf][2] + Pm1[col], 0.f),
                             fmaxf(acc[mf][nf][3] + Pm1[col + 1], 0.f)};
                *(float2*)(d0 + col) = o0;
                *(float2*)(d1 + col) = o1;
            }
        }
    }
}

// ---------------- housekeeping ----------------
__global__ __launch_bounds__(256)
void prep_kernel()
{
    int i = blockIdx.x * 256 + threadIdx.x;
    if (i < 5) g_acc[i] = 0.0;
    if (i == 5) { g_barc = 0; g_ccount = 0; }
    if (i == 6) g_bars = 0;
    if (i < Hh) {
        g_hbuf[(size_t)PADROW * Hh + i] = 0.f;
        g_hbufUr[(size_t)PADROW * Hh + i] = 0.f;
    }
    if (i < NCMP + 256) g_cmap[i] = 0;
}

__global__ __launch_bounds__(256)
void compact_kernel(const int* __restrict__ dirs)
{
    int i = blockIdx.x * 256 + threadIdx.x;
    if (dirs[i]) {
        int s = atomicAdd(&g_ccount, 1);
        g_cmap[s] = i;
    }
}

__global__ __launch_bounds__(256)
void build_curo(const int* __restrict__ oni, const int* __restrict__ roni)
{
    int i = blockIdx.x, tid = threadIdx.x;
    __shared__ int ids[MAXNB];
    if (tid < MAXNB)
        ids[tid] = (i < TBq) ? oni[(size_t)i * MAXNB + tid]
                             : roni[(size_t)(i - TBq) * MAXNB + tid];
    __syncthreads();
    for (int h = tid; h < Hh; h += 256) {
        float v = 0.f;
        #pragma unroll
        for (int n = 0; n < MAXNB; n++) {
            int id = ids[n];
            if (id == PADROW) continue;   // uniform branch, PAD rows are zero
            v += g_hbuf[(size_t)id * Hh + h];
        }
        g_curo[(size_t)i * Hh + h] = v;
    }
}

__global__ __launch_bounds__(512)
void phid0_kernel()
{
    int b = blockIdx.x, h = threadIdx.x;
    g_phidc[(size_t)b * Hh + h] = fmaxf(g_PmolW[(size_t)b * Hh + h], 0.f);
}

// ---------------- stop head finalize ----------------
__global__ __launch_bounds__(256)
void stop_final_kernel(const float* __restrict__ bs, const int* __restrict__ dirs)
{
    int i = blockIdx.x * 256 + threadIdx.x;
    float s = bs[0];
    #pragma unroll
    for (int k = 0; k < 8; k++) s += g_spart[(size_t)k * MSr + i];
    float tgt = (i < TBq) ? (float)dirs[i] : 0.f;
    float loss = fmaxf(s, 0.f) - s * tgt + log1pf(expf(-fabsf(s)));
    float corr = ((s >= 0.5f) == (tgt > 0.5f)) ? 1.f : 0.f;
    __shared__ double r0[256], r1[256];
    int tid = threadIdx.x;
    r0[tid] = (double)loss;
    r1[tid] = (double)corr;
    __syncthreads();
    for (int o = 128; o > 0; o >>= 1) {
        if (tid < o) { r0[tid] += r0[tid + o]; r1[tid] += r1[tid + o]; }
        __syncthreads();
    }
    if (tid == 0) {
        atomicAdd(&g_acc[0], r0[0]);
        atomicAdd(&g_acc[1], r1[0]);
    }
}

// ---------------- pred head: log-softmax CE + argmax ----------------
__global__ __launch_bounds__(256)
void pred_rows_kernel(const int* __restrict__ root_wid, const int* __restrict__ y_wid)
{
    int j = blockIdx.x, tid = threadIdx.x;
    const float* row = g_logitsc + (size_t)j * Vv;
    int tgt = (j < Bq) ? root_wid[j] : y_wid[g_cmap[j - Bq]];

    float mval = -1e30f; int midx = Vv;
    for (int k = tid; k < Vv; k += 256) {
        float v = row[k];
        if (v > mval) { mval = v; midx = k; }
    }
    __shared__ float rv[256];
    __shared__ int ri[256];
    rv[tid] = mval; ri[tid] = midx; __syncthreads();
    for (int s = 128; s > 0; s >>= 1) {
        if (tid < s) {
            if (rv[tid + s] > rv[tid] ||
                (rv[tid + s] == rv[tid] && ri[tid + s] < ri[tid])) {
                rv[tid] = rv[tid + s]; ri[tid] = ri[tid + s];
            }
        }
        __syncthreads();
    }
    float gmax = rv[0]; int gidx = ri[0];
    __syncthreads();
    float p = 0.f;
    for (int k = tid; k < Vv; k += 256) p += __expf(row[k] - gmax);
    rv[tid] = p; __syncthreads();
    for (int s = 128; s > 0; s >>= 1) {
        if (tid < s) rv[tid] += rv[tid + s];
        __syncthreads();
    }
    if (tid == 0) {
        float lse = gmax + logf(rv[0]);
        float ce = -(row[tgt] - lse);
        atomicAdd(&g_acc[2], (double)ce);
        if (gidx == tgt) atomicAdd(&g_acc[3], 1.0);
        atomicAdd(&g_acc[4], 1.0);
    }
}

__global__ void finalize_kernel(float* out)
{
    out[0] = (float)(g_acc[2] / (double)Bq);
    out[1] = (float)(g_acc[0] / (double)Bq);
    out[2] = (float)(g_acc[3] / g_acc[4]);
    out[3] = (float)(g_acc[1] / (double)MSr);
}

// ---------------- launch ----------------
extern "C" void kernel_launch(void* const* d_in, const int* in_sizes, int n_in,
                              void* d_out, int out_size)
{
    const float* mol_vec  = (const float*)d_in[0];
    const int*   wid      = (const int*)d_in[1];
    const int*   y_wid    = (const int*)d_in[2];
    const int*   dirs     = (const int*)d_in[3];
    const int*   hni      = (const int*)d_in[4];
    const int*   oni      = (const int*)d_in[5];
    const int*   root_wid = (const int*)d_in[6];
    const int*   roni     = (const int*)d_in[7];
    const float* emb      = (const float*)d_in[8];
    const float* Wz       = (const float*)d_in[9];
    const float* bz       = (const float*)d_in[10];
    const float* Wr       = (const float*)d_in[11];
    const float* br       = (const float*)d_in[12];
    const float* Ur       = (const float*)d_in[13];
    const float* Wh       = (const float*)d_in[14];
    const float* bh       = (const float*)d_in[15];
    const float* Wm       = (const float*)d_in[16];
    const float* bW       = (const float*)d_in[17];
    const float* U        = (const float*)d_in[18];
    const float* bU       = (const float*)d_in[19];
    const float* Wo       = (const float*)d_in[20];
    const float* bo       = (const float*)d_in[21];
    const float* Us       = (const float*)d_in[22];
    const float* bs       = (const float*)d_in[23];

    float *gPz, *gPr, *gPh, *gPembU, *gPmolU, *gPmolW, *gcuro, *gphidc, *glogitsc, *ghbuf;
    __nv_bfloat16 *gBuH, *gBuL, *gBwH, *gBwL, *gBoH, *gBoL;
    __nv_bfloat16 *gBzhH, *gBzhL, *gBUrH, *gBUrL;
    __nv_bfloat16 *gBz0H, *gBz0L, *gBr0H, *gBr0L, *gBh0H, *gBh0L, *gBU0H, *gBU0L;
    cudaGetSymbolAddress((void**)&gPz, g_Pz);
    cudaGetSymbolAddress((void**)&gPr, g_Pr);
    cudaGetSymbolAddress((void**)&gPh, g_Ph);
    cudaGetSymbolAddress((void**)&gPembU, g_PembU);
    cudaGetSymbolAddress((void**)&gPmolU, g_PmolU);
    cudaGetSymbolAddress((void**)&gPmolW, g_PmolW);
    cudaGetSymbolAddress((void**)&gcuro, g_curo);
    cudaGetSymbolAddress((void**)&gphidc, g_phidc);
    cudaGetSymbolAddress((void**)&glogitsc, g_logitsc);
    cudaGetSymbolAddress((void**)&ghbuf, g_hbuf);
    cudaGetSymbolAddress((void**)&gBuH, g_Bu_hi);
    cudaGetSymbolAddress((void**)&gBuL, g_Bu_lo);
    cudaGetSymbolAddress((void**)&gBwH, g_Bw_hi);
    cudaGetSymbolAddress((void**)&gBwL, g_Bw_lo);
    cudaGetSymbolAddress((void**)&gBoH, g_Bo_hi);
    cudaGetSymbolAddress((void**)&gBoL, g_Bo_lo);
    cudaGetSymbolAddress((void**)&gBzhH, g_Bzh_hi);
    cudaGetSymbolAddress((void**)&gBzhL, g_Bzh_lo);
    cudaGetSymbolAddress((void**)&gBUrH, g_BUr_hi);
    cudaGetSymbolAddress((void**)&gBUrL, g_BUr_lo);
    cudaGetSymbolAddress((void**)&gBz0H, g_Bz0_hi);
    cudaGetSymbolAddress((void**)&gBz0L, g_Bz0_lo);
    cudaGetSymbolAddress((void**)&gBr0H, g_Br0_hi);
    cudaGetSymbolAddress((void**)&gBr0L, g_Br0_lo);
    cudaGetSymbolAddress((void**)&gBh0H, g_Bh0_hi);
    cudaGetSymbolAddress((void**)&gBh0L, g_Bh0_lo);
    cudaGetSymbolAddress((void**)&gBU0H, g_BU0_hi);
    cudaGetSymbolAddress((void**)&gBU0L, g_BU0_lo);

    cudaFuncSetAttribute(tc_gemm_kernel,
                         cudaFuncAttributeMaxDynamicSharedMemorySize, TCSM_BYTES);
    cudaFuncSetAttribute(scan_kernel,
                         cudaFuncAttributeMaxDynamicSharedMemorySize, SCAN_SMEM);

    prep_kernel<<<47, 256>>>();
    compact_kernel<<<92, 256>>>(dirs);

    // weight transposes + bf16 split
    convT_kernel<<<dim3(16, 16), 256>>>(U + (size_t)Hh * Hh, Hh, Hh, gBuH, gBuL);
    convT_kernel<<<dim3(16, 16), 256>>>(Wm, Hh, Hh, gBwH, gBwL);
    convT_kernel<<<dim3(32, 16), 256>>>(Wo, Hh, Vv, gBoH, gBoL);
    convT_kernel<<<dim3(16, 16), 256>>>(Wz + (size_t)Hh * Hh, Hh, Hh, gBzhH, gBzhL);
    convT_kernel<<<dim3(16, 16), 256>>>(Wh + (size_t)Hh * Hh, Hh, Hh,
                                        gBzhH + (size_t)Hh * Hh, gBzhL + (size_t)Hh * Hh);
    convT_kernel<<<dim3(16, 16), 256>>>(Ur, Hh, Hh, gBUrH, gBUrL);
    convT_kernel<<<dim3(16, 16), 256>>>(Wz, Hh, Hh, gBz0H, gBz0L);
    convT_kernel<<<dim3(16, 16), 256>>>(Wr, Hh, Hh, gBr0H, gBr0L);
    convT_kernel<<<dim3(16, 16), 256>>>(Wh, Hh, Hh, gBh0H, gBh0L);
    convT_kernel<<<dim3(16, 16), 256>>>(U, Hh, Hh, gBU0H, gBU0L);

    // one-time precomputes via tensor cores (emb is fp32 A)
    tc_gemm_kernel<<<dim3(4, 8), 256, TCSM_BYTES>>>(
        emb, gBz0H, gBz0L, bz, gPz, Hh, 0, nullptr, nullptr, nullptr);
    tc_gemm_kernel<<<dim3(4, 8), 256, TCSM_BYTES>>>(
        emb, gBr0H, gBr0L, br, gPr, Hh, 0, nullptr, nullptr, nullptr);
    tc_gemm_kernel<<<dim3(4, 8), 256, TCSM_BYTES>>>(
        emb, gBh0H, gBh0L, bh, gPh, Hh, 0, nullptr, nullptr, nullptr);
    tc_gemm_kernel<<<dim3(4, 8), 256, TCSM_BYTES>>>(
        emb, gBU0H, gBU0L, bU, gPembU, Hh, 0, nullptr, nullptr, nullptr);
    // small K=64 mol projections stay fp32
    sgemm_kernel<<<dim3(Hh / BN, Bq / BM), 256>>>(Bq, Hh, Ll, mol_vec, U + (size_t)2 * Hh * Hh, nullptr, gPmolU);
    sgemm_kernel<<<dim3(Hh / BN, Bq / BM), 256>>>(Bq, Hh, Ll, mol_vec, Wm + (size_t)Hh * Hh, bW, gPmolW);

    // persistent fused GRU scan (tensor-core GEMMs)
    scan_kernel<<<NBLK, 256, SCAN_SMEM>>>(wid, hni);

    // stop head
    build_curo<<<MSr, 256>>>(oni, roni);
    tc_gemm_kernel<<<dim3(4, MSr / 128), 256, TCSM_BYTES>>>(
        gcuro, gBuH, gBuL, nullptr, nullptr, 0, 1, wid, root_wid, Us);
    stop_final_kernel<<<94, 256>>>(bs, dirs);

    // pred head (compacted)
    phid0_kernel<<<Bq, Hh>>>();
    tc_gemm_kernel<<<dim3(4, NCMP / 128), 256, TCSM_BYTES>>>(
        ghbuf, gBwH, gBwL, nullptr, nullptr, 0, 2, nullptr, nullptr, nullptr);
    tc_gemm_kernel<<<dim3(8, MPRED / 128), 256, TCSM_BYTES>>>(
        gphidc, gBoH, gBoL, bo, glogitsc, Vv, 0, nullptr, nullptr, nullptr);
    pred_rows_kernel<<<MPRED, 256>>>(root_wid, y_wid);

    finalize_kernel<<<1, 1>>>((float*)d_out);
}

// round 8
// speedup vs baseline: 5.3747x; 1.0858x over previous
#include <cuda_runtime.h>
#include <cuda_bf16.h>
#include <math.h>
#include <stdint.h>

// Problem constants
#define Bq 512
#define Hh 512
#define Ll 64
#define Vv 1024
#define Tt 46
#define TBq 23552          // T*B
#define PADROW 23552
#define MSr 24064          // TB + B
#define MAXNB 8
#define NCMP 11776         // compacted pred rows (dirs==1)
#define MPRED 12288        // B + NCMP
#define NBLK 128           // persistent scan grid

// ---------------- scratch ----------------
__device__ float g_hbuf[(size_t)(TBq + 1) * Hh];
__device__ float g_hbufUr[(size_t)(TBq + 1) * Hh];
__device__ float g_Pz[(size_t)Vv * Hh];
__device__ float g_Pr[(size_t)Vv * Hh];
__device__ float g_Ph[(size_t)Vv * Hh];
__device__ float g_PembU[(size_t)Vv * Hh];
__device__ float g_PmolU[(size_t)Bq * Hh];
__device__ float g_PmolW[(size_t)Bq * Hh];
__device__ float g_sumh[(size_t)Bq * Hh];
__device__ float g_curo[(size_t)MSr * Hh];
__device__ float g_phidc[(size_t)MPRED * Hh];
__device__ float g_logitsc[(size_t)MPRED * Vv];
__device__ float g_spart[(size_t)8 * MSr];
__device__ int   g_cmap[NCMP + 256];
__device__ int   g_ccount;
__device__ int   g_barc;
__device__ volatile int g_bars;
__device__ double g_acc[5];
// scan split activations
__device__ __nv_bfloat16 g_shg_hi[(size_t)2 * Bq * Hh];
__device__ __nv_bfloat16 g_shg_lo[(size_t)2 * Bq * Hh];
__device__ __nv_bfloat16 g_h_hi[(size_t)Bq * Hh];
__device__ __nv_bfloat16 g_h_lo[(size_t)Bq * Hh];
// bf16 split weights, stored [N, K]
__device__ __nv_bfloat16 g_Bu_hi[(size_t)Hh * Hh];
__device__ __nv_bfloat16 g_Bu_lo[(size_t)Hh * Hh];
__device__ __nv_bfloat16 g_Bw_hi[(size_t)Hh * Hh];
__device__ __nv_bfloat16 g_Bw_lo[(size_t)Hh * Hh];
__device__ __nv_bfloat16 g_Bo_hi[(size_t)Vv * Hh];
__device__ __nv_bfloat16 g_Bo_lo[(size_t)Vv * Hh];
__device__ __nv_bfloat16 g_Bzh_hi[(size_t)2 * Hh * Hh];
__device__ __nv_bfloat16 g_Bzh_lo[(size_t)2 * Hh * Hh];
__device__ __nv_bfloat16 g_BUr_hi[(size_t)Hh * Hh];
__device__ __nv_bfloat16 g_BUr_lo[(size_t)Hh * Hh];
__device__ __nv_bfloat16 g_Bz0_hi[(size_t)Hh * Hh];
__device__ __nv_bfloat16 g_Bz0_lo[(size_t)Hh * Hh];
__device__ __nv_bfloat16 g_Br0_hi[(size_t)Hh * Hh];
__device__ __nv_bfloat16 g_Br0_lo[(size_t)Hh * Hh];
__device__ __nv_bfloat16 g_Bh0_hi[(size_t)Hh * Hh];
__device__ __nv_bfloat16 g_Bh0_lo[(size_t)Hh * Hh];
__device__ __nv_bfloat16 g_BU0_hi[(size_t)Hh * Hh];
__device__ __nv_bfloat16 g_BU0_lo[(size_t)Hh * Hh];

// ---------------- helpers ----------------
__device__ __forceinline__ uint32_t smem_u32(const void* p) {
    uint32_t a;
    asm("{ .reg .u64 t; cvta.to.shared.u64 t, %1; cvt.u32.u64 %0, t; }"
        : "=r"(a) : "l"(p));
    return a;
}
__device__ __forceinline__ uint32_t lds32(uint32_t addr) {
    uint32_t v;
    asm volatile("ld.shared.b32 %0, [%1];" : "=r"(v) : "r"(addr));
    return v;
}
__device__ __forceinline__ void mma16816(float* d, const uint32_t* a,
                                         uint32_t b0, uint32_t b1) {
    asm volatile(
        "mma.sync.aligned.m16n8k16.row.col.f32.bf16.bf16.f32 "
        "{%0,%1,%2,%3}, {%4,%5,%6,%7}, {%8,%9}, {%0,%1,%2,%3};"
        : "+f"(d[0]), "+f"(d[1]), "+f"(d[2]), "+f"(d[3])
        : "r"(a[0]), "r"(a[1]), "r"(a[2]), "r"(a[3]), "r"(b0), "r"(b1));
}
__device__ __forceinline__ void splitbf(float v, __nv_bfloat16& h, __nv_bfloat16& l) {
    h = __float2bfloat16(v);
    l = __float2bfloat16(v - __bfloat162float(h));
}
__device__ __forceinline__ float fast_sigmoid(float x) {
    return __fdividef(1.f, 1.f + __expf(-x));
}

// ---------------- software grid barrier ----------------
__device__ __forceinline__ void grid_bar(int nb)
{
    __syncthreads();
    if (threadIdx.x == 0) {
        int s = g_bars;
        __threadfence();
        int t = atomicAdd(&g_barc, 1);
        if (t == nb - 1) {
            g_barc = 0;
            __threadfence();
            g_bars = s + 1;
        } else {
            while (g_bars == s) { __nanosleep(32); }
        }
        __threadfence();
    }
    __syncthreads();
}

// ---------------- generic 64x64 SGEMM (small precomputes) ----------------
#define BM 64
#define BN 64
#define BK 16

__global__ __launch_bounds__(256)
void sgemm_kernel(int M, int N, int K,
                  const float* __restrict__ A, const float* __restrict__ Bm,
                  const float* __restrict__ bias, float* __restrict__ C)
{
    __shared__ float As[BK][BM];
    __shared__ float Bs[BK][BN];
    const int tid = threadIdx.x;
    const int tx = tid & 15;
    const int ty = tid >> 4;
    const int m0 = blockIdx.y * BM;
    const int n0 = blockIdx.x * BN;

    const int a_row  = tid >> 2;
    const int a_col4 = (tid & 3) << 2;
    const int b_row  = tid >> 4;
    const int b_col4 = (tid & 15) << 2;

    const float* Aptr = A + (size_t)(m0 + a_row) * K + a_col4;
    const float* Bptr = Bm + (size_t)b_row * N + n0 + b_col4;

    float acc[4][4];
    #pragma unroll
    for (int i = 0; i < 4; i++)
        #pragma unroll
        for (int j = 0; j < 4; j++) acc[i][j] = 0.f;

    for (int k0 = 0; k0 < K; k0 += BK) {
        float4 av = *(const float4*)(Aptr + k0);
        float4 bv = *(const float4*)(Bptr + (size_t)k0 * N);
        As[a_col4 + 0][a_row] = av.x;
        As[a_col4 + 1][a_row] = av.y;
        As[a_col4 + 2][a_row] = av.z;
        As[a_col4 + 3][a_row] = av.w;
        *(float4*)&Bs[b_row][b_col4] = bv;
        __syncthreads();
        #pragma unroll
        for (int k = 0; k < BK; k++) {
            float4 a4 = *(const float4*)&As[k][ty << 2];
            float4 b4 = *(const float4*)&Bs[k][tx << 2];
            float a[4] = {a4.x, a4.y, a4.z, a4.w};
            float b[4] = {b4.x, b4.y, b4.z, b4.w};
            #pragma unroll
            for (int i = 0; i < 4; i++)
                #pragma unroll
                for (int j = 0; j < 4; j++) acc[i][j] = fmaf(a[i], b[j], acc[i][j]);
        }
        __syncthreads();
    }

    #pragma unroll
    for (int i = 0; i < 4; i++) {
        int row = m0 + (ty << 2) + i;
        int col = n0 + (tx << 2);
        float4 out;
        float b0 = bias ? bias[col + 0] : 0.f;
        float b1 = bias ? bias[col + 1] : 0.f;
        float b2 = bias ? bias[col + 2] : 0.f;
        float b3 = bias ? bias[col + 3] : 0.f;
        out.x = acc[i][0] + b0; out.y = acc[i][1] + b1;
        out.z = acc[i][2] + b2; out.w = acc[i][3] + b3;
        *(float4*)&C[(size_t)row * N + col] = out;
    }
}

// ---------------- batched weight transpose + bf16 split (one launch) ----------------
struct ConvJob {
    const float* src;
    __nv_bfloat16* hi;
    __nv_bfloat16* lo;
    int nx;   // N / 32
};
struct ConvJobs { ConvJob j[10]; };

__global__ __launch_bounds__(256)
void convT_all(ConvJobs jobs)
{
    ConvJob jb = jobs.j[blockIdx.z];
    if ((int)blockIdx.x >= jb.nx) return;
    const int N = jb.nx * 32;
    const int K = Hh;
    __shared__ float t[32][33];
    int k0 = blockIdx.y * 32, n0 = blockIdx.x * 32;
    int tx = threadIdx.x & 31, ty = threadIdx.x >> 5;
    for (int r = ty; r < 32; r += 8)
        t[r][tx] = jb.src[(size_t)(k0 + r) * N + n0 + tx];
    __syncthreads();
    for (int r = ty; r < 32; r += 8) {
        float v = t[tx][r];
        __nv_bfloat16 h, l;
        splitbf(v, h, l);
        jb.hi[(size_t)(n0 + r) * K + k0 + tx] = h;
        jb.lo[(size_t)(n0 + r) * K + k0 + tx] = l;
    }
}

// ---------------- persistent fused GRU scan (tensor-core GEMMs, prefetched) ----------------
#define SLDA 144
#define SA0 0
#define SA1 9216
#define SA2 18432
#define SA3 27648
#define SB0 36864
#define SB1 41472
#define SB2 46080
#define SB3 50688
#define SCAN_SMEM 55296

__global__ __launch_bounds__(256)
void scan_kernel(const int* __restrict__ wid, const int* __restrict__ hni)
{
    extern __shared__ char sms[];
    const uint32_t u0 = smem_u32(sms);
    __shared__ int s_raw[MAXNB];
    __shared__ int s_w;

    const int tid = threadIdx.x;
    const int nb = (int)gridDim.x;
    const int wid_ = tid >> 5;
    const int lane = tid & 31;
    const int wm = wid_ & 3;
    const int wg = wid_ >> 2;
    const int qrow = lane >> 2;
    const int qk = (lane & 3) << 1;

    for (int t = 0; t < Tt; t++) {
        // ---- P1: gather sum_h / sum_g (skip PAD neighbors) ----
        for (int b = (int)blockIdx.x; b < Bq; b += nb) {
            __syncthreads();
            if (tid < MAXNB) s_raw[tid] = hni[((size_t)(t * Bq + b)) * MAXNB + tid];
            if (tid == MAXNB) s_w = wid[t * Bq + b];
            __syncthreads();
            int w = s_w;
            #pragma unroll
            for (int hh = 0; hh < Hh; hh += 256) {
                int h = hh + tid;
                float xr = g_Pr[(size_t)w * Hh + h];
                float sh = 0.f, sg = 0.f;
                #pragma unroll
                for (int n = 0; n < MAXNB; n++) {
                    int id = s_raw[n];
                    if (id == PADROW) continue;
                    float hv = g_hbuf[(size_t)id * Hh + h];
                    float gv = g_hbufUr[(size_t)id * Hh + h];
                    float r = fast_sigmoid(xr + gv);
                    sh += hv;
                    sg += r * hv;
                }
                g_sumh[(size_t)b * Hh + h] = sh;
                __nv_bfloat16 hi, lo;
                splitbf(sh, hi, lo);
                g_shg_hi[(size_t)b * Hh + h] = hi;
                g_shg_lo[(size_t)b * Hh + h] = lo;
                splitbf(sg, hi, lo);
                g_shg_hi[(size_t)(Bq + b) * Hh + h] = hi;
                g_shg_lo[(size_t)(Bq + b) * Hh + h] = lo;
            }
        }
        grid_bar(nb);

        // ---- P2': dual 64x32 MMA (z & h_tilde) + fused h_new, prefetched ----
        {
            const int blk = (int)blockIdx.x;
            const int m0 = (blk >> 4) * 64;
            const int n0 = (blk & 15) * 32;

            float acc[4][4];
            #pragma unroll
            for (int nf = 0; nf < 4; nf++)
                #pragma unroll
                for (int r = 0; r < 4; r++) acc[nf][r] = 0.f;

            const int lr = tid >> 2, lq = tid & 3;
            const int rb = tid >> 3, qb = tid & 7;
            const char* gShH = (const char*)(g_shg_hi + (size_t)(m0 + lr) * Hh) + lq * 32;
            const char* gShL = (const char*)(g_shg_lo + (size_t)(m0 + lr) * Hh) + lq * 32;
            const char* gSgH = (const char*)(g_shg_hi + (size_t)(Bq + m0 + lr) * Hh) + lq * 32;
            const char* gSgL = (const char*)(g_shg_lo + (size_t)(Bq + m0 + lr) * Hh) + lq * 32;
            const char* gBzH = (const char*)(g_Bzh_hi + (size_t)(n0 + rb) * Hh) + qb * 16;
            const char* gBzL = (const char*)(g_Bzh_lo + (size_t)(n0 + rb) * Hh) + qb * 16;
            const char* gBtH = (const char*)(g_Bzh_hi + (size_t)(Hh + n0 + rb) * Hh) + qb * 16;
            const char* gBtL = (const char*)(g_Bzh_lo + (size_t)(Hh + n0 + rb) * Hh) + qb * 16;

            const uint32_t uAh = u0 + (wg ? SA2 : SA0);
            const uint32_t uAl = u0 + (wg ? SA3 : SA1);
            const uint32_t uBh = u0 + (wg ? SB2 : SB0);
            const uint32_t uBl = u0 + (wg ? SB3 : SB1);

            uint4 a0, a0b, a1, a1b, a2, a2b, a3, a3b, b0, b1, b2, b3;
            a0 = *(const uint4*)(gShH); a0b = *(const uint4*)(gShH + 16);
            a1 = *(const uint4*)(gShL); a1b = *(const uint4*)(gShL + 16);
            a2 = *(const uint4*)(gSgH); a2b = *(const uint4*)(gSgH + 16);
            a3 = *(const uint4*)(gSgL); a3b = *(const uint4*)(gSgL + 16);
            b0 = *(const uint4*)(gBzH); b1 = *(const uint4*)(gBzL);
            b2 = *(const uint4*)(gBtH); b3 = *(const uint4*)(gBtL);

            #pragma unroll 1
            for (int c = 0; c < 8; c++) {
                __syncthreads();
                char* d;
                d = sms + SA0 + lr * SLDA + lq * 32; *(uint4*)d = a0; *(uint4*)(d + 16) = a0b;
                d = sms + SA1 + lr * SLDA + lq * 32; *(uint4*)d = a1; *(uint4*)(d + 16) = a1b;
                d = sms + SA2 + lr * SLDA + lq * 32; *(uint4*)d = a2; *(uint4*)(d + 16) = a2b;
                d = sms + SA3 + lr * SLDA + lq * 32; *(uint4*)d = a3; *(uint4*)(d + 16) = a3b;
                *(uint4*)(sms + SB0 + rb * SLDA + qb * 16) = b0;
                *(uint4*)(sms + SB1 + rb * SLDA + qb * 16) = b1;
                *(uint4*)(sms + SB2 + rb * SLDA + qb * 16) = b2;
                *(uint4*)(sms + SB3 + rb * SLDA + qb * 16) = b3;
                __syncthreads();
                // prefetch next chunk while MMA runs
                uint4 na0, na0b, na1, na1b, na2, na2b, na3, na3b, nb0, nb1, nb2, nb3;
                if (c < 7) {
                    int o = (c + 1) * 128;
                    na0 = *(const uint4*)(gShH + o); na0b = *(const uint4*)(gShH + o + 16);
                    na1 = *(const uint4*)(gShL + o); na1b = *(const uint4*)(gShL + o + 16);
                    na2 = *(const uint4*)(gSgH + o); na2b = *(const uint4*)(gSgH + o + 16);
                    na3 = *(const uint4*)(gSgL + o); na3b = *(const uint4*)(gSgL + o + 16);
                    nb0 = *(const uint4*)(gBzH + o); nb1 = *(const uint4*)(gBzL + o);
                    nb2 = *(const uint4*)(gBtH + o); nb3 = *(const uint4*)(gBtL + o);
                }
                #pragma unroll
                for (int kk = 0; kk < 4; kk++) {
                    const uint32_t koff = (kk * 16 + qk) * 2;
                    uint32_t base = (wm * 16 + qrow) * SLDA + koff;
                    uint32_t ah[4], al[4];
                    ah[0] = lds32(uAh + base);
                    ah[1] = lds32(uAh + base + 8 * SLDA);
                    ah[2] = lds32(uAh + base + 16);
                    ah[3] = lds32(uAh + base + 8 * SLDA + 16);
                    al[0] = lds32(uAl + base);
                    al[1] = lds32(uAl + base + 8 * SLDA);
                    al[2] = lds32(uAl + base + 16);
                    al[3] = lds32(uAl + base + 8 * SLDA + 16);
                    #pragma unroll
                    for (int nf = 0; nf < 4; nf++) {
                        uint32_t bb = (nf * 8 + qrow) * SLDA + koff;
                        uint32_t bh0 = lds32(uBh + bb);
                        uint32_t bh1 = lds32(uBh + bb + 16);
                        uint32_t cl0 = lds32(uBl + bb);
                        uint32_t cl1 = lds32(uBl + bb + 16);
                        mma16816(acc[nf], ah, bh0, bh1);
                        mma16816(acc[nf], ah, cl0, cl1);
                        mma16816(acc[nf], al, bh0, bh1);
                    }
                }
                if (c < 7) {
                    a0 = na0; a0b = na0b; a1 = na1; a1b = na1b;
                    a2 = na2; a2b = na2b; a3 = na3; a3b = na3b;
                    b0 = nb0; b1 = nb1; b2 = nb2; b3 = nb3;
                }
            }
            // epilogue: activation into exchange buffers
            const float* P = wg ? g_Ph : g_Pz;
            const int rl0 = wm * 16 + qrow;
            const int row0 = m0 + rl0, row1 = row0 + 8;
            const int w0 = wid[t * Bq + row0], w1 = wid[t * Bq + row1];
            float* xbuf = (float*)(sms + (wg ? 8192 : 0));
            __syncthreads();
            #pragma unroll
            for (int nf = 0; nf < 4; nf++) {
                int cl = nf * 8 + qk;
                int col = n0 + cl;
                float v00 = acc[nf][0] + P[(size_t)w0 * Hh + col];
                float v01 = acc[nf][1] + P[(size_t)w0 * Hh + col + 1];
                float v10 = acc[nf][2] + P[(size_t)w1 * Hh + col];
                float v11 = acc[nf][3] + P[(size_t)w1 * Hh + col + 1];
                if (wg) {
                    v00 = tanhf(v00); v01 = tanhf(v01);
                    v10 = tanhf(v10); v11 = tanhf(v11);
                } else {
                    v00 = fast_sigmoid(v00); v01 = fast_sigmoid(v01);
                    v10 = fast_sigmoid(v10); v11 = fast_sigmoid(v11);
                }
                xbuf[rl0 * 32 + cl] = v00;
                xbuf[rl0 * 32 + cl + 1] = v01;
                xbuf[(rl0 + 8) * 32 + cl] = v10;
                xbuf[(rl0 + 8) * 32 + cl + 1] = v11;
            }
            __syncthreads();
            const float* zbuf = (const float*)(sms);
            const float* tbuf = (const float*)(sms + 8192);
            float* hdst = g_hbuf + (size_t)t * Bq * Hh;
            #pragma unroll
            for (int e = tid; e < 64 * 32; e += 256) {
                int rl = e >> 5, cl = e & 31;
                size_t gi = (size_t)(m0 + rl) * Hh + (n0 + cl);
                float z = zbuf[e], th = tbuf[e];
                float h = (1.f - z) * g_sumh[gi] + z * th;
                hdst[gi] = h;
                __nv_bfloat16 hi, lo;
                splitbf(h, hi, lo);
                g_h_hi[gi] = hi;
                g_h_lo[gi] = lo;
            }
        }
        grid_bar(nb);

        // ---- P4: hbufUr[t] = h_new @ Ur (64x32 tile, prefetched) ----
        {
            const int blk = (int)blockIdx.x;
            const int m0 = (blk >> 4) * 64;
            const int n0 = (blk & 15) * 32;

            float acc[2][4];
            #pragma unroll
            for (int nf = 0; nf < 2; nf++)
                #pragma unroll
                for (int r = 0; r < 4; r++) acc[nf][r] = 0.f;

            const int lr = tid >> 2, lq = tid & 3;
            const int br = tid >> 3, bq = tid & 7;
            const char* gAh = (const char*)(g_h_hi + (size_t)(m0 + lr) * Hh) + lq * 32;
            const char* gAl = (const char*)(g_h_lo + (size_t)(m0 + lr) * Hh) + lq * 32;
            const char* gBh = (const char*)(g_BUr_hi + (size_t)(n0 + br) * Hh) + bq * 16;
            const char* gBl = (const char*)(g_BUr_lo + (size_t)(n0 + br) * Hh) + bq * 16;
            const int wn = wg;

            uint4 ah0, ah1, al0, al1, bh0, bl0;
            ah0 = *(const uint4*)(gAh); ah1 = *(const uint4*)(gAh + 16);
            al0 = *(const uint4*)(gAl); al1 = *(const uint4*)(gAl + 16);
            bh0 = *(const uint4*)(gBh); bl0 = *(const uint4*)(gBl);

            #pragma unroll 1
            for (int c = 0; c < 8; c++) {
                __syncthreads();
                char* d = sms + SA0 + lr * SLDA + lq * 32;
                *(uint4*)d = ah0; *(uint4*)(d + 16) = ah1;
                d = sms + SA1 + lr * SLDA + lq * 32;
                *(uint4*)d = al0; *(uint4*)(d + 16) = al1;
                *(uint4*)(sms + SB0 + br * SLDA + bq * 16) = bh0;
                *(uint4*)(sms + SB1 + br * SLDA + bq * 16) = bl0;
                __syncthreads();
                uint4 nah0, nah1, nal0, nal1, nbh0, nbl0;
                if (c < 7) {
                    int o = (c + 1) * 128;
                    nah0 = *(const uint4*)(gAh + o); nah1 = *(const uint4*)(gAh + o + 16);
                    nal0 = *(const uint4*)(gAl + o); nal1 = *(const uint4*)(gAl + o + 16);
                    nbh0 = *(const uint4*)(gBh + o); nbl0 = *(const uint4*)(gBl + o);
                }
                #pragma unroll
                for (int kk = 0; kk < 4; kk++) {
                    const uint32_t koff = (kk * 16 + qk) * 2;
                    uint32_t base = (wm * 16 + qrow) * SLDA + koff;
                    uint32_t ah[4], al[4];
                    ah[0] = lds32(u0 + SA0 + base);
                    ah[1] = lds32(u0 + SA0 + base + 8 * SLDA);
                    ah[2] = lds32(u0 + SA0 + base + 16);
                    ah[3] = lds32(u0 + SA0 + base + 8 * SLDA + 16);
                    al[0] = lds32(u0 + SA1 + base);
                    al[1] = lds32(u0 + SA1 + base + 8 * SLDA);
                    al[2] = lds32(u0 + SA1 + base + 16);
                    al[3] = lds32(u0 + SA1 + base + 8 * SLDA + 16);
                    #pragma unroll
                    for (int nf = 0; nf < 2; nf++) {
                        uint32_t bb = (wn * 16 + nf * 8 + qrow) * SLDA + koff;
                        uint32_t b0 = lds32(u0 + SB0 + bb);
                        uint32_t b1 = lds32(u0 + SB0 + bb + 16);
                        uint32_t c0 = lds32(u0 + SB1 + bb);
                        uint32_t c1 = lds32(u0 + SB1 + bb + 16);
                        mma16816(acc[nf], ah, b0, b1);
                        mma16816(acc[nf], ah, c0, c1);
                        mma16816(acc[nf], al, b0, b1);
                    }
                }
                if (c < 7) {
                    ah0 = nah0; ah1 = nah1; al0 = nal0; al1 = nal1;
                    bh0 = nbh0; bl0 = nbl0;
                }
            }
            float* Cc = g_hbufUr + (size_t)t * Bq * Hh;
            int r0 = m0 + wm * 16 + qrow;
            #pragma unroll
            for (int nf = 0; nf < 2; nf++) {
                int col = n0 + wn * 16 + nf * 8 + qk;
                float2 o0 = {acc[nf][0], acc[nf][1]};
                float2 o1 = {acc[nf][2], acc[nf][3]};
                *(float2*)&Cc[(size_t)r0 * Hh + col] = o0;
                *(float2*)&Cc[(size_t)(r0 + 8) * Hh + col] = o1;
            }
        }
        grid_bar(nb);
    }
}

// ---------------- tensor-core (mma.sync) split-bf16 GEMM mainloop ----------------
#define LDA_B 144
#define OFF_ALO 18432
#define OFF_BHI 36864
#define OFF_BLO 55296
#define TCSM_BYTES 73728

__device__ __forceinline__ void tc_main(
    const float* Abase, const char* BhiBase, const char* BloBase,
    char* smc, uint32_t sbase, int tid, int wm, int wn, int qrow, int qk,
    float acc[2][8][4])
{
    const int ar = tid >> 1;
    const int ac = (tid & 1) * 32;
    const int bo = (tid & 1) * 64;

    float4 av[8];
    uint4 bh[4], bl[4];
    #pragma unroll
    for (int f = 0; f < 8; f++) av[f] = *(const float4*)(Abase + f * 4);
    #pragma unroll
    for (int u = 0; u < 4; u++) {
        bh[u] = *(const uint4*)(BhiBase + u * 16);
        bl[u] = *(const uint4*)(BloBase + u * 16);
    }

    #pragma unroll 1
    for (int c = 0; c < 8; c++) {
        __syncthreads();
        {
            char* sa = smc + ar * LDA_B + ac * 2;
            char* sl = sa + OFF_ALO;
            #pragma unroll
            for (int f = 0; f < 8; f++) {
                __nv_bfloat16 h0, h1, h2, h3, l0, l1, l2, l3;
                splitbf(av[f].x, h0, l0);
                splitbf(av[f].y, h1, l1);
                splitbf(av[f].z, h2, l2);
                splitbf(av[f].w, h3, l3);
                __nv_bfloat162 hh0, hh1, ll0, ll1;
                hh0.x = h0; hh0.y = h1; hh1.x = h2; hh1.y = h3;
                ll0.x = l0; ll0.y = l1; ll1.x = l2; ll1.y = l3;
                uint2 hv = {*(uint32_t*)&hh0, *(uint32_t*)&hh1};
                uint2 lv = {*(uint32_t*)&ll0, *(uint32_t*)&ll1};
                *(uint2*)(sa + f * 8) = hv;
                *(uint2*)(sl + f * 8) = lv;
            }
            char* sb = smc + OFF_BHI + ar * LDA_B + bo;
            char* sbl = smc + OFF_BLO + ar * LDA_B + bo;
            #pragma unroll
            for (int u = 0; u < 4; u++) {
                *(uint4*)(sb + u * 16) = bh[u];
                *(uint4*)(sbl + u * 16) = bl[u];
            }
        }
        __syncthreads();

        // prefetch next chunk
        float4 nav[8];
        uint4 nbh[4], nbl[4];
        if (c < 7) {
            #pragma unroll
            for (int f = 0; f < 8; f++)
                nav[f] = *(const float4*)(Abase + (c + 1) * 64 + f * 4);
            #pragma unroll
            for (int u = 0; u < 4; u++) {
                nbh[u] = *(const uint4*)(BhiBase + (c + 1) * 128 + u * 16);
                nbl[u] = *(const uint4*)(BloBase + (c + 1) * 128 + u * 16);
            }
        }

        #pragma unroll
        for (int kk = 0; kk < 4; kk++) {
            const uint32_t koff = (kk * 16 + qk) * 2;
            uint32_t ah[2][4], al[2][4];
            #pragma unroll
            for (int mf = 0; mf < 2; mf++) {
                uint32_t base = sbase + (wm * 32 + mf * 16 + qrow) * LDA_B + koff;
                ah[mf][0] = lds32(base);
                ah[mf][1] = lds32(base + 8 * LDA_B);
                ah[mf][2] = lds32(base + 16);
                ah[mf][3] = lds32(base + 8 * LDA_B + 16);
                al[mf][0] = lds32(base + OFF_ALO);
                al[mf][1] = lds32(base + OFF_ALO + 8 * LDA_B);
                al[mf][2] = lds32(base + OFF_ALO + 16);
                al[mf][3] = lds32(base + OFF_ALO + 8 * LDA_B + 16);
            }
            #pragma unroll
            for (int nf = 0; nf < 8; nf++) {
                uint32_t bb = sbase + OFF_BHI + (wn * 64 + nf * 8 + qrow) * LDA_B + koff;
                uint32_t bh0 = lds32(bb);
                uint32_t bh1 = lds32(bb + 16);
                uint32_t bl0 = lds32(bb + (OFF_BLO - OFF_BHI));
                uint32_t bl1 = lds32(bb + (OFF_BLO - OFF_BHI) + 16);
                #pragma unroll
                for (int mf = 0; mf < 2; mf++) {
                    mma16816(acc[mf][nf], ah[mf], bh0, bh1);
                    mma16816(acc[mf][nf], ah[mf], bl0, bl1);
                    mma16816(acc[mf][nf], al[mf], bh0, bh1);
                }
            }
        }
        if (c < 7) {
            #pragma unroll
            for (int f = 0; f < 8; f++) av[f] = nav[f];
            #pragma unroll
            for (int u = 0; u < 4; u++) { bh[u] = nbh[u]; bl[u] = nbl[u]; }
        }
    }
}

// post-head GEMM kernel (modes 0/1/2, same semantics as before)
__global__ __launch_bounds__(256)
void tc_gemm_kernel(const float* __restrict__ A,
                    const __nv_bfloat16* __restrict__ Bhi,
                    const __nv_bfloat16* __restrict__ Blo,
                    const float* __restrict__ bias, float* __restrict__ C, int ldc,
                    int mode, const int* __restrict__ widp,
                    const int* __restrict__ rootp, const float* __restrict__ Us)
{
    extern __shared__ char smc[];
    const uint32_t sbase = smem_u32(smc);
    __shared__ int s_rows[128];

    const int tid = threadIdx.x;
    const int wid_ = tid >> 5;
    const int lane = tid & 31;
    const int wm = wid_ & 3;
    const int wn = wid_ >> 2;
    const int qrow = lane >> 2;
    const int qk = (lane & 3) << 1;
    const int m0 = blockIdx.y * 128;
    const int n0 = blockIdx.x * 128;

    if (tid < 128) s_rows[tid] = (mode == 2) ? g_cmap[m0 + tid] : (m0 + tid);
    __syncthreads();

    const int ar = tid >> 1;
    const int ac = (tid & 1) * 32;
    const int bo = (tid & 1) * 64;
    const float* Abase = A + (size_t)s_rows[ar] * Hh + ac;
    const char* BhiBase = (const char*)(Bhi + (size_t)(n0 + ar) * Hh) + bo;
    const char* BloBase = (const char*)(Blo + (size_t)(n0 + ar) * Hh) + bo;

    float acc[2][8][4];
    #pragma unroll
    for (int mf = 0; mf < 2; mf++)
        #pragma unroll
        for (int nf = 0; nf < 8; nf++)
            #pragma unroll
            for (int r = 0; r < 4; r++) acc[mf][nf][r] = 0.f;

    tc_main(Abase, BhiBase, BloBase, smc, sbase, tid, wm, wn, qrow, qk, acc);

    if (mode == 0) {
        #pragma unroll
        for (int mf = 0; mf < 2; mf++) {
            int r0 = m0 + wm * 32 + mf * 16 + qrow;
            #pragma unroll
            for (int nf = 0; nf < 8; nf++) {
                int col = n0 + wn * 64 + nf * 8 + qk;
                float2 o0 = {acc[mf][nf][0] + bias[col], acc[mf][nf][1] + bias[col + 1]};
                float2 o1 = {acc[mf][nf][2] + bias[col], acc[mf][nf][3] + bias[col + 1]};
                *(float2*)&C[(size_t)r0 * ldc + col] = o0;
                *(float2*)&C[(size_t)(r0 + 8) * ldc + col] = o1;
            }
        }
    } else if (mode == 1) {
        int slot = blockIdx.x * 2 + wn;
        #pragma unroll
        for (int mf = 0; mf < 2; mf++) {
            int r0 = m0 + wm * 32 + mf * 16 + qrow;
            int r1 = r0 + 8;
            int w0, b0, w1, b1;
            if (r0 < TBq) { w0 = widp[r0]; b0 = r0 & (Bq - 1); }
            else          { w0 = rootp[r0 - TBq]; b0 = r0 - TBq; }
            if (r1 < TBq) { w1 = widp[r1]; b1 = r1 & (Bq - 1); }
            else          { w1 = rootp[r1 - TBq]; b1 = r1 - TBq; }
            const float* Pe0 = g_PembU + (size_t)w0 * Hh;
            const float* Pm0 = g_PmolU + (size_t)b0 * Hh;
            const float* Pe1 = g_PembU + (size_t)w1 * Hh;
            const float* Pm1 = g_PmolU + (size_t)b1 * Hh;
            float p0 = 0.f, p1 = 0.f;
            #pragma unroll
            for (int nf = 0; nf < 8; nf++) {
                int col = wn * 64 + nf * 8 + qk;
                int gc = blockIdx.x * 128 + col;
                float u0 = Us[gc], u1 = Us[gc + 1];
                p0 += fmaxf(acc[mf][nf][0] + Pe0[gc] + Pm0[gc], 0.f) * u0;
                p0 += fmaxf(acc[mf][nf][1] + Pe0[gc + 1] + Pm0[gc + 1], 0.f) * u1;
                p1 += fmaxf(acc[mf][nf][2] + Pe1[gc] + Pm1[gc], 0.f) * u0;
                p1 += fmaxf(acc[mf][nf][3] + Pe1[gc + 1] + Pm1[gc + 1], 0.f) * u1;
            }
            p0 += __shfl_xor_sync(0xffffffffu, p0, 1);
            p0 += __shfl_xor_sync(0xffffffffu, p0, 2);
            p1 += __shfl_xor_sync(0xffffffffu, p1, 1);
            p1 += __shfl_xor_sync(0xffffffffu, p1, 2);
            if ((lane & 3) == 0) {
                g_spart[(size_t)slot * MSr + r0] = p0;
                g_spart[(size_t)slot * MSr + r1] = p1;
            }
        }
    } else {
        #pragma unroll
        for (int mf = 0; mf < 2; mf++) {
            int rl0 = wm * 32 + mf * 16 + qrow;
            int j0 = m0 + rl0;
            int bc0 = s_rows[rl0] & (Bq - 1);
            int bc1 = s_rows[rl0 + 8] & (Bq - 1);
            const float* Pm0 = g_PmolW + (size_t)bc0 * Hh;
            const float* Pm1 = g_PmolW + (size_t)bc1 * Hh;
            float* d0 = g_phidc + (size_t)(Bq + j0) * Hh;
            float* d1 = g_phidc + (size_t)(Bq + j0 + 8) * Hh;
            #pragma unroll
            for (int nf = 0; nf < 8; nf++) {
                int col = n0 + wn * 64 + nf * 8 + qk;
                float2 o0 = {fmaxf(acc[mf][nf][0] + Pm0[col], 0.f),
                             fmaxf(acc[mf][nf][1] + Pm0[col + 1], 0.f)};
                float2 o1 = {fmaxf(acc[mf][nf][2] + Pm1[col], 0.f),
                             fmaxf(acc[mf][nf][3] + Pm1[col + 1], 0.f)};
                *(float2*)(d0 + col) = o0;
                *(float2*)(d1 + col) = o1;
            }
        }
    }
}

// fused emb-precompute: 4 GEMMs (Pz, Pr, Ph, PembU) selected by blockIdx.z
__global__ __launch_bounds__(256)
void tc_gemm_pre4(const float* __restrict__ A,
                  const __nv_bfloat16* b0h, const __nv_bfloat16* b0l,
                  const float* bias0, float* C0,
                  const __nv_bfloat16* b1h, const __nv_bfloat16* b1l,
                  const float* bias1, float* C1,
                  const __nv_bfloat16* b2h, const __nv_bfloat16* b2l,
                  const float* bias2, float* C2,
                  const __nv_bfloat16* b3h, const __nv_bfloat16* b3l,
                  const float* bias3, float* C3)
{
    extern __shared__ char smc[];
    const uint32_t sbase = smem_u32(smc);
    const int z = blockIdx.z;
    const __nv_bfloat16* Bhi = (z == 0) ? b0h : (z == 1) ? b1h : (z == 2) ? b2h : b3h;
    const __nv_bfloat16* Blo = (z == 0) ? b0l : (z == 1) ? b1l : (z == 2) ? b2l : b3l;
    const float* bias = (z == 0) ? bias0 : (z == 1) ? bias1 : (z == 2) ? bias2 : bias3;
    float* C = (z == 0) ? C0 : (z == 1) ? C1 : (z == 2) ? C2 : C3;

    const int tid = threadIdx.x;
    const int wid_ = tid >> 5;
    const int lane = tid & 31;
    const int wm = wid_ & 3;
    const int wn = wid_ >> 2;
    const int qrow = lane >> 2;
    const int qk = (lane & 3) << 1;
    const int m0 = blockIdx.y * 128;
    const int n0 = blockIdx.x * 128;

    const int ar = tid >> 1;
    const int ac = (tid & 1) * 32;
    const int bo = (tid & 1) * 64;
    const float* Abase = A + (size_t)(m0 + ar) * Hh + ac;
    const char* BhiBase = (const char*)(Bhi + (size_t)(n0 + ar) * Hh) + bo;
    const char* BloBase = (const char*)(Blo + (size_t)(n0 + ar) * Hh) + bo;

    float acc[2][8][4];
    #pragma unroll
    for (int mf = 0; mf < 2; mf++)
        #pragma unroll
        for (int nf = 0; nf < 8; nf++)
            #pragma unroll
            for (int r = 0; r < 4; r++) acc[mf][nf][r] = 0.f;

    tc_main(Abase, BhiBase, BloBase, smc, sbase, tid, wm, wn, qrow, qk, acc);

    #pragma unroll
    for (int mf = 0; mf < 2; mf++) {
        int r0 = m0 + wm * 32 + mf * 16 + qrow;
        #pragma unroll
        for (int nf = 0; nf < 8; nf++) {
            int col = n0 + wn * 64 + nf * 8 + qk;
            float2 o0 = {acc[mf][nf][0] + bias[col], acc[mf][nf][1] + bias[col + 1]};
            float2 o1 = {acc[mf][nf][2] + bias[col], acc[mf][nf][3] + bias[col + 1]};
            *(float2*)&C[(size_t)r0 * Hh + col] = o0;
            *(float2*)&C[(size_t)(r0 + 8) * Hh + col] = o1;
        }
    }
}

// ---------------- housekeeping ----------------
__global__ __launch_bounds__(256)
void prep_kernel()
{
    int i = blockIdx.x * 256 + threadIdx.x;
    if (i < 5) g_acc[i] = 0.0;
    if (i == 5) { g_barc = 0; g_ccount = 0; }
    if (i == 6) g_bars = 0;
    if (i < Hh) {
        g_hbuf[(size_t)PADROW * Hh + i] = 0.f;
        g_hbufUr[(size_t)PADROW * Hh + i] = 0.f;
    }
    if (i < NCMP + 256) g_cmap[i] = 0;
}

__global__ __launch_bounds__(256)
void compact_kernel(const int* __restrict__ dirs)
{
    int i = blockIdx.x * 256 + threadIdx.x;
    if (dirs[i]) {
        int s = atomicAdd(&g_ccount, 1);
        g_cmap[s] = i;
    }
}

__global__ __launch_bounds__(256)
void build_curo(const int* __restrict__ oni, const int* __restrict__ roni)
{
    int i = blockIdx.x, tid = threadIdx.x;
    __shared__ int ids[MAXNB];
    if (tid < MAXNB)
        ids[tid] = (i < TBq) ? oni[(size_t)i * MAXNB + tid]
                             : roni[(size_t)(i - TBq) * MAXNB + tid];
    __syncthreads();
    for (int h = tid; h < Hh; h += 256) {
        float v = 0.f;
        #pragma unroll
        for (int n = 0; n < MAXNB; n++) {
            int id = ids[n];
            if (id == PADROW) continue;
            v += g_hbuf[(size_t)id * Hh + h];
        }
        g_curo[(size_t)i * Hh + h] = v;
    }
}

__global__ __launch_bounds__(512)
void phid0_kernel()
{
    int b = blockIdx.x, h = threadIdx.x;
    g_phidc[(size_t)b * Hh + h] = fmaxf(g_PmolW[(size_t)b * Hh + h], 0.f);
}

// ---------------- stop head finalize ----------------
__global__ __launch_bounds__(256)
void stop_final_kernel(const float* __restrict__ bs, const int* __restrict__ dirs)
{
    int i = blockIdx.x * 256 + threadIdx.x;
    float s = bs[0];
    #pragma unroll
    for (int k = 0; k < 8; k++) s += g_spart[(size_t)k * MSr + i];
    float tgt = (i < TBq) ? (float)dirs[i] : 0.f;
    float loss = fmaxf(s, 0.f) - s * tgt + log1pf(expf(-fabsf(s)));
    float corr = ((s >= 0.5f) == (tgt > 0.5f)) ? 1.f : 0.f;
    __shared__ double r0[256], r1[256];
    int tid = threadIdx.x;
    r0[tid] = (double)loss;
    r1[tid] = (double)corr;
    __syncthreads();
    for (int o = 128; o > 0; o >>= 1) {
        if (tid < o) { r0[tid] += r0[tid + o]; r1[tid] += r1[tid + o]; }
        __syncthreads();
    }
    if (tid == 0) {
        atomicAdd(&g_acc[0], r0[0]);
        atomicAdd(&g_acc[1], r1[0]);
    }
}

// ---------------- pred head: log-softmax CE + argmax ----------------
__global__ __launch_bounds__(256)
void pred_rows_kernel(const int* __restrict__ root_wid, const int* __restrict__ y_wid)
{
    int j = blockIdx.x, tid = threadIdx.x;
    const float* row = g_logitsc + (size_t)j * Vv;
    int tgt = (j < Bq) ? root_wid[j] : y_wid[g_cmap[j - Bq]];

    float mval = -1e30f; int midx = Vv;
    for (int k = tid; k < Vv; k += 256) {
        float v = row[k];
        if (v > mval) { mval = v; midx = k; }
    }
    __shared__ float rv[256];
    __shared__ int ri[256];
    rv[tid] = mval; ri[tid] = midx; __syncthreads();
    for (int s = 128; s > 0; s >>= 1) {
        if (tid < s) {
            if (rv[tid + s] > rv[tid] ||
                (rv[tid + s] == rv[tid] && ri[tid + s] < ri[tid])) {
                rv[tid] = rv[tid + s]; ri[tid] = ri[tid + s];
            }
        }
        __syncthreads();
    }
    float gmax = rv[0]; int gidx = ri[0];
    __syncthreads();
    float p = 0.f;
    for (int k = tid; k < Vv; k += 256) p += __expf(row[k] - gmax);
    rv[tid] = p; __syncthreads();
    for (int s = 128; s > 0; s >>= 1) {
        if (tid < s) rv[tid] += rv[tid + s];
        __syncthreads();
    }
    if (tid == 0) {
        float lse = gmax + logf(rv[0]);
        float ce = -(row[tgt] - lse);
        atomicAdd(&g_acc[2], (double)ce);
        if (gidx == tgt) atomicAdd(&g_acc[3], 1.0);
        atomicAdd(&g_acc[4], 1.0);
    }
}

__global__ void finalize_kernel(float* out)
{
    out[0] = (float)(g_acc[2] / (double)Bq);
    out[1] = (float)(g_acc[0] / (double)Bq);
    out[2] = (float)(g_acc[3] / g_acc[4]);
    out[3] = (float)(g_acc[1] / (double)MSr);
}

// ---------------- launch ----------------
extern "C" void kernel_launch(void* const* d_in, const int* in_sizes, int n_in,
                              void* d_out, int out_size)
{
    const float* mol_vec  = (const float*)d_in[0];
    const int*   wid      = (const int*)d_in[1];
    const int*   y_wid    = (const int*)d_in[2];
    const int*   dirs     = (const int*)d_in[3];
    const int*   hni      = (const int*)d_in[4];
    const int*   oni      = (const int*)d_in[5];
    const int*   root_wid = (const int*)d_in[6];
    const int*   roni     = (const int*)d_in[7];
    const float* emb      = (const float*)d_in[8];
    const float* Wz       = (const float*)d_in[9];
    const float* bz       = (const float*)d_in[10];
    const float* Wr       = (const float*)d_in[11];
    const float* br       = (const float*)d_in[12];
    const float* Ur       = (const float*)d_in[13];
    const float* Wh       = (const float*)d_in[14];
    const float* bh       = (const float*)d_in[15];
    const float* Wm       = (const float*)d_in[16];
    const float* bW       = (const float*)d_in[17];
    const float* U        = (const float*)d_in[18];
    const float* bU       = (const float*)d_in[19];
    const float* Wo       = (const float*)d_in[20];
    const float* bo       = (const float*)d_in[21];
    const float* Us       = (const float*)d_in[22];
    const float* bs       = (const float*)d_in[23];

    float *gPz, *gPr, *gPh, *gPembU, *gPmolU, *gPmolW, *gcuro, *gphidc, *glogitsc, *ghbuf;
    __nv_bfloat16 *gBuH, *gBuL, *gBwH, *gBwL, *gBoH, *gBoL;
    __nv_bfloat16 *gBzhH, *gBzhL, *gBUrH, *gBUrL;
    __nv_bfloat16 *gBz0H, *gBz0L, *gBr0H, *gBr0L, *gBh0H, *gBh0L, *gBU0H, *gBU0L;
    cudaGetSymbolAddress((void**)&gPz, g_Pz);
    cudaGetSymbolAddress((void**)&gPr, g_Pr);
    cudaGetSymbolAddress((void**)&gPh, g_Ph);
    cudaGetSymbolAddress((void**)&gPembU, g_PembU);
    cudaGetSymbolAddress((void**)&gPmolU, g_PmolU);
    cudaGetSymbolAddress((void**)&gPmolW, g_PmolW);
    cudaGetSymbolAddress((void**)&gcuro, g_curo);
    cudaGetSymbolAddress((void**)&gphidc, g_phidc);
    cudaGetSymbolAddress((void**)&glogitsc, g_logitsc);
    cudaGetSymbolAddress((void**)&ghbuf, g_hbuf);
    cudaGetSymbolAddress((void**)&gBuH, g_Bu_hi);
    cudaGetSymbolAddress((void**)&gBuL, g_Bu_lo);
    cudaGetSymbolAddress((void**)&gBwH, g_Bw_hi);
    cudaGetSymbolAddress((void**)&gBwL, g_Bw_lo);
    cudaGetSymbolAddress((void**)&gBoH, g_Bo_hi);
    cudaGetSymbolAddress((void**)&gBoL, g_Bo_lo);
    cudaGetSymbolAddress((void**)&gBzhH, g_Bzh_hi);
    cudaGetSymbolAddress((void**)&gBzhL, g_Bzh_lo);
    cudaGetSymbolAddress((void**)&gBUrH, g_BUr_hi);
    cudaGetSymbolAddress((void**)&gBUrL, g_BUr_lo);
    cudaGetSymbolAddress((void**)&gBz0H, g_Bz0_hi);
    cudaGetSymbolAddress((void**)&gBz0L, g_Bz0_lo);
    cudaGetSymbolAddress((void**)&gBr0H, g_Br0_hi);
    cudaGetSymbolAddress((void**)&gBr0L, g_Br0_lo);
    cudaGetSymbolAddress((void**)&gBh0H, g_Bh0_hi);
    cudaGetSymbolAddress((void**)&gBh0L, g_Bh0_lo);
    cudaGetSymbolAddress((void**)&gBU0H, g_BU0_hi);
    cudaGetSymbolAddress((void**)&gBU0L, g_BU0_lo);

    cudaFuncSetAttribute(tc_gemm_kernel,
                         cudaFuncAttributeMaxDynamicSharedMemorySize, TCSM_BYTES);
    cudaFuncSetAttribute(tc_gemm_pre4,
                         cudaFuncAttributeMaxDynamicSharedMemorySize, TCSM_BYTES);
    cudaFuncSetAttribute(scan_kernel,
                         cudaFuncAttributeMaxDynamicSharedMemorySize, SCAN_SMEM);

    prep_kernel<<<47, 256>>>();
    compact_kernel<<<92, 256>>>(dirs);

    // batched weight transposes + bf16 split (one launch)
    ConvJobs jobs;
    jobs.j[0] = {U + (size_t)Hh * Hh, gBuH, gBuL, 16};
    jobs.j[1] = {Wm, gBwH, gBwL, 16};
    jobs.j[2] = {Wo, gBoH, gBoL, 32};
    jobs.j[3] = {Wz + (size_t)Hh * Hh, gBzhH, gBzhL, 16};
    jobs.j[4] = {Wh + (size_t)Hh * Hh, gBzhH + (size_t)Hh * Hh, gBzhL + (size_t)Hh * Hh, 16};
    jobs.j[5] = {Ur, gBUrH, gBUrL, 16};
    jobs.j[6] = {Wz, gBz0H, gBz0L, 16};
    jobs.j[7] = {Wr, gBr0H, gBr0L, 16};
    jobs.j[8] = {Wh, gBh0H, gBh0L, 16};
    jobs.j[9] = {U, gBU0H, gBU0L, 16};
    convT_all<<<dim3(32, 16, 10), 256>>>(jobs);

    // fused emb precomputes (one launch, 4 GEMMs)
    tc_gemm_pre4<<<dim3(4, 8, 4), 256, TCSM_BYTES>>>(
        emb,
        gBz0H, gBz0L, bz, gPz,
        gBr0H, gBr0L, br, gPr,
        gBh0H, gBh0L, bh, gPh,
        gBU0H, gBU0L, bU, gPembU);
    // small K=64 mol projections stay fp32
    sgemm_kernel<<<dim3(Hh / BN, Bq / BM), 256>>>(Bq, Hh, Ll, mol_vec, U + (size_t)2 * Hh * Hh, nullptr, gPmolU);
    sgemm_kernel<<<dim3(Hh / BN, Bq / BM), 256>>>(Bq, Hh, Ll, mol_vec, Wm + (size_t)Hh * Hh, bW, gPmolW);

    // persistent fused GRU scan
    scan_kernel<<<NBLK, 256, SCAN_SMEM>>>(wid, hni);

    // stop head
    build_curo<<<MSr, 256>>>(oni, roni);
    tc_gemm_kernel<<<dim3(4, MSr / 128), 256, TCSM_BYTES>>>(
        gcuro, gBuH, gBuL, nullptr, nullptr, 0, 1, wid, root_wid, Us);
    stop_final_kernel<<<94, 256>>>(bs, dirs);

    // pred head (compacted)
    phid0_kernel<<<Bq, Hh>>>();
    tc_gemm_kernel<<<dim3(4, NCMP / 128), 256, TCSM_BYTES>>>(
        ghbuf, gBwH, gBwL, nullptr, nullptr, 0, 2, nullptr, nullptr, nullptr);
    tc_gemm_kernel<<<dim3(8, MPRED / 128), 256, TCSM_BYTES>>>(
        gphidc, gBoH, gBoL, bo, glogitsc, Vv, 0, nullptr, nullptr, nullptr);
    pred_rows_kernel<<<MPRED, 256>>>(root_wid, y_wid);

    finalize_kernel<<<1, 1>>>((float*)d_out);
}

// round 9
// speedup vs baseline: 5.9189x; 1.1012x over previous
#include <cuda_runtime.h>
#include <cuda_bf16.h>
#include <math.h>
#include <stdint.h>

// Problem constants
#define Bq 512
#define Hh 512
#define Ll 64
#define Vv 1024
#define Tt 46
#define TBq 23552          // T*B
#define PADROW 23552
#define MSr 24064          // TB + B
#define MAXNB 8
#define NCMP 11776         // compacted pred rows (dirs==1)
#define MPRED 12288        // B + NCMP
#define NBLK 128           // persistent scan grid

// ---------------- scratch ----------------
__device__ float g_hbuf[(size_t)(TBq + 1) * Hh];
__device__ float g_hbufUr[(size_t)(TBq + 1) * Hh];
__device__ __nv_bfloat16 g_hbuf_hi[(size_t)(TBq + 1) * Hh];
__device__ __nv_bfloat16 g_hbuf_lo[(size_t)(TBq + 1) * Hh];
__device__ float g_Pz[(size_t)Vv * Hh];
__device__ float g_Pr[(size_t)Vv * Hh];
__device__ float g_Ph[(size_t)Vv * Hh];
__device__ float g_PembU[(size_t)Vv * Hh];
__device__ float g_PmolU[(size_t)Bq * Hh];
__device__ float g_PmolW[(size_t)Bq * Hh];
__device__ float g_sumh[(size_t)Bq * Hh];
__device__ __nv_bfloat16 g_curo_hi[(size_t)MSr * Hh];
__device__ __nv_bfloat16 g_curo_lo[(size_t)MSr * Hh];
__device__ __nv_bfloat16 g_phid_hi[(size_t)MPRED * Hh];
__device__ __nv_bfloat16 g_phid_lo[(size_t)MPRED * Hh];
__device__ float g_logitsc[(size_t)MPRED * Vv];
__device__ float g_spart[(size_t)8 * MSr];
__device__ int   g_cmap[NCMP + 256];
__device__ int   g_ccount;
__device__ int   g_barc;
__device__ volatile int g_bars;
__device__ double g_acc[5];
// scan split activations (per-step)
__device__ __nv_bfloat16 g_shg_hi[(size_t)2 * Bq * Hh];
__device__ __nv_bfloat16 g_shg_lo[(size_t)2 * Bq * Hh];
// bf16 split weights, stored [N, K]
__device__ __nv_bfloat16 g_Bu_hi[(size_t)Hh * Hh];
__device__ __nv_bfloat16 g_Bu_lo[(size_t)Hh * Hh];
__device__ __nv_bfloat16 g_Bw_hi[(size_t)Hh * Hh];
__device__ __nv_bfloat16 g_Bw_lo[(size_t)Hh * Hh];
__device__ __nv_bfloat16 g_Bo_hi[(size_t)Vv * Hh];
__device__ __nv_bfloat16 g_Bo_lo[(size_t)Vv * Hh];
__device__ __nv_bfloat16 g_Bzh_hi[(size_t)2 * Hh * Hh];
__device__ __nv_bfloat16 g_Bzh_lo[(size_t)2 * Hh * Hh];
__device__ __nv_bfloat16 g_BUr_hi[(size_t)Hh * Hh];
__device__ __nv_bfloat16 g_BUr_lo[(size_t)Hh * Hh];
__device__ __nv_bfloat16 g_Bz0_hi[(size_t)Hh * Hh];
__device__ __nv_bfloat16 g_Bz0_lo[(size_t)Hh * Hh];
__device__ __nv_bfloat16 g_Br0_hi[(size_t)Hh * Hh];
__device__ __nv_bfloat16 g_Br0_lo[(size_t)Hh * Hh];
__device__ __nv_bfloat16 g_Bh0_hi[(size_t)Hh * Hh];
__device__ __nv_bfloat16 g_Bh0_lo[(size_t)Hh * Hh];
__device__ __nv_bfloat16 g_BU0_hi[(size_t)Hh * Hh];
__device__ __nv_bfloat16 g_BU0_lo[(size_t)Hh * Hh];

// ---------------- helpers ----------------
__device__ __forceinline__ uint32_t smem_u32(const void* p) {
    uint32_t a;
    asm("{ .reg .u64 t; cvta.to.shared.u64 t, %1; cvt.u32.u64 %0, t; }"
        : "=r"(a) : "l"(p));
    return a;
}
__device__ __forceinline__ uint32_t lds32(uint32_t addr) {
    uint32_t v;
    asm volatile("ld.shared.b32 %0, [%1];" : "=r"(v) : "r"(addr));
    return v;
}
__device__ __forceinline__ void mma16816(float* d, const uint32_t* a,
                                         uint32_t b0, uint32_t b1) {
    asm volatile(
        "mma.sync.aligned.m16n8k16.row.col.f32.bf16.bf16.f32 "
        "{%0,%1,%2,%3}, {%4,%5,%6,%7}, {%8,%9}, {%0,%1,%2,%3};"
        : "+f"(d[0]), "+f"(d[1]), "+f"(d[2]), "+f"(d[3])
        : "r"(a[0]), "r"(a[1]), "r"(a[2]), "r"(a[3]), "r"(b0), "r"(b1));
}
__device__ __forceinline__ void splitbf(float v, __nv_bfloat16& h, __nv_bfloat16& l) {
    h = __float2bfloat16(v);
    l = __float2bfloat16(v - __bfloat162float(h));
}
__device__ __forceinline__ float fast_sigmoid(float x) {
    return __fdividef(1.f, 1.f + __expf(-x));
}

// ---------------- software grid barrier ----------------
__device__ __forceinline__ void grid_bar(int nb)
{
    __syncthreads();
    if (threadIdx.x == 0) {
        int s = g_bars;
        __threadfence();
        int t = atomicAdd(&g_barc, 1);
        if (t == nb - 1) {
            g_barc = 0;
            __threadfence();
            g_bars = s + 1;
        } else {
            while (g_bars == s) { __nanosleep(32); }
        }
        __threadfence();
    }
    __syncthreads();
}

// ---------------- generic 64x64 SGEMM (small precomputes) ----------------
#define BM 64
#define BN 64
#define BK 16

__global__ __launch_bounds__(256)
void sgemm_kernel(int M, int N, int K,
                  const float* __restrict__ A, const float* __restrict__ Bm,
                  const float* __restrict__ bias, float* __restrict__ C)
{
    __shared__ float As[BK][BM];
    __shared__ float Bs[BK][BN];
    const int tid = threadIdx.x;
    const int tx = tid & 15;
    const int ty = tid >> 4;
    const int m0 = blockIdx.y * BM;
    const int n0 = blockIdx.x * BN;

    const int a_row  = tid >> 2;
    const int a_col4 = (tid & 3) << 2;
    const int b_row  = tid >> 4;
    const int b_col4 = (tid & 15) << 2;

    const float* Aptr = A + (size_t)(m0 + a_row) * K + a_col4;
    const float* Bptr = Bm + (size_t)b_row * N + n0 + b_col4;

    float acc[4][4];
    #pragma unroll
    for (int i = 0; i < 4; i++)
        #pragma unroll
        for (int j = 0; j < 4; j++) acc[i][j] = 0.f;

    for (int k0 = 0; k0 < K; k0 += BK) {
        float4 av = *(const float4*)(Aptr + k0);
        float4 bv = *(const float4*)(Bptr + (size_t)k0 * N);
        As[a_col4 + 0][a_row] = av.x;
        As[a_col4 + 1][a_row] = av.y;
        As[a_col4 + 2][a_row] = av.z;
        As[a_col4 + 3][a_row] = av.w;
        *(float4*)&Bs[b_row][b_col4] = bv;
        __syncthreads();
        #pragma unroll
        for (int k = 0; k < BK; k++) {
            float4 a4 = *(const float4*)&As[k][ty << 2];
            float4 b4 = *(const float4*)&Bs[k][tx << 2];
            float a[4] = {a4.x, a4.y, a4.z, a4.w};
            float b[4] = {b4.x, b4.y, b4.z, b4.w};
            #pragma unroll
            for (int i = 0; i < 4; i++)
                #pragma unroll
                for (int j = 0; j < 4; j++) acc[i][j] = fmaf(a[i], b[j], acc[i][j]);
        }
        __syncthreads();
    }

    #pragma unroll
    for (int i = 0; i < 4; i++) {
        int row = m0 + (ty << 2) + i;
        int col = n0 + (tx << 2);
        float4 out;
        float b0 = bias ? bias[col + 0] : 0.f;
        float b1 = bias ? bias[col + 1] : 0.f;
        float b2 = bias ? bias[col + 2] : 0.f;
        float b3 = bias ? bias[col + 3] : 0.f;
        out.x = acc[i][0] + b0; out.y = acc[i][1] + b1;
        out.z = acc[i][2] + b2; out.w = acc[i][3] + b3;
        *(float4*)&C[(size_t)row * N + col] = out;
    }
}

// ---------------- batched weight transpose + bf16 split ----------------
struct ConvJob {
    const float* src;
    __nv_bfloat16* hi;
    __nv_bfloat16* lo;
    int nx;
};
struct ConvJobs { ConvJob j[10]; };

__global__ __launch_bounds__(256)
void convT_all(ConvJobs jobs)
{
    ConvJob jb = jobs.j[blockIdx.z];
    if ((int)blockIdx.x >= jb.nx) return;
    const int N = jb.nx * 32;
    const int K = Hh;
    __shared__ float t[32][33];
    int k0 = blockIdx.y * 32, n0 = blockIdx.x * 32;
    int tx = threadIdx.x & 31, ty = threadIdx.x >> 5;
    for (int r = ty; r < 32; r += 8)
        t[r][tx] = jb.src[(size_t)(k0 + r) * N + n0 + tx];
    __syncthreads();
    for (int r = ty; r < 32; r += 8) {
        float v = t[tx][r];
        __nv_bfloat16 h, l;
        splitbf(v, h, l);
        jb.hi[(size_t)(n0 + r) * K + k0 + tx] = h;
        jb.lo[(size_t)(n0 + r) * K + k0 + tx] = l;
    }
}

// ---------------- persistent fused GRU scan ----------------
#define SLDA 144
#define SA0 0
#define SA1 9216
#define SA2 18432
#define SA3 27648
#define SB0 36864
#define SB1 41472
#define SB2 46080
#define SB3 50688
#define SCAN_SMEM 55296

__global__ __launch_bounds__(256)
void scan_kernel(const int* __restrict__ wid, const int* __restrict__ hni)
{
    extern __shared__ char sms[];
    const uint32_t u0 = smem_u32(sms);
    __shared__ int s_ids4[4 * MAXNB];
    __shared__ int s_w4[4];

    const int tid = threadIdx.x;
    const int nb = (int)gridDim.x;
    const int wid_ = tid >> 5;
    const int lane = tid & 31;
    const int wm = wid_ & 3;
    const int wg = wid_ >> 2;
    const int qrow = lane >> 2;
    const int qk = (lane & 3) << 1;

    for (int t = 0; t < Tt; t++) {
        // ---- P1: gather sum_h / sum_g; 4 b's per block, one sync ----
        {
            const int b0 = (int)blockIdx.x * 4;
            if (tid < 32)
                s_ids4[tid] = hni[((size_t)(t * Bq + b0 + (tid >> 3))) * MAXNB + (tid & 7)];
            else if (tid < 36)
                s_w4[tid - 32] = wid[t * Bq + b0 + (tid - 32)];
            __syncthreads();
            #pragma unroll
            for (int bl = 0; bl < 4; bl++) {
                const int b = b0 + bl;
                const int w = s_w4[bl];
                #pragma unroll
                for (int hh = 0; hh < Hh; hh += 256) {
                    int h = hh + tid;
                    float xr = g_Pr[(size_t)w * Hh + h];
                    float sh = 0.f, sg = 0.f;
                    #pragma unroll
                    for (int n = 0; n < MAXNB; n++) {
                        int id = s_ids4[bl * 8 + n];
                        if (id == PADROW) continue;
                        float hv = g_hbuf[(size_t)id * Hh + h];
                        float gv = g_hbufUr[(size_t)id * Hh + h];
                        float r = fast_sigmoid(xr + gv);
                        sh += hv;
                        sg += r * hv;
                    }
                    g_sumh[(size_t)b * Hh + h] = sh;
                    __nv_bfloat16 hi, lo;
                    splitbf(sh, hi, lo);
                    g_shg_hi[(size_t)b * Hh + h] = hi;
                    g_shg_lo[(size_t)b * Hh + h] = lo;
                    splitbf(sg, hi, lo);
                    g_shg_hi[(size_t)(Bq + b) * Hh + h] = hi;
                    g_shg_lo[(size_t)(Bq + b) * Hh + h] = lo;
                }
            }
        }
        grid_bar(nb);

        // ---- P2': dual 64x32 MMA (z & h_tilde) + fused h_new, prefetched ----
        {
            const int blk = (int)blockIdx.x;
            const int m0 = (blk >> 4) * 64;
            const int n0 = (blk & 15) * 32;

            float acc[4][4];
            #pragma unroll
            for (int nf = 0; nf < 4; nf++)
                #pragma unroll
                for (int r = 0; r < 4; r++) acc[nf][r] = 0.f;

            const int lr = tid >> 2, lq = tid & 3;
            const int rb = tid >> 3, qb = tid & 7;
            const char* gShH = (const char*)(g_shg_hi + (size_t)(m0 + lr) * Hh) + lq * 32;
            const char* gShL = (const char*)(g_shg_lo + (size_t)(m0 + lr) * Hh) + lq * 32;
            const char* gSgH = (const char*)(g_shg_hi + (size_t)(Bq + m0 + lr) * Hh) + lq * 32;
            const char* gSgL = (const char*)(g_shg_lo + (size_t)(Bq + m0 + lr) * Hh) + lq * 32;
            const char* gBzH = (const char*)(g_Bzh_hi + (size_t)(n0 + rb) * Hh) + qb * 16;
            const char* gBzL = (const char*)(g_Bzh_lo + (size_t)(n0 + rb) * Hh) + qb * 16;
            const char* gBtH = (const char*)(g_Bzh_hi + (size_t)(Hh + n0 + rb) * Hh) + qb * 16;
            const char* gBtL = (const char*)(g_Bzh_lo + (size_t)(Hh + n0 + rb) * Hh) + qb * 16;

            const uint32_t uAh = u0 + (wg ? SA2 : SA0);
            const uint32_t uAl = u0 + (wg ? SA3 : SA1);
            const uint32_t uBh = u0 + (wg ? SB2 : SB0);
            const uint32_t uBl = u0 + (wg ? SB3 : SB1);

            uint4 a0, a0b, a1, a1b, a2, a2b, a3, a3b, b0, b1, b2, b3;
            a0 = *(const uint4*)(gShH); a0b = *(const uint4*)(gShH + 16);
            a1 = *(const uint4*)(gShL); a1b = *(const uint4*)(gShL + 16);
            a2 = *(const uint4*)(gSgH); a2b = *(const uint4*)(gSgH + 16);
            a3 = *(const uint4*)(gSgL); a3b = *(const uint4*)(gSgL + 16);
            b0 = *(const uint4*)(gBzH); b1 = *(const uint4*)(gBzL);
            b2 = *(const uint4*)(gBtH); b3 = *(const uint4*)(gBtL);

            #pragma unroll 1
            for (int c = 0; c < 8; c++) {
                __syncthreads();
                char* d;
                d = sms + SA0 + lr * SLDA + lq * 32; *(uint4*)d = a0; *(uint4*)(d + 16) = a0b;
                d = sms + SA1 + lr * SLDA + lq * 32; *(uint4*)d = a1; *(uint4*)(d + 16) = a1b;
                d = sms + SA2 + lr * SLDA + lq * 32; *(uint4*)d = a2; *(uint4*)(d + 16) = a2b;
                d = sms + SA3 + lr * SLDA + lq * 32; *(uint4*)d = a3; *(uint4*)(d + 16) = a3b;
                *(uint4*)(sms + SB0 + rb * SLDA + qb * 16) = b0;
                *(uint4*)(sms + SB1 + rb * SLDA + qb * 16) = b1;
                *(uint4*)(sms + SB2 + rb * SLDA + qb * 16) = b2;
                *(uint4*)(sms + SB3 + rb * SLDA + qb * 16) = b3;
                __syncthreads();
                uint4 na0, na0b, na1, na1b, na2, na2b, na3, na3b, nb0, nb1, nb2, nb3;
                if (c < 7) {
                    int o = (c + 1) * 128;
                    na0 = *(const uint4*)(gShH + o); na0b = *(const uint4*)(gShH + o + 16);
                    na1 = *(const uint4*)(gShL + o); na1b = *(const uint4*)(gShL + o + 16);
                    na2 = *(const uint4*)(gSgH + o); na2b = *(const uint4*)(gSgH + o + 16);
                    na3 = *(const uint4*)(gSgL + o); na3b = *(const uint4*)(gSgL + o + 16);
                    nb0 = *(const uint4*)(gBzH + o); nb1 = *(const uint4*)(gBzL + o);
                    nb2 = *(const uint4*)(gBtH + o); nb3 = *(const uint4*)(gBtL + o);
                }
                #pragma unroll
                for (int kk = 0; kk < 4; kk++) {
                    const uint32_t koff = (kk * 16 + qk) * 2;
                    uint32_t base = (wm * 16 + qrow) * SLDA + koff;
                    uint32_t ah[4], al[4];
                    ah[0] = lds32(uAh + base);
                    ah[1] = lds32(uAh + base + 8 * SLDA);
                    ah[2] = lds32(uAh + base + 16);
                    ah[3] = lds32(uAh + base + 8 * SLDA + 16);
                    al[0] = lds32(uAl + base);
                    al[1] = lds32(uAl + base + 8 * SLDA);
                    al[2] = lds32(uAl + base + 16);
                    al[3] = lds32(uAl + base + 8 * SLDA + 16);
                    #pragma unroll
                    for (int nf = 0; nf < 4; nf++) {
                        uint32_t bb = (nf * 8 + qrow) * SLDA + koff;
                        uint32_t bh0 = lds32(uBh + bb);
                        uint32_t bh1 = lds32(uBh + bb + 16);
                        uint32_t cl0 = lds32(uBl + bb);
                        uint32_t cl1 = lds32(uBl + bb + 16);
                        mma16816(acc[nf], ah, bh0, bh1);
                        mma16816(acc[nf], ah, cl0, cl1);
                        mma16816(acc[nf], al, bh0, bh1);
                    }
                }
                if (c < 7) {
                    a0 = na0; a0b = na0b; a1 = na1; a1b = na1b;
                    a2 = na2; a2b = na2b; a3 = na3; a3b = na3b;
                    b0 = nb0; b1 = nb1; b2 = nb2; b3 = nb3;
                }
            }
            // epilogue: activation into exchange buffers
            const float* P = wg ? g_Ph : g_Pz;
            const int rl0 = wm * 16 + qrow;
            const int row0 = m0 + rl0, row1 = row0 + 8;
            const int w0 = wid[t * Bq + row0], w1 = wid[t * Bq + row1];
            float* xbuf = (float*)(sms + (wg ? 8192 : 0));
            __syncthreads();
            #pragma unroll
            for (int nf = 0; nf < 4; nf++) {
                int cl = nf * 8 + qk;
                int col = n0 + cl;
                float v00 = acc[nf][0] + P[(size_t)w0 * Hh + col];
                float v01 = acc[nf][1] + P[(size_t)w0 * Hh + col + 1];
                float v10 = acc[nf][2] + P[(size_t)w1 * Hh + col];
                float v11 = acc[nf][3] + P[(size_t)w1 * Hh + col + 1];
                if (wg) {
                    v00 = tanhf(v00); v01 = tanhf(v01);
                    v10 = tanhf(v10); v11 = tanhf(v11);
                } else {
                    v00 = fast_sigmoid(v00); v01 = fast_sigmoid(v01);
                    v10 = fast_sigmoid(v10); v11 = fast_sigmoid(v11);
                }
                xbuf[rl0 * 32 + cl] = v00;
                xbuf[rl0 * 32 + cl + 1] = v01;
                xbuf[(rl0 + 8) * 32 + cl] = v10;
                xbuf[(rl0 + 8) * 32 + cl + 1] = v11;
            }
            __syncthreads();
            const float* zbuf = (const float*)(sms);
            const float* tbuf = (const float*)(sms + 8192);
            const size_t toff = (size_t)t * Bq * Hh;
            #pragma unroll
            for (int e = tid; e < 64 * 32; e += 256) {
                int rl = e >> 5, cl = e & 31;
                size_t gi = (size_t)(m0 + rl) * Hh + (n0 + cl);
                float z = zbuf[e], th = tbuf[e];
                float h = (1.f - z) * g_sumh[gi] + z * th;
                g_hbuf[toff + gi] = h;
                __nv_bfloat16 hi, lo;
                splitbf(h, hi, lo);
                g_hbuf_hi[toff + gi] = hi;
                g_hbuf_lo[toff + gi] = lo;
            }
        }
        grid_bar(nb);

        // ---- P4: hbufUr[t] = h_new @ Ur (64x32 tile, prefetched) ----
        {
            const int blk = (int)blockIdx.x;
            const int m0 = (blk >> 4) * 64;
            const int n0 = (blk & 15) * 32;
            const size_t toff = (size_t)t * Bq * Hh;

            float acc[2][4];
            #pragma unroll
            for (int nf = 0; nf < 2; nf++)
                #pragma unroll
                for (int r = 0; r < 4; r++) acc[nf][r] = 0.f;

            const int lr = tid >> 2, lq = tid & 3;
            const int br = tid >> 3, bq = tid & 7;
            const char* gAh = (const char*)(g_hbuf_hi + toff + (size_t)(m0 + lr) * Hh) + lq * 32;
            const char* gAl = (const char*)(g_hbuf_lo + toff + (size_t)(m0 + lr) * Hh) + lq * 32;
            const char* gBh = (const char*)(g_BUr_hi + (size_t)(n0 + br) * Hh) + bq * 16;
            const char* gBl = (const char*)(g_BUr_lo + (size_t)(n0 + br) * Hh) + bq * 16;
            const int wn = wg;

            uint4 ah0, ah1, al0, al1, bh0, bl0;
            ah0 = *(const uint4*)(gAh); ah1 = *(const uint4*)(gAh + 16);
            al0 = *(const uint4*)(gAl); al1 = *(const uint4*)(gAl + 16);
            bh0 = *(const uint4*)(gBh); bl0 = *(const uint4*)(gBl);

            #pragma unroll 1
            for (int c = 0; c < 8; c++) {
                __syncthreads();
                char* d = sms + SA0 + lr * SLDA + lq * 32;
                *(uint4*)d = ah0; *(uint4*)(d + 16) = ah1;
                d = sms + SA1 + lr * SLDA + lq * 32;
                *(uint4*)d = al0; *(uint4*)(d + 16) = al1;
                *(uint4*)(sms + SB0 + br * SLDA + bq * 16) = bh0;
                *(uint4*)(sms + SB1 + br * SLDA + bq * 16) = bl0;
                __syncthreads();
                uint4 nah0, nah1, nal0, nal1, nbh0, nbl0;
                if (c < 7) {
                    int o = (c + 1) * 128;
                    nah0 = *(const uint4*)(gAh + o); nah1 = *(const uint4*)(gAh + o + 16);
                    nal0 = *(const uint4*)(gAl + o); nal1 = *(const uint4*)(gAl + o + 16);
                    nbh0 = *(const uint4*)(gBh + o); nbl0 = *(const uint4*)(gBl + o);
                }
                #pragma unroll
                for (int kk = 0; kk < 4; kk++) {
                    const uint32_t koff = (kk * 16 + qk) * 2;
                    uint32_t base = (wm * 16 + qrow) * SLDA + koff;
                    uint32_t ah[4], al[4];
                    ah[0] = lds32(u0 + SA0 + base);
                    ah[1] = lds32(u0 + SA0 + base + 8 * SLDA);
                    ah[2] = lds32(u0 + SA0 + base + 16);
                    ah[3] = lds32(u0 + SA0 + base + 8 * SLDA + 16);
                    al[0] = lds32(u0 + SA1 + base);
                    al[1] = lds32(u0 + SA1 + base + 8 * SLDA);
                    al[2] = lds32(u0 + SA1 + base + 16);
                    al[3] = lds32(u0 + SA1 + base + 8 * SLDA + 16);
                    #pragma unroll
                    for (int nf = 0; nf < 2; nf++) {
                        uint32_t bb = (wn * 16 + nf * 8 + qrow) * SLDA + koff;
                        uint32_t b0 = lds32(u0 + SB0 + bb);
                        uint32_t b1 = lds32(u0 + SB0 + bb + 16);
                        uint32_t c0 = lds32(u0 + SB1 + bb);
                        uint32_t c1 = lds32(u0 + SB1 + bb + 16);
                        mma16816(acc[nf], ah, b0, b1);
                        mma16816(acc[nf], ah, c0, c1);
                        mma16816(acc[nf], al, b0, b1);
                    }
                }
                if (c < 7) {
                    ah0 = nah0; ah1 = nah1; al0 = nal0; al1 = nal1;
                    bh0 = nbh0; bl0 = nbl0;
                }
            }
            float* Cc = g_hbufUr + toff;
            int r0 = m0 + wm * 16 + qrow;
            #pragma unroll
            for (int nf = 0; nf < 2; nf++) {
                int col = n0 + wn * 16 + nf * 8 + qk;
                float2 o0 = {acc[nf][0], acc[nf][1]};
                float2 o1 = {acc[nf][2], acc[nf][3]};
                *(float2*)&Cc[(size_t)r0 * Hh + col] = o0;
                *(float2*)&Cc[(size_t)(r0 + 8) * Hh + col] = o1;
            }
        }
        grid_bar(nb);
    }
}

// ---------------- tc mainloops ----------------
#define LDA_B 144
#define OFF_ALO 18432
#define OFF_BHI 36864
#define OFF_BLO 55296
#define TCSM_BYTES 73728

// fp32-A mainloop (emb precompute only)
__device__ __forceinline__ void tc_main(
    const float* Abase, const char* BhiBase, const char* BloBase,
    char* smc, uint32_t sbase, int tid, int wm, int wn, int qrow, int qk,
    float acc[2][8][4])
{
    const int ar = tid >> 1;
    const int ac = (tid & 1) * 32;
    const int bo = (tid & 1) * 64;

    float4 av[8];
    uint4 bh[4], bl[4];
    #pragma unroll
    for (int f = 0; f < 8; f++) av[f] = *(const float4*)(Abase + f * 4);
    #pragma unroll
    for (int u = 0; u < 4; u++) {
        bh[u] = *(const uint4*)(BhiBase + u * 16);
        bl[u] = *(const uint4*)(BloBase + u * 16);
    }

    #pragma unroll 1
    for (int c = 0; c < 8; c++) {
        __syncthreads();
        {
            char* sa = smc + ar * LDA_B + ac * 2;
            char* sl = sa + OFF_ALO;
            #pragma unroll
            for (int f = 0; f < 8; f++) {
                __nv_bfloat16 h0, h1, h2, h3, l0, l1, l2, l3;
                splitbf(av[f].x, h0, l0);
                splitbf(av[f].y, h1, l1);
                splitbf(av[f].z, h2, l2);
                splitbf(av[f].w, h3, l3);
                __nv_bfloat162 hh0, hh1, ll0, ll1;
                hh0.x = h0; hh0.y = h1; hh1.x = h2; hh1.y = h3;
                ll0.x = l0; ll0.y = l1; ll1.x = l2; ll1.y = l3;
                uint2 hv = {*(uint32_t*)&hh0, *(uint32_t*)&hh1};
                uint2 lv = {*(uint32_t*)&ll0, *(uint32_t*)&ll1};
                *(uint2*)(sa + f * 8) = hv;
                *(uint2*)(sl + f * 8) = lv;
            }
            char* sb = smc + OFF_BHI + ar * LDA_B + bo;
            char* sbl = smc + OFF_BLO + ar * LDA_B + bo;
            #pragma unroll
            for (int u = 0; u < 4; u++) {
                *(uint4*)(sb + u * 16) = bh[u];
                *(uint4*)(sbl + u * 16) = bl[u];
            }
        }
        __syncthreads();

        float4 nav[8];
        uint4 nbh[4], nbl[4];
        if (c < 7) {
            #pragma unroll
            for (int f = 0; f < 8; f++)
                nav[f] = *(const float4*)(Abase + (c + 1) * 64 + f * 4);
            #pragma unroll
            for (int u = 0; u < 4; u++) {
                nbh[u] = *(const uint4*)(BhiBase + (c + 1) * 128 + u * 16);
                nbl[u] = *(const uint4*)(BloBase + (c + 1) * 128 + u * 16);
            }
        }

        #pragma unroll
        for (int kk = 0; kk < 4; kk++) {
            const uint32_t koff = (kk * 16 + qk) * 2;
            uint32_t ah[2][4], al[2][4];
            #pragma unroll
            for (int mf = 0; mf < 2; mf++) {
                uint32_t base = sbase + (wm * 32 + mf * 16 + qrow) * LDA_B + koff;
                ah[mf][0] = lds32(base);
                ah[mf][1] = lds32(base + 8 * LDA_B);
                ah[mf][2] = lds32(base + 16);
                ah[mf][3] = lds32(base + 8 * LDA_B + 16);
                al[mf][0] = lds32(base + OFF_ALO);
                al[mf][1] = lds32(base + OFF_ALO + 8 * LDA_B);
                al[mf][2] = lds32(base + OFF_ALO + 16);
                al[mf][3] = lds32(base + OFF_ALO + 8 * LDA_B + 16);
            }
            #pragma unroll
            for (int nf = 0; nf < 8; nf++) {
                uint32_t bb = sbase + OFF_BHI + (wn * 64 + nf * 8 + qrow) * LDA_B + koff;
                uint32_t bh0 = lds32(bb);
                uint32_t bh1 = lds32(bb + 16);
                uint32_t bl0 = lds32(bb + (OFF_BLO - OFF_BHI));
                uint32_t bl1 = lds32(bb + (OFF_BLO - OFF_BHI) + 16);
                #pragma unroll
                for (int mf = 0; mf < 2; mf++) {
                    mma16816(acc[mf][nf], ah[mf], bh0, bh1);
                    mma16816(acc[mf][nf], ah[mf], bl0, bl1);
                    mma16816(acc[mf][nf], al[mf], bh0, bh1);
                }
            }
        }
        if (c < 7) {
            #pragma unroll
            for (int f = 0; f < 8; f++) av[f] = nav[f];
            #pragma unroll
            for (int u = 0; u < 4; u++) { bh[u] = nbh[u]; bl[u] = nbl[u]; }
        }
    }
}

// split-A mainloop (A already bf16 hi/lo): pure copies + MMA
__device__ __forceinline__ void tc_main_sa(
    const char* AhiBase, const char* AloBase,
    const char* BhiBase, const char* BloBase,
    char* smc, uint32_t sbase, int tid, int wm, int wn, int qrow, int qk,
    float acc[2][8][4])
{
    const int ar = tid >> 1;
    const int bo = (tid & 1) * 64;

    uint4 xa[4], xl[4], xb[4], xc[4];
    #pragma unroll
    for (int u = 0; u < 4; u++) {
        xa[u] = *(const uint4*)(AhiBase + u * 16);
        xl[u] = *(const uint4*)(AloBase + u * 16);
        xb[u] = *(const uint4*)(BhiBase + u * 16);
        xc[u] = *(const uint4*)(BloBase + u * 16);
    }

    #pragma unroll 1
    for (int c = 0; c < 8; c++) {
        __syncthreads();
        {
            char* d = smc + ar * LDA_B + bo;
            #pragma unroll
            for (int u = 0; u < 4; u++) {
                *(uint4*)(d + u * 16) = xa[u];
                *(uint4*)(d + OFF_ALO + u * 16) = xl[u];
                *(uint4*)(d + OFF_BHI + u * 16) = xb[u];
                *(uint4*)(d + OFF_BLO + u * 16) = xc[u];
            }
        }
        __syncthreads();

        uint4 na[4], nl[4], nb[4], nc[4];
        if (c < 7) {
            int o = (c + 1) * 128;
            #pragma unroll
            for (int u = 0; u < 4; u++) {
                na[u] = *(const uint4*)(AhiBase + o + u * 16);
                nl[u] = *(const uint4*)(AloBase + o + u * 16);
                nb[u] = *(const uint4*)(BhiBase + o + u * 16);
                nc[u] = *(const uint4*)(BloBase + o + u * 16);
            }
        }

        #pragma unroll
        for (int kk = 0; kk < 4; kk++) {
            const uint32_t koff = (kk * 16 + qk) * 2;
            uint32_t ah[2][4], al[2][4];
            #pragma unroll
            for (int mf = 0; mf < 2; mf++) {
                uint32_t base = sbase + (wm * 32 + mf * 16 + qrow) * LDA_B + koff;
                ah[mf][0] = lds32(base);
                ah[mf][1] = lds32(base + 8 * LDA_B);
                ah[mf][2] = lds32(base + 16);
                ah[mf][3] = lds32(base + 8 * LDA_B + 16);
                al[mf][0] = lds32(base + OFF_ALO);
                al[mf][1] = lds32(base + OFF_ALO + 8 * LDA_B);
                al[mf][2] = lds32(base + OFF_ALO + 16);
                al[mf][3] = lds32(base + OFF_ALO + 8 * LDA_B + 16);
            }
            #pragma unroll
            for (int nf = 0; nf < 8; nf++) {
                uint32_t bb = sbase + OFF_BHI + (wn * 64 + nf * 8 + qrow) * LDA_B + koff;
                uint32_t bh0 = lds32(bb);
                uint32_t bh1 = lds32(bb + 16);
                uint32_t bl0 = lds32(bb + (OFF_BLO - OFF_BHI));
                uint32_t bl1 = lds32(bb + (OFF_BLO - OFF_BHI) + 16);
                #pragma unroll
                for (int mf = 0; mf < 2; mf++) {
                    mma16816(acc[mf][nf], ah[mf], bh0, bh1);
                    mma16816(acc[mf][nf], ah[mf], bl0, bl1);
                    mma16816(acc[mf][nf], al[mf], bh0, bh1);
                }
            }
        }
        if (c < 7) {
            #pragma unroll
            for (int u = 0; u < 4; u++) {
                xa[u] = na[u]; xl[u] = nl[u]; xb[u] = nb[u]; xc[u] = nc[u];
            }
        }
    }
}

// split-A GEMM kernel. modes: 0 logits (C=acc+bias), 1 stop (Us-dot partials),
// 2 pred-phid (A rows via cmap, writes split phid)
__global__ __launch_bounds__(256)
void tc_gemm_sa(const __nv_bfloat16* __restrict__ Ahi,
                const __nv_bfloat16* __restrict__ Alo,
                const __nv_bfloat16* __restrict__ Bhi,
                const __nv_bfloat16* __restrict__ Blo,
                const float* __restrict__ bias, float* __restrict__ C, int ldc,
                int mode, const int* __restrict__ widp,
                const int* __restrict__ rootp, const float* __restrict__ Us)
{
    extern __shared__ char smc[];
    const uint32_t sbase = smem_u32(smc);
    __shared__ int s_rows[128];

    const int tid = threadIdx.x;
    const int wid_ = tid >> 5;
    const int lane = tid & 31;
    const int wm = wid_ & 3;
    const int wn = wid_ >> 2;
    const int qrow = lane >> 2;
    const int qk = (lane & 3) << 1;
    const int m0 = blockIdx.y * 128;
    const int n0 = blockIdx.x * 128;

    if (tid < 128) s_rows[tid] = (mode == 2) ? g_cmap[m0 + tid] : (m0 + tid);
    __syncthreads();

    const int ar = tid >> 1;
    const int bo = (tid & 1) * 64;
    const char* AhiBase = (const char*)(Ahi + (size_t)s_rows[ar] * Hh) + bo;
    const char* AloBase = (const char*)(Alo + (size_t)s_rows[ar] * Hh) + bo;
    const char* BhiBase = (const char*)(Bhi + (size_t)(n0 + ar) * Hh) + bo;
    const char* BloBase = (const char*)(Blo + (size_t)(n0 + ar) * Hh) + bo;

    float acc[2][8][4];
    #pragma unroll
    for (int mf = 0; mf < 2; mf++)
        #pragma unroll
        for (int nf = 0; nf < 8; nf++)
            #pragma unroll
            for (int r = 0; r < 4; r++) acc[mf][nf][r] = 0.f;

    tc_main_sa(AhiBase, AloBase, BhiBase, BloBase, smc, sbase, tid, wm, wn, qrow, qk, acc);

    if (mode == 0) {
        #pragma unroll
        for (int mf = 0; mf < 2; mf++) {
            int r0 = m0 + wm * 32 + mf * 16 + qrow;
            #pragma unroll
            for (int nf = 0; nf < 8; nf++) {
                int col = n0 + wn * 64 + nf * 8 + qk;
                float2 o0 = {acc[mf][nf][0] + bias[col], acc[mf][nf][1] + bias[col + 1]};
                float2 o1 = {acc[mf][nf][2] + bias[col], acc[mf][nf][3] + bias[col + 1]};
                *(float2*)&C[(size_t)r0 * ldc + col] = o0;
                *(float2*)&C[(size_t)(r0 + 8) * ldc + col] = o1;
            }
        }
    } else if (mode == 1) {
        int slot = blockIdx.x * 2 + wn;
        #pragma unroll
        for (int mf = 0; mf < 2; mf++) {
            int r0 = m0 + wm * 32 + mf * 16 + qrow;
            int r1 = r0 + 8;
            int w0, b0, w1, b1;
            if (r0 < TBq) { w0 = widp[r0]; b0 = r0 & (Bq - 1); }
            else          { w0 = rootp[r0 - TBq]; b0 = r0 - TBq; }
            if (r1 < TBq) { w1 = widp[r1]; b1 = r1 & (Bq - 1); }
            else          { w1 = rootp[r1 - TBq]; b1 = r1 - TBq; }
            const float* Pe0 = g_PembU + (size_t)w0 * Hh;
            const float* Pm0 = g_PmolU + (size_t)b0 * Hh;
            const float* Pe1 = g_PembU + (size_t)w1 * Hh;
            const float* Pm1 = g_PmolU + (size_t)b1 * Hh;
            float p0 = 0.f, p1 = 0.f;
            #pragma unroll
            for (int nf = 0; nf < 8; nf++) {
                int col = wn * 64 + nf * 8 + qk;
                int gc = blockIdx.x * 128 + col;
                float u0 = Us[gc], u1 = Us[gc + 1];
                p0 += fmaxf(acc[mf][nf][0] + Pe0[gc] + Pm0[gc], 0.f) * u0;
                p0 += fmaxf(acc[mf][nf][1] + Pe0[gc + 1] + Pm0[gc + 1], 0.f) * u1;
                p1 += fmaxf(acc[mf][nf][2] + Pe1[gc] + Pm1[gc], 0.f) * u0;
                p1 += fmaxf(acc[mf][nf][3] + Pe1[gc + 1] + Pm1[gc + 1], 0.f) * u1;
            }
            p0 += __shfl_xor_sync(0xffffffffu, p0, 1);
            p0 += __shfl_xor_sync(0xffffffffu, p0, 2);
            p1 += __shfl_xor_sync(0xffffffffu, p1, 1);
            p1 += __shfl_xor_sync(0xffffffffu, p1, 2);
            if ((lane & 3) == 0) {
                g_spart[(size_t)slot * MSr + r0] = p0;
                g_spart[(size_t)slot * MSr + r1] = p1;
            }
        }
    } else {
        #pragma unroll
        for (int mf = 0; mf < 2; mf++) {
            int rl0 = wm * 32 + mf * 16 + qrow;
            int j0 = m0 + rl0;
            int bc0 = s_rows[rl0] & (Bq - 1);
            int bc1 = s_rows[rl0 + 8] & (Bq - 1);
            const float* Pm0 = g_PmolW + (size_t)bc0 * Hh;
            const float* Pm1 = g_PmolW + (size_t)bc1 * Hh;
            #pragma unroll
            for (int nf = 0; nf < 8; nf++) {
                int col = n0 + wn * 64 + nf * 8 + qk;
                float v00 = fmaxf(acc[mf][nf][0] + Pm0[col], 0.f);
                float v01 = fmaxf(acc[mf][nf][1] + Pm0[col + 1], 0.f);
                float v10 = fmaxf(acc[mf][nf][2] + Pm1[col], 0.f);
                float v11 = fmaxf(acc[mf][nf][3] + Pm1[col + 1], 0.f);
                __nv_bfloat162 h2, l2;
                __nv_bfloat16 h, l;
                splitbf(v00, h, l); h2.x = h; l2.x = l;
                splitbf(v01, h, l); h2.y = h; l2.y = l;
                *(__nv_bfloat162*)&g_phid_hi[(size_t)(Bq + j0) * Hh + col] = h2;
                *(__nv_bfloat162*)&g_phid_lo[(size_t)(Bq + j0) * Hh + col] = l2;
                splitbf(v10, h, l); h2.x = h; l2.x = l;
                splitbf(v11, h, l); h2.y = h; l2.y = l;
                *(__nv_bfloat162*)&g_phid_hi[(size_t)(Bq + j0 + 8) * Hh + col] = h2;
                *(__nv_bfloat162*)&g_phid_lo[(size_t)(Bq + j0 + 8) * Hh + col] = l2;
            }
        }
    }
}

// fused emb-precompute: 4 GEMMs selected by blockIdx.z
__global__ __launch_bounds__(256)
void tc_gemm_pre4(const float* __restrict__ A,
                  const __nv_bfloat16* b0h, const __nv_bfloat16* b0l,
                  const float* bias0, float* C0,
                  const __nv_bfloat16* b1h, const __nv_bfloat16* b1l,
                  const float* bias1, float* C1,
                  const __nv_bfloat16* b2h, const __nv_bfloat16* b2l,
                  const float* bias2, float* C2,
                  const __nv_bfloat16* b3h, const __nv_bfloat16* b3l,
                  const float* bias3, float* C3)
{
    extern __shared__ char smc[];
    const uint32_t sbase = smem_u32(smc);
    const int z = blockIdx.z;
    const __nv_bfloat16* Bhi = (z == 0) ? b0h : (z == 1) ? b1h : (z == 2) ? b2h : b3h;
    const __nv_bfloat16* Blo = (z == 0) ? b0l : (z == 1) ? b1l : (z == 2) ? b2l : b3l;
    const float* bias = (z == 0) ? bias0 : (z == 1) ? bias1 : (z == 2) ? bias2 : bias3;
    float* C = (z == 0) ? C0 : (z == 1) ? C1 : (z == 2) ? C2 : C3;

    const int tid = threadIdx.x;
    const int wid_ = tid >> 5;
    const int lane = tid & 31;
    const int wm = wid_ & 3;
    const int wn = wid_ >> 2;
    const int qrow = lane >> 2;
    const int qk = (lane & 3) << 1;
    const int m0 = blockIdx.y * 128;
    const int n0 = blockIdx.x * 128;

    const int ar = tid >> 1;
    const int ac = (tid & 1) * 32;
    const int bo = (tid & 1) * 64;
    const float* Abase = A + (size_t)(m0 + ar) * Hh + ac;
    const char* BhiBase = (const char*)(Bhi + (size_t)(n0 + ar) * Hh) + bo;
    const char* BloBase = (const char*)(Blo + (size_t)(n0 + ar) * Hh) + bo;

    float acc[2][8][4];
    #pragma unroll
    for (int mf = 0; mf < 2; mf++)
        #pragma unroll
        for (int nf = 0; nf < 8; nf++)
            #pragma unroll
            for (int r = 0; r < 4; r++) acc[mf][nf][r] = 0.f;

    tc_main(Abase, BhiBase, BloBase, smc, sbase, tid, wm, wn, qrow, qk, acc);

    #pragma unroll
    for (int mf = 0; mf < 2; mf++) {
        int r0 = m0 + wm * 32 + mf * 16 + qrow;
        #pragma unroll
        for (int nf = 0; nf < 8; nf++) {
            int col = n0 + wn * 64 + nf * 8 + qk;
            float2 o0 = {acc[mf][nf][0] + bias[col], acc[mf][nf][1] + bias[col + 1]};
            float2 o1 = {acc[mf][nf][2] + bias[col], acc[mf][nf][3] + bias[col + 1]};
            *(float2*)&C[(size_t)r0 * Hh + col] = o0;
            *(float2*)&C[(size_t)(r0 + 8) * Hh + col] = o1;
        }
    }
}

// ---------------- housekeeping ----------------
__global__ __launch_bounds__(256)
void prep_kernel()
{
    int i = blockIdx.x * 256 + threadIdx.x;
    if (i < 5) g_acc[i] = 0.0;
    if (i == 5) { g_barc = 0; g_ccount = 0; }
    if (i == 6) g_bars = 0;
    if (i < Hh) {
        g_hbuf[(size_t)PADROW * Hh + i] = 0.f;
        g_hbufUr[(size_t)PADROW * Hh + i] = 0.f;
        g_hbuf_hi[(size_t)PADROW * Hh + i] = __float2bfloat16(0.f);
        g_hbuf_lo[(size_t)PADROW * Hh + i] = __float2bfloat16(0.f);
    }
    if (i < NCMP + 256) g_cmap[i] = 0;
}

__global__ __launch_bounds__(256)
void compact_kernel(const int* __restrict__ dirs)
{
    int i = blockIdx.x * 256 + threadIdx.x;
    if (dirs[i]) {
        int s = atomicAdd(&g_ccount, 1);
        g_cmap[s] = i;
    }
}

__global__ __launch_bounds__(256)
void build_curo(const int* __restrict__ oni, const int* __restrict__ roni)
{
    int i = blockIdx.x, tid = threadIdx.x;
    __shared__ int ids[MAXNB];
    if (tid < MAXNB)
        ids[tid] = (i < TBq) ? oni[(size_t)i * MAXNB + tid]
                             : roni[(size_t)(i - TBq) * MAXNB + tid];
    __syncthreads();
    for (int h = tid; h < Hh; h += 256) {
        float v = 0.f;
        #pragma unroll
        for (int n = 0; n < MAXNB; n++) {
            int id = ids[n];
            if (id == PADROW) continue;
            v += g_hbuf[(size_t)id * Hh + h];
        }
        __nv_bfloat16 hh, ll;
        splitbf(v, hh, ll);
        g_curo_hi[(size_t)i * Hh + h] = hh;
        g_curo_lo[(size_t)i * Hh + h] = ll;
    }
}

__global__ __launch_bounds__(512)
void phid0_kernel()
{
    int b = blockIdx.x, h = threadIdx.x;
    float v = fmaxf(g_PmolW[(size_t)b * Hh + h], 0.f);
    __nv_bfloat16 hh, ll;
    splitbf(v, hh, ll);
    g_phid_hi[(size_t)b * Hh + h] = hh;
    g_phid_lo[(size_t)b * Hh + h] = ll;
}

// ---------------- stop head finalize ----------------
__global__ __launch_bounds__(256)
void stop_final_kernel(const float* __restrict__ bs, const int* __restrict__ dirs)
{
    int i = blockIdx.x * 256 + threadIdx.x;
    float s = bs[0];
    #pragma unroll
    for (int k = 0; k < 8; k++) s += g_spart[(size_t)k * MSr + i];
    float tgt = (i < TBq) ? (float)dirs[i] : 0.f;
    float loss = fmaxf(s, 0.f) - s * tgt + log1pf(expf(-fabsf(s)));
    float corr = ((s >= 0.5f) == (tgt > 0.5f)) ? 1.f : 0.f;
    __shared__ double r0[256], r1[256];
    int tid = threadIdx.x;
    r0[tid] = (double)loss;
    r1[tid] = (double)corr;
    __syncthreads();
    for (int o = 128; o > 0; o >>= 1) {
        if (tid < o) { r0[tid] += r0[tid + o]; r1[tid] += r1[tid + o]; }
        __syncthreads();
    }
    if (tid == 0) {
        atomicAdd(&g_acc[0], r0[0]);
        atomicAdd(&g_acc[1], r1[0]);
    }
}

// ---------------- pred head: log-softmax CE + argmax ----------------
__global__ __launch_bounds__(256)
void pred_rows_kernel(const int* __restrict__ root_wid, const int* __restrict__ y_wid)
{
    int j = blockIdx.x, tid = threadIdx.x;
    const float* row = g_logitsc + (size_t)j * Vv;
    int tgt = (j < Bq) ? root_wid[j] : y_wid[g_cmap[j - Bq]];

    float mval = -1e30f; int midx = Vv;
    for (int k = tid; k < Vv; k += 256) {
        float v = row[k];
        if (v > mval) { mval = v; midx = k; }
    }
    __shared__ float rv[256];
    __shared__ int ri[256];
    rv[tid] = mval; ri[tid] = midx; __syncthreads();
    for (int s = 128; s > 0; s >>= 1) {
        if (tid < s) {
            if (rv[tid + s] > rv[tid] ||
                (rv[tid + s] == rv[tid] && ri[tid + s] < ri[tid])) {
                rv[tid] = rv[tid + s]; ri[tid] = ri[tid + s];
            }
        }
        __syncthreads();
    }
    float gmax = rv[0]; int gidx = ri[0];
    __syncthreads();
    float p = 0.f;
    for (int k = tid; k < Vv; k += 256) p += __expf(row[k] - gmax);
    rv[tid] = p; __syncthreads();
    for (int s = 128; s > 0; s >>= 1) {
        if (tid < s) rv[tid] += rv[tid + s];
        __syncthreads();
    }
    if (tid == 0) {
        float lse = gmax + logf(rv[0]);
        float ce = -(row[tgt] - lse);
        atomicAdd(&g_acc[2], (double)ce);
        if (gidx == tgt) atomicAdd(&g_acc[3], 1.0);
        atomicAdd(&g_acc[4], 1.0);
    }
}

__global__ void finalize_kernel(float* out)
{
    out[0] = (float)(g_acc[2] / (double)Bq);
    out[1] = (float)(g_acc[0] / (double)Bq);
    out[2] = (float)(g_acc[3] / g_acc[4]);
    out[3] = (float)(g_acc[1] / (double)MSr);
}

// ---------------- launch ----------------
extern "C" void kernel_launch(void* const* d_in, const int* in_sizes, int n_in,
                              void* d_out, int out_size)
{
    const float* mol_vec  = (const float*)d_in[0];
    const int*   wid      = (const int*)d_in[1];
    const int*   y_wid    = (const int*)d_in[2];
    const int*   dirs     = (const int*)d_in[3];
    const int*   hni      = (const int*)d_in[4];
    const int*   oni      = (const int*)d_in[5];
    const int*   root_wid = (const int*)d_in[6];
    const int*   roni     = (const int*)d_in[7];
    const float* emb      = (const float*)d_in[8];
    const float* Wz       = (const float*)d_in[9];
    const float* bz       = (const float*)d_in[10];
    const float* Wr       = (const float*)d_in[11];
    const float* br       = (const float*)d_in[12];
    const float* Ur       = (const float*)d_in[13];
    const float* Wh       = (const float*)d_in[14];
    const float* bh       = (const float*)d_in[15];
    const float* Wm       = (const float*)d_in[16];
    const float* bW       = (const float*)d_in[17];
    const float* U        = (const float*)d_in[18];
    const float* bU       = (const float*)d_in[19];
    const float* Wo       = (const float*)d_in[20];
    const float* bo       = (const float*)d_in[21];
    const float* Us       = (const float*)d_in[22];
    const float* bs       = (const float*)d_in[23];

    float *gPz, *gPr, *gPh, *gPembU, *gPmolU, *gPmolW, *glogitsc;
    __nv_bfloat16 *gBuH, *gBuL, *gBwH, *gBwL, *gBoH, *gBoL;
    __nv_bfloat16 *gBzhH, *gBzhL, *gBUrH, *gBUrL;
    __nv_bfloat16 *gBz0H, *gBz0L, *gBr0H, *gBr0L, *gBh0H, *gBh0L, *gBU0H, *gBU0L;
    __nv_bfloat16 *gCuH, *gCuL, *gPhH, *gPhL, *gHbH, *gHbL;
    cudaGetSymbolAddress((void**)&gPz, g_Pz);
    cudaGetSymbolAddress((void**)&gPr, g_Pr);
    cudaGetSymbolAddress((void**)&gPh, g_Ph);
    cudaGetSymbolAddress((void**)&gPembU, g_PembU);
    cudaGetSymbolAddress((void**)&gPmolU, g_PmolU);
    cudaGetSymbolAddress((void**)&gPmolW, g_PmolW);
    cudaGetSymbolAddress((void**)&glogitsc, g_logitsc);
    cudaGetSymbolAddress((void**)&gBuH, g_Bu_hi);
    cudaGetSymbolAddress((void**)&gBuL, g_Bu_lo);
    cudaGetSymbolAddress((void**)&gBwH, g_Bw_hi);
    cudaGetSymbolAddress((void**)&gBwL, g_Bw_lo);
    cudaGetSymbolAddress((void**)&gBoH, g_Bo_hi);
    cudaGetSymbolAddress((void**)&gBoL, g_Bo_lo);
    cudaGetSymbolAddress((void**)&gBzhH, g_Bzh_hi);
    cudaGetSymbolAddress((void**)&gBzhL, g_Bzh_lo);
    cudaGetSymbolAddress((void**)&gBUrH, g_BUr_hi);
    cudaGetSymbolAddress((void**)&gBUrL, g_BUr_lo);
    cudaGetSymbolAddress((void**)&gBz0H, g_Bz0_hi);
    cudaGetSymbolAddress((void**)&gBz0L, g_Bz0_lo);
    cudaGetSymbolAddress((void**)&gBr0H, g_Br0_hi);
    cudaGetSymbolAddress((void**)&gBr0L, g_Br0_lo);
    cudaGetSymbolAddress((void**)&gBh0H, g_Bh0_hi);
    cudaGetSymbolAddress((void**)&gBh0L, g_Bh0_lo);
    cudaGetSymbolAddress((void**)&gBU0H, g_BU0_hi);
    cudaGetSymbolAddress((void**)&gBU0L, g_BU0_lo);
    cudaGetSymbolAddress((void**)&gCuH, g_curo_hi);
    cudaGetSymbolAddress((void**)&gCuL, g_curo_lo);
    cudaGetSymbolAddress((void**)&gPhH, g_phid_hi);
    cudaGetSymbolAddress((void**)&gPhL, g_phid_lo);
    cudaGetSymbolAddress((void**)&gHbH, g_hbuf_hi);
    cudaGetSymbolAddress((void**)&gHbL, g_hbuf_lo);

    cudaFuncSetAttribute(tc_gemm_sa,
                         cudaFuncAttributeMaxDynamicSharedMemorySize, TCSM_BYTES);
    cudaFuncSetAttribute(tc_gemm_pre4,
                         cudaFuncAttributeMaxDynamicSharedMemorySize, TCSM_BYTES);
    cudaFuncSetAttribute(scan_kernel,
                         cudaFuncAttributeMaxDynamicSharedMemorySize, SCAN_SMEM);

    prep_kernel<<<47, 256>>>();
    compact_kernel<<<92, 256>>>(dirs);

    // batched weight transposes + bf16 split
    ConvJobs jobs;
    jobs.j[0] = {U + (size_t)Hh * Hh, gBuH, gBuL, 16};
    jobs.j[1] = {Wm, gBwH, gBwL, 16};
    jobs.j[2] = {Wo, gBoH, gBoL, 32};
    jobs.j[3] = {Wz + (size_t)Hh * Hh, gBzhH, gBzhL, 16};
    jobs.j[4] = {Wh + (size_t)Hh * Hh, gBzhH + (size_t)Hh * Hh, gBzhL + (size_t)Hh * Hh, 16};
    jobs.j[5] = {Ur, gBUrH, gBUrL, 16};
    jobs.j[6] = {Wz, gBz0H, gBz0L, 16};
    jobs.j[7] = {Wr, gBr0H, gBr0L, 16};
    jobs.j[8] = {Wh, gBh0H, gBh0L, 16};
    jobs.j[9] = {U, gBU0H, gBU0L, 16};
    convT_all<<<dim3(32, 16, 10), 256>>>(jobs);

    // fused emb precomputes (4 GEMMs, one launch)
    tc_gemm_pre4<<<dim3(4, 8, 4), 256, TCSM_BYTES>>>(
        emb,
        gBz0H, gBz0L, bz, gPz,
        gBr0H, gBr0L, br, gPr,
        gBh0H, gBh0L, bh, gPh,
        gBU0H, gBU0L, bU, gPembU);
    sgemm_kernel<<<dim3(Hh / BN, Bq / BM), 256>>>(Bq, Hh, Ll, mol_vec, U + (size_t)2 * Hh * Hh, nullptr, gPmolU);
    sgemm_kernel<<<dim3(Hh / BN, Bq / BM), 256>>>(Bq, Hh, Ll, mol_vec, Wm + (size_t)Hh * Hh, bW, gPmolW);

    // persistent fused GRU scan
    scan_kernel<<<NBLK, 256, SCAN_SMEM>>>(wid, hni);

    // stop head (split-A)
    build_curo<<<MSr, 256>>>(oni, roni);
    tc_gemm_sa<<<dim3(4, MSr / 128), 256, TCSM_BYTES>>>(
        gCuH, gCuL, gBuH, gBuL, nullptr, nullptr, 0, 1, wid, root_wid, Us);
    stop_final_kernel<<<94, 256>>>(bs, dirs);

    // pred head (compacted, split-A)
    phid0_kernel<<<Bq, Hh>>>();
    tc_gemm_sa<<<dim3(4, NCMP / 128), 256, TCSM_BYTES>>>(
        gHbH, gHbL, gBwH, gBwL, nullptr, nullptr, 0, 2, nullptr, nullptr, nullptr);
    tc_gemm_sa<<<dim3(8, MPRED / 128), 256, TCSM_BYTES>>>(
        gPhH, gPhL, gBoH, gBoL, bo, glogitsc, Vv, 0, nullptr, nullptr, nullptr);
    pred_rows_kernel<<<MPRED, 256>>>(root_wid, y_wid);

    finalize_kernel<<<1, 1>>>((float*)d_out);
}

// round 10
// speedup vs baseline: 6.7941x; 1.1479x over previous
#include <cuda_runtime.h>
#include <cuda_bf16.h>
#include <math.h>
#include <stdint.h>

// Problem constants
#define Bq 512
#define Hh 512
#define Ll 64
#define Vv 1024
#define Tt 46
#define TBq 23552          // T*B
#define PADROW 23552
#define MSr 24064          // TB + B
#define MAXNB 8
#define NCMP 11776         // compacted pred rows (dirs==1)
#define MPRED 12288        // B + NCMP
#define NBLK 128           // persistent scan grid

// ---------------- scratch ----------------
__device__ float g_hbuf[(size_t)(TBq + 1) * Hh];
__device__ float g_hbufUr[(size_t)(TBq + 1) * Hh];
__device__ __nv_bfloat16 g_hbuf_hi[(size_t)(TBq + 1) * Hh];
__device__ __nv_bfloat16 g_hbuf_lo[(size_t)(TBq + 1) * Hh];
__device__ float g_Pz[(size_t)Vv * Hh];
__device__ float g_Pr[(size_t)Vv * Hh];
__device__ float g_Ph[(size_t)Vv * Hh];
__device__ float g_PembU[(size_t)Vv * Hh];
__device__ float g_PmolU[(size_t)Bq * Hh];
__device__ float g_PmolW[(size_t)Bq * Hh];
__device__ float g_sumh[(size_t)Bq * Hh];
__device__ __nv_bfloat16 g_curo_hi[(size_t)MSr * Hh];
__device__ __nv_bfloat16 g_curo_lo[(size_t)MSr * Hh];
__device__ __nv_bfloat16 g_phid_hi[(size_t)MPRED * Hh];
__device__ __nv_bfloat16 g_phid_lo[(size_t)MPRED * Hh];
__device__ float g_logitsc[(size_t)MPRED * Vv];
__device__ float g_spart[(size_t)8 * MSr];
__device__ int   g_cmap[NCMP + 256];
__device__ int   g_ccount;
__device__ int   g_barc;
__device__ volatile int g_bars;
__device__ double g_acc[5];
// scan split activations (per-step)
__device__ __nv_bfloat16 g_shg_hi[(size_t)2 * Bq * Hh];
__device__ __nv_bfloat16 g_shg_lo[(size_t)2 * Bq * Hh];
// bf16 split weights, stored [N, K]
__device__ __nv_bfloat16 g_Bu_hi[(size_t)Hh * Hh];
__device__ __nv_bfloat16 g_Bu_lo[(size_t)Hh * Hh];
__device__ __nv_bfloat16 g_Bw_hi[(size_t)Hh * Hh];
__device__ __nv_bfloat16 g_Bw_lo[(size_t)Hh * Hh];
__device__ __nv_bfloat16 g_Bo_hi[(size_t)Vv * Hh];
__device__ __nv_bfloat16 g_Bo_lo[(size_t)Vv * Hh];
__device__ __nv_bfloat16 g_Bzh_hi[(size_t)2 * Hh * Hh];
__device__ __nv_bfloat16 g_Bzh_lo[(size_t)2 * Hh * Hh];
__device__ __nv_bfloat16 g_BUr_hi[(size_t)Hh * Hh];
__device__ __nv_bfloat16 g_BUr_lo[(size_t)Hh * Hh];
__device__ __nv_bfloat16 g_Bz0_hi[(size_t)Hh * Hh];
__device__ __nv_bfloat16 g_Bz0_lo[(size_t)Hh * Hh];
__device__ __nv_bfloat16 g_Br0_hi[(size_t)Hh * Hh];
__device__ __nv_bfloat16 g_Br0_lo[(size_t)Hh * Hh];
__device__ __nv_bfloat16 g_Bh0_hi[(size_t)Hh * Hh];
__device__ __nv_bfloat16 g_Bh0_lo[(size_t)Hh * Hh];
__device__ __nv_bfloat16 g_BU0_hi[(size_t)Hh * Hh];
__device__ __nv_bfloat16 g_BU0_lo[(size_t)Hh * Hh];

// ---------------- helpers ----------------
__device__ __forceinline__ uint32_t smem_u32(const void* p) {
    uint32_t a;
    asm("{ .reg .u64 t; cvta.to.shared.u64 t, %1; cvt.u32.u64 %0, t; }"
        : "=r"(a) : "l"(p));
    return a;
}
__device__ __forceinline__ uint32_t lds32(uint32_t addr) {
    uint32_t v;
    asm volatile("ld.shared.b32 %0, [%1];" : "=r"(v) : "r"(addr));
    return v;
}
__device__ __forceinline__ void mma16816(float* d, const uint32_t* a,
                                         uint32_t b0, uint32_t b1) {
    asm volatile(
        "mma.sync.aligned.m16n8k16.row.col.f32.bf16.bf16.f32 "
        "{%0,%1,%2,%3}, {%4,%5,%6,%7}, {%8,%9}, {%0,%1,%2,%3};"
        : "+f"(d[0]), "+f"(d[1]), "+f"(d[2]), "+f"(d[3])
        : "r"(a[0]), "r"(a[1]), "r"(a[2]), "r"(a[3]), "r"(b0), "r"(b1));
}
__device__ __forceinline__ void splitbf(float v, __nv_bfloat16& h, __nv_bfloat16& l) {
    h = __float2bfloat16(v);
    l = __float2bfloat16(v - __bfloat162float(h));
}
__device__ __forceinline__ float fast_sigmoid(float x) {
    return __fdividef(1.f, 1.f + __expf(-x));
}
__device__ __forceinline__ uint2 pack_hi4(float a, float b, float c, float d,
                                          uint2& lo_out) {
    __nv_bfloat16 h, l;
    __nv_bfloat162 h0, h1, l0, l1;
    splitbf(a, h, l); h0.x = h; l0.x = l;
    splitbf(b, h, l); h0.y = h; l0.y = l;
    splitbf(c, h, l); h1.x = h; l1.x = l;
    splitbf(d, h, l); h1.y = h; l1.y = l;
    lo_out.x = *(uint32_t*)&l0; lo_out.y = *(uint32_t*)&l1;
    uint2 r; r.x = *(uint32_t*)&h0; r.y = *(uint32_t*)&h1;
    return r;
}

// ---------------- software grid barrier ----------------
__device__ __forceinline__ void grid_bar(int nb)
{
    __syncthreads();
    if (threadIdx.x == 0) {
        int s = g_bars;
        __threadfence();
        int t = atomicAdd(&g_barc, 1);
        if (t == nb - 1) {
            g_barc = 0;
            __threadfence();
            g_bars = s + 1;
        } else {
            while (g_bars == s) { __nanosleep(32); }
        }
        __threadfence();
    }
    __syncthreads();
}

// ---------------- generic 64x64 SGEMM (small precomputes) ----------------
#define BM 64
#define BN 64
#define BK 16

__global__ __launch_bounds__(256)
void sgemm_kernel(int M, int N, int K,
                  const float* __restrict__ A, const float* __restrict__ Bm,
                  const float* __restrict__ bias, float* __restrict__ C)
{
    __shared__ float As[BK][BM];
    __shared__ float Bs[BK][BN];
    const int tid = threadIdx.x;
    const int tx = tid & 15;
    const int ty = tid >> 4;
    const int m0 = blockIdx.y * BM;
    const int n0 = blockIdx.x * BN;

    const int a_row  = tid >> 2;
    const int a_col4 = (tid & 3) << 2;
    const int b_row  = tid >> 4;
    const int b_col4 = (tid & 15) << 2;

    const float* Aptr = A + (size_t)(m0 + a_row) * K + a_col4;
    const float* Bptr = Bm + (size_t)b_row * N + n0 + b_col4;

    float acc[4][4];
    #pragma unroll
    for (int i = 0; i < 4; i++)
        #pragma unroll
        for (int j = 0; j < 4; j++) acc[i][j] = 0.f;

    for (int k0 = 0; k0 < K; k0 += BK) {
        float4 av = *(const float4*)(Aptr + k0);
        float4 bv = *(const float4*)(Bptr + (size_t)k0 * N);
        As[a_col4 + 0][a_row] = av.x;
        As[a_col4 + 1][a_row] = av.y;
        As[a_col4 + 2][a_row] = av.z;
        As[a_col4 + 3][a_row] = av.w;
        *(float4*)&Bs[b_row][b_col4] = bv;
        __syncthreads();
        #pragma unroll
        for (int k = 0; k < BK; k++) {
            float4 a4 = *(const float4*)&As[k][ty << 2];
            float4 b4 = *(const float4*)&Bs[k][tx << 2];
            float a[4] = {a4.x, a4.y, a4.z, a4.w};
            float b[4] = {b4.x, b4.y, b4.z, b4.w};
            #pragma unroll
            for (int i = 0; i < 4; i++)
                #pragma unroll
                for (int j = 0; j < 4; j++) acc[i][j] = fmaf(a[i], b[j], acc[i][j]);
        }
        __syncthreads();
    }

    #pragma unroll
    for (int i = 0; i < 4; i++) {
        int row = m0 + (ty << 2) + i;
        int col = n0 + (tx << 2);
        float4 out;
        float b0 = bias ? bias[col + 0] : 0.f;
        float b1 = bias ? bias[col + 1] : 0.f;
        float b2 = bias ? bias[col + 2] : 0.f;
        float b3 = bias ? bias[col + 3] : 0.f;
        out.x = acc[i][0] + b0; out.y = acc[i][1] + b1;
        out.z = acc[i][2] + b2; out.w = acc[i][3] + b3;
        *(float4*)&C[(size_t)row * N + col] = out;
    }
}

// ---------------- batched weight transpose + bf16 split ----------------
struct ConvJob {
    const float* src;
    __nv_bfloat16* hi;
    __nv_bfloat16* lo;
    int nx;
};
struct ConvJobs { ConvJob j[10]; };

__global__ __launch_bounds__(256)
void convT_all(ConvJobs jobs)
{
    ConvJob jb = jobs.j[blockIdx.z];
    if ((int)blockIdx.x >= jb.nx) return;
    const int N = jb.nx * 32;
    const int K = Hh;
    __shared__ float t[32][33];
    int k0 = blockIdx.y * 32, n0 = blockIdx.x * 32;
    int tx = threadIdx.x & 31, ty = threadIdx.x >> 5;
    for (int r = ty; r < 32; r += 8)
        t[r][tx] = jb.src[(size_t)(k0 + r) * N + n0 + tx];
    __syncthreads();
    for (int r = ty; r < 32; r += 8) {
        float v = t[tx][r];
        __nv_bfloat16 h, l;
        splitbf(v, h, l);
        jb.hi[(size_t)(n0 + r) * K + k0 + tx] = h;
        jb.lo[(size_t)(n0 + r) * K + k0 + tx] = l;
    }
}

// ---------------- persistent fused GRU scan (double-buffered MMA) ----------------
#define SLDA 144
#define SA0 0
#define SA1 9216
#define SA2 18432
#define SA3 27648
#define SB0 36864
#define SB1 41472
#define SB2 46080
#define SB3 50688
#define HBUF 55296
#define SCAN_SMEM (2 * HBUF)

__global__ __launch_bounds__(256)
void scan_kernel(const int* __restrict__ wid, const int* __restrict__ hni)
{
    extern __shared__ char sms[];
    const uint32_t u0 = smem_u32(sms);
    __shared__ int s_ids4[4 * MAXNB];
    __shared__ int s_w4[4];

    const int tid = threadIdx.x;
    const int nb = (int)gridDim.x;
    const int wid_ = tid >> 5;
    const int lane = tid & 31;
    const int wm = wid_ & 3;
    const int wg = wid_ >> 2;
    const int qrow = lane >> 2;
    const int qk = (lane & 3) << 1;

    for (int t = 0; t < Tt; t++) {
        // ---- P1: vectorized gather sum_h / sum_g ----
        {
            const int b0 = (int)blockIdx.x * 4;
            if (tid < 32)
                s_ids4[tid] = hni[((size_t)(t * Bq + b0 + (tid >> 3))) * MAXNB + (tid & 7)];
            else if (tid < 36)
                s_w4[tid - 32] = wid[t * Bq + b0 + (tid - 32)];
            __syncthreads();
            #pragma unroll
            for (int it = 0; it < 2; it++) {
                int item = it * 256 + tid;       // 0..511
                int bl = item >> 7;              // warp-uniform (128 items per b)
                int h4 = (item & 127) << 2;
                int b = b0 + bl;
                int w = s_w4[bl];
                float4 xr = *(const float4*)&g_Pr[(size_t)w * Hh + h4];
                float4 sh = {0.f, 0.f, 0.f, 0.f};
                float4 sg = {0.f, 0.f, 0.f, 0.f};
                #pragma unroll
                for (int n = 0; n < MAXNB; n++) {
                    int id = s_ids4[bl * 8 + n];
                    if (id == PADROW) continue;  // warp-uniform
                    float4 hv = *(const float4*)&g_hbuf[(size_t)id * Hh + h4];
                    float4 gv = *(const float4*)&g_hbufUr[(size_t)id * Hh + h4];
                    sh.x += hv.x; sh.y += hv.y; sh.z += hv.z; sh.w += hv.w;
                    sg.x += fast_sigmoid(xr.x + gv.x) * hv.x;
                    sg.y += fast_sigmoid(xr.y + gv.y) * hv.y;
                    sg.z += fast_sigmoid(xr.z + gv.z) * hv.z;
                    sg.w += fast_sigmoid(xr.w + gv.w) * hv.w;
                }
                *(float4*)&g_sumh[(size_t)b * Hh + h4] = sh;
                uint2 lo, hi;
                hi = pack_hi4(sh.x, sh.y, sh.z, sh.w, lo);
                *(uint2*)&g_shg_hi[(size_t)b * Hh + h4] = hi;
                *(uint2*)&g_shg_lo[(size_t)b * Hh + h4] = lo;
                hi = pack_hi4(sg.x, sg.y, sg.z, sg.w, lo);
                *(uint2*)&g_shg_hi[(size_t)(Bq + b) * Hh + h4] = hi;
                *(uint2*)&g_shg_lo[(size_t)(Bq + b) * Hh + h4] = lo;
            }
        }
        grid_bar(nb);

        // ---- P2': dual 64x32 MMA (z & h_tilde), double-buffered ----
        {
            const int blk = (int)blockIdx.x;
            const int m0 = (blk >> 4) * 64;
            const int n0 = (blk & 15) * 32;

            float acc[4][4];
            #pragma unroll
            for (int nf = 0; nf < 4; nf++)
                #pragma unroll
                for (int r = 0; r < 4; r++) acc[nf][r] = 0.f;

            const int lr = tid >> 2, lq = tid & 3;
            const int rb = tid >> 3, qb = tid & 7;
            const char* gShH = (const char*)(g_shg_hi + (size_t)(m0 + lr) * Hh) + lq * 32;
            const char* gShL = (const char*)(g_shg_lo + (size_t)(m0 + lr) * Hh) + lq * 32;
            const char* gSgH = (const char*)(g_shg_hi + (size_t)(Bq + m0 + lr) * Hh) + lq * 32;
            const char* gSgL = (const char*)(g_shg_lo + (size_t)(Bq + m0 + lr) * Hh) + lq * 32;
            const char* gBzH = (const char*)(g_Bzh_hi + (size_t)(n0 + rb) * Hh) + qb * 16;
            const char* gBzL = (const char*)(g_Bzh_lo + (size_t)(n0 + rb) * Hh) + qb * 16;
            const char* gBtH = (const char*)(g_Bzh_hi + (size_t)(Hh + n0 + rb) * Hh) + qb * 16;
            const char* gBtL = (const char*)(g_Bzh_lo + (size_t)(Hh + n0 + rb) * Hh) + qb * 16;

            const uint32_t oAh = (wg ? SA2 : SA0);
            const uint32_t oAl = (wg ? SA3 : SA1);
            const uint32_t oBh = (wg ? SB2 : SB0);
            const uint32_t oBl = (wg ? SB3 : SB1);

            // preload + store chunk 0 into buf0
            {
                uint4 a0 = *(const uint4*)(gShH), a0b = *(const uint4*)(gShH + 16);
                uint4 a1 = *(const uint4*)(gShL), a1b = *(const uint4*)(gShL + 16);
                uint4 a2 = *(const uint4*)(gSgH), a2b = *(const uint4*)(gSgH + 16);
                uint4 a3 = *(const uint4*)(gSgL), a3b = *(const uint4*)(gSgL + 16);
                uint4 b0v = *(const uint4*)(gBzH), b1v = *(const uint4*)(gBzL);
                uint4 b2v = *(const uint4*)(gBtH), b3v = *(const uint4*)(gBtL);
                char* d;
                d = sms + SA0 + lr * SLDA + lq * 32; *(uint4*)d = a0; *(uint4*)(d + 16) = a0b;
                d = sms + SA1 + lr * SLDA + lq * 32; *(uint4*)d = a1; *(uint4*)(d + 16) = a1b;
                d = sms + SA2 + lr * SLDA + lq * 32; *(uint4*)d = a2; *(uint4*)(d + 16) = a2b;
                d = sms + SA3 + lr * SLDA + lq * 32; *(uint4*)d = a3; *(uint4*)(d + 16) = a3b;
                *(uint4*)(sms + SB0 + rb * SLDA + qb * 16) = b0v;
                *(uint4*)(sms + SB1 + rb * SLDA + qb * 16) = b1v;
                *(uint4*)(sms + SB2 + rb * SLDA + qb * 16) = b2v;
                *(uint4*)(sms + SB3 + rb * SLDA + qb * 16) = b3v;
            }
            __syncthreads();

            #pragma unroll 1
            for (int c = 0; c < 8; c++) {
                const uint32_t ub = u0 + (c & 1) * HBUF;
                char* nxt = sms + ((c + 1) & 1) * HBUF;
                // issue next-chunk loads first (hidden under MMA)
                uint4 a0, a0b, a1, a1b, a2, a2b, a3, a3b, b0v, b1v, b2v, b3v;
                if (c < 7) {
                    int o = (c + 1) * 128;
                    a0 = *(const uint4*)(gShH + o); a0b = *(const uint4*)(gShH + o + 16);
                    a1 = *(const uint4*)(gShL + o); a1b = *(const uint4*)(gShL + o + 16);
                    a2 = *(const uint4*)(gSgH + o); a2b = *(const uint4*)(gSgH + o + 16);
                    a3 = *(const uint4*)(gSgL + o); a3b = *(const uint4*)(gSgL + o + 16);
                    b0v = *(const uint4*)(gBzH + o); b1v = *(const uint4*)(gBzL + o);
                    b2v = *(const uint4*)(gBtH + o); b3v = *(const uint4*)(gBtL + o);
                }
                #pragma unroll
                for (int kk = 0; kk < 4; kk++) {
                    const uint32_t koff = (kk * 16 + qk) * 2;
                    uint32_t base = (wm * 16 + qrow) * SLDA + koff;
                    uint32_t ah[4], al[4];
                    ah[0] = lds32(ub + oAh + base);
                    ah[1] = lds32(ub + oAh + base + 8 * SLDA);
                    ah[2] = lds32(ub + oAh + base + 16);
                    ah[3] = lds32(ub + oAh + base + 8 * SLDA + 16);
                    al[0] = lds32(ub + oAl + base);
                    al[1] = lds32(ub + oAl + base + 8 * SLDA);
                    al[2] = lds32(ub + oAl + base + 16);
                    al[3] = lds32(ub + oAl + base + 8 * SLDA + 16);
                    #pragma unroll
                    for (int nf = 0; nf < 4; nf++) {
                        uint32_t bb = (nf * 8 + qrow) * SLDA + koff;
                        uint32_t bh0 = lds32(ub + oBh + bb);
                        uint32_t bh1 = lds32(ub + oBh + bb + 16);
                        uint32_t cl0 = lds32(ub + oBl + bb);
                        uint32_t cl1 = lds32(ub + oBl + bb + 16);
                        mma16816(acc[nf], ah, bh0, bh1);
                        mma16816(acc[nf], ah, cl0, cl1);
                        mma16816(acc[nf], al, bh0, bh1);
                    }
                }
                if (c < 7) {
                    char* d;
                    d = nxt + SA0 + lr * SLDA + lq * 32; *(uint4*)d = a0; *(uint4*)(d + 16) = a0b;
                    d = nxt + SA1 + lr * SLDA + lq * 32; *(uint4*)d = a1; *(uint4*)(d + 16) = a1b;
                    d = nxt + SA2 + lr * SLDA + lq * 32; *(uint4*)d = a2; *(uint4*)(d + 16) = a2b;
                    d = nxt + SA3 + lr * SLDA + lq * 32; *(uint4*)d = a3; *(uint4*)(d + 16) = a3b;
                    *(uint4*)(nxt + SB0 + rb * SLDA + qb * 16) = b0v;
                    *(uint4*)(nxt + SB1 + rb * SLDA + qb * 16) = b1v;
                    *(uint4*)(nxt + SB2 + rb * SLDA + qb * 16) = b2v;
                    *(uint4*)(nxt + SB3 + rb * SLDA + qb * 16) = b3v;
                }
                __syncthreads();
            }

            // epilogue: activation into exchange buffers
            const float* P = wg ? g_Ph : g_Pz;
            const int rl0 = wm * 16 + qrow;
            const int row0 = m0 + rl0, row1 = row0 + 8;
            const int w0 = wid[t * Bq + row0], w1 = wid[t * Bq + row1];
            float* xbuf = (float*)(sms + (wg ? 8192 : 0));
            #pragma unroll
            for (int nf = 0; nf < 4; nf++) {
                int cl = nf * 8 + qk;
                int col = n0 + cl;
                float v00 = acc[nf][0] + P[(size_t)w0 * Hh + col];
                float v01 = acc[nf][1] + P[(size_t)w0 * Hh + col + 1];
                float v10 = acc[nf][2] + P[(size_t)w1 * Hh + col];
                float v11 = acc[nf][3] + P[(size_t)w1 * Hh + col + 1];
                if (wg) {
                    v00 = tanhf(v00); v01 = tanhf(v01);
                    v10 = tanhf(v10); v11 = tanhf(v11);
                } else {
                    v00 = fast_sigmoid(v00); v01 = fast_sigmoid(v01);
                    v10 = fast_sigmoid(v10); v11 = fast_sigmoid(v11);
                }
                xbuf[rl0 * 32 + cl] = v00;
                xbuf[rl0 * 32 + cl + 1] = v01;
                xbuf[(rl0 + 8) * 32 + cl] = v10;
                xbuf[(rl0 + 8) * 32 + cl + 1] = v11;
            }
            __syncthreads();
            const float* zbuf = (const float*)(sms);
            const float* tbuf = (const float*)(sms + 8192);
            const size_t toff = (size_t)t * Bq * Hh;
            #pragma unroll
            for (int e = tid; e < 64 * 32; e += 256) {
                int rl = e >> 5, cl = e & 31;
                size_t gi = (size_t)(m0 + rl) * Hh + (n0 + cl);
                float z = zbuf[e], th = tbuf[e];
                float h = (1.f - z) * g_sumh[gi] + z * th;
                g_hbuf[toff + gi] = h;
                __nv_bfloat16 hi, lo;
                splitbf(h, hi, lo);
                g_hbuf_hi[toff + gi] = hi;
                g_hbuf_lo[toff + gi] = lo;
            }
        }
        grid_bar(nb);

        // ---- P4: hbufUr[t] = h_new @ Ur (64x32 tile, double-buffered) ----
        {
            const int blk = (int)blockIdx.x;
            const int m0 = (blk >> 4) * 64;
            const int n0 = (blk & 15) * 32;
            const size_t toff = (size_t)t * Bq * Hh;

            float acc[2][4];
            #pragma unroll
            for (int nf = 0; nf < 2; nf++)
                #pragma unroll
                for (int r = 0; r < 4; r++) acc[nf][r] = 0.f;

            const int lr = tid >> 2, lq = tid & 3;
            const int br = tid >> 3, bq = tid & 7;
            const char* gAh = (const char*)(g_hbuf_hi + toff + (size_t)(m0 + lr) * Hh) + lq * 32;
            const char* gAl = (const char*)(g_hbuf_lo + toff + (size_t)(m0 + lr) * Hh) + lq * 32;
            const char* gBh = (const char*)(g_BUr_hi + (size_t)(n0 + br) * Hh) + bq * 16;
            const char* gBl = (const char*)(g_BUr_lo + (size_t)(n0 + br) * Hh) + bq * 16;
            const int wn = wg;

            {
                uint4 ah0 = *(const uint4*)(gAh), ah1 = *(const uint4*)(gAh + 16);
                uint4 al0 = *(const uint4*)(gAl), al1 = *(const uint4*)(gAl + 16);
                uint4 bh0 = *(const uint4*)(gBh), bl0 = *(const uint4*)(gBl);
                char* d = sms + SA0 + lr * SLDA + lq * 32;
                *(uint4*)d = ah0; *(uint4*)(d + 16) = ah1;
                d = sms + SA1 + lr * SLDA + lq * 32;
                *(uint4*)d = al0; *(uint4*)(d + 16) = al1;
                *(uint4*)(sms + SB0 + br * SLDA + bq * 16) = bh0;
                *(uint4*)(sms + SB1 + br * SLDA + bq * 16) = bl0;
            }
            __syncthreads();

            #pragma unroll 1
            for (int c = 0; c < 8; c++) {
                const uint32_t ub = u0 + (c & 1) * HBUF;
                char* nxt = sms + ((c + 1) & 1) * HBUF;
                uint4 nah0, nah1, nal0, nal1, nbh0, nbl0;
                if (c < 7) {
                    int o = (c + 1) * 128;
                    nah0 = *(const uint4*)(gAh + o); nah1 = *(const uint4*)(gAh + o + 16);
                    nal0 = *(const uint4*)(gAl + o); nal1 = *(const uint4*)(gAl + o + 16);
                    nbh0 = *(const uint4*)(gBh + o); nbl0 = *(const uint4*)(gBl + o);
                }
                #pragma unroll
                for (int kk = 0; kk < 4; kk++) {
                    const uint32_t koff = (kk * 16 + qk) * 2;
                    uint32_t base = (wm * 16 + qrow) * SLDA + koff;
                    uint32_t ah[4], al[4];
                    ah[0] = lds32(ub + SA0 + base);
                    ah[1] = lds32(ub + SA0 + base + 8 * SLDA);
                    ah[2] = lds32(ub + SA0 + base + 16);
                    ah[3] = lds32(ub + SA0 + base + 8 * SLDA + 16);
                    al[0] = lds32(ub + SA1 + base);
                    al[1] = lds32(ub + SA1 + base + 8 * SLDA);
                    al[2] = lds32(ub + SA1 + base + 16);
                    al[3] = lds32(ub + SA1 + base + 8 * SLDA + 16);
                    #pragma unroll
                    for (int nf = 0; nf < 2; nf++) {
                        uint32_t bb = (wn * 16 + nf * 8 + qrow) * SLDA + koff;
                        uint32_t b0 = lds32(ub + SB0 + bb);
                        uint32_t b1 = lds32(ub + SB0 + bb + 16);
                        uint32_t c0 = lds32(ub + SB1 + bb);
                        uint32_t c1 = lds32(ub + SB1 + bb + 16);
                        mma16816(acc[nf], ah, b0, b1);
                        mma16816(acc[nf], ah, c0, c1);
                        mma16816(acc[nf], al, b0, b1);
                    }
                }
                if (c < 7) {
                    char* d = nxt + SA0 + lr * SLDA + lq * 32;
                    *(uint4*)d = nah0; *(uint4*)(d + 16) = nah1;
                    d = nxt + SA1 + lr * SLDA + lq * 32;
                    *(uint4*)d = nal0; *(uint4*)(d + 16) = nal1;
                    *(uint4*)(nxt + SB0 + br * SLDA + bq * 16) = nbh0;
                    *(uint4*)(nxt + SB1 + br * SLDA + bq * 16) = nbl0;
                }
                __syncthreads();
            }
            float* Cc = g_hbufUr + toff;
            int r0 = m0 + wm * 16 + qrow;
            #pragma unroll
            for (int nf = 0; nf < 2; nf++) {
                int col = n0 + wn * 16 + nf * 8 + qk;
                float2 o0 = {acc[nf][0], acc[nf][1]};
                float2 o1 = {acc[nf][2], acc[nf][3]};
                *(float2*)&Cc[(size_t)r0 * Hh + col] = o0;
                *(float2*)&Cc[(size_t)(r0 + 8) * Hh + col] = o1;
            }
        }
        grid_bar(nb);
    }
}

// ---------------- tc mainloops ----------------
#define LDA_B 144
#define OFF_ALO 18432
#define OFF_BHI 36864
#define OFF_BLO 55296
#define TCSM_BYTES 73728

// fp32-A mainloop (emb precompute only)
__device__ __forceinline__ void tc_main(
    const float* Abase, const char* BhiBase, const char* BloBase,
    char* smc, uint32_t sbase, int tid, int wm, int wn, int qrow, int qk,
    float acc[2][8][4])
{
    const int ar = tid >> 1;
    const int ac = (tid & 1) * 32;
    const int bo = (tid & 1) * 64;

    float4 av[8];
    uint4 bh[4], bl[4];
    #pragma unroll
    for (int f = 0; f < 8; f++) av[f] = *(const float4*)(Abase + f * 4);
    #pragma unroll
    for (int u = 0; u < 4; u++) {
        bh[u] = *(const uint4*)(BhiBase + u * 16);
        bl[u] = *(const uint4*)(BloBase + u * 16);
    }

    #pragma unroll 1
    for (int c = 0; c < 8; c++) {
        __syncthreads();
        {
            char* sa = smc + ar * LDA_B + ac * 2;
            char* sl = sa + OFF_ALO;
            #pragma unroll
            for (int f = 0; f < 8; f++) {
                __nv_bfloat16 h0, h1, h2, h3, l0, l1, l2, l3;
                splitbf(av[f].x, h0, l0);
                splitbf(av[f].y, h1, l1);
                splitbf(av[f].z, h2, l2);
                splitbf(av[f].w, h3, l3);
                __nv_bfloat162 hh0, hh1, ll0, ll1;
                hh0.x = h0; hh0.y = h1; hh1.x = h2; hh1.y = h3;
                ll0.x = l0; ll0.y = l1; ll1.x = l2; ll1.y = l3;
                uint2 hv = {*(uint32_t*)&hh0, *(uint32_t*)&hh1};
                uint2 lv = {*(uint32_t*)&ll0, *(uint32_t*)&ll1};
                *(uint2*)(sa + f * 8) = hv;
                *(uint2*)(sl + f * 8) = lv;
            }
            char* sb = smc + OFF_BHI + ar * LDA_B + bo;
            char* sbl = smc + OFF_BLO + ar * LDA_B + bo;
            #pragma unroll
            for (int u = 0; u < 4; u++) {
                *(uint4*)(sb + u * 16) = bh[u];
                *(uint4*)(sbl + u * 16) = bl[u];
            }
        }
        __syncthreads();

        float4 nav[8];
        uint4 nbh[4], nbl[4];
        if (c < 7) {
            #pragma unroll
            for (int f = 0; f < 8; f++)
                nav[f] = *(const float4*)(Abase + (c + 1) * 64 + f * 4);
            #pragma unroll
            for (int u = 0; u < 4; u++) {
                nbh[u] = *(const uint4*)(BhiBase + (c + 1) * 128 + u * 16);
                nbl[u] = *(const uint4*)(BloBase + (c + 1) * 128 + u * 16);
            }
        }

        #pragma unroll
        for (int kk = 0; kk < 4; kk++) {
            const uint32_t koff = (kk * 16 + qk) * 2;
            uint32_t ah[2][4], al[2][4];
            #pragma unroll
            for (int mf = 0; mf < 2; mf++) {
                uint32_t base = sbase + (wm * 32 + mf * 16 + qrow) * LDA_B + koff;
                ah[mf][0] = lds32(base);
                ah[mf][1] = lds32(base + 8 * LDA_B);
                ah[mf][2] = lds32(base + 16);
                ah[mf][3] = lds32(base + 8 * LDA_B + 16);
                al[mf][0] = lds32(base + OFF_ALO);
                al[mf][1] = lds32(base + OFF_ALO + 8 * LDA_B);
                al[mf][2] = lds32(base + OFF_ALO + 16);
                al[mf][3] = lds32(base + OFF_ALO + 8 * LDA_B + 16);
            }
            #pragma unroll
            for (int nf = 0; nf < 8; nf++) {
                uint32_t bb = sbase + OFF_BHI + (wn * 64 + nf * 8 + qrow) * LDA_B + koff;
                uint32_t bh0 = lds32(bb);
                uint32_t bh1 = lds32(bb + 16);
                uint32_t bl0 = lds32(bb + (OFF_BLO - OFF_BHI));
                uint32_t bl1 = lds32(bb + (OFF_BLO - OFF_BHI) + 16);
                #pragma unroll
                for (int mf = 0; mf < 2; mf++) {
                    mma16816(acc[mf][nf], ah[mf], bh0, bh1);
                    mma16816(acc[mf][nf], ah[mf], bl0, bl1);
                    mma16816(acc[mf][nf], al[mf], bh0, bh1);
                }
            }
        }
        if (c < 7) {
            #pragma unroll
            for (int f = 0; f < 8; f++) av[f] = nav[f];
            #pragma unroll
            for (int u = 0; u < 4; u++) { bh[u] = nbh[u]; bl[u] = nbl[u]; }
        }
    }
}

// split-A mainloop (A already bf16 hi/lo): pure copies + MMA
__device__ __forceinline__ void tc_main_sa(
    const char* AhiBase, const char* AloBase,
    const char* BhiBase, const char* BloBase,
    char* smc, uint32_t sbase, int tid, int wm, int wn, int qrow, int qk,
    float acc[2][8][4])
{
    const int ar = tid >> 1;
    const int bo = (tid & 1) * 64;

    uint4 xa[4], xl[4], xb[4], xc[4];
    #pragma unroll
    for (int u = 0; u < 4; u++) {
        xa[u] = *(const uint4*)(AhiBase + u * 16);
        xl[u] = *(const uint4*)(AloBase + u * 16);
        xb[u] = *(const uint4*)(BhiBase + u * 16);
        xc[u] = *(const uint4*)(BloBase + u * 16);
    }

    #pragma unroll 1
    for (int c = 0; c < 8; c++) {
        __syncthreads();
        {
            char* d = smc + ar * LDA_B + bo;
            #pragma unroll
            for (int u = 0; u < 4; u++) {
                *(uint4*)(d + u * 16) = xa[u];
                *(uint4*)(d + OFF_ALO + u * 16) = xl[u];
                *(uint4*)(d + OFF_BHI + u * 16) = xb[u];
                *(uint4*)(d + OFF_BLO + u * 16) = xc[u];
            }
        }
        __syncthreads();

        uint4 na[4], nl[4], nb[4], nc[4];
        if (c < 7) {
            int o = (c + 1) * 128;
            #pragma unroll
            for (int u = 0; u < 4; u++) {
                na[u] = *(const uint4*)(AhiBase + o + u * 16);
                nl[u] = *(const uint4*)(AloBase + o + u * 16);
                nb[u] = *(const uint4*)(BhiBase + o + u * 16);
                nc[u] = *(const uint4*)(BloBase + o + u * 16);
            }
        }

        #pragma unroll
        for (int kk = 0; kk < 4; kk++) {
            const uint32_t koff = (kk * 16 + qk) * 2;
            uint32_t ah[2][4], al[2][4];
            #pragma unroll
            for (int mf = 0; mf < 2; mf++) {
                uint32_t base = sbase + (wm * 32 + mf * 16 + qrow) * LDA_B + koff;
                ah[mf][0] = lds32(base);
                ah[mf][1] = lds32(base + 8 * LDA_B);
                ah[mf][2] = lds32(base + 16);
                ah[mf][3] = lds32(base + 8 * LDA_B + 16);
                al[mf][0] = lds32(base + OFF_ALO);
                al[mf][1] = lds32(base + OFF_ALO + 8 * LDA_B);
                al[mf][2] = lds32(base + OFF_ALO + 16);
                al[mf][3] = lds32(base + OFF_ALO + 8 * LDA_B + 16);
            }
            #pragma unroll
            for (int nf = 0; nf < 8; nf++) {
                uint32_t bb = sbase + OFF_BHI + (wn * 64 + nf * 8 + qrow) * LDA_B + koff;
                uint32_t bh0 = lds32(bb);
                uint32_t bh1 = lds32(bb + 16);
                uint32_t bl0 = lds32(bb + (OFF_BLO - OFF_BHI));
                uint32_t bl1 = lds32(bb + (OFF_BLO - OFF_BHI) + 16);
                #pragma unroll
                for (int mf = 0; mf < 2; mf++) {
                    mma16816(acc[mf][nf], ah[mf], bh0, bh1);
                    mma16816(acc[mf][nf], ah[mf], bl0, bl1);
                    mma16816(acc[mf][nf], al[mf], bh0, bh1);
                }
            }
        }
        if (c < 7) {
            #pragma unroll
            for (int u = 0; u < 4; u++) {
                xa[u] = na[u]; xl[u] = nl[u]; xb[u] = nb[u]; xc[u] = nc[u];
            }
        }
    }
}

// split-A GEMM kernel. modes: 0 logits, 1 stop, 2 pred-phid
__global__ __launch_bounds__(256)
void tc_gemm_sa(const __nv_bfloat16* __restrict__ Ahi,
                const __nv_bfloat16* __restrict__ Alo,
                const __nv_bfloat16* __restrict__ Bhi,
                const __nv_bfloat16* __restrict__ Blo,
                const float* __restrict__ bias, float* __restrict__ C, int ldc,
                int mode, const int* __restrict__ widp,
                const int* __restrict__ rootp, const float* __restrict__ Us)
{
    extern __shared__ char smc[];
    const uint32_t sbase = smem_u32(smc);
    __shared__ int s_rows[128];

    const int tid = threadIdx.x;
    const int wid_ = tid >> 5;
    const int lane = tid & 31;
    const int wm = wid_ & 3;
    const int wn = wid_ >> 2;
    const int qrow = lane >> 2;
    const int qk = (lane & 3) << 1;
    const int m0 = blockIdx.y * 128;
    const int n0 = blockIdx.x * 128;

    if (tid < 128) s_rows[tid] = (mode == 2) ? g_cmap[m0 + tid] : (m0 + tid);
    __syncthreads();

    const int ar = tid >> 1;
    const int bo = (tid & 1) * 64;
    const char* AhiBase = (const char*)(Ahi + (size_t)s_rows[ar] * Hh) + bo;
    const char* AloBase = (const char*)(Alo + (size_t)s_rows[ar] * Hh) + bo;
    const char* BhiBase = (const char*)(Bhi + (size_t)(n0 + ar) * Hh) + bo;
    const char* BloBase = (const char*)(Blo + (size_t)(n0 + ar) * Hh) + bo;

    float acc[2][8][4];
    #pragma unroll
    for (int mf = 0; mf < 2; mf++)
        #pragma unroll
        for (int nf = 0; nf < 8; nf++)
            #pragma unroll
            for (int r = 0; r < 4; r++) acc[mf][nf][r] = 0.f;

    tc_main_sa(AhiBase, AloBase, BhiBase, BloBase, smc, sbase, tid, wm, wn, qrow, qk, acc);

    if (mode == 0) {
        #pragma unroll
        for (int mf = 0; mf < 2; mf++) {
            int r0 = m0 + wm * 32 + mf * 16 + qrow;
            #pragma unroll
            for (int nf = 0; nf < 8; nf++) {
                int col = n0 + wn * 64 + nf * 8 + qk;
                float2 o0 = {acc[mf][nf][0] + bias[col], acc[mf][nf][1] + bias[col + 1]};
                float2 o1 = {acc[mf][nf][2] + bias[col], acc[mf][nf][3] + bias[col + 1]};
                *(float2*)&C[(size_t)r0 * ldc + col] = o0;
                *(float2*)&C[(size_t)(r0 + 8) * ldc + col] = o1;
            }
        }
    } else if (mode == 1) {
        int slot = blockIdx.x * 2 + wn;
        #pragma unroll
        for (int mf = 0; mf < 2; mf++) {
            int r0 = m0 + wm * 32 + mf * 16 + qrow;
            int r1 = r0 + 8;
            int w0, b0, w1, b1;
            if (r0 < TBq) { w0 = widp[r0]; b0 = r0 & (Bq - 1); }
            else          { w0 = rootp[r0 - TBq]; b0 = r0 - TBq; }
            if (r1 < TBq) { w1 = widp[r1]; b1 = r1 & (Bq - 1); }
            else          { w1 = rootp[r1 - TBq]; b1 = r1 - TBq; }
            const float* Pe0 = g_PembU + (size_t)w0 * Hh;
            const float* Pm0 = g_PmolU + (size_t)b0 * Hh;
            const float* Pe1 = g_PembU + (size_t)w1 * Hh;
            const float* Pm1 = g_PmolU + (size_t)b1 * Hh;
            float p0 = 0.f, p1 = 0.f;
            #pragma unroll
            for (int nf = 0; nf < 8; nf++) {
                int col = wn * 64 + nf * 8 + qk;
                int gc = blockIdx.x * 128 + col;
                float u0 = Us[gc], u1 = Us[gc + 1];
                p0 += fmaxf(acc[mf][nf][0] + Pe0[gc] + Pm0[gc], 0.f) * u0;
                p0 += fmaxf(acc[mf][nf][1] + Pe0[gc + 1] + Pm0[gc + 1], 0.f) * u1;
                p1 += fmaxf(acc[mf][nf][2] + Pe1[gc] + Pm1[gc], 0.f) * u0;
                p1 += fmaxf(acc[mf][nf][3] + Pe1[gc + 1] + Pm1[gc + 1], 0.f) * u1;
            }
            p0 += __shfl_xor_sync(0xffffffffu, p0, 1);
            p0 += __shfl_xor_sync(0xffffffffu, p0, 2);
            p1 += __shfl_xor_sync(0xffffffffu, p1, 1);
            p1 += __shfl_xor_sync(0xffffffffu, p1, 2);
            if ((lane & 3) == 0) {
                g_spart[(size_t)slot * MSr + r0] = p0;
                g_spart[(size_t)slot * MSr + r1] = p1;
            }
        }
    } else {
        #pragma unroll
        for (int mf = 0; mf < 2; mf++) {
            int rl0 = wm * 32 + mf * 16 + qrow;
            int j0 = m0 + rl0;
            int bc0 = s_rows[rl0] & (Bq - 1);
            int bc1 = s_rows[rl0 + 8] & (Bq - 1);
            const float* Pm0 = g_PmolW + (size_t)bc0 * Hh;
            const float* Pm1 = g_PmolW + (size_t)bc1 * Hh;
            #pragma unroll
            for (int nf = 0; nf < 8; nf++) {
                int col = n0 + wn * 64 + nf * 8 + qk;
                float v00 = fmaxf(acc[mf][nf][0] + Pm0[col], 0.f);
                float v01 = fmaxf(acc[mf][nf][1] + Pm0[col + 1], 0.f);
                float v10 = fmaxf(acc[mf][nf][2] + Pm1[col], 0.f);
                float v11 = fmaxf(acc[mf][nf][3] + Pm1[col + 1], 0.f);
                __nv_bfloat162 h2, l2;
                __nv_bfloat16 h, l;
                splitbf(v00, h, l); h2.x = h; l2.x = l;
                splitbf(v01, h, l); h2.y = h; l2.y = l;
                *(__nv_bfloat162*)&g_phid_hi[(size_t)(Bq + j0) * Hh + col] = h2;
                *(__nv_bfloat162*)&g_phid_lo[(size_t)(Bq + j0) * Hh + col] = l2;
                splitbf(v10, h, l); h2.x = h; l2.x = l;
                splitbf(v11, h, l); h2.y = h; l2.y = l;
                *(__nv_bfloat162*)&g_phid_hi[(size_t)(Bq + j0 + 8) * Hh + col] = h2;
                *(__nv_bfloat162*)&g_phid_lo[(size_t)(Bq + j0 + 8) * Hh + col] = l2;
            }
        }
    }
}

// fused emb-precompute: 4 GEMMs selected by blockIdx.z
__global__ __launch_bounds__(256)
void tc_gemm_pre4(const float* __restrict__ A,
                  const __nv_bfloat16* b0h, const __nv_bfloat16* b0l,
                  const float* bias0, float* C0,
                  const __nv_bfloat16* b1h, const __nv_bfloat16* b1l,
                  const float* bias1, float* C1,
                  const __nv_bfloat16* b2h, const __nv_bfloat16* b2l,
                  const float* bias2, float* C2,
                  const __nv_bfloat16* b3h, const __nv_bfloat16* b3l,
                  const float* bias3, float* C3)
{
    extern __shared__ char smc[];
    const uint32_t sbase = smem_u32(smc);
    const int z = blockIdx.z;
    const __nv_bfloat16* Bhi = (z == 0) ? b0h : (z == 1) ? b1h : (z == 2) ? b2h : b3h;
    const __nv_bfloat16* Blo = (z == 0) ? b0l : (z == 1) ? b1l : (z == 2) ? b2l : b3l;
    const float* bias = (z == 0) ? bias0 : (z == 1) ? bias1 : (z == 2) ? bias2 : bias3;
    float* C = (z == 0) ? C0 : (z == 1) ? C1 : (z == 2) ? C2 : C3;

    const int tid = threadIdx.x;
    const int wid_ = tid >> 5;
    const int lane = tid & 31;
    const int wm = wid_ & 3;
    const int wn = wid_ >> 2;
    const int qrow = lane >> 2;
    const int qk = (lane & 3) << 1;
    const int m0 = blockIdx.y * 128;
    const int n0 = blockIdx.x * 128;

    const int ar = tid >> 1;
    const int ac = (tid & 1) * 32;
    const int bo = (tid & 1) * 64;
    const float* Abase = A + (size_t)(m0 + ar) * Hh + ac;
    const char* BhiBase = (const char*)(Bhi + (size_t)(n0 + ar) * Hh) + bo;
    const char* BloBase = (const char*)(Blo + (size_t)(n0 + ar) * Hh) + bo;

    float acc[2][8][4];
    #pragma unroll
    for (int mf = 0; mf < 2; mf++)
        #pragma unroll
        for (int nf = 0; nf < 8; nf++)
            #pragma unroll
            for (int r = 0; r < 4; r++) acc[mf][nf][r] = 0.f;

    tc_main(Abase, BhiBase, BloBase, smc, sbase, tid, wm, wn, qrow, qk, acc);

    #pragma unroll
    for (int mf = 0; mf < 2; mf++) {
        int r0 = m0 + wm * 32 + mf * 16 + qrow;
        #pragma unroll
        for (int nf = 0; nf < 8; nf++) {
            int col = n0 + wn * 64 + nf * 8 + qk;
            float2 o0 = {acc[mf][nf][0] + bias[col], acc[mf][nf][1] + bias[col + 1]};
            float2 o1 = {acc[mf][nf][2] + bias[col], acc[mf][nf][3] + bias[col + 1]};
            *(float2*)&C[(size_t)r0 * Hh + col] = o0;
            *(float2*)&C[(size_t)(r0 + 8) * Hh + col] = o1;
        }
    }
}

// ---------------- housekeeping ----------------
__global__ __launch_bounds__(256)
void prep_kernel()
{
    int i = blockIdx.x * 256 + threadIdx.x;
    if (i < 5) g_acc[i] = 0.0;
    if (i == 5) { g_barc = 0; g_ccount = 0; }
    if (i == 6) g_bars = 0;
    if (i < Hh) {
        g_hbuf[(size_t)PADROW * Hh + i] = 0.f;
        g_hbufUr[(size_t)PADROW * Hh + i] = 0.f;
        g_hbuf_hi[(size_t)PADROW * Hh + i] = __float2bfloat16(0.f);
        g_hbuf_lo[(size_t)PADROW * Hh + i] = __float2bfloat16(0.f);
    }
    if (i < NCMP + 256) g_cmap[i] = 0;
}

__global__ __launch_bounds__(256)
void compact_kernel(const int* __restrict__ dirs)
{
    int i = blockIdx.x * 256 + threadIdx.x;
    if (dirs[i]) {
        int s = atomicAdd(&g_ccount, 1);
        g_cmap[s] = i;
    }
}

__global__ __launch_bounds__(256)
void build_curo(const int* __restrict__ oni, const int* __restrict__ roni)
{
    int i = blockIdx.x, tid = threadIdx.x;
    __shared__ int ids[MAXNB];
    if (tid < MAXNB)
        ids[tid] = (i < TBq) ? oni[(size_t)i * MAXNB + tid]
                             : roni[(size_t)(i - TBq) * MAXNB + tid];
    __syncthreads();
    for (int h4 = tid * 4; h4 < Hh; h4 += 1024) {
        float4 v = {0.f, 0.f, 0.f, 0.f};
        #pragma unroll
        for (int n = 0; n < MAXNB; n++) {
            int id = ids[n];
            if (id == PADROW) continue;
            float4 hv = *(const float4*)&g_hbuf[(size_t)id * Hh + h4];
            v.x += hv.x; v.y += hv.y; v.z += hv.z; v.w += hv.w;
        }
        uint2 lo, hi;
        hi = pack_hi4(v.x, v.y, v.z, v.w, lo);
        *(uint2*)&g_curo_hi[(size_t)i * Hh + h4] = hi;
        *(uint2*)&g_curo_lo[(size_t)i * Hh + h4] = lo;
    }
}

__global__ __launch_bounds__(512)
void phid0_kernel()
{
    int b = blockIdx.x, h = threadIdx.x;
    float v = fmaxf(g_PmolW[(size_t)b * Hh + h], 0.f);
    __nv_bfloat16 hh, ll;
    splitbf(v, hh, ll);
    g_phid_hi[(size_t)b * Hh + h] = hh;
    g_phid_lo[(size_t)b * Hh + h] = ll;
}

// ---------------- stop head finalize ----------------
__global__ __launch_bounds__(256)
void stop_final_kernel(const float* __restrict__ bs, const int* __restrict__ dirs)
{
    int i = blockIdx.x * 256 + threadIdx.x;
    float s = bs[0];
    #pragma unroll
    for (int k = 0; k < 8; k++) s += g_spart[(size_t)k * MSr + i];
    float tgt = (i < TBq) ? (float)dirs[i] : 0.f;
    float loss = fmaxf(s, 0.f) - s * tgt + log1pf(expf(-fabsf(s)));
    float corr = ((s >= 0.5f) == (tgt > 0.5f)) ? 1.f : 0.f;
    __shared__ double r0[256], r1[256];
    int tid = threadIdx.x;
    r0[tid] = (double)loss;
    r1[tid] = (double)corr;
    __syncthreads();
    for (int o = 128; o > 0; o >>= 1) {
        if (tid < o) { r0[tid] += r0[tid + o]; r1[tid] += r1[tid + o]; }
        __syncthreads();
    }
    if (tid == 0) {
        atomicAdd(&g_acc[0], r0[0]);
        atomicAdd(&g_acc[1], r1[0]);
    }
}

// ---------------- pred head: log-softmax CE + argmax ----------------
__global__ __launch_bounds__(256)
void pred_rows_kernel(const int* __restrict__ root_wid, const int* __restrict__ y_wid)
{
    int j = blockIdx.x, tid = threadIdx.x;
    const float* row = g_logitsc + (size_t)j * Vv;
    int tgt = (j < Bq) ? root_wid[j] : y_wid[g_cmap[j - Bq]];

    float mval = -1e30f; int midx = Vv;
    for (int k = tid; k < Vv; k += 256) {
        float v = row[k];
        if (v > mval) { mval = v; midx = k; }
    }
    __shared__ float rv[256];
    __shared__ int ri[256];
    rv[tid] = mval; ri[tid] = midx; __syncthreads();
    for (int s = 128; s > 0; s >>= 1) {
        if (tid < s) {
            if (rv[tid + s] > rv[tid] ||
                (rv[tid + s] == rv[tid] && ri[tid + s] < ri[tid])) {
                rv[tid] = rv[tid + s]; ri[tid] = ri[tid + s];
            }
        }
        __syncthreads();
    }
    float gmax = rv[0]; int gidx = ri[0];
    __syncthreads();
    float p = 0.f;
    for (int k = tid; k < Vv; k += 256) p += __expf(row[k] - gmax);
    rv[tid] = p; __syncthreads();
    for (int s = 128; s > 0; s >>= 1) {
        if (tid < s) rv[tid] += rv[tid + s];
        __syncthreads();
    }
    if (tid == 0) {
        float lse = gmax + logf(rv[0]);
        float ce = -(row[tgt] - lse);
        atomicAdd(&g_acc[2], (double)ce);
        if (gidx == tgt) atomicAdd(&g_acc[3], 1.0);
        atomicAdd(&g_acc[4], 1.0);
    }
}

__global__ void finalize_kernel(float* out)
{
    out[0] = (float)(g_acc[2] / (double)Bq);
    out[1] = (float)(g_acc[0] / (double)Bq);
    out[2] = (float)(g_acc[3] / g_acc[4]);
    out[3] = (float)(g_acc[1] / (double)MSr);
}

// ---------------- launch ----------------
extern "C" void kernel_launch(void* const* d_in, const int* in_sizes, int n_in,
                              void* d_out, int out_size)
{
    const float* mol_vec  = (const float*)d_in[0];
    const int*   wid      = (const int*)d_in[1];
    const int*   y_wid    = (const int*)d_in[2];
    const int*   dirs     = (const int*)d_in[3];
    const int*   hni      = (const int*)d_in[4];
    const int*   oni      = (const int*)d_in[5];
    const int*   root_wid = (const int*)d_in[6];
    const int*   roni     = (const int*)d_in[7];
    const float* emb      = (const float*)d_in[8];
    const float* Wz       = (const float*)d_in[9];
    const float* bz       = (const float*)d_in[10];
    const float* Wr       = (const float*)d_in[11];
    const float* br       = (const float*)d_in[12];
    const float* Ur       = (const float*)d_in[13];
    const float* Wh       = (const float*)d_in[14];
    const float* bh       = (const float*)d_in[15];
    const float* Wm       = (const float*)d_in[16];
    const float* bW       = (const float*)d_in[17];
    const float* U        = (const float*)d_in[18];
    const float* bU       = (const float*)d_in[19];
    const float* Wo       = (const float*)d_in[20];
    const float* bo       = (const float*)d_in[21];
    const float* Us       = (const float*)d_in[22];
    const float* bs       = (const float*)d_in[23];

    float *gPz, *gPr, *gPh, *gPembU, *gPmolU, *gPmolW, *glogitsc;
    __nv_bfloat16 *gBuH, *gBuL, *gBwH, *gBwL, *gBoH, *gBoL;
    __nv_bfloat16 *gBzhH, *gBzhL, *gBUrH, *gBUrL;
    __nv_bfloat16 *gBz0H, *gBz0L, *gBr0H, *gBr0L, *gBh0H, *gBh0L, *gBU0H, *gBU0L;
    __nv_bfloat16 *gCuH, *gCuL, *gPhH, *gPhL, *gHbH, *gHbL;
    cudaGetSymbolAddress((void**)&gPz, g_Pz);
    cudaGetSymbolAddress((void**)&gPr, g_Pr);
    cudaGetSymbolAddress((void**)&gPh, g_Ph);
    cudaGetSymbolAddress((void**)&gPembU, g_PembU);
    cudaGetSymbolAddress((void**)&gPmolU, g_PmolU);
    cudaGetSymbolAddress((void**)&gPmolW, g_PmolW);
    cudaGetSymbolAddress((void**)&glogitsc, g_logitsc);
    cudaGetSymbolAddress((void**)&gBuH, g_Bu_hi);
    cudaGetSymbolAddress((void**)&gBuL, g_Bu_lo);
    cudaGetSymbolAddress((void**)&gBwH, g_Bw_hi);
    cudaGetSymbolAddress((void**)&gBwL, g_Bw_lo);
    cudaGetSymbolAddress((void**)&gBoH, g_Bo_hi);
    cudaGetSymbolAddress((void**)&gBoL, g_Bo_lo);
    cudaGetSymbolAddress((void**)&gBzhH, g_Bzh_hi);
    cudaGetSymbolAddress((void**)&gBzhL, g_Bzh_lo);
    cudaGetSymbolAddress((void**)&gBUrH, g_BUr_hi);
    cudaGetSymbolAddress((void**)&gBUrL, g_BUr_lo);
    cudaGetSymbolAddress((void**)&gBz0H, g_Bz0_hi);
    cudaGetSymbolAddress((void**)&gBz0L, g_Bz0_lo);
    cudaGetSymbolAddress((void**)&gBr0H, g_Br0_hi);
    cudaGetSymbolAddress((void**)&gBr0L, g_Br0_lo);
    cudaGetSymbolAddress((void**)&gBh0H, g_Bh0_hi);
    cudaGetSymbolAddress((void**)&gBh0L, g_Bh0_lo);
    cudaGetSymbolAddress((void**)&gBU0H, g_BU0_hi);
    cudaGetSymbolAddress((void**)&gBU0L, g_BU0_lo);
    cudaGetSymbolAddress((void**)&gCuH, g_curo_hi);
    cudaGetSymbolAddress((void**)&gCuL, g_curo_lo);
    cudaGetSymbolAddress((void**)&gPhH, g_phid_hi);
    cudaGetSymbolAddress((void**)&gPhL, g_phid_lo);
    cudaGetSymbolAddress((void**)&gHbH, g_hbuf_hi);
    cudaGetSymbolAddress((void**)&gHbL, g_hbuf_lo);

    cudaFuncSetAttribute(tc_gemm_sa,
                         cudaFuncAttributeMaxDynamicSharedMemorySize, TCSM_BYTES);
    cudaFuncSetAttribute(tc_gemm_pre4,
                         cudaFuncAttributeMaxDynamicSharedMemorySize, TCSM_BYTES);
    cudaFuncSetAttribute(scan_kernel,
                         cudaFuncAttributeMaxDynamicSharedMemorySize, SCAN_SMEM);

    prep_kernel<<<47, 256>>>();
    compact_kernel<<<92, 256>>>(dirs);

    // batched weight transposes + bf16 split
    ConvJobs jobs;
    jobs.j[0] = {U + (size_t)Hh * Hh, gBuH, gBuL, 16};
    jobs.j[1] = {Wm, gBwH, gBwL, 16};
    jobs.j[2] = {Wo, gBoH, gBoL, 32};
    jobs.j[3] = {Wz + (size_t)Hh * Hh, gBzhH, gBzhL, 16};
    jobs.j[4] = {Wh + (size_t)Hh * Hh, gBzhH + (size_t)Hh * Hh, gBzhL + (size_t)Hh * Hh, 16};
    jobs.j[5] = {Ur, gBUrH, gBUrL, 16};
    jobs.j[6] = {Wz, gBz0H, gBz0L, 16};
    jobs.j[7] = {Wr, gBr0H, gBr0L, 16};
    jobs.j[8] = {Wh, gBh0H, gBh0L, 16};
    jobs.j[9] = {U, gBU0H, gBU0L, 16};
    convT_all<<<dim3(32, 16, 10), 256>>>(jobs);

    // fused emb precomputes
    tc_gemm_pre4<<<dim3(4, 8, 4), 256, TCSM_BYTES>>>(
        emb,
        gBz0H, gBz0L, bz, gPz,
        gBr0H, gBr0L, br, gPr,
        gBh0H, gBh0L, bh, gPh,
        gBU0H, gBU0L, bU, gPembU);
    sgemm_kernel<<<dim3(Hh / BN, Bq / BM), 256>>>(Bq, Hh, Ll, mol_vec, U + (size_t)2 * Hh * Hh, nullptr, gPmolU);
    sgemm_kernel<<<dim3(Hh / BN, Bq / BM), 256>>>(Bq, Hh, Ll, mol_vec, Wm + (size_t)Hh * Hh, bW, gPmolW);

    // persistent fused GRU scan
    scan_kernel<<<NBLK, 256, SCAN_SMEM>>>(wid, hni);

    // stop head (split-A)
    build_curo<<<MSr, 256>>>(oni, roni);
    tc_gemm_sa<<<dim3(4, MSr / 128), 256, TCSM_BYTES>>>(
        gCuH, gCuL, gBuH, gBuL, nullptr, nullptr, 0, 1, wid, root_wid, Us);
    stop_final_kernel<<<94, 256>>>(bs, dirs);

    // pred head (compacted, split-A)
    phid0_kernel<<<Bq, Hh>>>();
    tc_gemm_sa<<<dim3(4, NCMP / 128), 256, TCSM_BYTES>>>(
        gHbH, gHbL, gBwH, gBwL, nullptr, nullptr, 0, 2, nullptr, nullptr, nullptr);
    tc_gemm_sa<<<dim3(8, MPRED / 128), 256, TCSM_BYTES>>>(
        gPhH, gPhL, gBoH, gBoL, bo, glogitsc, Vv, 0, nullptr, nullptr, nullptr);
    pred_rows_kernel<<<MPRED, 256>>>(root_wid, y_wid);

    finalize_kernel<<<1, 1>>>((float*)d_out);
}

// round 11
// speedup vs baseline: 7.1022x; 1.0453x over previous
#include <cuda_runtime.h>
#include <cuda_bf16.h>
#include <math.h>
#include <stdint.h>

// Problem constants
#define Bq 512
#define Hh 512
#define Ll 64
#define Vv 1024
#define Tt 46
#define TBq 23552          // T*B
#define PADROW 23552
#define MSr 24064          // TB + B
#define MAXNB 8
#define NCMP 11776         // compacted pred rows (dirs==1)
#define MPRED 12288        // B + NCMP
#define NBLK 128           // persistent scan grid

// ---------------- scratch ----------------
__device__ float g_hbuf[(size_t)(TBq + 1) * Hh];
__device__ float g_hbufUr[(size_t)(TBq + 1) * Hh];
__device__ __nv_bfloat16 g_hbuf_hi[(size_t)(TBq + 1) * Hh];
__device__ __nv_bfloat16 g_hbuf_lo[(size_t)(TBq + 1) * Hh];
__device__ float g_Pz[(size_t)Vv * Hh];
__device__ float g_Pr[(size_t)Vv * Hh];
__device__ float g_Ph[(size_t)Vv * Hh];
__device__ float g_PembU[(size_t)Vv * Hh];
__device__ float g_PmolU[(size_t)Bq * Hh];
__device__ float g_PmolW[(size_t)Bq * Hh];
__device__ float g_sumh[(size_t)Bq * Hh];
__device__ __nv_bfloat16 g_curo_hi[(size_t)MSr * Hh];
__device__ __nv_bfloat16 g_curo_lo[(size_t)MSr * Hh];
__device__ __nv_bfloat16 g_phid_hi[(size_t)MPRED * Hh];
__device__ __nv_bfloat16 g_phid_lo[(size_t)MPRED * Hh];
__device__ float g_logitsc[(size_t)MPRED * Vv];
__device__ float g_spart[(size_t)8 * MSr];
__device__ int   g_cmap[NCMP + 256];
__device__ int   g_ccount;
__device__ int   g_barc;
__device__ double g_acc[5];
// scan split activations (per-step)
__device__ __nv_bfloat16 g_shg_hi[(size_t)2 * Bq * Hh];
__device__ __nv_bfloat16 g_shg_lo[(size_t)2 * Bq * Hh];
// bf16 split weights, stored [N, K]
__device__ __nv_bfloat16 g_Bu_hi[(size_t)Hh * Hh];
__device__ __nv_bfloat16 g_Bu_lo[(size_t)Hh * Hh];
__device__ __nv_bfloat16 g_Bw_hi[(size_t)Hh * Hh];
__device__ __nv_bfloat16 g_Bw_lo[(size_t)Hh * Hh];
__device__ __nv_bfloat16 g_Bo_hi[(size_t)Vv * Hh];
__device__ __nv_bfloat16 g_Bo_lo[(size_t)Vv * Hh];
__device__ __nv_bfloat16 g_Bzh_hi[(size_t)2 * Hh * Hh];
__device__ __nv_bfloat16 g_Bzh_lo[(size_t)2 * Hh * Hh];
__device__ __nv_bfloat16 g_BUr_hi[(size_t)Hh * Hh];
__device__ __nv_bfloat16 g_BUr_lo[(size_t)Hh * Hh];
__device__ __nv_bfloat16 g_Bz0_hi[(size_t)Hh * Hh];
__device__ __nv_bfloat16 g_Bz0_lo[(size_t)Hh * Hh];
__device__ __nv_bfloat16 g_Br0_hi[(size_t)Hh * Hh];
__device__ __nv_bfloat16 g_Br0_lo[(size_t)Hh * Hh];
__device__ __nv_bfloat16 g_Bh0_hi[(size_t)Hh * Hh];
__device__ __nv_bfloat16 g_Bh0_lo[(size_t)Hh * Hh];
__device__ __nv_bfloat16 g_BU0_hi[(size_t)Hh * Hh];
__device__ __nv_bfloat16 g_BU0_lo[(size_t)Hh * Hh];

// ---------------- helpers ----------------
__device__ __forceinline__ uint32_t smem_u32(const void* p) {
    uint32_t a;
    asm("{ .reg .u64 t; cvta.to.shared.u64 t, %1; cvt.u32.u64 %0, t; }"
        : "=r"(a) : "l"(p));
    return a;
}
__device__ __forceinline__ uint32_t lds32(uint32_t addr) {
    uint32_t v;
    asm volatile("ld.shared.b32 %0, [%1];" : "=r"(v) : "r"(addr));
    return v;
}
__device__ __forceinline__ void mma16816(float* d, const uint32_t* a,
                                         uint32_t b0, uint32_t b1) {
    asm volatile(
        "mma.sync.aligned.m16n8k16.row.col.f32.bf16.bf16.f32 "
        "{%0,%1,%2,%3}, {%4,%5,%6,%7}, {%8,%9}, {%0,%1,%2,%3};"
        : "+f"(d[0]), "+f"(d[1]), "+f"(d[2]), "+f"(d[3])
        : "r"(a[0]), "r"(a[1]), "r"(a[2]), "r"(a[3]), "r"(b0), "r"(b1));
}
__device__ __forceinline__ void splitbf(float v, __nv_bfloat16& h, __nv_bfloat16& l) {
    h = __float2bfloat16(v);
    l = __float2bfloat16(v - __bfloat162float(h));
}
__device__ __forceinline__ float fast_sigmoid(float x) {
    return __fdividef(1.f, 1.f + __expf(-x));
}
__device__ __forceinline__ uint2 pack_hi4(float a, float b, float c, float d,
                                          uint2& lo_out) {
    __nv_bfloat16 h, l;
    __nv_bfloat162 h0, h1, l0, l1;
    splitbf(a, h, l); h0.x = h; l0.x = l;
    splitbf(b, h, l); h0.y = h; l0.y = l;
    splitbf(c, h, l); h1.x = h; l1.x = l;
    splitbf(d, h, l); h1.y = h; l1.y = l;
    lo_out.x = *(uint32_t*)&l0; lo_out.y = *(uint32_t*)&l1;
    uint2 r; r.x = *(uint32_t*)&h0; r.y = *(uint32_t*)&h1;
    return r;
}

// ---------------- light monotonic grid barrier ----------------
__device__ __forceinline__ void grid_bar(int nb, int& phase)
{
    __syncthreads();
    if (threadIdx.x == 0) {
        __threadfence();                 // release our writes
        atomicAdd(&g_barc, 1);
        phase += nb;
        while (*(volatile int*)&g_barc < phase) { __nanosleep(16); }
        __threadfence();                 // acquire others' writes
    }
    __syncthreads();
}

// ---------------- generic 64x64 SGEMM (small precomputes) ----------------
#define BM 64
#define BN 64
#define BK 16

__global__ __launch_bounds__(256)
void sgemm_kernel(int M, int N, int K,
                  const float* __restrict__ A, const float* __restrict__ Bm,
                  const float* __restrict__ bias, float* __restrict__ C)
{
    __shared__ float As[BK][BM];
    __shared__ float Bs[BK][BN];
    const int tid = threadIdx.x;
    const int tx = tid & 15;
    const int ty = tid >> 4;
    const int m0 = blockIdx.y * BM;
    const int n0 = blockIdx.x * BN;

    const int a_row  = tid >> 2;
    const int a_col4 = (tid & 3) << 2;
    const int b_row  = tid >> 4;
    const int b_col4 = (tid & 15) << 2;

    const float* Aptr = A + (size_t)(m0 + a_row) * K + a_col4;
    const float* Bptr = Bm + (size_t)b_row * N + n0 + b_col4;

    float acc[4][4];
    #pragma unroll
    for (int i = 0; i < 4; i++)
        #pragma unroll
        for (int j = 0; j < 4; j++) acc[i][j] = 0.f;

    for (int k0 = 0; k0 < K; k0 += BK) {
        float4 av = *(const float4*)(Aptr + k0);
        float4 bv = *(const float4*)(Bptr + (size_t)k0 * N);
        As[a_col4 + 0][a_row] = av.x;
        As[a_col4 + 1][a_row] = av.y;
        As[a_col4 + 2][a_row] = av.z;
        As[a_col4 + 3][a_row] = av.w;
        *(float4*)&Bs[b_row][b_col4] = bv;
        __syncthreads();
        #pragma unroll
        for (int k = 0; k < BK; k++) {
            float4 a4 = *(const float4*)&As[k][ty << 2];
            float4 b4 = *(const float4*)&Bs[k][tx << 2];
            float a[4] = {a4.x, a4.y, a4.z, a4.w};
            float b[4] = {b4.x, b4.y, b4.z, b4.w};
            #pragma unroll
            for (int i = 0; i < 4; i++)
                #pragma unroll
                for (int j = 0; j < 4; j++) acc[i][j] = fmaf(a[i], b[j], acc[i][j]);
        }
        __syncthreads();
    }

    #pragma unroll
    for (int i = 0; i < 4; i++) {
        int row = m0 + (ty << 2) + i;
        int col = n0 + (tx << 2);
        float4 out;
        float b0 = bias ? bias[col + 0] : 0.f;
        float b1 = bias ? bias[col + 1] : 0.f;
        float b2 = bias ? bias[col + 2] : 0.f;
        float b3 = bias ? bias[col + 3] : 0.f;
        out.x = acc[i][0] + b0; out.y = acc[i][1] + b1;
        out.z = acc[i][2] + b2; out.w = acc[i][3] + b3;
        *(float4*)&C[(size_t)row * N + col] = out;
    }
}

// ---------------- batched weight transpose + bf16 split ----------------
struct ConvJob {
    const float* src;
    __nv_bfloat16* hi;
    __nv_bfloat16* lo;
    int nx;
};
struct ConvJobs { ConvJob j[10]; };

__global__ __launch_bounds__(256)
void convT_all(ConvJobs jobs)
{
    ConvJob jb = jobs.j[blockIdx.z];
    if ((int)blockIdx.x >= jb.nx) return;
    const int N = jb.nx * 32;
    const int K = Hh;
    __shared__ float t[32][33];
    int k0 = blockIdx.y * 32, n0 = blockIdx.x * 32;
    int tx = threadIdx.x & 31, ty = threadIdx.x >> 5;
    for (int r = ty; r < 32; r += 8)
        t[r][tx] = jb.src[(size_t)(k0 + r) * N + n0 + tx];
    __syncthreads();
    for (int r = ty; r < 32; r += 8) {
        float v = t[tx][r];
        __nv_bfloat16 h, l;
        splitbf(v, h, l);
        jb.hi[(size_t)(n0 + r) * K + k0 + tx] = h;
        jb.lo[(size_t)(n0 + r) * K + k0 + tx] = l;
    }
}

// ---------------- persistent fused GRU scan (double-buffered MMA) ----------------
#define SLDA 144
#define SA0 0
#define SA1 9216
#define SA2 18432
#define SA3 27648
#define SB0 36864
#define SB1 41472
#define SB2 46080
#define SB3 50688
#define HBUF 55296
#define SCAN_SMEM (2 * HBUF)

__global__ __launch_bounds__(256)
void scan_kernel(const int* __restrict__ wid, const int* __restrict__ hni)
{
    extern __shared__ char sms[];
    const uint32_t u0 = smem_u32(sms);
    __shared__ int s_ids4[4 * MAXNB];
    __shared__ int s_w4[4];

    const int tid = threadIdx.x;
    const int nb = (int)gridDim.x;
    const int wid_ = tid >> 5;
    const int lane = tid & 31;
    const int wm = wid_ & 3;
    const int wg = wid_ >> 2;
    const int qrow = lane >> 2;
    const int qk = (lane & 3) << 1;
    int barph = 0;

    for (int t = 0; t < Tt; t++) {
        // ---- P1: vectorized gather sum_h / sum_g (strided b's for balance) ----
        {
            const int blk = (int)blockIdx.x;
            if (tid < 32)
                s_ids4[tid] = hni[((size_t)(t * Bq + blk + (tid >> 3) * NBLK)) * MAXNB + (tid & 7)];
            else if (tid < 36)
                s_w4[tid - 32] = wid[t * Bq + blk + (tid - 32) * NBLK];
            __syncthreads();
            #pragma unroll
            for (int it = 0; it < 2; it++) {
                int item = it * 256 + tid;       // 0..511
                int bl = item >> 7;              // warp-uniform (128 items per b)
                int h4 = (item & 127) << 2;
                int b = blk + bl * NBLK;
                int w = s_w4[bl];
                float4 xr = *(const float4*)&g_Pr[(size_t)w * Hh + h4];
                float4 sh = {0.f, 0.f, 0.f, 0.f};
                float4 sg = {0.f, 0.f, 0.f, 0.f};
                #pragma unroll
                for (int n = 0; n < MAXNB; n++) {
                    int id = s_ids4[bl * 8 + n];
                    if (id == PADROW) continue;  // warp-uniform
                    float4 hv = *(const float4*)&g_hbuf[(size_t)id * Hh + h4];
                    float4 gv = *(const float4*)&g_hbufUr[(size_t)id * Hh + h4];
                    sh.x += hv.x; sh.y += hv.y; sh.z += hv.z; sh.w += hv.w;
                    sg.x += fast_sigmoid(xr.x + gv.x) * hv.x;
                    sg.y += fast_sigmoid(xr.y + gv.y) * hv.y;
                    sg.z += fast_sigmoid(xr.z + gv.z) * hv.z;
                    sg.w += fast_sigmoid(xr.w + gv.w) * hv.w;
                }
                *(float4*)&g_sumh[(size_t)b * Hh + h4] = sh;
                uint2 lo, hi;
                hi = pack_hi4(sh.x, sh.y, sh.z, sh.w, lo);
                *(uint2*)&g_shg_hi[(size_t)b * Hh + h4] = hi;
                *(uint2*)&g_shg_lo[(size_t)b * Hh + h4] = lo;
                hi = pack_hi4(sg.x, sg.y, sg.z, sg.w, lo);
                *(uint2*)&g_shg_hi[(size_t)(Bq + b) * Hh + h4] = hi;
                *(uint2*)&g_shg_lo[(size_t)(Bq + b) * Hh + h4] = lo;
            }
        }
        grid_bar(nb, barph);

        // ---- P2': dual 64x32 MMA (z & h_tilde), double-buffered ----
        {
            const int blk = (int)blockIdx.x;
            const int m0 = (blk >> 4) * 64;
            const int n0 = (blk & 15) * 32;

            float acc[4][4];
            #pragma unroll
            for (int nf = 0; nf < 4; nf++)
                #pragma unroll
                for (int r = 0; r < 4; r++) acc[nf][r] = 0.f;

            const int lr = tid >> 2, lq = tid & 3;
            const int rb = tid >> 3, qb = tid & 7;
            const char* gShH = (const char*)(g_shg_hi + (size_t)(m0 + lr) * Hh) + lq * 32;
            const char* gShL = (const char*)(g_shg_lo + (size_t)(m0 + lr) * Hh) + lq * 32;
            const char* gSgH = (const char*)(g_shg_hi + (size_t)(Bq + m0 + lr) * Hh) + lq * 32;
            const char* gSgL = (const char*)(g_shg_lo + (size_t)(Bq + m0 + lr) * Hh) + lq * 32;
            const char* gBzH = (const char*)(g_Bzh_hi + (size_t)(n0 + rb) * Hh) + qb * 16;
            const char* gBzL = (const char*)(g_Bzh_lo + (size_t)(n0 + rb) * Hh) + qb * 16;
            const char* gBtH = (const char*)(g_Bzh_hi + (size_t)(Hh + n0 + rb) * Hh) + qb * 16;
            const char* gBtL = (const char*)(g_Bzh_lo + (size_t)(Hh + n0 + rb) * Hh) + qb * 16;

            const uint32_t oAh = (wg ? SA2 : SA0);
            const uint32_t oAl = (wg ? SA3 : SA1);
            const uint32_t oBh = (wg ? SB2 : SB0);
            const uint32_t oBl = (wg ? SB3 : SB1);

            // epilogue metadata + P-row prefetch (hidden under mainloop)
            const float* P = wg ? g_Ph : g_Pz;
            const int rl0 = wm * 16 + qrow;
            const int row0 = m0 + rl0, row1 = row0 + 8;
            const int w0 = wid[t * Bq + row0], w1 = wid[t * Bq + row1];
            float2 pv0[4], pv1[4];
            #pragma unroll
            for (int nf = 0; nf < 4; nf++) {
                int col = n0 + nf * 8 + qk;
                pv0[nf] = *(const float2*)&P[(size_t)w0 * Hh + col];
                pv1[nf] = *(const float2*)&P[(size_t)w1 * Hh + col];
            }

            // preload + store chunk 0 into buf0
            {
                uint4 a0 = *(const uint4*)(gShH), a0b = *(const uint4*)(gShH + 16);
                uint4 a1 = *(const uint4*)(gShL), a1b = *(const uint4*)(gShL + 16);
                uint4 a2 = *(const uint4*)(gSgH), a2b = *(const uint4*)(gSgH + 16);
                uint4 a3 = *(const uint4*)(gSgL), a3b = *(const uint4*)(gSgL + 16);
                uint4 b0v = *(const uint4*)(gBzH), b1v = *(const uint4*)(gBzL);
                uint4 b2v = *(const uint4*)(gBtH), b3v = *(const uint4*)(gBtL);
                char* d;
                d = sms + SA0 + lr * SLDA + lq * 32; *(uint4*)d = a0; *(uint4*)(d + 16) = a0b;
                d = sms + SA1 + lr * SLDA + lq * 32; *(uint4*)d = a1; *(uint4*)(d + 16) = a1b;
                d = sms + SA2 + lr * SLDA + lq * 32; *(uint4*)d = a2; *(uint4*)(d + 16) = a2b;
                d = sms + SA3 + lr * SLDA + lq * 32; *(uint4*)d = a3; *(uint4*)(d + 16) = a3b;
                *(uint4*)(sms + SB0 + rb * SLDA + qb * 16) = b0v;
                *(uint4*)(sms + SB1 + rb * SLDA + qb * 16) = b1v;
                *(uint4*)(sms + SB2 + rb * SLDA + qb * 16) = b2v;
                *(uint4*)(sms + SB3 + rb * SLDA + qb * 16) = b3v;
            }
            __syncthreads();

            #pragma unroll 1
            for (int c = 0; c < 8; c++) {
                const uint32_t ub = u0 + (c & 1) * HBUF;
                char* nxt = sms + ((c + 1) & 1) * HBUF;
                uint4 a0, a0b, a1, a1b, a2, a2b, a3, a3b, b0v, b1v, b2v, b3v;
                if (c < 7) {
                    int o = (c + 1) * 128;
                    a0 = *(const uint4*)(gShH + o); a0b = *(const uint4*)(gShH + o + 16);
                    a1 = *(const uint4*)(gShL + o); a1b = *(const uint4*)(gShL + o + 16);
                    a2 = *(const uint4*)(gSgH + o); a2b = *(const uint4*)(gSgH + o + 16);
                    a3 = *(const uint4*)(gSgL + o); a3b = *(const uint4*)(gSgL + o + 16);
                    b0v = *(const uint4*)(gBzH + o); b1v = *(const uint4*)(gBzL + o);
                    b2v = *(const uint4*)(gBtH + o); b3v = *(const uint4*)(gBtL + o);
                }
                #pragma unroll
                for (int kk = 0; kk < 4; kk++) {
                    const uint32_t koff = (kk * 16 + qk) * 2;
                    uint32_t base = (wm * 16 + qrow) * SLDA + koff;
                    uint32_t ah[4], al[4];
                    ah[0] = lds32(ub + oAh + base);
                    ah[1] = lds32(ub + oAh + base + 8 * SLDA);
                    ah[2] = lds32(ub + oAh + base + 16);
                    ah[3] = lds32(ub + oAh + base + 8 * SLDA + 16);
                    al[0] = lds32(ub + oAl + base);
                    al[1] = lds32(ub + oAl + base + 8 * SLDA);
                    al[2] = lds32(ub + oAl + base + 16);
                    al[3] = lds32(ub + oAl + base + 8 * SLDA + 16);
                    #pragma unroll
                    for (int nf = 0; nf < 4; nf++) {
                        uint32_t bb = (nf * 8 + qrow) * SLDA + koff;
                        uint32_t bh0 = lds32(ub + oBh + bb);
                        uint32_t bh1 = lds32(ub + oBh + bb + 16);
                        uint32_t cl0 = lds32(ub + oBl + bb);
                        uint32_t cl1 = lds32(ub + oBl + bb + 16);
                        mma16816(acc[nf], ah, bh0, bh1);
                        mma16816(acc[nf], ah, cl0, cl1);
                        mma16816(acc[nf], al, bh0, bh1);
                    }
                }
                if (c < 7) {
                    char* d;
                    d = nxt + SA0 + lr * SLDA + lq * 32; *(uint4*)d = a0; *(uint4*)(d + 16) = a0b;
                    d = nxt + SA1 + lr * SLDA + lq * 32; *(uint4*)d = a1; *(uint4*)(d + 16) = a1b;
                    d = nxt + SA2 + lr * SLDA + lq * 32; *(uint4*)d = a2; *(uint4*)(d + 16) = a2b;
                    d = nxt + SA3 + lr * SLDA + lq * 32; *(uint4*)d = a3; *(uint4*)(d + 16) = a3b;
                    *(uint4*)(nxt + SB0 + rb * SLDA + qb * 16) = b0v;
                    *(uint4*)(nxt + SB1 + rb * SLDA + qb * 16) = b1v;
                    *(uint4*)(nxt + SB2 + rb * SLDA + qb * 16) = b2v;
                    *(uint4*)(nxt + SB3 + rb * SLDA + qb * 16) = b3v;
                }
                __syncthreads();
            }

            // epilogue: activation into exchange buffers (P prefetched)
            float* xbuf = (float*)(sms + (wg ? 8192 : 0));
            #pragma unroll
            for (int nf = 0; nf < 4; nf++) {
                int cl = nf * 8 + qk;
                float v00 = acc[nf][0] + pv0[nf].x;
                float v01 = acc[nf][1] + pv0[nf].y;
                float v10 = acc[nf][2] + pv1[nf].x;
                float v11 = acc[nf][3] + pv1[nf].y;
                if (wg) {
                    v00 = tanhf(v00); v01 = tanhf(v01);
                    v10 = tanhf(v10); v11 = tanhf(v11);
                } else {
                    v00 = fast_sigmoid(v00); v01 = fast_sigmoid(v01);
                    v10 = fast_sigmoid(v10); v11 = fast_sigmoid(v11);
                }
                xbuf[rl0 * 32 + cl] = v00;
                xbuf[rl0 * 32 + cl + 1] = v01;
                xbuf[(rl0 + 8) * 32 + cl] = v10;
                xbuf[(rl0 + 8) * 32 + cl + 1] = v11;
            }
            __syncthreads();
            const float* zbuf = (const float*)(sms);
            const float* tbuf = (const float*)(sms + 8192);
            const size_t toff = (size_t)t * Bq * Hh;
            #pragma unroll
            for (int e = tid; e < 64 * 32; e += 256) {
                int rl = e >> 5, cl = e & 31;
                size_t gi = (size_t)(m0 + rl) * Hh + (n0 + cl);
                float z = zbuf[e], th = tbuf[e];
                float h = (1.f - z) * g_sumh[gi] + z * th;
                g_hbuf[toff + gi] = h;
                __nv_bfloat16 hi, lo;
                splitbf(h, hi, lo);
                g_hbuf_hi[toff + gi] = hi;
                g_hbuf_lo[toff + gi] = lo;
            }
        }
        grid_bar(nb, barph);

        // ---- P4: hbufUr[t] = h_new @ Ur (64x32 tile, double-buffered) ----
        {
            const int blk = (int)blockIdx.x;
            const int m0 = (blk >> 4) * 64;
            const int n0 = (blk & 15) * 32;
            const size_t toff = (size_t)t * Bq * Hh;

            float acc[2][4];
            #pragma unroll
            for (int nf = 0; nf < 2; nf++)
                #pragma unroll
                for (int r = 0; r < 4; r++) acc[nf][r] = 0.f;

            const int lr = tid >> 2, lq = tid & 3;
            const int br = tid >> 3, bq = tid & 7;
            const char* gAh = (const char*)(g_hbuf_hi + toff + (size_t)(m0 + lr) * Hh) + lq * 32;
            const char* gAl = (const char*)(g_hbuf_lo + toff + (size_t)(m0 + lr) * Hh) + lq * 32;
            const char* gBh = (const char*)(g_BUr_hi + (size_t)(n0 + br) * Hh) + bq * 16;
            const char* gBl = (const char*)(g_BUr_lo + (size_t)(n0 + br) * Hh) + bq * 16;
            const int wn = wg;

            {
                uint4 ah0 = *(const uint4*)(gAh), ah1 = *(const uint4*)(gAh + 16);
                uint4 al0 = *(const uint4*)(gAl), al1 = *(const uint4*)(gAl + 16);
                uint4 bh0 = *(const uint4*)(gBh), bl0 = *(const uint4*)(gBl);
                char* d = sms + SA0 + lr * SLDA + lq * 32;
                *(uint4*)d = ah0; *(uint4*)(d + 16) = ah1;
                d = sms + SA1 + lr * SLDA + lq * 32;
                *(uint4*)d = al0; *(uint4*)(d + 16) = al1;
                *(uint4*)(sms + SB0 + br * SLDA + bq * 16) = bh0;
                *(uint4*)(sms + SB1 + br * SLDA + bq * 16) = bl0;
            }
            __syncthreads();

            #pragma unroll 1
            for (int c = 0; c < 8; c++) {
                const uint32_t ub = u0 + (c & 1) * HBUF;
                char* nxt = sms + ((c + 1) & 1) * HBUF;
                uint4 nah0, nah1, nal0, nal1, nbh0, nbl0;
                if (c < 7) {
                    int o = (c + 1) * 128;
                    nah0 = *(const uint4*)(gAh + o); nah1 = *(const uint4*)(gAh + o + 16);
                    nal0 = *(const uint4*)(gAl + o); nal1 = *(const uint4*)(gAl + o + 16);
                    nbh0 = *(const uint4*)(gBh + o); nbl0 = *(const uint4*)(gBl + o);
                }
                #pragma unroll
                for (int kk = 0; kk < 4; kk++) {
                    const uint32_t koff = (kk * 16 + qk) * 2;
                    uint32_t base = (wm * 16 + qrow) * SLDA + koff;
                    uint32_t ah[4], al[4];
                    ah[0] = lds32(ub + SA0 + base);
                    ah[1] = lds32(ub + SA0 + base + 8 * SLDA);
                    ah[2] = lds32(ub + SA0 + base + 16);
                    ah[3] = lds32(ub + SA0 + base + 8 * SLDA + 16);
                    al[0] = lds32(ub + SA1 + base);
                    al[1] = lds32(ub + SA1 + base + 8 * SLDA);
                    al[2] = lds32(ub + SA1 + base + 16);
                    al[3] = lds32(ub + SA1 + base + 8 * SLDA + 16);
                    #pragma unroll
                    for (int nf = 0; nf < 2; nf++) {
                        uint32_t bb = (wn * 16 + nf * 8 + qrow) * SLDA + koff;
                        uint32_t b0 = lds32(ub + SB0 + bb);
                        uint32_t b1 = lds32(ub + SB0 + bb + 16);
                        uint32_t c0 = lds32(ub + SB1 + bb);
                        uint32_t c1 = lds32(ub + SB1 + bb + 16);
                        mma16816(acc[nf], ah, b0, b1);
                        mma16816(acc[nf], ah, c0, c1);
                        mma16816(acc[nf], al, b0, b1);
                    }
                }
                if (c < 7) {
                    char* d = nxt + SA0 + lr * SLDA + lq * 32;
                    *(uint4*)d = nah0; *(uint4*)(d + 16) = nah1;
                    d = nxt + SA1 + lr * SLDA + lq * 32;
                    *(uint4*)d = nal0; *(uint4*)(d + 16) = nal1;
                    *(uint4*)(nxt + SB0 + br * SLDA + bq * 16) = nbh0;
                    *(uint4*)(nxt + SB1 + br * SLDA + bq * 16) = nbl0;
                }
                __syncthreads();
            }
            float* Cc = g_hbufUr + toff;
            int r0 = m0 + wm * 16 + qrow;
            #pragma unroll
            for (int nf = 0; nf < 2; nf++) {
                int col = n0 + wn * 16 + nf * 8 + qk;
                float2 o0 = {acc[nf][0], acc[nf][1]};
                float2 o1 = {acc[nf][2], acc[nf][3]};
                *(float2*)&Cc[(size_t)r0 * Hh + col] = o0;
                *(float2*)&Cc[(size_t)(r0 + 8) * Hh + col] = o1;
            }
        }
        grid_bar(nb, barph);
    }
}

// ---------------- tc mainloops ----------------
#define LDA_B 144
#define OFF_ALO 18432
#define OFF_BHI 36864
#define OFF_BLO 55296
#define TCSM_BYTES 73728

// fp32-A mainloop (emb precompute only)
__device__ __forceinline__ void tc_main(
    const float* Abase, const char* BhiBase, const char* BloBase,
    char* smc, uint32_t sbase, int tid, int wm, int wn, int qrow, int qk,
    float acc[2][8][4])
{
    const int ar = tid >> 1;
    const int ac = (tid & 1) * 32;
    const int bo = (tid & 1) * 64;

    float4 av[8];
    uint4 bh[4], bl[4];
    #pragma unroll
    for (int f = 0; f < 8; f++) av[f] = *(const float4*)(Abase + f * 4);
    #pragma unroll
    for (int u = 0; u < 4; u++) {
        bh[u] = *(const uint4*)(BhiBase + u * 16);
        bl[u] = *(const uint4*)(BloBase + u * 16);
    }

    #pragma unroll 1
    for (int c = 0; c < 8; c++) {
        __syncthreads();
        {
            char* sa = smc + ar * LDA_B + ac * 2;
            char* sl = sa + OFF_ALO;
            #pragma unroll
            for (int f = 0; f < 8; f++) {
                __nv_bfloat16 h0, h1, h2, h3, l0, l1, l2, l3;
                splitbf(av[f].x, h0, l0);
                splitbf(av[f].y, h1, l1);
                splitbf(av[f].z, h2, l2);
                splitbf(av[f].w, h3, l3);
                __nv_bfloat162 hh0, hh1, ll0, ll1;
                hh0.x = h0; hh0.y = h1; hh1.x = h2; hh1.y = h3;
                ll0.x = l0; ll0.y = l1; ll1.x = l2; ll1.y = l3;
                uint2 hv = {*(uint32_t*)&hh0, *(uint32_t*)&hh1};
                uint2 lv = {*(uint32_t*)&ll0, *(uint32_t*)&ll1};
                *(uint2*)(sa + f * 8) = hv;
                *(uint2*)(sl + f * 8) = lv;
            }
            char* sb = smc + OFF_BHI + ar * LDA_B + bo;
            char* sbl = smc + OFF_BLO + ar * LDA_B + bo;
            #pragma unroll
            for (int u = 0; u < 4; u++) {
                *(uint4*)(sb + u * 16) = bh[u];
                *(uint4*)(sbl + u * 16) = bl[u];
            }
        }
        __syncthreads();

        float4 nav[8];
        uint4 nbh[4], nbl[4];
        if (c < 7) {
            #pragma unroll
            for (int f = 0; f < 8; f++)
                nav[f] = *(const float4*)(Abase + (c + 1) * 64 + f * 4);
            #pragma unroll
            for (int u = 0; u < 4; u++) {
                nbh[u] = *(const uint4*)(BhiBase + (c + 1) * 128 + u * 16);
                nbl[u] = *(const uint4*)(BloBase + (c + 1) * 128 + u * 16);
            }
        }

        #pragma unroll
        for (int kk = 0; kk < 4; kk++) {
            const uint32_t koff = (kk * 16 + qk) * 2;
            uint32_t ah[2][4], al[2][4];
            #pragma unroll
            for (int mf = 0; mf < 2; mf++) {
                uint32_t base = sbase + (wm * 32 + mf * 16 + qrow) * LDA_B + koff;
                ah[mf][0] = lds32(base);
                ah[mf][1] = lds32(base + 8 * LDA_B);
                ah[mf][2] = lds32(base + 16);
                ah[mf][3] = lds32(base + 8 * LDA_B + 16);
                al[mf][0] = lds32(base + OFF_ALO);
                al[mf][1] = lds32(base + OFF_ALO + 8 * LDA_B);
                al[mf][2] = lds32(base + OFF_ALO + 16);
                al[mf][3] = lds32(base + OFF_ALO + 8 * LDA_B + 16);
            }
            #pragma unroll
            for (int nf = 0; nf < 8; nf++) {
                uint32_t bb = sbase + OFF_BHI + (wn * 64 + nf * 8 + qrow) * LDA_B + koff;
                uint32_t bh0 = lds32(bb);
                uint32_t bh1 = lds32(bb + 16);
                uint32_t bl0 = lds32(bb + (OFF_BLO - OFF_BHI));
                uint32_t bl1 = lds32(bb + (OFF_BLO - OFF_BHI) + 16);
                #pragma unroll
                for (int mf = 0; mf < 2; mf++) {
                    mma16816(acc[mf][nf], ah[mf], bh0, bh1);
                    mma16816(acc[mf][nf], ah[mf], bl0, bl1);
                    mma16816(acc[mf][nf], al[mf], bh0, bh1);
                }
            }
        }
        if (c < 7) {
            #pragma unroll
            for (int f = 0; f < 8; f++) av[f] = nav[f];
            #pragma unroll
            for (int u = 0; u < 4; u++) { bh[u] = nbh[u]; bl[u] = nbl[u]; }
        }
    }
}

// split-A mainloop (A already bf16 hi/lo): pure copies + MMA
__device__ __forceinline__ void tc_main_sa(
    const char* AhiBase, const char* AloBase,
    const char* BhiBase, const char* BloBase,
    char* smc, uint32_t sbase, int tid, int wm, int wn, int qrow, int qk,
    float acc[2][8][4])
{
    const int ar = tid >> 1;
    const int bo = (tid & 1) * 64;

    uint4 xa[4], xl[4], xb[4], xc[4];
    #pragma unroll
    for (int u = 0; u < 4; u++) {
        xa[u] = *(const uint4*)(AhiBase + u * 16);
        xl[u] = *(const uint4*)(AloBase + u * 16);
        xb[u] = *(const uint4*)(BhiBase + u * 16);
        xc[u] = *(const uint4*)(BloBase + u * 16);
    }

    #pragma unroll 1
    for (int c = 0; c < 8; c++) {
        __syncthreads();
        {
            char* d = smc + ar * LDA_B + bo;
            #pragma unroll
            for (int u = 0; u < 4; u++) {
                *(uint4*)(d + u * 16) = xa[u];
                *(uint4*)(d + OFF_ALO + u * 16) = xl[u];
                *(uint4*)(d + OFF_BHI + u * 16) = xb[u];
                *(uint4*)(d + OFF_BLO + u * 16) = xc[u];
            }
        }
        __syncthreads();

        uint4 na[4], nl[4], nb[4], nc[4];
        if (c < 7) {
            int o = (c + 1) * 128;
            #pragma unroll
            for (int u = 0; u < 4; u++) {
                na[u] = *(const uint4*)(AhiBase + o + u * 16);
                nl[u] = *(const uint4*)(AloBase + o + u * 16);
                nb[u] = *(const uint4*)(BhiBase + o + u * 16);
                nc[u] = *(const uint4*)(BloBase + o + u * 16);
            }
        }

        #pragma unroll
        for (int kk = 0; kk < 4; kk++) {
            const uint32_t koff = (kk * 16 + qk) * 2;
            uint32_t ah[2][4], al[2][4];
            #pragma unroll
            for (int mf = 0; mf < 2; mf++) {
                uint32_t base = sbase + (wm * 32 + mf * 16 + qrow) * LDA_B + koff;
                ah[mf][0] = lds32(base);
                ah[mf][1] = lds32(base + 8 * LDA_B);
                ah[mf][2] = lds32(base + 16);
                ah[mf][3] = lds32(base + 8 * LDA_B + 16);
                al[mf][0] = lds32(base + OFF_ALO);
                al[mf][1] = lds32(base + OFF_ALO + 8 * LDA_B);
                al[mf][2] = lds32(base + OFF_ALO + 16);
                al[mf][3] = lds32(base + OFF_ALO + 8 * LDA_B + 16);
            }
            #pragma unroll
            for (int nf = 0; nf < 8; nf++) {
                uint32_t bb = sbase + OFF_BHI + (wn * 64 + nf * 8 + qrow) * LDA_B + koff;
                uint32_t bh0 = lds32(bb);
                uint32_t bh1 = lds32(bb + 16);
                uint32_t bl0 = lds32(bb + (OFF_BLO - OFF_BHI));
                uint32_t bl1 = lds32(bb + (OFF_BLO - OFF_BHI) + 16);
                #pragma unroll
                for (int mf = 0; mf < 2; mf++) {
                    mma16816(acc[mf][nf], ah[mf], bh0, bh1);
                    mma16816(acc[mf][nf], ah[mf], bl0, bl1);
                    mma16816(acc[mf][nf], al[mf], bh0, bh1);
                }
            }
        }
        if (c < 7) {
            #pragma unroll
            for (int u = 0; u < 4; u++) {
                xa[u] = na[u]; xl[u] = nl[u]; xb[u] = nb[u]; xc[u] = nc[u];
            }
        }
    }
}

// split-A GEMM kernel. modes: 0 logits, 1 stop, 2 pred-phid
__global__ __launch_bounds__(256)
void tc_gemm_sa(const __nv_bfloat16* __restrict__ Ahi,
                const __nv_bfloat16* __restrict__ Alo,
                const __nv_bfloat16* __restrict__ Bhi,
                const __nv_bfloat16* __restrict__ Blo,
                const float* __restrict__ bias, float* __restrict__ C, int ldc,
                int mode, const int* __restrict__ widp,
                const int* __restrict__ rootp, const float* __restrict__ Us)
{
    extern __shared__ char smc[];
    const uint32_t sbase = smem_u32(smc);
    __shared__ int s_rows[128];

    const int tid = threadIdx.x;
    const int wid_ = tid >> 5;
    const int lane = tid & 31;
    const int wm = wid_ & 3;
    const int wn = wid_ >> 2;
    const int qrow = lane >> 2;
    const int qk = (lane & 3) << 1;
    const int m0 = blockIdx.y * 128;
    const int n0 = blockIdx.x * 128;

    if (tid < 128) s_rows[tid] = (mode == 2) ? g_cmap[m0 + tid] : (m0 + tid);
    __syncthreads();

    const int ar = tid >> 1;
    const int bo = (tid & 1) * 64;
    const char* AhiBase = (const char*)(Ahi + (size_t)s_rows[ar] * Hh) + bo;
    const char* AloBase = (const char*)(Alo + (size_t)s_rows[ar] * Hh) + bo;
    const char* BhiBase = (const char*)(Bhi + (size_t)(n0 + ar) * Hh) + bo;
    const char* BloBase = (const char*)(Blo + (size_t)(n0 + ar) * Hh) + bo;

    float acc[2][8][4];
    #pragma unroll
    for (int mf = 0; mf < 2; mf++)
        #pragma unroll
        for (int nf = 0; nf < 8; nf++)
            #pragma unroll
            for (int r = 0; r < 4; r++) acc[mf][nf][r] = 0.f;

    tc_main_sa(AhiBase, AloBase, BhiBase, BloBase, smc, sbase, tid, wm, wn, qrow, qk, acc);

    if (mode == 0) {
        #pragma unroll
        for (int mf = 0; mf < 2; mf++) {
            int r0 = m0 + wm * 32 + mf * 16 + qrow;
            #pragma unroll
            for (int nf = 0; nf < 8; nf++) {
                int col = n0 + wn * 64 + nf * 8 + qk;
                float2 o0 = {acc[mf][nf][0] + bias[col], acc[mf][nf][1] + bias[col + 1]};
                float2 o1 = {acc[mf][nf][2] + bias[col], acc[mf][nf][3] + bias[col + 1]};
                *(float2*)&C[(size_t)r0 * ldc + col] = o0;
                *(float2*)&C[(size_t)(r0 + 8) * ldc + col] = o1;
            }
        }
    } else if (mode == 1) {
        int slot = blockIdx.x * 2 + wn;
        #pragma unroll
        for (int mf = 0; mf < 2; mf++) {
            int r0 = m0 + wm * 32 + mf * 16 + qrow;
            int r1 = r0 + 8;
            int w0, b0, w1, b1;
            if (r0 < TBq) { w0 = widp[r0]; b0 = r0 & (Bq - 1); }
            else          { w0 = rootp[r0 - TBq]; b0 = r0 - TBq; }
            if (r1 < TBq) { w1 = widp[r1]; b1 = r1 & (Bq - 1); }
            else          { w1 = rootp[r1 - TBq]; b1 = r1 - TBq; }
            const float* Pe0 = g_PembU + (size_t)w0 * Hh;
            const float* Pm0 = g_PmolU + (size_t)b0 * Hh;
            const float* Pe1 = g_PembU + (size_t)w1 * Hh;
            const float* Pm1 = g_PmolU + (size_t)b1 * Hh;
            float p0 = 0.f, p1 = 0.f;
            #pragma unroll
            for (int nf = 0; nf < 8; nf++) {
                int col = wn * 64 + nf * 8 + qk;
                int gc = blockIdx.x * 128 + col;
                float u0 = Us[gc], u1 = Us[gc + 1];
                p0 += fmaxf(acc[mf][nf][0] + Pe0[gc] + Pm0[gc], 0.f) * u0;
                p0 += fmaxf(acc[mf][nf][1] + Pe0[gc + 1] + Pm0[gc + 1], 0.f) * u1;
                p1 += fmaxf(acc[mf][nf][2] + Pe1[gc] + Pm1[gc], 0.f) * u0;
                p1 += fmaxf(acc[mf][nf][3] + Pe1[gc + 1] + Pm1[gc + 1], 0.f) * u1;
            }
            p0 += __shfl_xor_sync(0xffffffffu, p0, 1);
            p0 += __shfl_xor_sync(0xffffffffu, p0, 2);
            p1 += __shfl_xor_sync(0xffffffffu, p1, 1);
            p1 += __shfl_xor_sync(0xffffffffu, p1, 2);
            if ((lane & 3) == 0) {
                g_spart[(size_t)slot * MSr + r0] = p0;
                g_spart[(size_t)slot * MSr + r1] = p1;
            }
        }
    } else {
        #pragma unroll
        for (int mf = 0; mf < 2; mf++) {
            int rl0 = wm * 32 + mf * 16 + qrow;
            int j0 = m0 + rl0;
            int bc0 = s_rows[rl0] & (Bq - 1);
            int bc1 = s_rows[rl0 + 8] & (Bq - 1);
            const float* Pm0 = g_PmolW + (size_t)bc0 * Hh;
            const float* Pm1 = g_PmolW + (size_t)bc1 * Hh;
            #pragma unroll
            for (int nf = 0; nf < 8; nf++) {
                int col = n0 + wn * 64 + nf * 8 + qk;
                float v00 = fmaxf(acc[mf][nf][0] + Pm0[col], 0.f);
                float v01 = fmaxf(acc[mf][nf][1] + Pm0[col + 1], 0.f);
                float v10 = fmaxf(acc[mf][nf][2] + Pm1[col], 0.f);
                float v11 = fmaxf(acc[mf][nf][3] + Pm1[col + 1], 0.f);
                __nv_bfloat162 h2, l2;
                __nv_bfloat16 h, l;
                splitbf(v00, h, l); h2.x = h; l2.x = l;
                splitbf(v01, h, l); h2.y = h; l2.y = l;
                *(__nv_bfloat162*)&g_phid_hi[(size_t)(Bq + j0) * Hh + col] = h2;
                *(__nv_bfloat162*)&g_phid_lo[(size_t)(Bq + j0) * Hh + col] = l2;
                splitbf(v10, h, l); h2.x = h; l2.x = l;
                splitbf(v11, h, l); h2.y = h; l2.y = l;
                *(__nv_bfloat162*)&g_phid_hi[(size_t)(Bq + j0 + 8) * Hh + col] = h2;
                *(__nv_bfloat162*)&g_phid_lo[(size_t)(Bq + j0 + 8) * Hh + col] = l2;
            }
        }
    }
}

// fused emb-precompute: 4 GEMMs selected by blockIdx.z
__global__ __launch_bounds__(256)
void tc_gemm_pre4(const float* __restrict__ A,
                  const __nv_bfloat16* b0h, const __nv_bfloat16* b0l,
                  const float* bias0, float* C0,
                  const __nv_bfloat16* b1h, const __nv_bfloat16* b1l,
                  const float* bias1, float* C1,
                  const __nv_bfloat16* b2h, const __nv_bfloat16* b2l,
                  const float* bias2, float* C2,
                  const __nv_bfloat16* b3h, const __nv_bfloat16* b3l,
                  const float* bias3, float* C3)
{
    extern __shared__ char smc[];
    const uint32_t sbase = smem_u32(smc);
    const int z = blockIdx.z;
    const __nv_bfloat16* Bhi = (z == 0) ? b0h : (z == 1) ? b1h : (z == 2) ? b2h : b3h;
    const __nv_bfloat16* Blo = (z == 0) ? b0l : (z == 1) ? b1l : (z == 2) ? b2l : b3l;
    const float* bias = (z == 0) ? bias0 : (z == 1) ? bias1 : (z == 2) ? bias2 : bias3;
    float* C = (z == 0) ? C0 : (z == 1) ? C1 : (z == 2) ? C2 : C3;

    const int tid = threadIdx.x;
    const int wid_ = tid >> 5;
    const int lane = tid & 31;
    const int wm = wid_ & 3;
    const int wn = wid_ >> 2;
    const int qrow = lane >> 2;
    const int qk = (lane & 3) << 1;
    const int m0 = blockIdx.y * 128;
    const int n0 = blockIdx.x * 128;

    const int ar = tid >> 1;
    const int ac = (tid & 1) * 32;
    const int bo = (tid & 1) * 64;
    const float* Abase = A + (size_t)(m0 + ar) * Hh + ac;
    const char* BhiBase = (const char*)(Bhi + (size_t)(n0 + ar) * Hh) + bo;
    const char* BloBase = (const char*)(Blo + (size_t)(n0 + ar) * Hh) + bo;

    float acc[2][8][4];
    #pragma unroll
    for (int mf = 0; mf < 2; mf++)
        #pragma unroll
        for (int nf = 0; nf < 8; nf++)
            #pragma unroll
            for (int r = 0; r < 4; r++) acc[mf][nf][r] = 0.f;

    tc_main(Abase, BhiBase, BloBase, smc, sbase, tid, wm, wn, qrow, qk, acc);

    #pragma unroll
    for (int mf = 0; mf < 2; mf++) {
        int r0 = m0 + wm * 32 + mf * 16 + qrow;
        #pragma unroll
        for (int nf = 0; nf < 8; nf++) {
            int col = n0 + wn * 64 + nf * 8 + qk;
            float2 o0 = {acc[mf][nf][0] + bias[col], acc[mf][nf][1] + bias[col + 1]};
            float2 o1 = {acc[mf][nf][2] + bias[col], acc[mf][nf][3] + bias[col + 1]};
            *(float2*)&C[(size_t)r0 * Hh + col] = o0;
            *(float2*)&C[(size_t)(r0 + 8) * Hh + col] = o1;
        }
    }
}

// ---------------- housekeeping ----------------
__global__ __launch_bounds__(256)
void prep_kernel()
{
    int i = blockIdx.x * 256 + threadIdx.x;
    if (i < 5) g_acc[i] = 0.0;
    if (i == 5) { g_barc = 0; g_ccount = 0; }
    if (i < Hh) {
        g_hbuf[(size_t)PADROW * Hh + i] = 0.f;
        g_hbufUr[(size_t)PADROW * Hh + i] = 0.f;
        g_hbuf_hi[(size_t)PADROW * Hh + i] = __float2bfloat16(0.f);
        g_hbuf_lo[(size_t)PADROW * Hh + i] = __float2bfloat16(0.f);
    }
    if (i < NCMP + 256) g_cmap[i] = 0;
}

__global__ __launch_bounds__(256)
void compact_kernel(const int* __restrict__ dirs)
{
    int i = blockIdx.x * 256 + threadIdx.x;
    if (dirs[i]) {
        int s = atomicAdd(&g_ccount, 1);
        g_cmap[s] = i;
    }
}

__global__ __launch_bounds__(256)
void build_curo(const int* __restrict__ oni, const int* __restrict__ roni)
{
    int i = blockIdx.x, tid = threadIdx.x;
    __shared__ int ids[MAXNB];
    if (tid < MAXNB)
        ids[tid] = (i < TBq) ? oni[(size_t)i * MAXNB + tid]
                             : roni[(size_t)(i - TBq) * MAXNB + tid];
    __syncthreads();
    for (int h4 = tid * 4; h4 < Hh; h4 += 1024) {
        float4 v = {0.f, 0.f, 0.f, 0.f};
        #pragma unroll
        for (int n = 0; n < MAXNB; n++) {
            int id = ids[n];
            if (id == PADROW) continue;
            float4 hv = *(const float4*)&g_hbuf[(size_t)id * Hh + h4];
            v.x += hv.x; v.y += hv.y; v.z += hv.z; v.w += hv.w;
        }
        uint2 lo, hi;
        hi = pack_hi4(v.x, v.y, v.z, v.w, lo);
        *(uint2*)&g_curo_hi[(size_t)i * Hh + h4] = hi;
        *(uint2*)&g_curo_lo[(size_t)i * Hh + h4] = lo;
    }
}

__global__ __launch_bounds__(512)
void phid0_kernel()
{
    int b = blockIdx.x, h = threadIdx.x;
    float v = fmaxf(g_PmolW[(size_t)b * Hh + h], 0.f);
    __nv_bfloat16 hh, ll;
    splitbf(v, hh, ll);
    g_phid_hi[(size_t)b * Hh + h] = hh;
    g_phid_lo[(size_t)b * Hh + h] = ll;
}

// ---------------- stop head finalize ----------------
__global__ __launch_bounds__(256)
void stop_final_kernel(const float* __restrict__ bs, const int* __restrict__ dirs)
{
    int i = blockIdx.x * 256 + threadIdx.x;
    float s = bs[0];
    #pragma unroll
    for (int k = 0; k < 8; k++) s += g_spart[(size_t)k * MSr + i];
    float tgt = (i < TBq) ? (float)dirs[i] : 0.f;
    float loss = fmaxf(s, 0.f) - s * tgt + log1pf(expf(-fabsf(s)));
    float corr = ((s >= 0.5f) == (tgt > 0.5f)) ? 1.f : 0.f;
    __shared__ double r0[256], r1[256];
    int tid = threadIdx.x;
    r0[tid] = (double)loss;
    r1[tid] = (double)corr;
    __syncthreads();
    for (int o = 128; o > 0; o >>= 1) {
        if (tid < o) { r0[tid] += r0[tid + o]; r1[tid] += r1[tid + o]; }
        __syncthreads();
    }
    if (tid == 0) {
        atomicAdd(&g_acc[0], r0[0]);
        atomicAdd(&g_acc[1], r1[0]);
    }
}

// ---------------- pred head: log-softmax CE + argmax ----------------
__global__ __launch_bounds__(256)
void pred_rows_kernel(const int* __restrict__ root_wid, const int* __restrict__ y_wid)
{
    int j = blockIdx.x, tid = threadIdx.x;
    const float* row = g_logitsc + (size_t)j * Vv;
    int tgt = (j < Bq) ? root_wid[j] : y_wid[g_cmap[j - Bq]];

    float mval = -1e30f; int midx = Vv;
    for (int k = tid; k < Vv; k += 256) {
        float v = row[k];
        if (v > mval) { mval = v; midx = k; }
    }
    __shared__ float rv[256];
    __shared__ int ri[256];
    rv[tid] = mval; ri[tid] = midx; __syncthreads();
    for (int s = 128; s > 0; s >>= 1) {
        if (tid < s) {
            if (rv[tid + s] > rv[tid] ||
                (rv[tid + s] == rv[tid] && ri[tid + s] < ri[tid])) {
                rv[tid] = rv[tid + s]; ri[tid] = ri[tid + s];
            }
        }
        __syncthreads();
    }
    float gmax = rv[0]; int gidx = ri[0];
    __syncthreads();
    float p = 0.f;
    for (int k = tid; k < Vv; k += 256) p += __expf(row[k] - gmax);
    rv[tid] = p; __syncthreads();
    for (int s = 128; s > 0; s >>= 1) {
        if (tid < s) rv[tid] += rv[tid + s];
        __syncthreads();
    }
    if (tid == 0) {
        float lse = gmax + logf(rv[0]);
        float ce = -(row[tgt] - lse);
        atomicAdd(&g_acc[2], (double)ce);
        if (gidx == tgt) atomicAdd(&g_acc[3], 1.0);
        atomicAdd(&g_acc[4], 1.0);
    }
}

__global__ void finalize_kernel(float* out)
{
    out[0] = (float)(g_acc[2] / (double)Bq);
    out[1] = (float)(g_acc[0] / (double)Bq);
    out[2] = (float)(g_acc[3] / g_acc[4]);
    out[3] = (float)(g_acc[1] / (double)MSr);
}

// ---------------- launch ----------------
extern "C" void kernel_launch(void* const* d_in, const int* in_sizes, int n_in,
                              void* d_out, int out_size)
{
    const float* mol_vec  = (const float*)d_in[0];
    const int*   wid      = (const int*)d_in[1];
    const int*   y_wid    = (const int*)d_in[2];
    const int*   dirs     = (const int*)d_in[3];
    const int*   hni      = (const int*)d_in[4];
    const int*   oni      = (const int*)d_in[5];
    const int*   root_wid = (const int*)d_in[6];
    const int*   roni     = (const int*)d_in[7];
    const float* emb      = (const float*)d_in[8];
    const float* Wz       = (const float*)d_in[9];
    const float* bz       = (const float*)d_in[10];
    const float* Wr       = (const float*)d_in[11];
    const float* br       = (const float*)d_in[12];
    const float* Ur       = (const float*)d_in[13];
    const float* Wh       = (const float*)d_in[14];
    const float* bh       = (const float*)d_in[15];
    const float* Wm       = (const float*)d_in[16];
    const float* bW       = (const float*)d_in[17];
    const float* U        = (const float*)d_in[18];
    const float* bU       = (const float*)d_in[19];
    const float* Wo       = (const float*)d_in[20];
    const float* bo       = (const float*)d_in[21];
    const float* Us       = (const float*)d_in[22];
    const float* bs       = (const float*)d_in[23];

    float *gPz, *gPr, *gPh, *gPembU, *gPmolU, *gPmolW, *glogitsc;
    __nv_bfloat16 *gBuH, *gBuL, *gBwH, *gBwL, *gBoH, *gBoL;
    __nv_bfloat16 *gBzhH, *gBzhL, *gBUrH, *gBUrL;
    __nv_bfloat16 *gBz0H, *gBz0L, *gBr0H, *gBr0L, *gBh0H, *gBh0L, *gBU0H, *gBU0L;
    __nv_bfloat16 *gCuH, *gCuL, *gPhH, *gPhL, *gHbH, *gHbL;
    cudaGetSymbolAddress((void**)&gPz, g_Pz);
    cudaGetSymbolAddress((void**)&gPr, g_Pr);
    cudaGetSymbolAddress((void**)&gPh, g_Ph);
    cudaGetSymbolAddress((void**)&gPembU, g_PembU);
    cudaGetSymbolAddress((void**)&gPmolU, g_PmolU);
    cudaGetSymbolAddress((void**)&gPmolW, g_PmolW);
    cudaGetSymbolAddress((void**)&glogitsc, g_logitsc);
    cudaGetSymbolAddress((void**)&gBuH, g_Bu_hi);
    cudaGetSymbolAddress((void**)&gBuL, g_Bu_lo);
    cudaGetSymbolAddress((void**)&gBwH, g_Bw_hi);
    cudaGetSymbolAddress((void**)&gBwL, g_Bw_lo);
    cudaGetSymbolAddress((void**)&gBoH, g_Bo_hi);
    cudaGetSymbolAddress((void**)&gBoL, g_Bo_lo);
    cudaGetSymbolAddress((void**)&gBzhH, g_Bzh_hi);
    cudaGetSymbolAddress((void**)&gBzhL, g_Bzh_lo);
    cudaGetSymbolAddress((void**)&gBUrH, g_BUr_hi);
    cudaGetSymbolAddress((void**)&gBUrL, g_BUr_lo);
    cudaGetSymbolAddress((void**)&gBz0H, g_Bz0_hi);
    cudaGetSymbolAddress((void**)&gBz0L, g_Bz0_lo);
    cudaGetSymbolAddress((void**)&gBr0H, g_Br0_hi);
    cudaGetSymbolAddress((void**)&gBr0L, g_Br0_lo);
    cudaGetSymbolAddress((void**)&gBh0H, g_Bh0_hi);
    cudaGetSymbolAddress((void**)&gBh0L, g_Bh0_lo);
    cudaGetSymbolAddress((void**)&gBU0H, g_BU0_hi);
    cudaGetSymbolAddress((void**)&gBU0L, g_BU0_lo);
    cudaGetSymbolAddress((void**)&gCuH, g_curo_hi);
    cudaGetSymbolAddress((void**)&gCuL, g_curo_lo);
    cudaGetSymbolAddress((void**)&gPhH, g_phid_hi);
    cudaGetSymbolAddress((void**)&gPhL, g_phid_lo);
    cudaGetSymbolAddress((void**)&gHbH, g_hbuf_hi);
    cudaGetSymbolAddress((void**)&gHbL, g_hbuf_lo);

    cudaFuncSetAttribute(tc_gemm_sa,
                         cudaFuncAttributeMaxDynamicSharedMemorySize, TCSM_BYTES);
    cudaFuncSetAttribute(tc_gemm_pre4,
                         cudaFuncAttributeMaxDynamicSharedMemorySize, TCSM_BYTES);
    cudaFuncSetAttribute(scan_kernel,
                         cudaFuncAttributeMaxDynamicSharedMemorySize, SCAN_SMEM);

    prep_kernel<<<47, 256>>>();
    compact_kernel<<<92, 256>>>(dirs);

    // batched weight transposes + bf16 split
    ConvJobs jobs;
    jobs.j[0] = {U + (size_t)Hh * Hh, gBuH, gBuL, 16};
    jobs.j[1] = {Wm, gBwH, gBwL, 16};
    jobs.j[2] = {Wo, gBoH, gBoL, 32};
    jobs.j[3] = {Wz + (size_t)Hh * Hh, gBzhH, gBzhL, 16};
    jobs.j[4] = {Wh + (size_t)Hh * Hh, gBzhH + (size_t)Hh * Hh, gBzhL + (size_t)Hh * Hh, 16};
    jobs.j[5] = {Ur, gBUrH, gBUrL, 16};
    jobs.j[6] = {Wz, gBz0H, gBz0L, 16};
    jobs.j[7] = {Wr, gBr0H, gBr0L, 16};
    jobs.j[8] = {Wh, gBh0H, gBh0L, 16};
    jobs.j[9] = {U, gBU0H, gBU0L, 16};
    convT_all<<<dim3(32, 16, 10), 256>>>(jobs);

    // fused emb precomputes
    tc_gemm_pre4<<<dim3(4, 8, 4), 256, TCSM_BYTES>>>(
        emb,
        gBz0H, gBz0L, bz, gPz,
        gBr0H, gBr0L, br, gPr,
        gBh0H, gBh0L, bh, gPh,
        gBU0H, gBU0L, bU, gPembU);
    sgemm_kernel<<<dim3(Hh / BN, Bq / BM), 256>>>(Bq, Hh, Ll, mol_vec, U + (size_t)2 * Hh * Hh, nullptr, gPmolU);
    sgemm_kernel<<<dim3(Hh / BN, Bq / BM), 256>>>(Bq, Hh, Ll, mol_vec, Wm + (size_t)Hh * Hh, bW, gPmolW);

    // persistent fused GRU scan
    scan_kernel<<<NBLK, 256, SCAN_SMEM>>>(wid, hni);

    // stop head (split-A)
    build_curo<<<MSr, 256>>>(oni, roni);
    tc_gemm_sa<<<dim3(4, MSr / 128), 256, TCSM_BYTES>>>(
        gCuH, gCuL, gBuH, gBuL, nullptr, nullptr, 0, 1, wid, root_wid, Us);
    stop_final_kernel<<<94, 256>>>(bs, dirs);

    // pred head (compacted, split-A)
    phid0_kernel<<<Bq, Hh>>>();
    tc_gemm_sa<<<dim3(4, NCMP / 128), 256, TCSM_BYTES>>>(
        gHbH, gHbL, gBwH, gBwL, nullptr, nullptr, 0, 2, nullptr, nullptr, nullptr);
    tc_gemm_sa<<<dim3(8, MPRED / 128), 256, TCSM_BYTES>>>(
        gPhH, gPhL, gBoH, gBoL, bo, glogitsc, Vv, 0, nullptr, nullptr, nullptr);
    pred_rows_kernel<<<MPRED, 256>>>(root_wid, y_wid);

    finalize_kernel<<<1, 1>>>((float*)d_out);
}